// round 2
// baseline (speedup 1.0000x reference)
#include <cuda_runtime.h>
#include <math.h>

#define H_DIM 4096
#define S_LEN 2048
#define NQ 32
#define NKV 8
#define HD 128
#define I_DIM 14336
#define QKV_N ((NQ + 2 * NKV) * HD) /* 6144 */
#define EPS 1e-5f

// ---------------------------------------------------------------------------
// Scratch (device globals -- no runtime allocation allowed)
// ---------------------------------------------------------------------------
__device__ float g_xnorm[(size_t)S_LEN * H_DIM];        // 32 MB
__device__ float g_qkv[(size_t)S_LEN * QKV_N];          // 48 MB
__device__ float g_attn[(size_t)S_LEN * NQ * HD];       // 32 MB
__device__ float g_resid[(size_t)S_LEN * H_DIM];        // 32 MB
__device__ float g_gu[(size_t)S_LEN * 2 * I_DIM];       // 235 MB
__device__ float g_h[(size_t)S_LEN * I_DIM];            // 117 MB

// ---------------------------------------------------------------------------
// RMSNorm: one block per row, 256 threads, H=4096 -> 16 floats/thread
// ---------------------------------------------------------------------------
__global__ void rmsnorm_kernel(const float* __restrict__ x,
                               const float* __restrict__ w,
                               float* __restrict__ out)
{
    const int row = blockIdx.x;
    const int t = threadIdx.x;
    const float4* xr = (const float4*)(x + (size_t)row * H_DIM);
    const float4* wr = (const float4*)w;

    float4 v[4];
    float ss = 0.f;
#pragma unroll
    for (int i = 0; i < 4; i++) {
        v[i] = xr[t + 256 * i];
        ss += v[i].x * v[i].x + v[i].y * v[i].y + v[i].z * v[i].z + v[i].w * v[i].w;
    }
#pragma unroll
    for (int o = 16; o; o >>= 1) ss += __shfl_xor_sync(0xffffffffu, ss, o);

    __shared__ float wsum[8];
    if ((t & 31) == 0) wsum[t >> 5] = ss;
    __syncthreads();
    float tot = wsum[0] + wsum[1] + wsum[2] + wsum[3] +
                wsum[4] + wsum[5] + wsum[6] + wsum[7];
    const float sc = rsqrtf(tot * (1.f / H_DIM) + EPS);

    float4* outr = (float4*)(out + (size_t)row * H_DIM);
#pragma unroll
    for (int i = 0; i < 4; i++) {
        float4 wv = wr[t + 256 * i];
        float4 r;
        r.x = v[i].x * sc * wv.x;
        r.y = v[i].y * sc * wv.y;
        r.z = v[i].z * sc * wv.z;
        r.w = v[i].w * sc * wv.w;
        outr[t + 256 * i] = r;
    }
}

// ---------------------------------------------------------------------------
// RoPE (in-place on qkv q+k columns). positions == arange(S) by construction.
// ---------------------------------------------------------------------------
__global__ void rope_kernel(float* __restrict__ qkv)
{
    const int idx = blockIdx.x * blockDim.x + threadIdx.x;
    const int total = S_LEN * (NQ + NKV) * 64;
    if (idx >= total) return;
    const int d = idx & 63;
    const int rem = idx >> 6;
    const int head = rem % (NQ + NKV);
    const int s = rem / (NQ + NKV);

    const float inv = powf(10000.f, -(float)d * (1.f / 64.f));
    const float ang = (float)s * inv;
    float sn, c;
    sincosf(ang, &sn, &c);

    float* base = qkv + (size_t)s * QKV_N + head * HD;  // q then k are contiguous
    const float x1 = base[d];
    const float x2 = base[d + 64];
    base[d] = x1 * c - x2 * sn;
    base[d + 64] = x2 * c + x1 * sn;
}

// ---------------------------------------------------------------------------
// SGEMM: C[M,N] = A[M,K] @ B[K,N] (row-major). 128x128x16 tile, 256 threads,
// 8x8 microtile. Optional epilogue: +add, dual write.
// ---------------------------------------------------------------------------
__global__ __launch_bounds__(256)
void sgemm_kernel(const float* __restrict__ A, const float* __restrict__ B,
                  float* __restrict__ C, int M, int N, int K,
                  const float* __restrict__ add, float* __restrict__ C2)
{
    __shared__ float As[16][132];
    __shared__ float Bs[16][132];

    const int tid = threadIdx.x;
    const int tx = tid & 15, ty = tid >> 4;
    const int bx = blockIdx.x, by = blockIdx.y;

    const int arow = tid >> 2;           // 0..63
    const int acol = (tid & 3) << 2;     // 0,4,8,12
    const int brow = tid >> 5;           // 0..7
    const int bcol = (tid & 31) << 2;    // 0..124

    const float* Ab = A + (size_t)(by * 128) * K;
    const float* Bb = B + (size_t)bx * 128;

    float acc[8][8];
#pragma unroll
    for (int i = 0; i < 8; i++)
#pragma unroll
        for (int j = 0; j < 8; j++) acc[i][j] = 0.f;

    for (int k0 = 0; k0 < K; k0 += 16) {
        float4 a0 = *(const float4*)(Ab + (size_t)arow * K + k0 + acol);
        float4 a1 = *(const float4*)(Ab + (size_t)(arow + 64) * K + k0 + acol);
        float4 b0 = *(const float4*)(Bb + (size_t)(k0 + brow) * N + bcol);
        float4 b1 = *(const float4*)(Bb + (size_t)(k0 + brow + 8) * N + bcol);

        As[acol + 0][arow] = a0.x; As[acol + 1][arow] = a0.y;
        As[acol + 2][arow] = a0.z; As[acol + 3][arow] = a0.w;
        As[acol + 0][arow + 64] = a1.x; As[acol + 1][arow + 64] = a1.y;
        As[acol + 2][arow + 64] = a1.z; As[acol + 3][arow + 64] = a1.w;
        *(float4*)&Bs[brow][bcol] = b0;
        *(float4*)&Bs[brow + 8][bcol] = b1;
        __syncthreads();

#pragma unroll
        for (int kk = 0; kk < 16; kk++) {
            float a[8], b[8];
            *(float4*)&a[0] = *(const float4*)&As[kk][ty * 4];
            *(float4*)&a[4] = *(const float4*)&As[kk][ty * 4 + 64];
            *(float4*)&b[0] = *(const float4*)&Bs[kk][tx * 4];
            *(float4*)&b[4] = *(const float4*)&Bs[kk][tx * 4 + 64];
#pragma unroll
            for (int i = 0; i < 8; i++)
#pragma unroll
                for (int j = 0; j < 8; j++)
                    acc[i][j] = fmaf(a[i], b[j], acc[i][j]);
        }
        __syncthreads();
    }

#pragma unroll
    for (int ih = 0; ih < 2; ih++)
#pragma unroll
        for (int i = 0; i < 4; i++) {
            const int m = by * 128 + ih * 64 + ty * 4 + i;
#pragma unroll
            for (int jh = 0; jh < 2; jh++) {
                const int n = bx * 128 + jh * 64 + tx * 4;
                float4 v;
                v.x = acc[ih * 4 + i][jh * 4 + 0];
                v.y = acc[ih * 4 + i][jh * 4 + 1];
                v.z = acc[ih * 4 + i][jh * 4 + 2];
                v.w = acc[ih * 4 + i][jh * 4 + 3];
                const size_t off = (size_t)m * N + n;
                if (add) {
                    float4 r = *(const float4*)(add + off);
                    v.x += r.x; v.y += r.y; v.z += r.z; v.w += r.w;
                }
                *(float4*)(C + off) = v;
                if (C2) *(float4*)(C2 + off) = v;
            }
        }
}

// ---------------------------------------------------------------------------
// Flash attention, fp32, causal. One CTA per (q-head, 64-row block).
// Dynamic smem: Q[64][128] K[64][129] V[64][128] S[64][65] + stats.
// ---------------------------------------------------------------------------
__global__ __launch_bounds__(256)
void attn_kernel(const float* __restrict__ qkv, float* __restrict__ out)
{
    extern __shared__ float sm[];
    float* Qs = sm;                       // 64*128
    float* Ks = Qs + 64 * 128;            // 64*129
    float* Vs = Ks + 64 * 129;            // 64*128
    float* Ss = Vs + 64 * 128;            // 64*65
    float* m_sm = Ss + 64 * 65;           // 64
    float* l_sm = m_sm + 64;              // 64
    float* c_sm = l_sm + 64;              // 64

    const int tid = threadIdx.x;
    const int mb = blockIdx.x;            // 0..31 row block
    const int qh = blockIdx.y;            // 0..31 q head
    const int kh = qh >> 2;               // GQA group of 4
    const float scale = 0.088388347648318447f;  // 1/sqrt(128)

    const int kcol = NQ * HD + kh * HD;
    const int vcol = (NQ + NKV) * HD + kh * HD;

    // Load Q tile
    for (int idx = tid; idx < 64 * 32; idx += 256) {
        const int r = idx >> 5, c4 = (idx & 31) << 2;
        *(float4*)&Qs[r * 128 + c4] =
            *(const float4*)&qkv[(size_t)(mb * 64 + r) * QKV_N + qh * HD + c4];
    }
    if (tid < 64) { m_sm[tid] = -1e30f; l_sm[tid] = 0.f; }
    __syncthreads();

    const int sy = tid >> 4, sx = tid & 15;   // score phase 16x16
    const int prow = tid >> 2, ppart = tid & 3;  // softmax/PV: 64 rows x 4 parts

    float acc[32];
#pragma unroll
    for (int i = 0; i < 32; i++) acc[i] = 0.f;

    for (int nb = 0; nb <= mb; nb++) {
        // Load K (transposed-row padded) and V
        for (int idx = tid; idx < 64 * 32; idx += 256) {
            const int r = idx >> 5, c4 = (idx & 31) << 2;
            const float* src = &qkv[(size_t)(nb * 64 + r) * QKV_N];
            float4 kv = *(const float4*)(src + kcol + c4);
            Ks[r * 129 + c4 + 0] = kv.x; Ks[r * 129 + c4 + 1] = kv.y;
            Ks[r * 129 + c4 + 2] = kv.z; Ks[r * 129 + c4 + 3] = kv.w;
            *(float4*)&Vs[r * 128 + c4] = *(const float4*)(src + vcol + c4);
        }
        __syncthreads();

        // Scores: each thread computes a 4x4 tile of S[64][64]
        float s4[4][4];
#pragma unroll
        for (int i = 0; i < 4; i++)
#pragma unroll
            for (int j = 0; j < 4; j++) s4[i][j] = 0.f;

        for (int kk = 0; kk < 128; kk += 4) {
            float a[4][4];
#pragma unroll
            for (int i = 0; i < 4; i++)
                *(float4*)&a[i][0] = *(const float4*)&Qs[(sy * 4 + i) * 128 + kk];
#pragma unroll
            for (int t = 0; t < 4; t++) {
                float b[4];
#pragma unroll
                for (int j = 0; j < 4; j++) b[j] = Ks[(sx * 4 + j) * 129 + kk + t];
#pragma unroll
                for (int i = 0; i < 4; i++)
#pragma unroll
                    for (int j = 0; j < 4; j++)
                        s4[i][j] = fmaf(a[i][t], b[j], s4[i][j]);
            }
        }
        const bool diag = (nb == mb);
#pragma unroll
        for (int i = 0; i < 4; i++) {
            const int r = sy * 4 + i;
#pragma unroll
            for (int j = 0; j < 4; j++) {
                const int c = sx * 4 + j;
                float v = s4[i][j] * scale;
                if (diag && c > r) v = -1e30f;
                Ss[r * 65 + c] = v;
            }
        }
        __syncthreads();

        // Online softmax: 4 threads per row
        {
            float mloc = -1e30f;
#pragma unroll
            for (int jj = 0; jj < 16; jj++)
                mloc = fmaxf(mloc, Ss[prow * 65 + ppart * 16 + jj]);
            mloc = fmaxf(mloc, __shfl_xor_sync(0xffffffffu, mloc, 1));
            mloc = fmaxf(mloc, __shfl_xor_sync(0xffffffffu, mloc, 2));
            const float mold = m_sm[prow];
            const float mnew = fmaxf(mold, mloc);
            float ssum = 0.f;
#pragma unroll
            for (int jj = 0; jj < 16; jj++) {
                const int c = ppart * 16 + jj;
                const float p = expf(Ss[prow * 65 + c] - mnew);
                Ss[prow * 65 + c] = p;
                ssum += p;
            }
            ssum += __shfl_xor_sync(0xffffffffu, ssum, 1);
            ssum += __shfl_xor_sync(0xffffffffu, ssum, 2);
            if (ppart == 0) {
                const float cf = expf(mold - mnew);
                m_sm[prow] = mnew;
                l_sm[prow] = l_sm[prow] * cf + ssum;
                c_sm[prow] = cf;
            }
        }
        __syncthreads();

        // PV: thread owns dims d = ppart*4 + g*16 + e  (g<8, e<4)
        {
            const float cf = c_sm[prow];
#pragma unroll
            for (int i = 0; i < 32; i++) acc[i] *= cf;
            for (int j = 0; j < 64; j++) {
                const float p = Ss[prow * 65 + j];
#pragma unroll
                for (int g = 0; g < 8; g++) {
                    float4 v = *(const float4*)&Vs[j * 128 + ppart * 4 + g * 16];
                    acc[g * 4 + 0] = fmaf(p, v.x, acc[g * 4 + 0]);
                    acc[g * 4 + 1] = fmaf(p, v.y, acc[g * 4 + 1]);
                    acc[g * 4 + 2] = fmaf(p, v.z, acc[g * 4 + 2]);
                    acc[g * 4 + 3] = fmaf(p, v.w, acc[g * 4 + 3]);
                }
            }
        }
        __syncthreads();
    }

    const float linv = 1.f / l_sm[prow];
    const size_t base = (size_t)(mb * 64 + prow) * (NQ * HD) + qh * HD;
#pragma unroll
    for (int g = 0; g < 8; g++) {
        float4 v;
        v.x = acc[g * 4 + 0] * linv;
        v.y = acc[g * 4 + 1] * linv;
        v.z = acc[g * 4 + 2] * linv;
        v.w = acc[g * 4 + 3] * linv;
        *(float4*)&out[base + ppart * 4 + g * 16] = v;
    }
}

// ---------------------------------------------------------------------------
// SiLU(gate) * up
// ---------------------------------------------------------------------------
__global__ void silu_mul_kernel(const float* __restrict__ gu, float* __restrict__ h)
{
    const size_t idx = (size_t)blockIdx.x * blockDim.x + threadIdx.x;
    const size_t total = (size_t)S_LEN * I_DIM / 4;
    if (idx >= total) return;
    const size_t row = idx / (I_DIM / 4);
    const size_t c4 = (idx % (I_DIM / 4)) * 4;
    const float4 g = *(const float4*)(gu + row * 2 * I_DIM + c4);
    const float4 u = *(const float4*)(gu + row * 2 * I_DIM + I_DIM + c4);
    float4 r;
    r.x = g.x / (1.f + expf(-g.x)) * u.x;
    r.y = g.y / (1.f + expf(-g.y)) * u.y;
    r.z = g.z / (1.f + expf(-g.z)) * u.z;
    r.w = g.w / (1.f + expf(-g.w)) * u.w;
    *(float4*)(h + row * I_DIM + c4) = r;
}

// ---------------------------------------------------------------------------
// Launch
// ---------------------------------------------------------------------------
extern "C" void kernel_launch(void* const* d_in, const int* in_sizes, int n_in,
                              void* d_out, int out_size)
{
    (void)in_sizes; (void)n_in;
    const float* hidden = (const float*)d_in[1];
    const float* w_qkv = (const float*)d_in[2];
    const float* w_o = (const float*)d_in[3];
    const float* w_gu = (const float*)d_in[4];
    const float* w_down = (const float*)d_in[5];
    const float* ln1 = (const float*)d_in[6];
    const float* ln2 = (const float*)d_in[7];

    float* out = (float*)d_out;
    const size_t SH = (size_t)S_LEN * H_DIM;
    float* out_resid = ((size_t)out_size >= 2 * SH) ? (out + SH) : nullptr;

    float *xnorm, *qkv, *attn, *resid, *gu, *hbuf;
    cudaGetSymbolAddress((void**)&xnorm, g_xnorm);
    cudaGetSymbolAddress((void**)&qkv, g_qkv);
    cudaGetSymbolAddress((void**)&attn, g_attn);
    cudaGetSymbolAddress((void**)&resid, g_resid);
    cudaGetSymbolAddress((void**)&gu, g_gu);
    cudaGetSymbolAddress((void**)&hbuf, g_h);

    const int ATT_SMEM = (64 * 128 + 64 * 129 + 64 * 128 + 64 * 65 + 192) * 4;
    cudaFuncSetAttribute(attn_kernel, cudaFuncAttributeMaxDynamicSharedMemorySize,
                         ATT_SMEM);

    // 1. RMSNorm 1
    rmsnorm_kernel<<<S_LEN, 256>>>(hidden, ln1, xnorm);

    // 2. QKV projection: [2048,4096] @ [4096,6144]
    sgemm_kernel<<<dim3(QKV_N / 128, S_LEN / 128), 256>>>(
        xnorm, w_qkv, qkv, S_LEN, QKV_N, H_DIM, nullptr, nullptr);

    // 3. RoPE in place on q,k
    {
        const int total = S_LEN * (NQ + NKV) * 64;
        rope_kernel<<<(total + 255) / 256, 256>>>(qkv);
    }

    // 4. Attention
    attn_kernel<<<dim3(S_LEN / 64, NQ), 256, ATT_SMEM>>>(qkv, attn);

    // 5. O projection + residual add (writes resid scratch and d_out residual)
    sgemm_kernel<<<dim3(H_DIM / 128, S_LEN / 128), 256>>>(
        attn, w_o, resid, S_LEN, H_DIM, NQ * HD, hidden, out_resid);

    // 6. RMSNorm 2
    rmsnorm_kernel<<<S_LEN, 256>>>(resid, ln2, xnorm);

    // 7. gate_up: [2048,4096] @ [4096,28672]
    sgemm_kernel<<<dim3(2 * I_DIM / 128, S_LEN / 128), 256>>>(
        xnorm, w_gu, gu, S_LEN, 2 * I_DIM, H_DIM, nullptr, nullptr);

    // 8. SiLU * up
    {
        const size_t total = (size_t)S_LEN * I_DIM / 4;
        silu_mul_kernel<<<(int)((total + 255) / 256), 256>>>(gu, hbuf);
    }

    // 9. down: [2048,14336] @ [14336,4096] -> out
    sgemm_kernel<<<dim3(H_DIM / 128, S_LEN / 128), 256>>>(
        hbuf, w_down, out, S_LEN, H_DIM, I_DIM, nullptr, nullptr);
}

// round 4
// speedup vs baseline: 1.8531x; 1.8531x over previous
#include <cuda_runtime.h>
#include <cuda_bf16.h>
#include <math.h>
#include <stdint.h>

#define H_DIM 4096
#define S_LEN 2048
#define NQ 32
#define NKV 8
#define HD 128
#define I_DIM 14336
#define QKV_N ((NQ + 2 * NKV) * HD) /* 6144 */
#define EPS 1e-5f

// GEMM tiling (mma.sync path)
#define BM 128
#define BN 128
#define KC 32
#define ROWB 80                       // bytes per smem row (64B data + 16B pad)
#define TILE_B (128 * ROWB)           // 10240 bytes per bf16 tile
#define STAGE (4 * TILE_B)            // Ahi,Alo,Bhi,Blo = 40960
#define SMEM_GEMM (2 * STAGE)         // double buffer = 81920

// ---------------------------------------------------------------------------
// Scratch (device globals)
// ---------------------------------------------------------------------------
__device__ float g_qkv[(size_t)S_LEN * QKV_N];
__device__ float g_attn[(size_t)S_LEN * NQ * HD];
__device__ float g_resid[(size_t)S_LEN * H_DIM];
__device__ float g_gu[(size_t)S_LEN * 2 * I_DIM];

__device__ __nv_bfloat16 g_wqkvT_hi[(size_t)QKV_N * H_DIM];
__device__ __nv_bfloat16 g_wqkvT_lo[(size_t)QKV_N * H_DIM];
__device__ __nv_bfloat16 g_woT_hi[(size_t)H_DIM * (NQ * HD)];
__device__ __nv_bfloat16 g_woT_lo[(size_t)H_DIM * (NQ * HD)];
__device__ __nv_bfloat16 g_wguT_hi[(size_t)(2 * I_DIM) * H_DIM];
__device__ __nv_bfloat16 g_wguT_lo[(size_t)(2 * I_DIM) * H_DIM];
__device__ __nv_bfloat16 g_wdownT_hi[(size_t)H_DIM * I_DIM];
__device__ __nv_bfloat16 g_wdownT_lo[(size_t)H_DIM * I_DIM];

__device__ __nv_bfloat16 g_xb_hi[(size_t)S_LEN * H_DIM];
__device__ __nv_bfloat16 g_xb_lo[(size_t)S_LEN * H_DIM];
__device__ __nv_bfloat16 g_ab_hi[(size_t)S_LEN * NQ * HD];
__device__ __nv_bfloat16 g_ab_lo[(size_t)S_LEN * NQ * HD];
__device__ __nv_bfloat16 g_hb_hi[(size_t)S_LEN * I_DIM];
__device__ __nv_bfloat16 g_hb_lo[(size_t)S_LEN * I_DIM];

// ---------------------------------------------------------------------------
// PTX helpers (portable ISA only: mma.sync / ldmatrix / cp.async)
// ---------------------------------------------------------------------------
__device__ __forceinline__ uint32_t smem_u32(const void* p) {
    uint32_t a;
    asm("{ .reg .u64 t; cvta.to.shared.u64 t, %1; cvt.u32.u64 %0, t; }"
        : "=r"(a) : "l"(p));
    return a;
}
__device__ __forceinline__ void cp16(uint32_t saddr, const void* g) {
    asm volatile("cp.async.cg.shared.global [%0], [%1], 16;"
                 :: "r"(saddr), "l"(g) : "memory");
}
__device__ __forceinline__ void cp_commit() {
    asm volatile("cp.async.commit_group;" ::: "memory");
}
template <int N>
__device__ __forceinline__ void cp_wait() {
    asm volatile("cp.async.wait_group %0;" :: "n"(N) : "memory");
}
__device__ __forceinline__ void ldm4(uint32_t* r, uint32_t addr) {
    asm volatile("ldmatrix.sync.aligned.m8n8.x4.shared.b16 {%0,%1,%2,%3}, [%4];"
                 : "=r"(r[0]), "=r"(r[1]), "=r"(r[2]), "=r"(r[3]) : "r"(addr));
}
__device__ __forceinline__ void mma_bf16(float* d, const uint32_t* a,
                                         const uint32_t* b) {
    asm volatile(
        "mma.sync.aligned.m16n8k16.row.col.f32.bf16.bf16.f32 "
        "{%0,%1,%2,%3}, {%4,%5,%6,%7}, {%8,%9}, {%0,%1,%2,%3};"
        : "+f"(d[0]), "+f"(d[1]), "+f"(d[2]), "+f"(d[3])
        : "r"(a[0]), "r"(a[1]), "r"(a[2]), "r"(a[3]), "r"(b[0]), "r"(b[1]));
}
__device__ __forceinline__ void split1(float x, __nv_bfloat16& h, __nv_bfloat16& l) {
    h = __float2bfloat16(x);
    l = __float2bfloat16(x - __bfloat162float(h));
}
__device__ __forceinline__ void split4(float4 v, uint2& hi, uint2& lo) {
    __nv_bfloat16 h0, h1, h2, h3, l0, l1, l2, l3;
    split1(v.x, h0, l0); split1(v.y, h1, l1);
    split1(v.z, h2, l2); split1(v.w, h3, l3);
    hi.x = ((uint32_t)__bfloat16_as_ushort(h1) << 16) | __bfloat16_as_ushort(h0);
    hi.y = ((uint32_t)__bfloat16_as_ushort(h3) << 16) | __bfloat16_as_ushort(h2);
    lo.x = ((uint32_t)__bfloat16_as_ushort(l1) << 16) | __bfloat16_as_ushort(l0);
    lo.y = ((uint32_t)__bfloat16_as_ushort(l3) << 16) | __bfloat16_as_ushort(l2);
}

// ---------------------------------------------------------------------------
// Weight transpose + hi/lo split: W[K,N] fp32 -> Thi/Tlo[N,K] bf16
// ---------------------------------------------------------------------------
__global__ __launch_bounds__(256)
void wt_transpose_kernel(const float* __restrict__ W,
                         __nv_bfloat16* __restrict__ Thi,
                         __nv_bfloat16* __restrict__ Tlo, int K, int N)
{
    __shared__ float t[32][33];
    const int tx = threadIdx.x & 31, ty = threadIdx.x >> 5;
    const int n = blockIdx.x * 32 + tx;
#pragma unroll
    for (int i = 0; i < 4; i++) {
        const int k = blockIdx.y * 32 + ty + i * 8;
        t[ty + i * 8][tx] = W[(size_t)k * N + n];
    }
    __syncthreads();
    const int k2 = blockIdx.y * 32 + tx;
#pragma unroll
    for (int i = 0; i < 4; i++) {
        const int n2 = blockIdx.x * 32 + ty + i * 8;
        const float v = t[tx][ty + i * 8];
        __nv_bfloat16 h, l;
        split1(v, h, l);
        Thi[(size_t)n2 * K + k2] = h;
        Tlo[(size_t)n2 * K + k2] = l;
    }
}

// ---------------------------------------------------------------------------
// Activation split: fp32 -> hi/lo bf16
// ---------------------------------------------------------------------------
__global__ void act_split_kernel(const float* __restrict__ x,
                                 __nv_bfloat16* __restrict__ hi,
                                 __nv_bfloat16* __restrict__ lo, size_t n4)
{
    const size_t idx = (size_t)blockIdx.x * blockDim.x + threadIdx.x;
    if (idx >= n4) return;
    float4 v = ((const float4*)x)[idx];
    uint2 h, l;
    split4(v, h, l);
    ((uint2*)hi)[idx] = h;
    ((uint2*)lo)[idx] = l;
}

// ---------------------------------------------------------------------------
// RMSNorm + split output
// ---------------------------------------------------------------------------
__global__ __launch_bounds__(256)
void rmsnorm_split_kernel(const float* __restrict__ x, const float* __restrict__ w,
                          __nv_bfloat16* __restrict__ ohi,
                          __nv_bfloat16* __restrict__ olo)
{
    const int row = blockIdx.x;
    const int t = threadIdx.x;
    const float4* xr = (const float4*)(x + (size_t)row * H_DIM);
    const float4* wr = (const float4*)w;

    float4 v[4];
    float ss = 0.f;
#pragma unroll
    for (int i = 0; i < 4; i++) {
        v[i] = xr[t + 256 * i];
        ss += v[i].x * v[i].x + v[i].y * v[i].y + v[i].z * v[i].z + v[i].w * v[i].w;
    }
#pragma unroll
    for (int o = 16; o; o >>= 1) ss += __shfl_xor_sync(0xffffffffu, ss, o);
    __shared__ float wsum[8];
    if ((t & 31) == 0) wsum[t >> 5] = ss;
    __syncthreads();
    float tot = wsum[0] + wsum[1] + wsum[2] + wsum[3] +
                wsum[4] + wsum[5] + wsum[6] + wsum[7];
    const float sc = rsqrtf(tot * (1.f / H_DIM) + EPS);

    uint2* hr = (uint2*)(ohi + (size_t)row * H_DIM);
    uint2* lr = (uint2*)(olo + (size_t)row * H_DIM);
#pragma unroll
    for (int i = 0; i < 4; i++) {
        float4 wv = wr[t + 256 * i];
        float4 r;
        r.x = v[i].x * sc * wv.x;
        r.y = v[i].y * sc * wv.y;
        r.z = v[i].z * sc * wv.z;
        r.w = v[i].w * sc * wv.w;
        uint2 h, l;
        split4(r, h, l);
        hr[t + 256 * i] = h;
        lr[t + 256 * i] = l;
    }
}

// ---------------------------------------------------------------------------
// mma.sync bf16 hi/lo GEMM: C[M,N] = A[M,K] @ B^T  (B stored [N,K] bf16).
// 128x128 tile, KC=32, 8 warps (4m x 2n), double-buffered cp.async.
// blockIdx.x = m-block (fast) so a wave shares the A panel in L2.
// ---------------------------------------------------------------------------
__global__ __launch_bounds__(256, 1)
void gemm_mma_kernel(const __nv_bfloat16* __restrict__ Ahi,
                     const __nv_bfloat16* __restrict__ Alo,
                     const __nv_bfloat16* __restrict__ Bhi,
                     const __nv_bfloat16* __restrict__ Blo,
                     float* __restrict__ C, int M, int N, int K,
                     const float* __restrict__ add, float* __restrict__ C2)
{
    extern __shared__ char smc[];
    const uint32_t sbase = smem_u32(smc);
    const int tid = threadIdx.x;
    const int lane = tid & 31;
    const int wm = (tid >> 5) & 3;       // warp m 0..3 (32 rows each)
    const int wn = tid >> 7;             // warp n 0..1 (64 cols each)
    const int m0 = blockIdx.x * BM;
    const int n0 = blockIdx.y * BN;
    const int NCH = K / KC;

    // cp.async mapping: q in [0,512): r=q>>2, c=q&3 (16B chunks of 64B rows)
    const int q0r = tid >> 2, q0c = tid & 3;
    const int q1r = (tid + 256) >> 2, q1c = tid & 3;

    float acc[2][8][4];
#pragma unroll
    for (int mt = 0; mt < 2; mt++)
#pragma unroll
        for (int nt = 0; nt < 8; nt++)
#pragma unroll
            for (int e = 0; e < 4; e++) acc[mt][nt][e] = 0.f;

    auto issue = [&](int kc, int buf) {
        const uint32_t st = sbase + buf * STAGE;
        const int kb = kc * KC;
        {
            const size_t gA0 = (size_t)(m0 + q0r) * K + kb + q0c * 8;
            const size_t gA1 = (size_t)(m0 + q1r) * K + kb + q1c * 8;
            const size_t gB0 = (size_t)(n0 + q0r) * K + kb + q0c * 8;
            const size_t gB1 = (size_t)(n0 + q1r) * K + kb + q1c * 8;
            const uint32_t s0 = st + q0r * ROWB + q0c * 16;
            const uint32_t s1 = st + q1r * ROWB + q1c * 16;
            cp16(s0, Ahi + gA0);
            cp16(s1, Ahi + gA1);
            cp16(s0 + TILE_B, Alo + gA0);
            cp16(s1 + TILE_B, Alo + gA1);
            cp16(s0 + 2 * TILE_B, Bhi + gB0);
            cp16(s1 + 2 * TILE_B, Bhi + gB1);
            cp16(s0 + 3 * TILE_B, Blo + gB0);
            cp16(s1 + 3 * TILE_B, Blo + gB1);
        }
        cp_commit();
    };

    issue(0, 0);

    for (int kc = 0; kc < NCH; kc++) {
        if (kc + 1 < NCH) {
            issue(kc + 1, (kc + 1) & 1);
            cp_wait<1>();
        } else {
            cp_wait<0>();
        }
        __syncthreads();

        const uint32_t st = sbase + (kc & 1) * STAGE;
        const uint32_t sAh = st;
        const uint32_t sAl = st + TILE_B;
        const uint32_t sBh = st + 2 * TILE_B;
        const uint32_t sBl = st + 3 * TILE_B;

        // A ldmatrix lane addr: row = wm*32 + mt*16 + (lane&15), k = ks + (lane>>4)*8
        const int aRow = wm * 32 + (lane & 15);
        const int aKof = (lane >> 4) * 8;
        // B ldmatrix lane addr: n = wn*64 + p*16 + (sel>>1)*8 + idx, k = ks + (sel&1)*8
        const int bIdx = lane & 7;
        const int bSel = lane >> 3;
        const int bRowBase = wn * 64 + ((bSel >> 1) * 8) + bIdx;
        const int bKof = (bSel & 1) * 8;

#pragma unroll
        for (int ks = 0; ks < KC; ks += 16) {
            uint32_t ah[2][4], al[2][4];
#pragma unroll
            for (int mt = 0; mt < 2; mt++) {
                const uint32_t off = (uint32_t)(aRow + mt * 16) * ROWB +
                                     (uint32_t)(ks + aKof) * 2;
                ldm4(ah[mt], sAh + off);
                ldm4(al[mt], sAl + off);
            }
            uint32_t bh[8][2], bl[8][2];
#pragma unroll
            for (int p = 0; p < 4; p++) {
                const uint32_t off = (uint32_t)(bRowBase + p * 16) * ROWB +
                                     (uint32_t)(ks + bKof) * 2;
                uint32_t r4[4];
                ldm4(r4, sBh + off);
                bh[2 * p][0] = r4[0]; bh[2 * p][1] = r4[1];
                bh[2 * p + 1][0] = r4[2]; bh[2 * p + 1][1] = r4[3];
                ldm4(r4, sBl + off);
                bl[2 * p][0] = r4[0]; bl[2 * p][1] = r4[1];
                bl[2 * p + 1][0] = r4[2]; bl[2 * p + 1][1] = r4[3];
            }
#pragma unroll
            for (int mt = 0; mt < 2; mt++)
#pragma unroll
                for (int nt = 0; nt < 8; nt++) {
                    mma_bf16(acc[mt][nt], ah[mt], bh[nt]);
                    mma_bf16(acc[mt][nt], ah[mt], bl[nt]);
                    mma_bf16(acc[mt][nt], al[mt], bh[nt]);
                }
        }
        __syncthreads();
    }

    // Epilogue: direct global stores (float2 per fragment half)
    const int erow = m0 + wm * 32 + (lane >> 2);
    const int ecol = n0 + wn * 64 + (lane & 3) * 2;
#pragma unroll
    for (int mt = 0; mt < 2; mt++) {
#pragma unroll
        for (int nt = 0; nt < 8; nt++) {
            const int r0 = erow + mt * 16;
            const int c = ecol + nt * 8;
            const size_t off0 = (size_t)r0 * N + c;
            const size_t off1 = (size_t)(r0 + 8) * N + c;
            float2 v0 = make_float2(acc[mt][nt][0], acc[mt][nt][1]);
            float2 v1 = make_float2(acc[mt][nt][2], acc[mt][nt][3]);
            if (add) {
                float2 a0 = *(const float2*)(add + off0);
                float2 a1 = *(const float2*)(add + off1);
                v0.x += a0.x; v0.y += a0.y;
                v1.x += a1.x; v1.y += a1.y;
            }
            *(float2*)(C + off0) = v0;
            *(float2*)(C + off1) = v1;
            if (C2) {
                *(float2*)(C2 + off0) = v0;
                *(float2*)(C2 + off1) = v1;
            }
        }
    }
}

// ---------------------------------------------------------------------------
// RoPE (in-place on qkv q+k columns)
// ---------------------------------------------------------------------------
__global__ void rope_kernel(float* __restrict__ qkv)
{
    const int idx = blockIdx.x * blockDim.x + threadIdx.x;
    const int total = S_LEN * (NQ + NKV) * 64;
    if (idx >= total) return;
    const int d = idx & 63;
    const int rem = idx >> 6;
    const int head = rem % (NQ + NKV);
    const int s = rem / (NQ + NKV);

    const float inv = powf(10000.f, -(float)d * (1.f / 64.f));
    const float ang = (float)s * inv;
    float sn, c;
    sincosf(ang, &sn, &c);

    float* base = qkv + (size_t)s * QKV_N + head * HD;
    const float x1 = base[d];
    const float x2 = base[d + 64];
    base[d] = x1 * c - x2 * sn;
    base[d + 64] = x2 * c + x1 * sn;
}

// ---------------------------------------------------------------------------
// Flash attention, fp32, causal (unchanged)
// ---------------------------------------------------------------------------
__global__ __launch_bounds__(256)
void attn_kernel(const float* __restrict__ qkv, float* __restrict__ out)
{
    extern __shared__ float sm[];
    float* Qs = sm;
    float* Ks = Qs + 64 * 128;
    float* Vs = Ks + 64 * 129;
    float* Ss = Vs + 64 * 128;
    float* m_sm = Ss + 64 * 65;
    float* l_sm = m_sm + 64;
    float* c_sm = l_sm + 64;

    const int tid = threadIdx.x;
    const int mb = blockIdx.x;
    const int qh = blockIdx.y;
    const int kh = qh >> 2;
    const float scale = 0.088388347648318447f;

    const int kcol = NQ * HD + kh * HD;
    const int vcol = (NQ + NKV) * HD + kh * HD;

    for (int idx = tid; idx < 64 * 32; idx += 256) {
        const int r = idx >> 5, c4 = (idx & 31) << 2;
        *(float4*)&Qs[r * 128 + c4] =
            *(const float4*)&qkv[(size_t)(mb * 64 + r) * QKV_N + qh * HD + c4];
    }
    if (tid < 64) { m_sm[tid] = -1e30f; l_sm[tid] = 0.f; }
    __syncthreads();

    const int sy = tid >> 4, sx = tid & 15;
    const int prow = tid >> 2, ppart = tid & 3;

    float acc[32];
#pragma unroll
    for (int i = 0; i < 32; i++) acc[i] = 0.f;

    for (int nb = 0; nb <= mb; nb++) {
        for (int idx = tid; idx < 64 * 32; idx += 256) {
            const int r = idx >> 5, c4 = (idx & 31) << 2;
            const float* src = &qkv[(size_t)(nb * 64 + r) * QKV_N];
            float4 kv = *(const float4*)(src + kcol + c4);
            Ks[r * 129 + c4 + 0] = kv.x; Ks[r * 129 + c4 + 1] = kv.y;
            Ks[r * 129 + c4 + 2] = kv.z; Ks[r * 129 + c4 + 3] = kv.w;
            *(float4*)&Vs[r * 128 + c4] = *(const float4*)(src + vcol + c4);
        }
        __syncthreads();

        float s4[4][4];
#pragma unroll
        for (int i = 0; i < 4; i++)
#pragma unroll
            for (int j = 0; j < 4; j++) s4[i][j] = 0.f;

        for (int kk = 0; kk < 128; kk += 4) {
            float a[4][4];
#pragma unroll
            for (int i = 0; i < 4; i++)
                *(float4*)&a[i][0] = *(const float4*)&Qs[(sy * 4 + i) * 128 + kk];
#pragma unroll
            for (int t = 0; t < 4; t++) {
                float bb[4];
#pragma unroll
                for (int j = 0; j < 4; j++) bb[j] = Ks[(sx * 4 + j) * 129 + kk + t];
#pragma unroll
                for (int i = 0; i < 4; i++)
#pragma unroll
                    for (int j = 0; j < 4; j++)
                        s4[i][j] = fmaf(a[i][t], bb[j], s4[i][j]);
            }
        }
        const bool diag = (nb == mb);
#pragma unroll
        for (int i = 0; i < 4; i++) {
            const int r = sy * 4 + i;
#pragma unroll
            for (int j = 0; j < 4; j++) {
                const int c = sx * 4 + j;
                float v = s4[i][j] * scale;
                if (diag && c > r) v = -1e30f;
                Ss[r * 65 + c] = v;
            }
        }
        __syncthreads();

        {
            float mloc = -1e30f;
#pragma unroll
            for (int jj = 0; jj < 16; jj++)
                mloc = fmaxf(mloc, Ss[prow * 65 + ppart * 16 + jj]);
            mloc = fmaxf(mloc, __shfl_xor_sync(0xffffffffu, mloc, 1));
            mloc = fmaxf(mloc, __shfl_xor_sync(0xffffffffu, mloc, 2));
            const float mold = m_sm[prow];
            const float mnew = fmaxf(mold, mloc);
            float ssum = 0.f;
#pragma unroll
            for (int jj = 0; jj < 16; jj++) {
                const int c = ppart * 16 + jj;
                const float p = expf(Ss[prow * 65 + c] - mnew);
                Ss[prow * 65 + c] = p;
                ssum += p;
            }
            ssum += __shfl_xor_sync(0xffffffffu, ssum, 1);
            ssum += __shfl_xor_sync(0xffffffffu, ssum, 2);
            if (ppart == 0) {
                const float cf = expf(mold - mnew);
                m_sm[prow] = mnew;
                l_sm[prow] = l_sm[prow] * cf + ssum;
                c_sm[prow] = cf;
            }
        }
        __syncthreads();

        {
            const float cf = c_sm[prow];
#pragma unroll
            for (int i = 0; i < 32; i++) acc[i] *= cf;
            for (int j = 0; j < 64; j++) {
                const float p = Ss[prow * 65 + j];
#pragma unroll
                for (int g = 0; g < 8; g++) {
                    float4 v = *(const float4*)&Vs[j * 128 + ppart * 4 + g * 16];
                    acc[g * 4 + 0] = fmaf(p, v.x, acc[g * 4 + 0]);
                    acc[g * 4 + 1] = fmaf(p, v.y, acc[g * 4 + 1]);
                    acc[g * 4 + 2] = fmaf(p, v.z, acc[g * 4 + 2]);
                    acc[g * 4 + 3] = fmaf(p, v.w, acc[g * 4 + 3]);
                }
            }
        }
        __syncthreads();
    }

    const float linv = 1.f / l_sm[prow];
    const size_t base = (size_t)(mb * 64 + prow) * (NQ * HD) + qh * HD;
#pragma unroll
    for (int g = 0; g < 8; g++) {
        float4 v;
        v.x = acc[g * 4 + 0] * linv;
        v.y = acc[g * 4 + 1] * linv;
        v.z = acc[g * 4 + 2] * linv;
        v.w = acc[g * 4 + 3] * linv;
        *(float4*)&out[base + ppart * 4 + g * 16] = v;
    }
}

// ---------------------------------------------------------------------------
// SiLU(gate)*up -> hi/lo bf16
// ---------------------------------------------------------------------------
__global__ void silu_mul_split_kernel(const float* __restrict__ gu,
                                      __nv_bfloat16* __restrict__ hhi,
                                      __nv_bfloat16* __restrict__ hlo)
{
    const size_t idx = (size_t)blockIdx.x * blockDim.x + threadIdx.x;
    const size_t total = (size_t)S_LEN * I_DIM / 4;
    if (idx >= total) return;
    const size_t row = idx / (I_DIM / 4);
    const size_t c4 = (idx % (I_DIM / 4)) * 4;
    const float4 g = *(const float4*)(gu + row * 2 * I_DIM + c4);
    const float4 u = *(const float4*)(gu + row * 2 * I_DIM + I_DIM + c4);
    float4 r;
    r.x = g.x / (1.f + expf(-g.x)) * u.x;
    r.y = g.y / (1.f + expf(-g.y)) * u.y;
    r.z = g.z / (1.f + expf(-g.z)) * u.z;
    r.w = g.w / (1.f + expf(-g.w)) * u.w;
    uint2 h, l;
    split4(r, h, l);
    ((uint2*)(hhi + row * I_DIM))[c4 / 4] = h;
    ((uint2*)(hlo + row * I_DIM))[c4 / 4] = l;
}

// ---------------------------------------------------------------------------
// Launch
// ---------------------------------------------------------------------------
extern "C" void kernel_launch(void* const* d_in, const int* in_sizes, int n_in,
                              void* d_out, int out_size)
{
    (void)in_sizes; (void)n_in;
    const float* hidden = (const float*)d_in[1];
    const float* w_qkv = (const float*)d_in[2];
    const float* w_o = (const float*)d_in[3];
    const float* w_gu = (const float*)d_in[4];
    const float* w_down = (const float*)d_in[5];
    const float* ln1 = (const float*)d_in[6];
    const float* ln2 = (const float*)d_in[7];

    float* out = (float*)d_out;
    const size_t SH = (size_t)S_LEN * H_DIM;
    float* out_resid = ((size_t)out_size >= 2 * SH) ? (out + SH) : nullptr;

    float *qkv, *attn, *resid, *gu;
    cudaGetSymbolAddress((void**)&qkv, g_qkv);
    cudaGetSymbolAddress((void**)&attn, g_attn);
    cudaGetSymbolAddress((void**)&resid, g_resid);
    cudaGetSymbolAddress((void**)&gu, g_gu);
    __nv_bfloat16 *wqkvh, *wqkvl, *woh, *wol, *wguh, *wgul, *wdh, *wdl;
    __nv_bfloat16 *xbh, *xbl, *abh, *abl, *hbh, *hbl;
    cudaGetSymbolAddress((void**)&wqkvh, g_wqkvT_hi);
    cudaGetSymbolAddress((void**)&wqkvl, g_wqkvT_lo);
    cudaGetSymbolAddress((void**)&woh, g_woT_hi);
    cudaGetSymbolAddress((void**)&wol, g_woT_lo);
    cudaGetSymbolAddress((void**)&wguh, g_wguT_hi);
    cudaGetSymbolAddress((void**)&wgul, g_wguT_lo);
    cudaGetSymbolAddress((void**)&wdh, g_wdownT_hi);
    cudaGetSymbolAddress((void**)&wdl, g_wdownT_lo);
    cudaGetSymbolAddress((void**)&xbh, g_xb_hi);
    cudaGetSymbolAddress((void**)&xbl, g_xb_lo);
    cudaGetSymbolAddress((void**)&abh, g_ab_hi);
    cudaGetSymbolAddress((void**)&abl, g_ab_lo);
    cudaGetSymbolAddress((void**)&hbh, g_hb_hi);
    cudaGetSymbolAddress((void**)&hbl, g_hb_lo);

    const int ATT_SMEM = (64 * 128 + 64 * 129 + 64 * 128 + 64 * 65 + 192) * 4;
    cudaFuncSetAttribute(attn_kernel, cudaFuncAttributeMaxDynamicSharedMemorySize,
                         ATT_SMEM);
    cudaFuncSetAttribute(gemm_mma_kernel,
                         cudaFuncAttributeMaxDynamicSharedMemorySize, SMEM_GEMM);

    // 0. Weight transpose + split
    wt_transpose_kernel<<<dim3(QKV_N / 32, H_DIM / 32), 256>>>(w_qkv, wqkvh, wqkvl, H_DIM, QKV_N);
    wt_transpose_kernel<<<dim3(H_DIM / 32, (NQ * HD) / 32), 256>>>(w_o, woh, wol, NQ * HD, H_DIM);
    wt_transpose_kernel<<<dim3((2 * I_DIM) / 32, H_DIM / 32), 256>>>(w_gu, wguh, wgul, H_DIM, 2 * I_DIM);
    wt_transpose_kernel<<<dim3(H_DIM / 32, I_DIM / 32), 256>>>(w_down, wdh, wdl, I_DIM, H_DIM);

    // 1. RMSNorm 1 -> hi/lo
    rmsnorm_split_kernel<<<S_LEN, 256>>>(hidden, ln1, xbh, xbl);

    // 2. QKV projection (grid: m-fast)
    gemm_mma_kernel<<<dim3(S_LEN / BM, QKV_N / BN), 256, SMEM_GEMM>>>(
        xbh, xbl, wqkvh, wqkvl, qkv, S_LEN, QKV_N, H_DIM, nullptr, nullptr);

    // 3. RoPE
    {
        const int total = S_LEN * (NQ + NKV) * 64;
        rope_kernel<<<(total + 255) / 256, 256>>>(qkv);
    }

    // 4. Attention
    attn_kernel<<<dim3(S_LEN / 64, NQ), 256, ATT_SMEM>>>(qkv, attn);

    // 5. attn -> hi/lo, then O projection + residual
    {
        const size_t n4 = (size_t)S_LEN * NQ * HD / 4;
        act_split_kernel<<<(int)((n4 + 255) / 256), 256>>>(attn, abh, abl, n4);
    }
    gemm_mma_kernel<<<dim3(S_LEN / BM, H_DIM / BN), 256, SMEM_GEMM>>>(
        abh, abl, woh, wol, resid, S_LEN, H_DIM, NQ * HD, hidden, out_resid);

    // 6. RMSNorm 2 -> hi/lo
    rmsnorm_split_kernel<<<S_LEN, 256>>>(resid, ln2, xbh, xbl);

    // 7. gate_up
    gemm_mma_kernel<<<dim3(S_LEN / BM, (2 * I_DIM) / BN), 256, SMEM_GEMM>>>(
        xbh, xbl, wguh, wgul, gu, S_LEN, 2 * I_DIM, H_DIM, nullptr, nullptr);

    // 8. SiLU * up -> hi/lo
    {
        const size_t total = (size_t)S_LEN * I_DIM / 4;
        silu_mul_split_kernel<<<(int)((total + 255) / 256), 256>>>(gu, hbh, hbl);
    }

    // 9. down -> out
    gemm_mma_kernel<<<dim3(S_LEN / BM, H_DIM / BN), 256, SMEM_GEMM>>>(
        hbh, hbl, wdh, wdl, out, S_LEN, H_DIM, I_DIM, nullptr, nullptr);
}

// round 5
// speedup vs baseline: 2.3752x; 1.2817x over previous
#include <cuda_runtime.h>
#include <cuda_fp16.h>
#include <math.h>
#include <stdint.h>

#define H_DIM 4096
#define S_LEN 2048
#define NQ 32
#define NKV 8
#define HD 128
#define I_DIM 14336
#define QKV_N ((NQ + 2 * NKV) * HD) /* 6144 */
#define EPS 1e-5f

// GEMM tiling (mma.sync path)
#define BM 128
#define BN 128
#define KC 32
#define ROWB 80                       // bytes per smem row (64B data + 16B pad)
#define TILE_B (128 * ROWB)           // 10240 bytes per fp16 tile

// ---------------------------------------------------------------------------
// Scratch (device globals)
// ---------------------------------------------------------------------------
__device__ float g_qkv[(size_t)S_LEN * QKV_N];
__device__ float g_attn[(size_t)S_LEN * NQ * HD];
__device__ float g_resid[(size_t)S_LEN * H_DIM];
__device__ float g_gu[(size_t)S_LEN * 2 * I_DIM];

__device__ __half g_wqkvT_hi[(size_t)QKV_N * H_DIM];
__device__ __half g_wqkvT_lo[(size_t)QKV_N * H_DIM];
__device__ __half g_woT_hi[(size_t)H_DIM * (NQ * HD)];
__device__ __half g_wguT_hi[(size_t)(2 * I_DIM) * H_DIM];
__device__ __half g_wdownT_hi[(size_t)H_DIM * I_DIM];

__device__ __half g_xb_hi[(size_t)S_LEN * H_DIM];
__device__ __half g_xb_lo[(size_t)S_LEN * H_DIM];
__device__ __half g_ab_hi[(size_t)S_LEN * NQ * HD];
__device__ __half g_ab_lo[(size_t)S_LEN * NQ * HD];
__device__ __half g_hb_hi[(size_t)S_LEN * I_DIM];
__device__ __half g_hb_lo[(size_t)S_LEN * I_DIM];

// ---------------------------------------------------------------------------
// PTX helpers (portable ISA: mma.sync / ldmatrix / cp.async)
// ---------------------------------------------------------------------------
__device__ __forceinline__ uint32_t smem_u32(const void* p) {
    uint32_t a;
    asm("{ .reg .u64 t; cvta.to.shared.u64 t, %1; cvt.u32.u64 %0, t; }"
        : "=r"(a) : "l"(p));
    return a;
}
__device__ __forceinline__ void cp16(uint32_t saddr, const void* g) {
    asm volatile("cp.async.cg.shared.global [%0], [%1], 16;"
                 :: "r"(saddr), "l"(g) : "memory");
}
__device__ __forceinline__ void cp_commit() {
    asm volatile("cp.async.commit_group;" ::: "memory");
}
template <int N>
__device__ __forceinline__ void cp_wait() {
    asm volatile("cp.async.wait_group %0;" :: "n"(N) : "memory");
}
__device__ __forceinline__ void ldm4(uint32_t* r, uint32_t addr) {
    asm volatile("ldmatrix.sync.aligned.m8n8.x4.shared.b16 {%0,%1,%2,%3}, [%4];"
                 : "=r"(r[0]), "=r"(r[1]), "=r"(r[2]), "=r"(r[3]) : "r"(addr));
}
__device__ __forceinline__ void mma_f16(float* d, const uint32_t* a,
                                        const uint32_t* b) {
    asm volatile(
        "mma.sync.aligned.m16n8k16.row.col.f32.f16.f16.f32 "
        "{%0,%1,%2,%3}, {%4,%5,%6,%7}, {%8,%9}, {%0,%1,%2,%3};"
        : "+f"(d[0]), "+f"(d[1]), "+f"(d[2]), "+f"(d[3])
        : "r"(a[0]), "r"(a[1]), "r"(a[2]), "r"(a[3]), "r"(b[0]), "r"(b[1]));
}
__device__ __forceinline__ void split1(float x, __half& h, __half& l) {
    h = __float2half_rn(x);
    l = __float2half_rn(x - __half2float(h));
}
__device__ __forceinline__ void split4(float4 v, uint2& hi, uint2& lo) {
    __half h0, h1, h2, h3, l0, l1, l2, l3;
    split1(v.x, h0, l0); split1(v.y, h1, l1);
    split1(v.z, h2, l2); split1(v.w, h3, l3);
    hi.x = ((uint32_t)__half_as_ushort(h1) << 16) | __half_as_ushort(h0);
    hi.y = ((uint32_t)__half_as_ushort(h3) << 16) | __half_as_ushort(h2);
    lo.x = ((uint32_t)__half_as_ushort(l1) << 16) | __half_as_ushort(l0);
    lo.y = ((uint32_t)__half_as_ushort(l3) << 16) | __half_as_ushort(l2);
}

// ---------------------------------------------------------------------------
// Weight transpose + split: W[K,N] fp32 -> Thi (and optional Tlo) [N,K] fp16
// ---------------------------------------------------------------------------
__global__ __launch_bounds__(256)
void wt_transpose_kernel(const float* __restrict__ W,
                         __half* __restrict__ Thi,
                         __half* __restrict__ Tlo, int K, int N)
{
    __shared__ float t[32][33];
    const int tx = threadIdx.x & 31, ty = threadIdx.x >> 5;
    const int n = blockIdx.x * 32 + tx;
#pragma unroll
    for (int i = 0; i < 4; i++) {
        const int k = blockIdx.y * 32 + ty + i * 8;
        t[ty + i * 8][tx] = W[(size_t)k * N + n];
    }
    __syncthreads();
    const int k2 = blockIdx.y * 32 + tx;
#pragma unroll
    for (int i = 0; i < 4; i++) {
        const int n2 = blockIdx.x * 32 + ty + i * 8;
        const float v = t[tx][ty + i * 8];
        __half h, l;
        split1(v, h, l);
        Thi[(size_t)n2 * K + k2] = h;
        if (Tlo) Tlo[(size_t)n2 * K + k2] = l;
    }
}

// ---------------------------------------------------------------------------
// Activation split: fp32 -> hi/lo fp16
// ---------------------------------------------------------------------------
__global__ void act_split_kernel(const float* __restrict__ x,
                                 __half* __restrict__ hi,
                                 __half* __restrict__ lo, size_t n4)
{
    const size_t idx = (size_t)blockIdx.x * blockDim.x + threadIdx.x;
    if (idx >= n4) return;
    float4 v = ((const float4*)x)[idx];
    uint2 h, l;
    split4(v, h, l);
    ((uint2*)hi)[idx] = h;
    ((uint2*)lo)[idx] = l;
}

// ---------------------------------------------------------------------------
// RMSNorm + split output
// ---------------------------------------------------------------------------
__global__ __launch_bounds__(256)
void rmsnorm_split_kernel(const float* __restrict__ x, const float* __restrict__ w,
                          __half* __restrict__ ohi, __half* __restrict__ olo)
{
    const int row = blockIdx.x;
    const int t = threadIdx.x;
    const float4* xr = (const float4*)(x + (size_t)row * H_DIM);
    const float4* wr = (const float4*)w;

    float4 v[4];
    float ss = 0.f;
#pragma unroll
    for (int i = 0; i < 4; i++) {
        v[i] = xr[t + 256 * i];
        ss += v[i].x * v[i].x + v[i].y * v[i].y + v[i].z * v[i].z + v[i].w * v[i].w;
    }
#pragma unroll
    for (int o = 16; o; o >>= 1) ss += __shfl_xor_sync(0xffffffffu, ss, o);
    __shared__ float wsum[8];
    if ((t & 31) == 0) wsum[t >> 5] = ss;
    __syncthreads();
    float tot = wsum[0] + wsum[1] + wsum[2] + wsum[3] +
                wsum[4] + wsum[5] + wsum[6] + wsum[7];
    const float sc = rsqrtf(tot * (1.f / H_DIM) + EPS);

    uint2* hr = (uint2*)(ohi + (size_t)row * H_DIM);
    uint2* lr = (uint2*)(olo + (size_t)row * H_DIM);
#pragma unroll
    for (int i = 0; i < 4; i++) {
        float4 wv = wr[t + 256 * i];
        float4 r;
        r.x = v[i].x * sc * wv.x;
        r.y = v[i].y * sc * wv.y;
        r.z = v[i].z * sc * wv.z;
        r.w = v[i].w * sc * wv.w;
        uint2 h, l;
        split4(r, h, l);
        hr[t + 256 * i] = h;
        lr[t + 256 * i] = l;
    }
}

// ---------------------------------------------------------------------------
// mma.sync fp16 hi/lo GEMM: C[M,N] = A[M,K] @ B^T  (B stored [N,K] fp16).
// NPROD=3: Ah*Bh + Ah*Bl + Al*Bh (B has lo plane). NPROD=2: Ah*Bh + Al*Bh.
// 128x128 tile, KC=32, 8 warps (4m x 2n), double-buffered cp.async.
// ---------------------------------------------------------------------------
template <int NPROD>
__global__ __launch_bounds__(256, 1)
void gemm_mma_kernel(const __half* __restrict__ Ahi,
                     const __half* __restrict__ Alo,
                     const __half* __restrict__ Bhi,
                     const __half* __restrict__ Blo,
                     float* __restrict__ C, int M, int N, int K,
                     const float* __restrict__ add, float* __restrict__ C2)
{
    constexpr int NTILES = (NPROD == 3) ? 4 : 3;
    constexpr uint32_t STG = NTILES * TILE_B;
    extern __shared__ char smc[];
    const uint32_t sbase = smem_u32(smc);
    const int tid = threadIdx.x;
    const int lane = tid & 31;
    const int wm = (tid >> 5) & 3;
    const int wn = tid >> 7;
    const int m0 = blockIdx.x * BM;
    const int n0 = blockIdx.y * BN;
    const int NCH = K / KC;

    const int q0r = tid >> 2, q0c = tid & 3;
    const int q1r = (tid + 256) >> 2, q1c = tid & 3;

    float acc[2][8][4];
#pragma unroll
    for (int mt = 0; mt < 2; mt++)
#pragma unroll
        for (int nt = 0; nt < 8; nt++)
#pragma unroll
            for (int e = 0; e < 4; e++) acc[mt][nt][e] = 0.f;

    auto issue = [&](int kc, int buf) {
        const uint32_t st = sbase + buf * STG;
        const int kb = kc * KC;
        const size_t gA0 = (size_t)(m0 + q0r) * K + kb + q0c * 8;
        const size_t gA1 = (size_t)(m0 + q1r) * K + kb + q1c * 8;
        const size_t gB0 = (size_t)(n0 + q0r) * K + kb + q0c * 8;
        const size_t gB1 = (size_t)(n0 + q1r) * K + kb + q1c * 8;
        const uint32_t s0 = st + q0r * ROWB + q0c * 16;
        const uint32_t s1 = st + q1r * ROWB + q1c * 16;
        cp16(s0, Ahi + gA0);
        cp16(s1, Ahi + gA1);
        cp16(s0 + TILE_B, Alo + gA0);
        cp16(s1 + TILE_B, Alo + gA1);
        cp16(s0 + 2 * TILE_B, Bhi + gB0);
        cp16(s1 + 2 * TILE_B, Bhi + gB1);
        if (NPROD == 3) {
            cp16(s0 + 3 * TILE_B, Blo + gB0);
            cp16(s1 + 3 * TILE_B, Blo + gB1);
        }
        cp_commit();
    };

    issue(0, 0);

    for (int kc = 0; kc < NCH; kc++) {
        if (kc + 1 < NCH) {
            issue(kc + 1, (kc + 1) & 1);
            cp_wait<1>();
        } else {
            cp_wait<0>();
        }
        __syncthreads();

        const uint32_t st = sbase + (kc & 1) * STG;
        const uint32_t sAh = st;
        const uint32_t sAl = st + TILE_B;
        const uint32_t sBh = st + 2 * TILE_B;
        const uint32_t sBl = st + 3 * TILE_B;

        const int aRow = wm * 32 + (lane & 15);
        const int aKof = (lane >> 4) * 8;
        const int bIdx = lane & 7;
        const int bSel = lane >> 3;
        const int bRowBase = wn * 64 + ((bSel >> 1) * 8) + bIdx;
        const int bKof = (bSel & 1) * 8;

#pragma unroll
        for (int ks = 0; ks < KC; ks += 16) {
            uint32_t ah[2][4], al[2][4];
#pragma unroll
            for (int mt = 0; mt < 2; mt++) {
                const uint32_t off = (uint32_t)(aRow + mt * 16) * ROWB +
                                     (uint32_t)(ks + aKof) * 2;
                ldm4(ah[mt], sAh + off);
                ldm4(al[mt], sAl + off);
            }
            uint32_t bh[8][2], bl[8][2];
#pragma unroll
            for (int p = 0; p < 4; p++) {
                const uint32_t off = (uint32_t)(bRowBase + p * 16) * ROWB +
                                     (uint32_t)(ks + bKof) * 2;
                uint32_t r4[4];
                ldm4(r4, sBh + off);
                bh[2 * p][0] = r4[0]; bh[2 * p][1] = r4[1];
                bh[2 * p + 1][0] = r4[2]; bh[2 * p + 1][1] = r4[3];
                if (NPROD == 3) {
                    ldm4(r4, sBl + off);
                    bl[2 * p][0] = r4[0]; bl[2 * p][1] = r4[1];
                    bl[2 * p + 1][0] = r4[2]; bl[2 * p + 1][1] = r4[3];
                }
            }
#pragma unroll
            for (int mt = 0; mt < 2; mt++)
#pragma unroll
                for (int nt = 0; nt < 8; nt++) {
                    mma_f16(acc[mt][nt], ah[mt], bh[nt]);
                    mma_f16(acc[mt][nt], al[mt], bh[nt]);
                    if (NPROD == 3) mma_f16(acc[mt][nt], ah[mt], bl[nt]);
                }
        }
        __syncthreads();
    }

    const int erow = m0 + wm * 32 + (lane >> 2);
    const int ecol = n0 + wn * 64 + (lane & 3) * 2;
#pragma unroll
    for (int mt = 0; mt < 2; mt++) {
#pragma unroll
        for (int nt = 0; nt < 8; nt++) {
            const int r0 = erow + mt * 16;
            const int c = ecol + nt * 8;
            const size_t off0 = (size_t)r0 * N + c;
            const size_t off1 = (size_t)(r0 + 8) * N + c;
            float2 v0 = make_float2(acc[mt][nt][0], acc[mt][nt][1]);
            float2 v1 = make_float2(acc[mt][nt][2], acc[mt][nt][3]);
            if (add) {
                float2 a0 = *(const float2*)(add + off0);
                float2 a1 = *(const float2*)(add + off1);
                v0.x += a0.x; v0.y += a0.y;
                v1.x += a1.x; v1.y += a1.y;
            }
            *(float2*)(C + off0) = v0;
            *(float2*)(C + off1) = v1;
            if (C2) {
                *(float2*)(C2 + off0) = v0;
                *(float2*)(C2 + off1) = v1;
            }
        }
    }
}

// ---------------------------------------------------------------------------
// RoPE (in-place on qkv q+k columns)
// ---------------------------------------------------------------------------
__global__ void rope_kernel(float* __restrict__ qkv)
{
    const int idx = blockIdx.x * blockDim.x + threadIdx.x;
    const int total = S_LEN * (NQ + NKV) * 64;
    if (idx >= total) return;
    const int d = idx & 63;
    const int rem = idx >> 6;
    const int head = rem % (NQ + NKV);
    const int s = rem / (NQ + NKV);

    // 10000^(-d/64) = exp2(-d * log2(10000)/64)
    const float inv = exp2f((float)d * (-13.287712379549449f / 64.f));
    const float ang = (float)s * inv;
    float sn, c;
    sincosf(ang, &sn, &c);

    float* base = qkv + (size_t)s * QKV_N + head * HD;
    const float x1 = base[d];
    const float x2 = base[d + 64];
    base[d] = x1 * c - x2 * sn;
    base[d + 64] = x2 * c + x1 * sn;
}

// ---------------------------------------------------------------------------
// Flash attention, fp32, causal (expf -> __expf)
// ---------------------------------------------------------------------------
__global__ __launch_bounds__(256)
void attn_kernel(const float* __restrict__ qkv, float* __restrict__ out)
{
    extern __shared__ float sm[];
    float* Qs = sm;
    float* Ks = Qs + 64 * 128;
    float* Vs = Ks + 64 * 129;
    float* Ss = Vs + 64 * 128;
    float* m_sm = Ss + 64 * 65;
    float* l_sm = m_sm + 64;
    float* c_sm = l_sm + 64;

    const int tid = threadIdx.x;
    const int mb = blockIdx.x;
    const int qh = blockIdx.y;
    const int kh = qh >> 2;
    const float scale = 0.088388347648318447f;

    const int kcol = NQ * HD + kh * HD;
    const int vcol = (NQ + NKV) * HD + kh * HD;

    for (int idx = tid; idx < 64 * 32; idx += 256) {
        const int r = idx >> 5, c4 = (idx & 31) << 2;
        *(float4*)&Qs[r * 128 + c4] =
            *(const float4*)&qkv[(size_t)(mb * 64 + r) * QKV_N + qh * HD + c4];
    }
    if (tid < 64) { m_sm[tid] = -1e30f; l_sm[tid] = 0.f; }
    __syncthreads();

    const int sy = tid >> 4, sx = tid & 15;
    const int prow = tid >> 2, ppart = tid & 3;

    float acc[32];
#pragma unroll
    for (int i = 0; i < 32; i++) acc[i] = 0.f;

    for (int nb = 0; nb <= mb; nb++) {
        for (int idx = tid; idx < 64 * 32; idx += 256) {
            const int r = idx >> 5, c4 = (idx & 31) << 2;
            const float* src = &qkv[(size_t)(nb * 64 + r) * QKV_N];
            float4 kv = *(const float4*)(src + kcol + c4);
            Ks[r * 129 + c4 + 0] = kv.x; Ks[r * 129 + c4 + 1] = kv.y;
            Ks[r * 129 + c4 + 2] = kv.z; Ks[r * 129 + c4 + 3] = kv.w;
            *(float4*)&Vs[r * 128 + c4] = *(const float4*)(src + vcol + c4);
        }
        __syncthreads();

        float s4[4][4];
#pragma unroll
        for (int i = 0; i < 4; i++)
#pragma unroll
            for (int j = 0; j < 4; j++) s4[i][j] = 0.f;

        for (int kk = 0; kk < 128; kk += 4) {
            float a[4][4];
#pragma unroll
            for (int i = 0; i < 4; i++)
                *(float4*)&a[i][0] = *(const float4*)&Qs[(sy * 4 + i) * 128 + kk];
#pragma unroll
            for (int t = 0; t < 4; t++) {
                float bb[4];
#pragma unroll
                for (int j = 0; j < 4; j++) bb[j] = Ks[(sx * 4 + j) * 129 + kk + t];
#pragma unroll
                for (int i = 0; i < 4; i++)
#pragma unroll
                    for (int j = 0; j < 4; j++)
                        s4[i][j] = fmaf(a[i][t], bb[j], s4[i][j]);
            }
        }
        const bool diag = (nb == mb);
#pragma unroll
        for (int i = 0; i < 4; i++) {
            const int r = sy * 4 + i;
#pragma unroll
            for (int j = 0; j < 4; j++) {
                const int c = sx * 4 + j;
                float v = s4[i][j] * scale;
                if (diag && c > r) v = -1e30f;
                Ss[r * 65 + c] = v;
            }
        }
        __syncthreads();

        {
            float mloc = -1e30f;
#pragma unroll
            for (int jj = 0; jj < 16; jj++)
                mloc = fmaxf(mloc, Ss[prow * 65 + ppart * 16 + jj]);
            mloc = fmaxf(mloc, __shfl_xor_sync(0xffffffffu, mloc, 1));
            mloc = fmaxf(mloc, __shfl_xor_sync(0xffffffffu, mloc, 2));
            const float mold = m_sm[prow];
            const float mnew = fmaxf(mold, mloc);
            float ssum = 0.f;
#pragma unroll
            for (int jj = 0; jj < 16; jj++) {
                const int c = ppart * 16 + jj;
                const float p = __expf(Ss[prow * 65 + c] - mnew);
                Ss[prow * 65 + c] = p;
                ssum += p;
            }
            ssum += __shfl_xor_sync(0xffffffffu, ssum, 1);
            ssum += __shfl_xor_sync(0xffffffffu, ssum, 2);
            if (ppart == 0) {
                const float cf = __expf(mold - mnew);
                m_sm[prow] = mnew;
                l_sm[prow] = l_sm[prow] * cf + ssum;
                c_sm[prow] = cf;
            }
        }
        __syncthreads();

        {
            const float cf = c_sm[prow];
#pragma unroll
            for (int i = 0; i < 32; i++) acc[i] *= cf;
            for (int j = 0; j < 64; j++) {
                const float p = Ss[prow * 65 + j];
#pragma unroll
                for (int g = 0; g < 8; g++) {
                    float4 v = *(const float4*)&Vs[j * 128 + ppart * 4 + g * 16];
                    acc[g * 4 + 0] = fmaf(p, v.x, acc[g * 4 + 0]);
                    acc[g * 4 + 1] = fmaf(p, v.y, acc[g * 4 + 1]);
                    acc[g * 4 + 2] = fmaf(p, v.z, acc[g * 4 + 2]);
                    acc[g * 4 + 3] = fmaf(p, v.w, acc[g * 4 + 3]);
                }
            }
        }
        __syncthreads();
    }

    const float linv = 1.f / l_sm[prow];
    const size_t base = (size_t)(mb * 64 + prow) * (NQ * HD) + qh * HD;
#pragma unroll
    for (int g = 0; g < 8; g++) {
        float4 v;
        v.x = acc[g * 4 + 0] * linv;
        v.y = acc[g * 4 + 1] * linv;
        v.z = acc[g * 4 + 2] * linv;
        v.w = acc[g * 4 + 3] * linv;
        *(float4*)&out[base + ppart * 4 + g * 16] = v;
    }
}

// ---------------------------------------------------------------------------
// SiLU(gate)*up -> hi/lo fp16
// ---------------------------------------------------------------------------
__global__ void silu_mul_split_kernel(const float* __restrict__ gu,
                                      __half* __restrict__ hhi,
                                      __half* __restrict__ hlo)
{
    const size_t idx = (size_t)blockIdx.x * blockDim.x + threadIdx.x;
    const size_t total = (size_t)S_LEN * I_DIM / 4;
    if (idx >= total) return;
    const size_t row = idx / (I_DIM / 4);
    const size_t c4 = (idx % (I_DIM / 4)) * 4;
    const float4 g = *(const float4*)(gu + row * 2 * I_DIM + c4);
    const float4 u = *(const float4*)(gu + row * 2 * I_DIM + I_DIM + c4);
    float4 r;
    r.x = g.x / (1.f + __expf(-g.x)) * u.x;
    r.y = g.y / (1.f + __expf(-g.y)) * u.y;
    r.z = g.z / (1.f + __expf(-g.z)) * u.z;
    r.w = g.w / (1.f + __expf(-g.w)) * u.w;
    uint2 h, l;
    split4(r, h, l);
    ((uint2*)(hhi + row * I_DIM))[c4 / 4] = h;
    ((uint2*)(hlo + row * I_DIM))[c4 / 4] = l;
}

// ---------------------------------------------------------------------------
// Launch
// ---------------------------------------------------------------------------
extern "C" void kernel_launch(void* const* d_in, const int* in_sizes, int n_in,
                              void* d_out, int out_size)
{
    (void)in_sizes; (void)n_in;
    const float* hidden = (const float*)d_in[1];
    const float* w_qkv = (const float*)d_in[2];
    const float* w_o = (const float*)d_in[3];
    const float* w_gu = (const float*)d_in[4];
    const float* w_down = (const float*)d_in[5];
    const float* ln1 = (const float*)d_in[6];
    const float* ln2 = (const float*)d_in[7];

    float* out = (float*)d_out;
    const size_t SH = (size_t)S_LEN * H_DIM;
    float* out_resid = ((size_t)out_size >= 2 * SH) ? (out + SH) : nullptr;

    float *qkv, *attn, *resid, *gu;
    cudaGetSymbolAddress((void**)&qkv, g_qkv);
    cudaGetSymbolAddress((void**)&attn, g_attn);
    cudaGetSymbolAddress((void**)&resid, g_resid);
    cudaGetSymbolAddress((void**)&gu, g_gu);
    __half *wqkvh, *wqkvl, *woh, *wguh, *wdh;
    __half *xbh, *xbl, *abh, *abl, *hbh, *hbl;
    cudaGetSymbolAddress((void**)&wqkvh, g_wqkvT_hi);
    cudaGetSymbolAddress((void**)&wqkvl, g_wqkvT_lo);
    cudaGetSymbolAddress((void**)&woh, g_woT_hi);
    cudaGetSymbolAddress((void**)&wguh, g_wguT_hi);
    cudaGetSymbolAddress((void**)&wdh, g_wdownT_hi);
    cudaGetSymbolAddress((void**)&xbh, g_xb_hi);
    cudaGetSymbolAddress((void**)&xbl, g_xb_lo);
    cudaGetSymbolAddress((void**)&abh, g_ab_hi);
    cudaGetSymbolAddress((void**)&abl, g_ab_lo);
    cudaGetSymbolAddress((void**)&hbh, g_hb_hi);
    cudaGetSymbolAddress((void**)&hbl, g_hb_lo);

    const int ATT_SMEM = (64 * 128 + 64 * 129 + 64 * 128 + 64 * 65 + 192) * 4;
    cudaFuncSetAttribute(attn_kernel, cudaFuncAttributeMaxDynamicSharedMemorySize,
                         ATT_SMEM);
    const int SMEM3 = 2 * 4 * TILE_B;   // 81920
    const int SMEM2 = 2 * 3 * TILE_B;   // 61440
    cudaFuncSetAttribute(gemm_mma_kernel<3>,
                         cudaFuncAttributeMaxDynamicSharedMemorySize, SMEM3);
    cudaFuncSetAttribute(gemm_mma_kernel<2>,
                         cudaFuncAttributeMaxDynamicSharedMemorySize, SMEM2);

    // 0. Weight transpose + split (qkv: hi+lo; rest: hi only)
    wt_transpose_kernel<<<dim3(QKV_N / 32, H_DIM / 32), 256>>>(w_qkv, wqkvh, wqkvl, H_DIM, QKV_N);
    wt_transpose_kernel<<<dim3(H_DIM / 32, (NQ * HD) / 32), 256>>>(w_o, woh, nullptr, NQ * HD, H_DIM);
    wt_transpose_kernel<<<dim3((2 * I_DIM) / 32, H_DIM / 32), 256>>>(w_gu, wguh, nullptr, H_DIM, 2 * I_DIM);
    wt_transpose_kernel<<<dim3(H_DIM / 32, I_DIM / 32), 256>>>(w_down, wdh, nullptr, I_DIM, H_DIM);

    // 1. RMSNorm 1 -> hi/lo
    rmsnorm_split_kernel<<<S_LEN, 256>>>(hidden, ln1, xbh, xbl);

    // 2. QKV projection (3-product: exact logits)
    gemm_mma_kernel<3><<<dim3(S_LEN / BM, QKV_N / BN), 256, SMEM3>>>(
        xbh, xbl, wqkvh, wqkvl, qkv, S_LEN, QKV_N, H_DIM, nullptr, nullptr);

    // 3. RoPE
    {
        const int total = S_LEN * (NQ + NKV) * 64;
        rope_kernel<<<(total + 255) / 256, 256>>>(qkv);
    }

    // 4. Attention
    attn_kernel<<<dim3(S_LEN / 64, NQ), 256, ATT_SMEM>>>(qkv, attn);

    // 5. attn -> hi/lo, then O projection (2-product) + residual
    {
        const size_t n4 = (size_t)S_LEN * NQ * HD / 4;
        act_split_kernel<<<(int)((n4 + 255) / 256), 256>>>(attn, abh, abl, n4);
    }
    gemm_mma_kernel<2><<<dim3(S_LEN / BM, H_DIM / BN), 256, SMEM2>>>(
        abh, abl, woh, nullptr, resid, S_LEN, H_DIM, NQ * HD, hidden, out_resid);

    // 6. RMSNorm 2 -> hi/lo
    rmsnorm_split_kernel<<<S_LEN, 256>>>(resid, ln2, xbh, xbl);

    // 7. gate_up (2-product)
    gemm_mma_kernel<2><<<dim3(S_LEN / BM, (2 * I_DIM) / BN), 256, SMEM2>>>(
        xbh, xbl, wguh, nullptr, gu, S_LEN, 2 * I_DIM, H_DIM, nullptr, nullptr);

    // 8. SiLU * up -> hi/lo
    {
        const size_t total = (size_t)S_LEN * I_DIM / 4;
        silu_mul_split_kernel<<<(int)((total + 255) / 256), 256>>>(gu, hbh, hbl);
    }

    // 9. down (2-product) -> out
    gemm_mma_kernel<2><<<dim3(S_LEN / BM, H_DIM / BN), 256, SMEM2>>>(
        hbh, hbl, wdh, nullptr, out, S_LEN, H_DIM, I_DIM, nullptr, nullptr);
}

// round 7
// speedup vs baseline: 2.8815x; 1.2131x over previous
#include <cuda_runtime.h>
#include <cuda_fp16.h>
#include <math.h>
#include <stdint.h>

#define H_DIM 4096
#define S_LEN 2048
#define NQ 32
#define NKV 8
#define HD 128
#define I_DIM 14336
#define QKV_N ((NQ + 2 * NKV) * HD) /* 6144 */
#define EPS 1e-5f

// GEMM tiling (mma.sync path)
#define BM 128
#define BN 128
#define KC 32
#define ROWB 80                       // bytes per smem row (64B data + 16B pad)
#define TILE_B (128 * ROWB)

// Attention tiling
#define BR 128
#define BC 64
#define AROWB 272                     // 128 halves * 2B + 16B pad
#define ATT_SMEM (2 * BR * AROWB + 4 * BC * AROWB)   // 139264

// ---------------------------------------------------------------------------
// Scratch (device globals)
// ---------------------------------------------------------------------------
__device__ float g_qkv[(size_t)S_LEN * QKV_N];
__device__ float g_resid[(size_t)S_LEN * H_DIM];
__device__ float g_gu[(size_t)S_LEN * 2 * I_DIM];

__device__ __half g_qkvh[(size_t)S_LEN * QKV_N];
__device__ __half g_qkvl[(size_t)S_LEN * QKV_N];

__device__ __half g_wqkvT_hi[(size_t)QKV_N * H_DIM];
__device__ __half g_wqkvT_lo[(size_t)QKV_N * H_DIM];
__device__ __half g_woT_hi[(size_t)H_DIM * (NQ * HD)];
__device__ __half g_wguT_hi[(size_t)(2 * I_DIM) * H_DIM];
__device__ __half g_wdownT_hi[(size_t)H_DIM * I_DIM];

__device__ __half g_xb_hi[(size_t)S_LEN * H_DIM];
__device__ __half g_xb_lo[(size_t)S_LEN * H_DIM];
__device__ __half g_ab_hi[(size_t)S_LEN * NQ * HD];
__device__ __half g_ab_lo[(size_t)S_LEN * NQ * HD];
__device__ __half g_hb_hi[(size_t)S_LEN * I_DIM];
__device__ __half g_hb_lo[(size_t)S_LEN * I_DIM];

// ---------------------------------------------------------------------------
// PTX helpers
// ---------------------------------------------------------------------------
__device__ __forceinline__ uint32_t smem_u32(const void* p) {
    uint32_t a;
    asm("{ .reg .u64 t; cvta.to.shared.u64 t, %1; cvt.u32.u64 %0, t; }"
        : "=r"(a) : "l"(p));
    return a;
}
__device__ __forceinline__ void cp16(uint32_t saddr, const void* g) {
    asm volatile("cp.async.cg.shared.global [%0], [%1], 16;"
                 :: "r"(saddr), "l"(g) : "memory");
}
__device__ __forceinline__ void cp_commit() {
    asm volatile("cp.async.commit_group;" ::: "memory");
}
template <int N>
__device__ __forceinline__ void cp_wait() {
    asm volatile("cp.async.wait_group %0;" :: "n"(N) : "memory");
}
__device__ __forceinline__ void ldm4(uint32_t* r, uint32_t addr) {
    asm volatile("ldmatrix.sync.aligned.m8n8.x4.shared.b16 {%0,%1,%2,%3}, [%4];"
                 : "=r"(r[0]), "=r"(r[1]), "=r"(r[2]), "=r"(r[3]) : "r"(addr));
}
__device__ __forceinline__ void ldm4t(uint32_t* r, uint32_t addr) {
    asm volatile("ldmatrix.sync.aligned.m8n8.x4.trans.shared.b16 {%0,%1,%2,%3}, [%4];"
                 : "=r"(r[0]), "=r"(r[1]), "=r"(r[2]), "=r"(r[3]) : "r"(addr));
}
__device__ __forceinline__ void mma_f16(float* d, const uint32_t* a,
                                        const uint32_t* b) {
    asm volatile(
        "mma.sync.aligned.m16n8k16.row.col.f32.f16.f16.f32 "
        "{%0,%1,%2,%3}, {%4,%5,%6,%7}, {%8,%9}, {%0,%1,%2,%3};"
        : "+f"(d[0]), "+f"(d[1]), "+f"(d[2]), "+f"(d[3])
        : "r"(a[0]), "r"(a[1]), "r"(a[2]), "r"(a[3]), "r"(b[0]), "r"(b[1]));
}
__device__ __forceinline__ void split1(float x, __half& h, __half& l) {
    h = __float2half_rn(x);
    l = __float2half_rn(x - __half2float(h));
}
__device__ __forceinline__ void split4(float4 v, uint2& hi, uint2& lo) {
    __half h0, h1, h2, h3, l0, l1, l2, l3;
    split1(v.x, h0, l0); split1(v.y, h1, l1);
    split1(v.z, h2, l2); split1(v.w, h3, l3);
    hi.x = ((uint32_t)__half_as_ushort(h1) << 16) | __half_as_ushort(h0);
    hi.y = ((uint32_t)__half_as_ushort(h3) << 16) | __half_as_ushort(h2);
    lo.x = ((uint32_t)__half_as_ushort(l1) << 16) | __half_as_ushort(l0);
    lo.y = ((uint32_t)__half_as_ushort(l3) << 16) | __half_as_ushort(l2);
}
__device__ __forceinline__ uint32_t packh2(float a, float b) {
    __half2 h = __floats2half2_rn(a, b);
    return *(uint32_t*)&h;
}

// ---------------------------------------------------------------------------
// Weight transpose + split: W[K,N] fp32 -> Thi (and optional Tlo) [N,K] fp16
// ---------------------------------------------------------------------------
__global__ __launch_bounds__(256)
void wt_transpose_kernel(const float* __restrict__ W,
                         __half* __restrict__ Thi,
                         __half* __restrict__ Tlo, int K, int N)
{
    __shared__ float t[32][33];
    const int tx = threadIdx.x & 31, ty = threadIdx.x >> 5;
    const int n = blockIdx.x * 32 + tx;
#pragma unroll
    for (int i = 0; i < 4; i++) {
        const int k = blockIdx.y * 32 + ty + i * 8;
        t[ty + i * 8][tx] = W[(size_t)k * N + n];
    }
    __syncthreads();
    const int k2 = blockIdx.y * 32 + tx;
#pragma unroll
    for (int i = 0; i < 4; i++) {
        const int n2 = blockIdx.x * 32 + ty + i * 8;
        const float v = t[tx][ty + i * 8];
        __half h, l;
        split1(v, h, l);
        Thi[(size_t)n2 * K + k2] = h;
        if (Tlo) Tlo[(size_t)n2 * K + k2] = l;
    }
}

// ---------------------------------------------------------------------------
// RMSNorm + split output
// ---------------------------------------------------------------------------
__global__ __launch_bounds__(256)
void rmsnorm_split_kernel(const float* __restrict__ x, const float* __restrict__ w,
                          __half* __restrict__ ohi, __half* __restrict__ olo)
{
    const int row = blockIdx.x;
    const int t = threadIdx.x;
    const float4* xr = (const float4*)(x + (size_t)row * H_DIM);
    const float4* wr = (const float4*)w;

    float4 v[4];
    float ss = 0.f;
#pragma unroll
    for (int i = 0; i < 4; i++) {
        v[i] = xr[t + 256 * i];
        ss += v[i].x * v[i].x + v[i].y * v[i].y + v[i].z * v[i].z + v[i].w * v[i].w;
    }
#pragma unroll
    for (int o = 16; o; o >>= 1) ss += __shfl_xor_sync(0xffffffffu, ss, o);
    __shared__ float wsum[8];
    if ((t & 31) == 0) wsum[t >> 5] = ss;
    __syncthreads();
    float tot = wsum[0] + wsum[1] + wsum[2] + wsum[3] +
                wsum[4] + wsum[5] + wsum[6] + wsum[7];
    const float sc = rsqrtf(tot * (1.f / H_DIM) + EPS);

    uint2* hr = (uint2*)(ohi + (size_t)row * H_DIM);
    uint2* lr = (uint2*)(olo + (size_t)row * H_DIM);
#pragma unroll
    for (int i = 0; i < 4; i++) {
        float4 wv = wr[t + 256 * i];
        float4 r;
        r.x = v[i].x * sc * wv.x;
        r.y = v[i].y * sc * wv.y;
        r.z = v[i].z * sc * wv.z;
        r.w = v[i].w * sc * wv.w;
        uint2 h, l;
        split4(r, h, l);
        hr[t + 256 * i] = h;
        lr[t + 256 * i] = l;
    }
}

// ---------------------------------------------------------------------------
// mma.sync fp16 hi/lo GEMM (unchanged from R5)
// ---------------------------------------------------------------------------
template <int NPROD>
__global__ __launch_bounds__(256, 1)
void gemm_mma_kernel(const __half* __restrict__ Ahi,
                     const __half* __restrict__ Alo,
                     const __half* __restrict__ Bhi,
                     const __half* __restrict__ Blo,
                     float* __restrict__ C, int M, int N, int K,
                     const float* __restrict__ add, float* __restrict__ C2)
{
    constexpr int NTILES = (NPROD == 3) ? 4 : 3;
    constexpr uint32_t STG = NTILES * TILE_B;
    extern __shared__ char smc[];
    const uint32_t sbase = smem_u32(smc);
    const int tid = threadIdx.x;
    const int lane = tid & 31;
    const int wm = (tid >> 5) & 3;
    const int wn = tid >> 7;
    const int m0 = blockIdx.x * BM;
    const int n0 = blockIdx.y * BN;
    const int NCH = K / KC;

    const int q0r = tid >> 2, q0c = tid & 3;
    const int q1r = (tid + 256) >> 2, q1c = tid & 3;

    float acc[2][8][4];
#pragma unroll
    for (int mt = 0; mt < 2; mt++)
#pragma unroll
        for (int nt = 0; nt < 8; nt++)
#pragma unroll
            for (int e = 0; e < 4; e++) acc[mt][nt][e] = 0.f;

    auto issue = [&](int kc, int buf) {
        const uint32_t st = sbase + buf * STG;
        const int kb = kc * KC;
        const size_t gA0 = (size_t)(m0 + q0r) * K + kb + q0c * 8;
        const size_t gA1 = (size_t)(m0 + q1r) * K + kb + q1c * 8;
        const size_t gB0 = (size_t)(n0 + q0r) * K + kb + q0c * 8;
        const size_t gB1 = (size_t)(n0 + q1r) * K + kb + q1c * 8;
        const uint32_t s0 = st + q0r * ROWB + q0c * 16;
        const uint32_t s1 = st + q1r * ROWB + q1c * 16;
        cp16(s0, Ahi + gA0);
        cp16(s1, Ahi + gA1);
        cp16(s0 + TILE_B, Alo + gA0);
        cp16(s1 + TILE_B, Alo + gA1);
        cp16(s0 + 2 * TILE_B, Bhi + gB0);
        cp16(s1 + 2 * TILE_B, Bhi + gB1);
        if (NPROD == 3) {
            cp16(s0 + 3 * TILE_B, Blo + gB0);
            cp16(s1 + 3 * TILE_B, Blo + gB1);
        }
        cp_commit();
    };

    issue(0, 0);

    for (int kc = 0; kc < NCH; kc++) {
        if (kc + 1 < NCH) {
            issue(kc + 1, (kc + 1) & 1);
            cp_wait<1>();
        } else {
            cp_wait<0>();
        }
        __syncthreads();

        const uint32_t st = sbase + (kc & 1) * STG;
        const uint32_t sAh = st;
        const uint32_t sAl = st + TILE_B;
        const uint32_t sBh = st + 2 * TILE_B;
        const uint32_t sBl = st + 3 * TILE_B;

        const int aRow = wm * 32 + (lane & 15);
        const int aKof = (lane >> 4) * 8;
        const int bIdx = lane & 7;
        const int bSel = lane >> 3;
        const int bRowBase = wn * 64 + ((bSel >> 1) * 8) + bIdx;
        const int bKof = (bSel & 1) * 8;

#pragma unroll
        for (int ks = 0; ks < KC; ks += 16) {
            uint32_t ah[2][4], al[2][4];
#pragma unroll
            for (int mt = 0; mt < 2; mt++) {
                const uint32_t off = (uint32_t)(aRow + mt * 16) * ROWB +
                                     (uint32_t)(ks + aKof) * 2;
                ldm4(ah[mt], sAh + off);
                ldm4(al[mt], sAl + off);
            }
            uint32_t bh[8][2], bl[8][2];
#pragma unroll
            for (int p = 0; p < 4; p++) {
                const uint32_t off = (uint32_t)(bRowBase + p * 16) * ROWB +
                                     (uint32_t)(ks + bKof) * 2;
                uint32_t r4[4];
                ldm4(r4, sBh + off);
                bh[2 * p][0] = r4[0]; bh[2 * p][1] = r4[1];
                bh[2 * p + 1][0] = r4[2]; bh[2 * p + 1][1] = r4[3];
                if (NPROD == 3) {
                    ldm4(r4, sBl + off);
                    bl[2 * p][0] = r4[0]; bl[2 * p][1] = r4[1];
                    bl[2 * p + 1][0] = r4[2]; bl[2 * p + 1][1] = r4[3];
                }
            }
#pragma unroll
            for (int mt = 0; mt < 2; mt++)
#pragma unroll
                for (int nt = 0; nt < 8; nt++) {
                    mma_f16(acc[mt][nt], ah[mt], bh[nt]);
                    mma_f16(acc[mt][nt], al[mt], bh[nt]);
                    if (NPROD == 3) mma_f16(acc[mt][nt], ah[mt], bl[nt]);
                }
        }
        __syncthreads();
    }

    const int erow = m0 + wm * 32 + (lane >> 2);
    const int ecol = n0 + wn * 64 + (lane & 3) * 2;
#pragma unroll
    for (int mt = 0; mt < 2; mt++) {
#pragma unroll
        for (int nt = 0; nt < 8; nt++) {
            const int r0 = erow + mt * 16;
            const int c = ecol + nt * 8;
            const size_t off0 = (size_t)r0 * N + c;
            const size_t off1 = (size_t)(r0 + 8) * N + c;
            float2 v0 = make_float2(acc[mt][nt][0], acc[mt][nt][1]);
            float2 v1 = make_float2(acc[mt][nt][2], acc[mt][nt][3]);
            if (add) {
                float2 a0 = *(const float2*)(add + off0);
                float2 a1 = *(const float2*)(add + off1);
                v0.x += a0.x; v0.y += a0.y;
                v1.x += a1.x; v1.y += a1.y;
            }
            *(float2*)(C + off0) = v0;
            *(float2*)(C + off1) = v1;
            if (C2) {
                *(float2*)(C2 + off0) = v0;
                *(float2*)(C2 + off1) = v1;
            }
        }
    }
}

// ---------------------------------------------------------------------------
// RoPE + split qkv fp32 -> fp16 hi/lo planes (v passthrough-split)
// FIX R7: slot/s computed with % and / (3072 is not a power of two!)
// ---------------------------------------------------------------------------
__global__ void rope_split_kernel(const float* __restrict__ qkv,
                                  __half* __restrict__ oh,
                                  __half* __restrict__ ol)
{
    const int idx = blockIdx.x * blockDim.x + threadIdx.x;
    const int total = S_LEN * 3072;
    if (idx >= total) return;
    const int slot = idx % 3072;
    const int s = idx / 3072;
    const size_t rb = (size_t)s * QKV_N;

    if (slot < 2560) {
        const int head = slot >> 6;
        const int d = slot & 63;
        const int col = head * HD + d;
        const float inv = exp2f((float)d * (-13.287712379549449f / 64.f));
        const float ang = (float)s * inv;
        float sn, c;
        sincosf(ang, &sn, &c);
        const float x1 = qkv[rb + col];
        const float x2 = qkv[rb + col + 64];
        const float y1 = x1 * c - x2 * sn;
        const float y2 = x2 * c + x1 * sn;
        __half h1, l1, h2, l2;
        split1(y1, h1, l1);
        split1(y2, h2, l2);
        oh[rb + col] = h1; oh[rb + col + 64] = h2;
        ol[rb + col] = l1; ol[rb + col + 64] = l2;
    } else {
        const int c0 = 5120 + (slot - 2560) * 2;
        const float x1 = qkv[rb + c0];
        const float x2 = qkv[rb + c0 + 1];
        __half h1, l1, h2, l2;
        split1(x1, h1, l1);
        split1(x2, h2, l2);
        oh[rb + c0] = h1; oh[rb + c0 + 1] = h2;
        ol[rb + c0] = l1; ol[rb + c0 + 1] = l2;
    }
}

// ---------------------------------------------------------------------------
// Tensor-core flash attention (fp16 hi/lo, 3-product: near-exact).
// CTA = (head, 128-row block); 8 warps x 16 rows. K/V tiles 64x128.
// Writes o-proj hi/lo operands directly.
// ---------------------------------------------------------------------------
__global__ __launch_bounds__(256, 1)
void attn_mma_kernel(const __half* __restrict__ qph,
                     const __half* __restrict__ qpl,
                     __half* __restrict__ outh, __half* __restrict__ outl)
{
    extern __shared__ char smc[];
    const uint32_t sb = smem_u32(smc);
    const uint32_t sQh = sb;
    const uint32_t sQl = sb + BR * AROWB;
    const uint32_t sKh = sb + 2 * BR * AROWB;
    const uint32_t sKl = sKh + BC * AROWB;
    const uint32_t sVh = sKl + BC * AROWB;
    const uint32_t sVl = sVh + BC * AROWB;

    const int tid = threadIdx.x;
    const int lane = tid & 31;
    const int warp = tid >> 5;
    const int mb = blockIdx.x;
    const int head = blockIdx.y;
    const int kh = head >> 2;
    const float scale = 0.088388347648318447f;

    const int qcol = head * HD;
    const int kcol = NQ * HD + kh * HD;
    const int vcol = (NQ + NKV) * HD + kh * HD;

    // Load Q (hi/lo): 128 rows x 16 chunks
    {
        const int chunk = tid & 15;
        const int rbase = tid >> 4;
#pragma unroll
        for (int i = 0; i < 8; i++) {
            const int row = rbase + i * 16;
            const size_t g = (size_t)(mb * BR + row) * QKV_N + qcol + chunk * 8;
            const uint32_t so = row * AROWB + chunk * 16;
            cp16(sQh + so, qph + g);
            cp16(sQl + so, qpl + g);
        }
    }
    cp_commit();

    float m0 = -1e30f, m1 = -1e30f, l0 = 0.f, l1 = 0.f;
    float acc_o[16][4];
#pragma unroll
    for (int nt = 0; nt < 16; nt++)
#pragma unroll
        for (int e = 0; e < 4; e++) acc_o[nt][e] = 0.f;

    const int aRow = warp * 16 + (lane & 15);
    const int aKof = (lane >> 4) * 8;
    const int bIdx = lane & 7;
    const int bSel = lane >> 3;
    const int bRowBase = (bSel >> 1) * 8 + bIdx;
    const int bKof = (bSel & 1) * 8;
    const int vRow = lane & 15;
    const int vCof = (lane >> 4) * 8;

    const int r0 = lane >> 2;
    const int cq = lane & 3;
    const int grow0 = mb * BR + warp * 16 + r0;
    const int grow1 = grow0 + 8;

    const int ntiles = 2 * mb + 2;
    for (int nb = 0; nb < ntiles; nb++) {
        __syncthreads();   // previous tile fully consumed before overwrite
        {
            const int chunk = tid & 15;
            const int rbase = tid >> 4;
#pragma unroll
            for (int i = 0; i < 4; i++) {
                const int row = rbase + i * 16;
                const size_t gk = (size_t)(nb * BC + row) * QKV_N + kcol + chunk * 8;
                const size_t gv = (size_t)(nb * BC + row) * QKV_N + vcol + chunk * 8;
                const uint32_t so = row * AROWB + chunk * 16;
                cp16(sKh + so, qph + gk);
                cp16(sKl + so, qpl + gk);
                cp16(sVh + so, qph + gv);
                cp16(sVl + so, qpl + gv);
            }
        }
        cp_commit();
        cp_wait<0>();
        __syncthreads();

        // ---- S = Q K^T (3-product) ----
        float accs[8][4];
#pragma unroll
        for (int nt = 0; nt < 8; nt++)
#pragma unroll
            for (int e = 0; e < 4; e++) accs[nt][e] = 0.f;

#pragma unroll
        for (int ks = 0; ks < 8; ks++) {
            uint32_t aqh[4], aql[4];
            const uint32_t aoff = (uint32_t)aRow * AROWB + (uint32_t)(ks * 16 + aKof) * 2;
            ldm4(aqh, sQh + aoff);
            ldm4(aql, sQl + aoff);
            uint32_t bh[8][2], bl[8][2];
#pragma unroll
            for (int p = 0; p < 4; p++) {
                const uint32_t boff = (uint32_t)(bRowBase + p * 16) * AROWB +
                                      (uint32_t)(ks * 16 + bKof) * 2;
                uint32_t r4[4];
                ldm4(r4, sKh + boff);
                bh[2 * p][0] = r4[0]; bh[2 * p][1] = r4[1];
                bh[2 * p + 1][0] = r4[2]; bh[2 * p + 1][1] = r4[3];
                ldm4(r4, sKl + boff);
                bl[2 * p][0] = r4[0]; bl[2 * p][1] = r4[1];
                bl[2 * p + 1][0] = r4[2]; bl[2 * p + 1][1] = r4[3];
            }
#pragma unroll
            for (int nt = 0; nt < 8; nt++) {
                mma_f16(accs[nt], aqh, bh[nt]);
                mma_f16(accs[nt], aqh, bl[nt]);
                mma_f16(accs[nt], aql, bh[nt]);
            }
        }

        // ---- scale + causal mask + online softmax ----
        float rmax0 = -1e30f, rmax1 = -1e30f;
#pragma unroll
        for (int nt = 0; nt < 8; nt++) {
            const int cbase = nb * BC + nt * 8 + cq * 2;
#pragma unroll
            for (int e = 0; e < 4; e++) {
                float s = accs[nt][e] * scale;
                const int col = cbase + (e & 1);
                const int row = (e < 2) ? grow0 : grow1;
                if (col > row) s = -1e30f;
                accs[nt][e] = s;
            }
            rmax0 = fmaxf(rmax0, fmaxf(accs[nt][0], accs[nt][1]));
            rmax1 = fmaxf(rmax1, fmaxf(accs[nt][2], accs[nt][3]));
        }
        rmax0 = fmaxf(rmax0, __shfl_xor_sync(0xffffffffu, rmax0, 1));
        rmax0 = fmaxf(rmax0, __shfl_xor_sync(0xffffffffu, rmax0, 2));
        rmax1 = fmaxf(rmax1, __shfl_xor_sync(0xffffffffu, rmax1, 1));
        rmax1 = fmaxf(rmax1, __shfl_xor_sync(0xffffffffu, rmax1, 2));
        const float mn0 = fmaxf(m0, rmax0), mn1 = fmaxf(m1, rmax1);
        const float cf0 = __expf(m0 - mn0), cf1 = __expf(m1 - mn1);
        m0 = mn0; m1 = mn1;
        float s0 = 0.f, s1 = 0.f;
#pragma unroll
        for (int nt = 0; nt < 8; nt++) {
            accs[nt][0] = __expf(accs[nt][0] - mn0);
            accs[nt][1] = __expf(accs[nt][1] - mn0);
            accs[nt][2] = __expf(accs[nt][2] - mn1);
            accs[nt][3] = __expf(accs[nt][3] - mn1);
            s0 += accs[nt][0] + accs[nt][1];
            s1 += accs[nt][2] + accs[nt][3];
        }
        s0 += __shfl_xor_sync(0xffffffffu, s0, 1);
        s0 += __shfl_xor_sync(0xffffffffu, s0, 2);
        s1 += __shfl_xor_sync(0xffffffffu, s1, 1);
        s1 += __shfl_xor_sync(0xffffffffu, s1, 2);
        l0 = l0 * cf0 + s0;
        l1 = l1 * cf1 + s1;
#pragma unroll
        for (int nt = 0; nt < 16; nt++) {
            acc_o[nt][0] *= cf0; acc_o[nt][1] *= cf0;
            acc_o[nt][2] *= cf1; acc_o[nt][3] *= cf1;
        }

        // ---- O += P V (3-product; P frags repacked from S registers) ----
#pragma unroll
        for (int kb = 0; kb < 4; kb++) {
            uint32_t ph[4], pl[4];
            {
                const float* s0p = accs[2 * kb];
                const float* s1p = accs[2 * kb + 1];
                float h00 = __half2float(__float2half_rn(s0p[0]));
                float h01 = __half2float(__float2half_rn(s0p[1]));
                float h02 = __half2float(__float2half_rn(s0p[2]));
                float h03 = __half2float(__float2half_rn(s0p[3]));
                float h10 = __half2float(__float2half_rn(s1p[0]));
                float h11 = __half2float(__float2half_rn(s1p[1]));
                float h12 = __half2float(__float2half_rn(s1p[2]));
                float h13 = __half2float(__float2half_rn(s1p[3]));
                ph[0] = packh2(s0p[0], s0p[1]);
                ph[1] = packh2(s0p[2], s0p[3]);
                ph[2] = packh2(s1p[0], s1p[1]);
                ph[3] = packh2(s1p[2], s1p[3]);
                pl[0] = packh2(s0p[0] - h00, s0p[1] - h01);
                pl[1] = packh2(s0p[2] - h02, s0p[3] - h03);
                pl[2] = packh2(s1p[0] - h10, s1p[1] - h11);
                pl[3] = packh2(s1p[2] - h12, s1p[3] - h13);
            }
#pragma unroll
            for (int np = 0; np < 8; np++) {
                const uint32_t voff = (uint32_t)(kb * 16 + vRow) * AROWB +
                                      (uint32_t)(np * 16 + vCof) * 2;
                uint32_t rv[4], rl[4];
                ldm4t(rv, sVh + voff);
                ldm4t(rl, sVl + voff);
                uint32_t vh0[2] = {rv[0], rv[1]};
                uint32_t vh1[2] = {rv[2], rv[3]};
                uint32_t vl0[2] = {rl[0], rl[1]};
                uint32_t vl1[2] = {rl[2], rl[3]};
                mma_f16(acc_o[2 * np], ph, vh0);
                mma_f16(acc_o[2 * np], ph, vl0);
                mma_f16(acc_o[2 * np], pl, vh0);
                mma_f16(acc_o[2 * np + 1], ph, vh1);
                mma_f16(acc_o[2 * np + 1], ph, vl1);
                mma_f16(acc_o[2 * np + 1], pl, vh1);
            }
        }
    }

    // ---- epilogue: normalize + split to hi/lo fp16 ----
    const float inv0 = 1.f / l0, inv1 = 1.f / l1;
#pragma unroll
    for (int nt = 0; nt < 16; nt++) {
        const float v00 = acc_o[nt][0] * inv0;
        const float v01 = acc_o[nt][1] * inv0;
        const float v10 = acc_o[nt][2] * inv1;
        const float v11 = acc_o[nt][3] * inv1;
        const size_t o0 = (size_t)grow0 * (NQ * HD) + qcol + nt * 8 + cq * 2;
        const size_t o1 = (size_t)grow1 * (NQ * HD) + qcol + nt * 8 + cq * 2;
        const uint32_t h0 = packh2(v00, v01);
        const uint32_t h1 = packh2(v10, v11);
        *(uint32_t*)&outh[o0] = h0;
        *(uint32_t*)&outh[o1] = h1;
        const __half2* hp0 = (const __half2*)&h0;
        const __half2* hp1 = (const __half2*)&h1;
        *(uint32_t*)&outl[o0] = packh2(v00 - __half2float(hp0->x),
                                       v01 - __half2float(hp0->y));
        *(uint32_t*)&outl[o1] = packh2(v10 - __half2float(hp1->x),
                                       v11 - __half2float(hp1->y));
    }
}

// ---------------------------------------------------------------------------
// SiLU(gate)*up -> hi/lo fp16
// ---------------------------------------------------------------------------
__global__ void silu_mul_split_kernel(const float* __restrict__ gu,
                                      __half* __restrict__ hhi,
                                      __half* __restrict__ hlo)
{
    const size_t idx = (size_t)blockIdx.x * blockDim.x + threadIdx.x;
    const size_t total = (size_t)S_LEN * I_DIM / 4;
    if (idx >= total) return;
    const size_t row = idx / (I_DIM / 4);
    const size_t c4 = (idx % (I_DIM / 4)) * 4;
    const float4 g = *(const float4*)(gu + row * 2 * I_DIM + c4);
    const float4 u = *(const float4*)(gu + row * 2 * I_DIM + I_DIM + c4);
    float4 r;
    r.x = g.x / (1.f + __expf(-g.x)) * u.x;
    r.y = g.y / (1.f + __expf(-g.y)) * u.y;
    r.z = g.z / (1.f + __expf(-g.z)) * u.z;
    r.w = g.w / (1.f + __expf(-g.w)) * u.w;
    uint2 h, l;
    split4(r, h, l);
    ((uint2*)(hhi + row * I_DIM))[c4 / 4] = h;
    ((uint2*)(hlo + row * I_DIM))[c4 / 4] = l;
}

// ---------------------------------------------------------------------------
// Launch
// ---------------------------------------------------------------------------
extern "C" void kernel_launch(void* const* d_in, const int* in_sizes, int n_in,
                              void* d_out, int out_size)
{
    (void)in_sizes; (void)n_in;
    const float* hidden = (const float*)d_in[1];
    const float* w_qkv = (const float*)d_in[2];
    const float* w_o = (const float*)d_in[3];
    const float* w_gu = (const float*)d_in[4];
    const float* w_down = (const float*)d_in[5];
    const float* ln1 = (const float*)d_in[6];
    const float* ln2 = (const float*)d_in[7];

    float* out = (float*)d_out;
    const size_t SH = (size_t)S_LEN * H_DIM;
    float* out_resid = ((size_t)out_size >= 2 * SH) ? (out + SH) : nullptr;

    float *qkv, *resid, *gu;
    cudaGetSymbolAddress((void**)&qkv, g_qkv);
    cudaGetSymbolAddress((void**)&resid, g_resid);
    cudaGetSymbolAddress((void**)&gu, g_gu);
    __half *qkvh, *qkvl;
    cudaGetSymbolAddress((void**)&qkvh, g_qkvh);
    cudaGetSymbolAddress((void**)&qkvl, g_qkvl);
    __half *wqkvh, *wqkvl, *woh, *wguh, *wdh;
    __half *xbh, *xbl, *abh, *abl, *hbh, *hbl;
    cudaGetSymbolAddress((void**)&wqkvh, g_wqkvT_hi);
    cudaGetSymbolAddress((void**)&wqkvl, g_wqkvT_lo);
    cudaGetSymbolAddress((void**)&woh, g_woT_hi);
    cudaGetSymbolAddress((void**)&wguh, g_wguT_hi);
    cudaGetSymbolAddress((void**)&wdh, g_wdownT_hi);
    cudaGetSymbolAddress((void**)&xbh, g_xb_hi);
    cudaGetSymbolAddress((void**)&xbl, g_xb_lo);
    cudaGetSymbolAddress((void**)&abh, g_ab_hi);
    cudaGetSymbolAddress((void**)&abl, g_ab_lo);
    cudaGetSymbolAddress((void**)&hbh, g_hb_hi);
    cudaGetSymbolAddress((void**)&hbl, g_hb_lo);

    cudaFuncSetAttribute(attn_mma_kernel,
                         cudaFuncAttributeMaxDynamicSharedMemorySize, ATT_SMEM);
    const int SMEM3 = 2 * 4 * TILE_B;
    const int SMEM2 = 2 * 3 * TILE_B;
    cudaFuncSetAttribute(gemm_mma_kernel<3>,
                         cudaFuncAttributeMaxDynamicSharedMemorySize, SMEM3);
    cudaFuncSetAttribute(gemm_mma_kernel<2>,
                         cudaFuncAttributeMaxDynamicSharedMemorySize, SMEM2);

    // 0. Weight transpose + split
    wt_transpose_kernel<<<dim3(QKV_N / 32, H_DIM / 32), 256>>>(w_qkv, wqkvh, wqkvl, H_DIM, QKV_N);
    wt_transpose_kernel<<<dim3(H_DIM / 32, (NQ * HD) / 32), 256>>>(w_o, woh, nullptr, NQ * HD, H_DIM);
    wt_transpose_kernel<<<dim3((2 * I_DIM) / 32, H_DIM / 32), 256>>>(w_gu, wguh, nullptr, H_DIM, 2 * I_DIM);
    wt_transpose_kernel<<<dim3(H_DIM / 32, I_DIM / 32), 256>>>(w_down, wdh, nullptr, I_DIM, H_DIM);

    // 1. RMSNorm 1 -> hi/lo
    rmsnorm_split_kernel<<<S_LEN, 256>>>(hidden, ln1, xbh, xbl);

    // 2. QKV projection (3-product)
    gemm_mma_kernel<3><<<dim3(S_LEN / BM, QKV_N / BN), 256, SMEM3>>>(
        xbh, xbl, wqkvh, wqkvl, qkv, S_LEN, QKV_N, H_DIM, nullptr, nullptr);

    // 3. RoPE + split qkv -> fp16 hi/lo planes
    {
        const int total = S_LEN * 3072;
        rope_split_kernel<<<(total + 255) / 256, 256>>>(qkv, qkvh, qkvl);
    }

    // 4. Tensor-core attention -> o-proj operands (hi/lo)
    attn_mma_kernel<<<dim3(S_LEN / BR, NQ), 256, ATT_SMEM>>>(qkvh, qkvl, abh, abl);

    // 5. O projection (2-product) + residual
    gemm_mma_kernel<2><<<dim3(S_LEN / BM, H_DIM / BN), 256, SMEM2>>>(
        abh, abl, woh, nullptr, resid, S_LEN, H_DIM, NQ * HD, hidden, out_resid);

    // 6. RMSNorm 2 -> hi/lo
    rmsnorm_split_kernel<<<S_LEN, 256>>>(resid, ln2, xbh, xbl);

    // 7. gate_up (2-product)
    gemm_mma_kernel<2><<<dim3(S_LEN / BM, (2 * I_DIM) / BN), 256, SMEM2>>>(
        xbh, xbl, wguh, nullptr, gu, S_LEN, 2 * I_DIM, H_DIM, nullptr, nullptr);

    // 8. SiLU * up -> hi/lo
    {
        const size_t total = (size_t)S_LEN * I_DIM / 4;
        silu_mul_split_kernel<<<(int)((total + 255) / 256), 256>>>(gu, hbh, hbl);
    }

    // 9. down (2-product) -> out
    gemm_mma_kernel<2><<<dim3(S_LEN / BM, H_DIM / BN), 256, SMEM2>>>(
        hbh, hbl, wdh, nullptr, out, S_LEN, H_DIM, I_DIM, nullptr, nullptr);
}

// round 8
// speedup vs baseline: 3.7429x; 1.2990x over previous
#include <cuda_runtime.h>
#include <cuda_fp16.h>
#include <math.h>
#include <stdint.h>

#define H_DIM 4096
#define S_LEN 2048
#define NQ 32
#define NKV 8
#define HD 128
#define I_DIM 14336
#define QKV_N ((NQ + 2 * NKV) * HD) /* 6144 */
#define EPS 1e-5f

// GEMM tiling (mma.sync path)
#define BM 128
#define BN 128
#define KC 32
#define ROWB 80                       // bytes per smem row (64B data + 16B pad)
#define TILE_B (128 * ROWB)

// Attention tiling
#define BR 128
#define BC 64
#define AROWB 272                     // 128 halves * 2B + 16B pad
#define ATT_SMEM (2 * BR * AROWB + 4 * BC * AROWB)   // 139264

// ---------------------------------------------------------------------------
// Scratch (device globals)
// ---------------------------------------------------------------------------
__device__ float g_qkv[(size_t)S_LEN * QKV_N];
__device__ float g_resid[(size_t)S_LEN * H_DIM];
__device__ float g_gu[(size_t)S_LEN * 2 * I_DIM];

__device__ __half g_qkvh[(size_t)S_LEN * QKV_N];
__device__ __half g_qkvl[(size_t)S_LEN * QKV_N];

__device__ __half g_wqkvT_hi[(size_t)QKV_N * H_DIM];
__device__ __half g_wqkvT_lo[(size_t)QKV_N * H_DIM];
__device__ __half g_woT_hi[(size_t)H_DIM * (NQ * HD)];
__device__ __half g_wguT_hi[(size_t)(2 * I_DIM) * H_DIM];
__device__ __half g_wdownT_hi[(size_t)H_DIM * I_DIM];

__device__ __half g_xb_hi[(size_t)S_LEN * H_DIM];
__device__ __half g_xb_lo[(size_t)S_LEN * H_DIM];
__device__ __half g_ab_hi[(size_t)S_LEN * NQ * HD];
__device__ __half g_ab_lo[(size_t)S_LEN * NQ * HD];
__device__ __half g_hb_hi[(size_t)S_LEN * I_DIM];

// ---------------------------------------------------------------------------
// PTX helpers
// ---------------------------------------------------------------------------
__device__ __forceinline__ uint32_t smem_u32(const void* p) {
    uint32_t a;
    asm("{ .reg .u64 t; cvta.to.shared.u64 t, %1; cvt.u32.u64 %0, t; }"
        : "=r"(a) : "l"(p));
    return a;
}
__device__ __forceinline__ void cp16(uint32_t saddr, const void* g) {
    asm volatile("cp.async.cg.shared.global [%0], [%1], 16;"
                 :: "r"(saddr), "l"(g) : "memory");
}
__device__ __forceinline__ void cp_commit() {
    asm volatile("cp.async.commit_group;" ::: "memory");
}
template <int N>
__device__ __forceinline__ void cp_wait() {
    asm volatile("cp.async.wait_group %0;" :: "n"(N) : "memory");
}
__device__ __forceinline__ void ldm4(uint32_t* r, uint32_t addr) {
    asm volatile("ldmatrix.sync.aligned.m8n8.x4.shared.b16 {%0,%1,%2,%3}, [%4];"
                 : "=r"(r[0]), "=r"(r[1]), "=r"(r[2]), "=r"(r[3]) : "r"(addr));
}
__device__ __forceinline__ void ldm4t(uint32_t* r, uint32_t addr) {
    asm volatile("ldmatrix.sync.aligned.m8n8.x4.trans.shared.b16 {%0,%1,%2,%3}, [%4];"
                 : "=r"(r[0]), "=r"(r[1]), "=r"(r[2]), "=r"(r[3]) : "r"(addr));
}
__device__ __forceinline__ void mma_f16(float* d, const uint32_t* a,
                                        const uint32_t* b) {
    asm volatile(
        "mma.sync.aligned.m16n8k16.row.col.f32.f16.f16.f32 "
        "{%0,%1,%2,%3}, {%4,%5,%6,%7}, {%8,%9}, {%0,%1,%2,%3};"
        : "+f"(d[0]), "+f"(d[1]), "+f"(d[2]), "+f"(d[3])
        : "r"(a[0]), "r"(a[1]), "r"(a[2]), "r"(a[3]), "r"(b[0]), "r"(b[1]));
}
__device__ __forceinline__ void split1(float x, __half& h, __half& l) {
    h = __float2half_rn(x);
    l = __float2half_rn(x - __half2float(h));
}
__device__ __forceinline__ void split4(float4 v, uint2& hi, uint2& lo) {
    __half h0, h1, h2, h3, l0, l1, l2, l3;
    split1(v.x, h0, l0); split1(v.y, h1, l1);
    split1(v.z, h2, l2); split1(v.w, h3, l3);
    hi.x = ((uint32_t)__half_as_ushort(h1) << 16) | __half_as_ushort(h0);
    hi.y = ((uint32_t)__half_as_ushort(h3) << 16) | __half_as_ushort(h2);
    lo.x = ((uint32_t)__half_as_ushort(l1) << 16) | __half_as_ushort(l0);
    lo.y = ((uint32_t)__half_as_ushort(l3) << 16) | __half_as_ushort(l2);
}
__device__ __forceinline__ uint32_t packh2(float a, float b) {
    __half2 h = __floats2half2_rn(a, b);
    return *(uint32_t*)&h;
}

// ---------------------------------------------------------------------------
// Weight transpose + split: W[K,N] fp32 -> Thi (and optional Tlo) [N,K] fp16
// ---------------------------------------------------------------------------
__global__ __launch_bounds__(256)
void wt_transpose_kernel(const float* __restrict__ W,
                         __half* __restrict__ Thi,
                         __half* __restrict__ Tlo, int K, int N)
{
    __shared__ float t[32][33];
    const int tx = threadIdx.x & 31, ty = threadIdx.x >> 5;
    const int n = blockIdx.x * 32 + tx;
#pragma unroll
    for (int i = 0; i < 4; i++) {
        const int k = blockIdx.y * 32 + ty + i * 8;
        t[ty + i * 8][tx] = W[(size_t)k * N + n];
    }
    __syncthreads();
    const int k2 = blockIdx.y * 32 + tx;
#pragma unroll
    for (int i = 0; i < 4; i++) {
        const int n2 = blockIdx.x * 32 + ty + i * 8;
        const float v = t[tx][ty + i * 8];
        __half h, l;
        split1(v, h, l);
        Thi[(size_t)n2 * K + k2] = h;
        if (Tlo) Tlo[(size_t)n2 * K + k2] = l;
    }
}

// ---------------------------------------------------------------------------
// RMSNorm + split output (lo plane optional)
// ---------------------------------------------------------------------------
__global__ __launch_bounds__(256)
void rmsnorm_split_kernel(const float* __restrict__ x, const float* __restrict__ w,
                          __half* __restrict__ ohi, __half* __restrict__ olo)
{
    const int row = blockIdx.x;
    const int t = threadIdx.x;
    const float4* xr = (const float4*)(x + (size_t)row * H_DIM);
    const float4* wr = (const float4*)w;

    float4 v[4];
    float ss = 0.f;
#pragma unroll
    for (int i = 0; i < 4; i++) {
        v[i] = xr[t + 256 * i];
        ss += v[i].x * v[i].x + v[i].y * v[i].y + v[i].z * v[i].z + v[i].w * v[i].w;
    }
#pragma unroll
    for (int o = 16; o; o >>= 1) ss += __shfl_xor_sync(0xffffffffu, ss, o);
    __shared__ float wsum[8];
    if ((t & 31) == 0) wsum[t >> 5] = ss;
    __syncthreads();
    float tot = wsum[0] + wsum[1] + wsum[2] + wsum[3] +
                wsum[4] + wsum[5] + wsum[6] + wsum[7];
    const float sc = rsqrtf(tot * (1.f / H_DIM) + EPS);

    uint2* hr = (uint2*)(ohi + (size_t)row * H_DIM);
    uint2* lr = (uint2*)(olo + (size_t)row * H_DIM);
#pragma unroll
    for (int i = 0; i < 4; i++) {
        float4 wv = wr[t + 256 * i];
        float4 r;
        r.x = v[i].x * sc * wv.x;
        r.y = v[i].y * sc * wv.y;
        r.z = v[i].z * sc * wv.z;
        r.w = v[i].w * sc * wv.w;
        uint2 h, l;
        split4(r, h, l);
        hr[t + 256 * i] = h;
        if (olo) lr[t + 256 * i] = l;
    }
}

// ---------------------------------------------------------------------------
// mma.sync fp16 hi/lo GEMM: C[M,N] = A[M,K] @ B^T  (B stored [N,K] fp16).
// NPROD=3: Ah*Bh+Ah*Bl+Al*Bh. NPROD=2: Ah*Bh+Al*Bh. NPROD=1: Ah*Bh.
// ---------------------------------------------------------------------------
template <int NPROD>
__global__ __launch_bounds__(256, 1)
void gemm_mma_kernel(const __half* __restrict__ Ahi,
                     const __half* __restrict__ Alo,
                     const __half* __restrict__ Bhi,
                     const __half* __restrict__ Blo,
                     float* __restrict__ C, int M, int N, int K,
                     const float* __restrict__ add, float* __restrict__ C2)
{
    constexpr int A_TILES = (NPROD >= 2) ? 2 : 1;
    constexpr int NTILES = A_TILES + ((NPROD == 3) ? 2 : 1);
    constexpr uint32_t STG = NTILES * TILE_B;
    extern __shared__ char smc[];
    const uint32_t sbase = smem_u32(smc);
    const int tid = threadIdx.x;
    const int lane = tid & 31;
    const int wm = (tid >> 5) & 3;
    const int wn = tid >> 7;
    const int m0 = blockIdx.x * BM;
    const int n0 = blockIdx.y * BN;
    const int NCH = K / KC;

    const int q0r = tid >> 2, q0c = tid & 3;
    const int q1r = (tid + 256) >> 2, q1c = tid & 3;

    float acc[2][8][4];
#pragma unroll
    for (int mt = 0; mt < 2; mt++)
#pragma unroll
        for (int nt = 0; nt < 8; nt++)
#pragma unroll
            for (int e = 0; e < 4; e++) acc[mt][nt][e] = 0.f;

    auto issue = [&](int kc, int buf) {
        const uint32_t st = sbase + buf * STG;
        const int kb = kc * KC;
        const size_t gA0 = (size_t)(m0 + q0r) * K + kb + q0c * 8;
        const size_t gA1 = (size_t)(m0 + q1r) * K + kb + q1c * 8;
        const size_t gB0 = (size_t)(n0 + q0r) * K + kb + q0c * 8;
        const size_t gB1 = (size_t)(n0 + q1r) * K + kb + q1c * 8;
        const uint32_t s0 = st + q0r * ROWB + q0c * 16;
        const uint32_t s1 = st + q1r * ROWB + q1c * 16;
        cp16(s0, Ahi + gA0);
        cp16(s1, Ahi + gA1);
        if (NPROD >= 2) {
            cp16(s0 + TILE_B, Alo + gA0);
            cp16(s1 + TILE_B, Alo + gA1);
        }
        cp16(s0 + A_TILES * TILE_B, Bhi + gB0);
        cp16(s1 + A_TILES * TILE_B, Bhi + gB1);
        if (NPROD == 3) {
            cp16(s0 + 3 * TILE_B, Blo + gB0);
            cp16(s1 + 3 * TILE_B, Blo + gB1);
        }
        cp_commit();
    };

    issue(0, 0);

    for (int kc = 0; kc < NCH; kc++) {
        if (kc + 1 < NCH) {
            issue(kc + 1, (kc + 1) & 1);
            cp_wait<1>();
        } else {
            cp_wait<0>();
        }
        __syncthreads();

        const uint32_t st = sbase + (kc & 1) * STG;
        const uint32_t sAh = st;
        const uint32_t sAl = st + TILE_B;              // valid only NPROD>=2
        const uint32_t sBh = st + A_TILES * TILE_B;
        const uint32_t sBl = st + 3 * TILE_B;          // valid only NPROD==3

        const int aRow = wm * 32 + (lane & 15);
        const int aKof = (lane >> 4) * 8;
        const int bIdx = lane & 7;
        const int bSel = lane >> 3;
        const int bRowBase = wn * 64 + ((bSel >> 1) * 8) + bIdx;
        const int bKof = (bSel & 1) * 8;

#pragma unroll
        for (int ks = 0; ks < KC; ks += 16) {
            uint32_t ah[2][4], al[2][4];
#pragma unroll
            for (int mt = 0; mt < 2; mt++) {
                const uint32_t off = (uint32_t)(aRow + mt * 16) * ROWB +
                                     (uint32_t)(ks + aKof) * 2;
                ldm4(ah[mt], sAh + off);
                if (NPROD >= 2) ldm4(al[mt], sAl + off);
            }
            uint32_t bh[8][2], bl[8][2];
#pragma unroll
            for (int p = 0; p < 4; p++) {
                const uint32_t off = (uint32_t)(bRowBase + p * 16) * ROWB +
                                     (uint32_t)(ks + bKof) * 2;
                uint32_t r4[4];
                ldm4(r4, sBh + off);
                bh[2 * p][0] = r4[0]; bh[2 * p][1] = r4[1];
                bh[2 * p + 1][0] = r4[2]; bh[2 * p + 1][1] = r4[3];
                if (NPROD == 3) {
                    ldm4(r4, sBl + off);
                    bl[2 * p][0] = r4[0]; bl[2 * p][1] = r4[1];
                    bl[2 * p + 1][0] = r4[2]; bl[2 * p + 1][1] = r4[3];
                }
            }
#pragma unroll
            for (int mt = 0; mt < 2; mt++)
#pragma unroll
                for (int nt = 0; nt < 8; nt++) {
                    mma_f16(acc[mt][nt], ah[mt], bh[nt]);
                    if (NPROD >= 2) mma_f16(acc[mt][nt], al[mt], bh[nt]);
                    if (NPROD == 3) mma_f16(acc[mt][nt], ah[mt], bl[nt]);
                }
        }
        __syncthreads();
    }

    const int erow = m0 + wm * 32 + (lane >> 2);
    const int ecol = n0 + wn * 64 + (lane & 3) * 2;
#pragma unroll
    for (int mt = 0; mt < 2; mt++) {
#pragma unroll
        for (int nt = 0; nt < 8; nt++) {
            const int r0 = erow + mt * 16;
            const int c = ecol + nt * 8;
            const size_t off0 = (size_t)r0 * N + c;
            const size_t off1 = (size_t)(r0 + 8) * N + c;
            float2 v0 = make_float2(acc[mt][nt][0], acc[mt][nt][1]);
            float2 v1 = make_float2(acc[mt][nt][2], acc[mt][nt][3]);
            if (add) {
                float2 a0 = *(const float2*)(add + off0);
                float2 a1 = *(const float2*)(add + off1);
                v0.x += a0.x; v0.y += a0.y;
                v1.x += a1.x; v1.y += a1.y;
            }
            *(float2*)(C + off0) = v0;
            *(float2*)(C + off1) = v1;
            if (C2) {
                *(float2*)(C2 + off0) = v0;
                *(float2*)(C2 + off1) = v1;
            }
        }
    }
}

// ---------------------------------------------------------------------------
// RoPE + split qkv fp32 -> fp16 hi/lo planes (v passthrough-split)
// ---------------------------------------------------------------------------
__global__ void rope_split_kernel(const float* __restrict__ qkv,
                                  __half* __restrict__ oh,
                                  __half* __restrict__ ol)
{
    const int idx = blockIdx.x * blockDim.x + threadIdx.x;
    const int total = S_LEN * 3072;
    if (idx >= total) return;
    const int slot = idx % 3072;
    const int s = idx / 3072;
    const size_t rb = (size_t)s * QKV_N;

    if (slot < 2560) {
        const int head = slot >> 6;
        const int d = slot & 63;
        const int col = head * HD + d;
        const float inv = exp2f((float)d * (-13.287712379549449f / 64.f));
        const float ang = (float)s * inv;
        float sn, c;
        sincosf(ang, &sn, &c);
        const float x1 = qkv[rb + col];
        const float x2 = qkv[rb + col + 64];
        const float y1 = x1 * c - x2 * sn;
        const float y2 = x2 * c + x1 * sn;
        __half h1, l1, h2, l2;
        split1(y1, h1, l1);
        split1(y2, h2, l2);
        oh[rb + col] = h1; oh[rb + col + 64] = h2;
        ol[rb + col] = l1; ol[rb + col + 64] = l2;
    } else {
        const int c0 = 5120 + (slot - 2560) * 2;
        const float x1 = qkv[rb + c0];
        const float x2 = qkv[rb + c0 + 1];
        __half h1, l1, h2, l2;
        split1(x1, h1, l1);
        split1(x2, h2, l2);
        oh[rb + c0] = h1; oh[rb + c0 + 1] = h2;
        ol[rb + c0] = l1; ol[rb + c0 + 1] = l2;
    }
}

// ---------------------------------------------------------------------------
// Tensor-core flash attention (fp16 hi/lo, 3-product; unchanged from R7)
// ---------------------------------------------------------------------------
__global__ __launch_bounds__(256, 1)
void attn_mma_kernel(const __half* __restrict__ qph,
                     const __half* __restrict__ qpl,
                     __half* __restrict__ outh, __half* __restrict__ outl)
{
    extern __shared__ char smc[];
    const uint32_t sb = smem_u32(smc);
    const uint32_t sQh = sb;
    const uint32_t sQl = sb + BR * AROWB;
    const uint32_t sKh = sb + 2 * BR * AROWB;
    const uint32_t sKl = sKh + BC * AROWB;
    const uint32_t sVh = sKl + BC * AROWB;
    const uint32_t sVl = sVh + BC * AROWB;

    const int tid = threadIdx.x;
    const int lane = tid & 31;
    const int warp = tid >> 5;
    const int mb = blockIdx.x;
    const int head = blockIdx.y;
    const int kh = head >> 2;
    const float scale = 0.088388347648318447f;

    const int qcol = head * HD;
    const int kcol = NQ * HD + kh * HD;
    const int vcol = (NQ + NKV) * HD + kh * HD;

    {
        const int chunk = tid & 15;
        const int rbase = tid >> 4;
#pragma unroll
        for (int i = 0; i < 8; i++) {
            const int row = rbase + i * 16;
            const size_t g = (size_t)(mb * BR + row) * QKV_N + qcol + chunk * 8;
            const uint32_t so = row * AROWB + chunk * 16;
            cp16(sQh + so, qph + g);
            cp16(sQl + so, qpl + g);
        }
    }
    cp_commit();

    float m0 = -1e30f, m1 = -1e30f, l0 = 0.f, l1 = 0.f;
    float acc_o[16][4];
#pragma unroll
    for (int nt = 0; nt < 16; nt++)
#pragma unroll
        for (int e = 0; e < 4; e++) acc_o[nt][e] = 0.f;

    const int aRow = warp * 16 + (lane & 15);
    const int aKof = (lane >> 4) * 8;
    const int bIdx = lane & 7;
    const int bSel = lane >> 3;
    const int bRowBase = (bSel >> 1) * 8 + bIdx;
    const int bKof = (bSel & 1) * 8;
    const int vRow = lane & 15;
    const int vCof = (lane >> 4) * 8;

    const int r0 = lane >> 2;
    const int cq = lane & 3;
    const int grow0 = mb * BR + warp * 16 + r0;
    const int grow1 = grow0 + 8;

    const int ntiles = 2 * mb + 2;
    for (int nb = 0; nb < ntiles; nb++) {
        __syncthreads();
        {
            const int chunk = tid & 15;
            const int rbase = tid >> 4;
#pragma unroll
            for (int i = 0; i < 4; i++) {
                const int row = rbase + i * 16;
                const size_t gk = (size_t)(nb * BC + row) * QKV_N + kcol + chunk * 8;
                const size_t gv = (size_t)(nb * BC + row) * QKV_N + vcol + chunk * 8;
                const uint32_t so = row * AROWB + chunk * 16;
                cp16(sKh + so, qph + gk);
                cp16(sKl + so, qpl + gk);
                cp16(sVh + so, qph + gv);
                cp16(sVl + so, qpl + gv);
            }
        }
        cp_commit();
        cp_wait<0>();
        __syncthreads();

        float accs[8][4];
#pragma unroll
        for (int nt = 0; nt < 8; nt++)
#pragma unroll
            for (int e = 0; e < 4; e++) accs[nt][e] = 0.f;

#pragma unroll
        for (int ks = 0; ks < 8; ks++) {
            uint32_t aqh[4], aql[4];
            const uint32_t aoff = (uint32_t)aRow * AROWB + (uint32_t)(ks * 16 + aKof) * 2;
            ldm4(aqh, sQh + aoff);
            ldm4(aql, sQl + aoff);
            uint32_t bh[8][2], bl[8][2];
#pragma unroll
            for (int p = 0; p < 4; p++) {
                const uint32_t boff = (uint32_t)(bRowBase + p * 16) * AROWB +
                                      (uint32_t)(ks * 16 + bKof) * 2;
                uint32_t r4[4];
                ldm4(r4, sKh + boff);
                bh[2 * p][0] = r4[0]; bh[2 * p][1] = r4[1];
                bh[2 * p + 1][0] = r4[2]; bh[2 * p + 1][1] = r4[3];
                ldm4(r4, sKl + boff);
                bl[2 * p][0] = r4[0]; bl[2 * p][1] = r4[1];
                bl[2 * p + 1][0] = r4[2]; bl[2 * p + 1][1] = r4[3];
            }
#pragma unroll
            for (int nt = 0; nt < 8; nt++) {
                mma_f16(accs[nt], aqh, bh[nt]);
                mma_f16(accs[nt], aqh, bl[nt]);
                mma_f16(accs[nt], aql, bh[nt]);
            }
        }

        float rmax0 = -1e30f, rmax1 = -1e30f;
#pragma unroll
        for (int nt = 0; nt < 8; nt++) {
            const int cbase = nb * BC + nt * 8 + cq * 2;
#pragma unroll
            for (int e = 0; e < 4; e++) {
                float s = accs[nt][e] * scale;
                const int col = cbase + (e & 1);
                const int row = (e < 2) ? grow0 : grow1;
                if (col > row) s = -1e30f;
                accs[nt][e] = s;
            }
            rmax0 = fmaxf(rmax0, fmaxf(accs[nt][0], accs[nt][1]));
            rmax1 = fmaxf(rmax1, fmaxf(accs[nt][2], accs[nt][3]));
        }
        rmax0 = fmaxf(rmax0, __shfl_xor_sync(0xffffffffu, rmax0, 1));
        rmax0 = fmaxf(rmax0, __shfl_xor_sync(0xffffffffu, rmax0, 2));
        rmax1 = fmaxf(rmax1, __shfl_xor_sync(0xffffffffu, rmax1, 1));
        rmax1 = fmaxf(rmax1, __shfl_xor_sync(0xffffffffu, rmax1, 2));
        const float mn0 = fmaxf(m0, rmax0), mn1 = fmaxf(m1, rmax1);
        const float cf0 = __expf(m0 - mn0), cf1 = __expf(m1 - mn1);
        m0 = mn0; m1 = mn1;
        float s0 = 0.f, s1 = 0.f;
#pragma unroll
        for (int nt = 0; nt < 8; nt++) {
            accs[nt][0] = __expf(accs[nt][0] - mn0);
            accs[nt][1] = __expf(accs[nt][1] - mn0);
            accs[nt][2] = __expf(accs[nt][2] - mn1);
            accs[nt][3] = __expf(accs[nt][3] - mn1);
            s0 += accs[nt][0] + accs[nt][1];
            s1 += accs[nt][2] + accs[nt][3];
        }
        s0 += __shfl_xor_sync(0xffffffffu, s0, 1);
        s0 += __shfl_xor_sync(0xffffffffu, s0, 2);
        s1 += __shfl_xor_sync(0xffffffffu, s1, 1);
        s1 += __shfl_xor_sync(0xffffffffu, s1, 2);
        l0 = l0 * cf0 + s0;
        l1 = l1 * cf1 + s1;
#pragma unroll
        for (int nt = 0; nt < 16; nt++) {
            acc_o[nt][0] *= cf0; acc_o[nt][1] *= cf0;
            acc_o[nt][2] *= cf1; acc_o[nt][3] *= cf1;
        }

#pragma unroll
        for (int kb = 0; kb < 4; kb++) {
            uint32_t ph[4], pl[4];
            {
                const float* s0p = accs[2 * kb];
                const float* s1p = accs[2 * kb + 1];
                float h00 = __half2float(__float2half_rn(s0p[0]));
                float h01 = __half2float(__float2half_rn(s0p[1]));
                float h02 = __half2float(__float2half_rn(s0p[2]));
                float h03 = __half2float(__float2half_rn(s0p[3]));
                float h10 = __half2float(__float2half_rn(s1p[0]));
                float h11 = __half2float(__float2half_rn(s1p[1]));
                float h12 = __half2float(__float2half_rn(s1p[2]));
                float h13 = __half2float(__float2half_rn(s1p[3]));
                ph[0] = packh2(s0p[0], s0p[1]);
                ph[1] = packh2(s0p[2], s0p[3]);
                ph[2] = packh2(s1p[0], s1p[1]);
                ph[3] = packh2(s1p[2], s1p[3]);
                pl[0] = packh2(s0p[0] - h00, s0p[1] - h01);
                pl[1] = packh2(s0p[2] - h02, s0p[3] - h03);
                pl[2] = packh2(s1p[0] - h10, s1p[1] - h11);
                pl[3] = packh2(s1p[2] - h12, s1p[3] - h13);
            }
#pragma unroll
            for (int np = 0; np < 8; np++) {
                const uint32_t voff = (uint32_t)(kb * 16 + vRow) * AROWB +
                                      (uint32_t)(np * 16 + vCof) * 2;
                uint32_t rv[4], rl[4];
                ldm4t(rv, sVh + voff);
                ldm4t(rl, sVl + voff);
                uint32_t vh0[2] = {rv[0], rv[1]};
                uint32_t vh1[2] = {rv[2], rv[3]};
                uint32_t vl0[2] = {rl[0], rl[1]};
                uint32_t vl1[2] = {rl[2], rl[3]};
                mma_f16(acc_o[2 * np], ph, vh0);
                mma_f16(acc_o[2 * np], ph, vl0);
                mma_f16(acc_o[2 * np], pl, vh0);
                mma_f16(acc_o[2 * np + 1], ph, vh1);
                mma_f16(acc_o[2 * np + 1], ph, vl1);
                mma_f16(acc_o[2 * np + 1], pl, vh1);
            }
        }
    }

    const float inv0 = 1.f / l0, inv1 = 1.f / l1;
#pragma unroll
    for (int nt = 0; nt < 16; nt++) {
        const float v00 = acc_o[nt][0] * inv0;
        const float v01 = acc_o[nt][1] * inv0;
        const float v10 = acc_o[nt][2] * inv1;
        const float v11 = acc_o[nt][3] * inv1;
        const size_t o0 = (size_t)grow0 * (NQ * HD) + qcol + nt * 8 + cq * 2;
        const size_t o1 = (size_t)grow1 * (NQ * HD) + qcol + nt * 8 + cq * 2;
        const uint32_t h0 = packh2(v00, v01);
        const uint32_t h1 = packh2(v10, v11);
        *(uint32_t*)&outh[o0] = h0;
        *(uint32_t*)&outh[o1] = h1;
        const __half2* hp0 = (const __half2*)&h0;
        const __half2* hp1 = (const __half2*)&h1;
        *(uint32_t*)&outl[o0] = packh2(v00 - __half2float(hp0->x),
                                       v01 - __half2float(hp0->y));
        *(uint32_t*)&outl[o1] = packh2(v10 - __half2float(hp1->x),
                                       v11 - __half2float(hp1->y));
    }
}

// ---------------------------------------------------------------------------
// SiLU(gate)*up -> fp16 (hi only; down GEMM is 1-product)
// ---------------------------------------------------------------------------
__global__ void silu_mul_split_kernel(const float* __restrict__ gu,
                                      __half* __restrict__ hhi)
{
    const size_t idx = (size_t)blockIdx.x * blockDim.x + threadIdx.x;
    const size_t total = (size_t)S_LEN * I_DIM / 4;
    if (idx >= total) return;
    const size_t row = idx / (I_DIM / 4);
    const size_t c4 = (idx % (I_DIM / 4)) * 4;
    const float4 g = *(const float4*)(gu + row * 2 * I_DIM + c4);
    const float4 u = *(const float4*)(gu + row * 2 * I_DIM + I_DIM + c4);
    float4 r;
    r.x = g.x / (1.f + __expf(-g.x)) * u.x;
    r.y = g.y / (1.f + __expf(-g.y)) * u.y;
    r.z = g.z / (1.f + __expf(-g.z)) * u.z;
    r.w = g.w / (1.f + __expf(-g.w)) * u.w;
    uint2 h, l;
    split4(r, h, l);
    ((uint2*)(hhi + row * I_DIM))[c4 / 4] = h;
}

// ---------------------------------------------------------------------------
// Launch
// ---------------------------------------------------------------------------
extern "C" void kernel_launch(void* const* d_in, const int* in_sizes, int n_in,
                              void* d_out, int out_size)
{
    (void)in_sizes; (void)n_in;
    const float* hidden = (const float*)d_in[1];
    const float* w_qkv = (const float*)d_in[2];
    const float* w_o = (const float*)d_in[3];
    const float* w_gu = (const float*)d_in[4];
    const float* w_down = (const float*)d_in[5];
    const float* ln1 = (const float*)d_in[6];
    const float* ln2 = (const float*)d_in[7];

    float* out = (float*)d_out;
    const size_t SH = (size_t)S_LEN * H_DIM;
    float* out_resid = ((size_t)out_size >= 2 * SH) ? (out + SH) : nullptr;

    float *qkv, *resid, *gu;
    cudaGetSymbolAddress((void**)&qkv, g_qkv);
    cudaGetSymbolAddress((void**)&resid, g_resid);
    cudaGetSymbolAddress((void**)&gu, g_gu);
    __half *qkvh, *qkvl;
    cudaGetSymbolAddress((void**)&qkvh, g_qkvh);
    cudaGetSymbolAddress((void**)&qkvl, g_qkvl);
    __half *wqkvh, *wqkvl, *woh, *wguh, *wdh;
    __half *xbh, *xbl, *abh, *abl, *hbh;
    cudaGetSymbolAddress((void**)&wqkvh, g_wqkvT_hi);
    cudaGetSymbolAddress((void**)&wqkvl, g_wqkvT_lo);
    cudaGetSymbolAddress((void**)&woh, g_woT_hi);
    cudaGetSymbolAddress((void**)&wguh, g_wguT_hi);
    cudaGetSymbolAddress((void**)&wdh, g_wdownT_hi);
    cudaGetSymbolAddress((void**)&xbh, g_xb_hi);
    cudaGetSymbolAddress((void**)&xbl, g_xb_lo);
    cudaGetSymbolAddress((void**)&abh, g_ab_hi);
    cudaGetSymbolAddress((void**)&abl, g_ab_lo);
    cudaGetSymbolAddress((void**)&hbh, g_hb_hi);

    cudaFuncSetAttribute(attn_mma_kernel,
                         cudaFuncAttributeMaxDynamicSharedMemorySize, ATT_SMEM);
    const int SMEM3 = 2 * 4 * TILE_B;
    const int SMEM2 = 2 * 3 * TILE_B;
    const int SMEM1 = 2 * 2 * TILE_B;
    cudaFuncSetAttribute(gemm_mma_kernel<3>,
                         cudaFuncAttributeMaxDynamicSharedMemorySize, SMEM3);
    cudaFuncSetAttribute(gemm_mma_kernel<2>,
                         cudaFuncAttributeMaxDynamicSharedMemorySize, SMEM2);
    cudaFuncSetAttribute(gemm_mma_kernel<1>,
                         cudaFuncAttributeMaxDynamicSharedMemorySize, SMEM1);

    // 0. Weight transpose + split
    wt_transpose_kernel<<<dim3(QKV_N / 32, H_DIM / 32), 256>>>(w_qkv, wqkvh, wqkvl, H_DIM, QKV_N);
    wt_transpose_kernel<<<dim3(H_DIM / 32, (NQ * HD) / 32), 256>>>(w_o, woh, nullptr, NQ * HD, H_DIM);
    wt_transpose_kernel<<<dim3((2 * I_DIM) / 32, H_DIM / 32), 256>>>(w_gu, wguh, nullptr, H_DIM, 2 * I_DIM);
    wt_transpose_kernel<<<dim3(H_DIM / 32, I_DIM / 32), 256>>>(w_down, wdh, nullptr, I_DIM, H_DIM);

    // 1. RMSNorm 1 -> hi/lo
    rmsnorm_split_kernel<<<S_LEN, 256>>>(hidden, ln1, xbh, xbl);

    // 2. QKV projection (3-product)
    gemm_mma_kernel<3><<<dim3(S_LEN / BM, QKV_N / BN), 256, SMEM3>>>(
        xbh, xbl, wqkvh, wqkvl, qkv, S_LEN, QKV_N, H_DIM, nullptr, nullptr);

    // 3. RoPE + split qkv -> fp16 hi/lo planes
    {
        const int total = S_LEN * 3072;
        rope_split_kernel<<<(total + 255) / 256, 256>>>(qkv, qkvh, qkvl);
    }

    // 4. Tensor-core attention -> o-proj operands (hi/lo)
    attn_mma_kernel<<<dim3(S_LEN / BR, NQ), 256, ATT_SMEM>>>(qkvh, qkvl, abh, abl);

    // 5. O projection (2-product) + residual
    gemm_mma_kernel<2><<<dim3(S_LEN / BM, H_DIM / BN), 256, SMEM2>>>(
        abh, abl, woh, nullptr, resid, S_LEN, H_DIM, NQ * HD, hidden, out_resid);

    // 6. RMSNorm 2 -> hi only (gate_up is 1-product)
    rmsnorm_split_kernel<<<S_LEN, 256>>>(resid, ln2, xbh, nullptr);

    // 7. gate_up (1-product)
    gemm_mma_kernel<1><<<dim3(S_LEN / BM, (2 * I_DIM) / BN), 256, SMEM1>>>(
        xbh, nullptr, wguh, nullptr, gu, S_LEN, 2 * I_DIM, H_DIM, nullptr, nullptr);

    // 8. SiLU * up -> hi only
    {
        const size_t total = (size_t)S_LEN * I_DIM / 4;
        silu_mul_split_kernel<<<(int)((total + 255) / 256), 256>>>(gu, hbh);
    }

    // 9. down (1-product) -> out
    gemm_mma_kernel<1><<<dim3(S_LEN / BM, H_DIM / BN), 256, SMEM1>>>(
        hbh, nullptr, wdh, nullptr, out, S_LEN, H_DIM, I_DIM, nullptr, nullptr);
}

// round 9
// speedup vs baseline: 4.2400x; 1.1328x over previous
#include <cuda_runtime.h>
#include <cuda_fp16.h>
#include <math.h>
#include <stdint.h>

#define H_DIM 4096
#define S_LEN 2048
#define NQ 32
#define NKV 8
#define HD 128
#define I_DIM 14336
#define QKV_N ((NQ + 2 * NKV) * HD) /* 6144 */
#define EPS 1e-5f

// GEMM tiling (mma.sync path)
#define BM 128
#define BN 128
#define KC 32
#define ROWB 80                       // bytes per smem row (64B data + 16B pad)
#define TILE_B (128 * ROWB)

// Attention tiling
#define BR 128
#define BC 64
#define AROWB 272
#define ATT_SMEM (2 * BR * AROWB + 4 * BC * AROWB)   // 139264

// ---------------------------------------------------------------------------
// Scratch (device globals)
// ---------------------------------------------------------------------------
__device__ float g_qkv[(size_t)S_LEN * QKV_N];
__device__ float g_resid[(size_t)S_LEN * H_DIM];

__device__ __half g_qkvh[(size_t)S_LEN * QKV_N];
__device__ __half g_qkvl[(size_t)S_LEN * QKV_N];

__device__ __half g_wqkvT_hi[(size_t)QKV_N * H_DIM];
__device__ __half g_woT_hi[(size_t)H_DIM * (NQ * HD)];
__device__ __half g_wguT_hi[(size_t)(2 * I_DIM) * H_DIM];
__device__ __half g_wdownT_hi[(size_t)H_DIM * I_DIM];

__device__ __half g_xb_hi[(size_t)S_LEN * H_DIM];
__device__ __half g_xb_lo[(size_t)S_LEN * H_DIM];
__device__ __half g_ab_hi[(size_t)S_LEN * NQ * HD];
__device__ __half g_ab_lo[(size_t)S_LEN * NQ * HD];
__device__ __half g_hb_hi[(size_t)S_LEN * I_DIM];

// ---------------------------------------------------------------------------
// PTX helpers
// ---------------------------------------------------------------------------
__device__ __forceinline__ uint32_t smem_u32(const void* p) {
    uint32_t a;
    asm("{ .reg .u64 t; cvta.to.shared.u64 t, %1; cvt.u32.u64 %0, t; }"
        : "=r"(a) : "l"(p));
    return a;
}
__device__ __forceinline__ void cp16(uint32_t saddr, const void* g) {
    asm volatile("cp.async.cg.shared.global [%0], [%1], 16;"
                 :: "r"(saddr), "l"(g) : "memory");
}
__device__ __forceinline__ void cp_commit() {
    asm volatile("cp.async.commit_group;" ::: "memory");
}
template <int N>
__device__ __forceinline__ void cp_wait() {
    asm volatile("cp.async.wait_group %0;" :: "n"(N) : "memory");
}
__device__ __forceinline__ void ldm4(uint32_t* r, uint32_t addr) {
    asm volatile("ldmatrix.sync.aligned.m8n8.x4.shared.b16 {%0,%1,%2,%3}, [%4];"
                 : "=r"(r[0]), "=r"(r[1]), "=r"(r[2]), "=r"(r[3]) : "r"(addr));
}
__device__ __forceinline__ void ldm4t(uint32_t* r, uint32_t addr) {
    asm volatile("ldmatrix.sync.aligned.m8n8.x4.trans.shared.b16 {%0,%1,%2,%3}, [%4];"
                 : "=r"(r[0]), "=r"(r[1]), "=r"(r[2]), "=r"(r[3]) : "r"(addr));
}
__device__ __forceinline__ void mma_f16(float* d, const uint32_t* a,
                                        const uint32_t* b) {
    asm volatile(
        "mma.sync.aligned.m16n8k16.row.col.f32.f16.f16.f32 "
        "{%0,%1,%2,%3}, {%4,%5,%6,%7}, {%8,%9}, {%0,%1,%2,%3};"
        : "+f"(d[0]), "+f"(d[1]), "+f"(d[2]), "+f"(d[3])
        : "r"(a[0]), "r"(a[1]), "r"(a[2]), "r"(a[3]), "r"(b[0]), "r"(b[1]));
}
__device__ __forceinline__ void split1(float x, __half& h, __half& l) {
    h = __float2half_rn(x);
    l = __float2half_rn(x - __half2float(h));
}
__device__ __forceinline__ void split4(float4 v, uint2& hi, uint2& lo) {
    __half h0, h1, h2, h3, l0, l1, l2, l3;
    split1(v.x, h0, l0); split1(v.y, h1, l1);
    split1(v.z, h2, l2); split1(v.w, h3, l3);
    hi.x = ((uint32_t)__half_as_ushort(h1) << 16) | __half_as_ushort(h0);
    hi.y = ((uint32_t)__half_as_ushort(h3) << 16) | __half_as_ushort(h2);
    lo.x = ((uint32_t)__half_as_ushort(l1) << 16) | __half_as_ushort(l0);
    lo.y = ((uint32_t)__half_as_ushort(l3) << 16) | __half_as_ushort(l2);
}
__device__ __forceinline__ uint32_t packh2(float a, float b) {
    __half2 h = __floats2half2_rn(a, b);
    return *(uint32_t*)&h;
}
__device__ __forceinline__ float silu_mul(float g, float u) {
    return g / (1.f + __expf(-g)) * u;
}

// ---------------------------------------------------------------------------
// Weight transpose + split: W[K,N] fp32 -> Thi (and optional Tlo) [N,K] fp16
// ---------------------------------------------------------------------------
__global__ __launch_bounds__(256)
void wt_transpose_kernel(const float* __restrict__ W,
                         __half* __restrict__ Thi,
                         __half* __restrict__ Tlo, int K, int N)
{
    __shared__ float t[32][33];
    const int tx = threadIdx.x & 31, ty = threadIdx.x >> 5;
    const int n = blockIdx.x * 32 + tx;
#pragma unroll
    for (int i = 0; i < 4; i++) {
        const int k = blockIdx.y * 32 + ty + i * 8;
        t[ty + i * 8][tx] = W[(size_t)k * N + n];
    }
    __syncthreads();
    const int k2 = blockIdx.y * 32 + tx;
#pragma unroll
    for (int i = 0; i < 4; i++) {
        const int n2 = blockIdx.x * 32 + ty + i * 8;
        const float v = t[tx][ty + i * 8];
        __half h, l;
        split1(v, h, l);
        Thi[(size_t)n2 * K + k2] = h;
        if (Tlo) Tlo[(size_t)n2 * K + k2] = l;
    }
}

// ---------------------------------------------------------------------------
// RMSNorm + split output (lo plane optional)
// ---------------------------------------------------------------------------
__global__ __launch_bounds__(256)
void rmsnorm_split_kernel(const float* __restrict__ x, const float* __restrict__ w,
                          __half* __restrict__ ohi, __half* __restrict__ olo)
{
    const int row = blockIdx.x;
    const int t = threadIdx.x;
    const float4* xr = (const float4*)(x + (size_t)row * H_DIM);
    const float4* wr = (const float4*)w;

    float4 v[4];
    float ss = 0.f;
#pragma unroll
    for (int i = 0; i < 4; i++) {
        v[i] = xr[t + 256 * i];
        ss += v[i].x * v[i].x + v[i].y * v[i].y + v[i].z * v[i].z + v[i].w * v[i].w;
    }
#pragma unroll
    for (int o = 16; o; o >>= 1) ss += __shfl_xor_sync(0xffffffffu, ss, o);
    __shared__ float wsum[8];
    if ((t & 31) == 0) wsum[t >> 5] = ss;
    __syncthreads();
    float tot = wsum[0] + wsum[1] + wsum[2] + wsum[3] +
                wsum[4] + wsum[5] + wsum[6] + wsum[7];
    const float sc = rsqrtf(tot * (1.f / H_DIM) + EPS);

    uint2* hr = (uint2*)(ohi + (size_t)row * H_DIM);
    uint2* lr = (uint2*)(olo + (size_t)row * H_DIM);
#pragma unroll
    for (int i = 0; i < 4; i++) {
        float4 wv = wr[t + 256 * i];
        float4 r;
        r.x = v[i].x * sc * wv.x;
        r.y = v[i].y * sc * wv.y;
        r.z = v[i].z * sc * wv.z;
        r.w = v[i].w * sc * wv.w;
        uint2 h, l;
        split4(r, h, l);
        hr[t + 256 * i] = h;
        if (olo) lr[t + 256 * i] = l;
    }
}

// ---------------------------------------------------------------------------
// mma.sync fp16 hi/lo GEMM: C[M,N] = A[M,K] @ B^T  (B stored [N,K] fp16).
// NPROD=2: Ah*Bh+Al*Bh. NPROD=1: Ah*Bh.
// ---------------------------------------------------------------------------
template <int NPROD>
__global__ __launch_bounds__(256, 1)
void gemm_mma_kernel(const __half* __restrict__ Ahi,
                     const __half* __restrict__ Alo,
                     const __half* __restrict__ Bhi,
                     float* __restrict__ C, int M, int N, int K,
                     const float* __restrict__ add, float* __restrict__ C2)
{
    constexpr int A_TILES = (NPROD >= 2) ? 2 : 1;
    constexpr int NTILES = A_TILES + 1;
    constexpr uint32_t STG = NTILES * TILE_B;
    extern __shared__ char smc[];
    const uint32_t sbase = smem_u32(smc);
    const int tid = threadIdx.x;
    const int lane = tid & 31;
    const int wm = (tid >> 5) & 3;
    const int wn = tid >> 7;
    const int m0 = blockIdx.x * BM;
    const int n0 = blockIdx.y * BN;
    const int NCH = K / KC;

    const int q0r = tid >> 2, q0c = tid & 3;
    const int q1r = (tid + 256) >> 2, q1c = tid & 3;

    float acc[2][8][4];
#pragma unroll
    for (int mt = 0; mt < 2; mt++)
#pragma unroll
        for (int nt = 0; nt < 8; nt++)
#pragma unroll
            for (int e = 0; e < 4; e++) acc[mt][nt][e] = 0.f;

    auto issue = [&](int kc, int buf) {
        const uint32_t st = sbase + buf * STG;
        const int kb = kc * KC;
        const size_t gA0 = (size_t)(m0 + q0r) * K + kb + q0c * 8;
        const size_t gA1 = (size_t)(m0 + q1r) * K + kb + q1c * 8;
        const size_t gB0 = (size_t)(n0 + q0r) * K + kb + q0c * 8;
        const size_t gB1 = (size_t)(n0 + q1r) * K + kb + q1c * 8;
        const uint32_t s0 = st + q0r * ROWB + q0c * 16;
        const uint32_t s1 = st + q1r * ROWB + q1c * 16;
        cp16(s0, Ahi + gA0);
        cp16(s1, Ahi + gA1);
        if (NPROD >= 2) {
            cp16(s0 + TILE_B, Alo + gA0);
            cp16(s1 + TILE_B, Alo + gA1);
        }
        cp16(s0 + A_TILES * TILE_B, Bhi + gB0);
        cp16(s1 + A_TILES * TILE_B, Bhi + gB1);
        cp_commit();
    };

    issue(0, 0);

    for (int kc = 0; kc < NCH; kc++) {
        if (kc + 1 < NCH) {
            issue(kc + 1, (kc + 1) & 1);
            cp_wait<1>();
        } else {
            cp_wait<0>();
        }
        __syncthreads();

        const uint32_t st = sbase + (kc & 1) * STG;
        const uint32_t sAh = st;
        const uint32_t sAl = st + TILE_B;
        const uint32_t sBh = st + A_TILES * TILE_B;

        const int aRow = wm * 32 + (lane & 15);
        const int aKof = (lane >> 4) * 8;
        const int bIdx = lane & 7;
        const int bSel = lane >> 3;
        const int bRowBase = wn * 64 + ((bSel >> 1) * 8) + bIdx;
        const int bKof = (bSel & 1) * 8;

#pragma unroll
        for (int ks = 0; ks < KC; ks += 16) {
            uint32_t ah[2][4], al[2][4];
#pragma unroll
            for (int mt = 0; mt < 2; mt++) {
                const uint32_t off = (uint32_t)(aRow + mt * 16) * ROWB +
                                     (uint32_t)(ks + aKof) * 2;
                ldm4(ah[mt], sAh + off);
                if (NPROD >= 2) ldm4(al[mt], sAl + off);
            }
            uint32_t bh[8][2];
#pragma unroll
            for (int p = 0; p < 4; p++) {
                const uint32_t off = (uint32_t)(bRowBase + p * 16) * ROWB +
                                     (uint32_t)(ks + bKof) * 2;
                uint32_t r4[4];
                ldm4(r4, sBh + off);
                bh[2 * p][0] = r4[0]; bh[2 * p][1] = r4[1];
                bh[2 * p + 1][0] = r4[2]; bh[2 * p + 1][1] = r4[3];
            }
#pragma unroll
            for (int mt = 0; mt < 2; mt++)
#pragma unroll
                for (int nt = 0; nt < 8; nt++) {
                    mma_f16(acc[mt][nt], ah[mt], bh[nt]);
                    if (NPROD >= 2) mma_f16(acc[mt][nt], al[mt], bh[nt]);
                }
        }
        __syncthreads();
    }

    const int erow = m0 + wm * 32 + (lane >> 2);
    const int ecol = n0 + wn * 64 + (lane & 3) * 2;
#pragma unroll
    for (int mt = 0; mt < 2; mt++) {
#pragma unroll
        for (int nt = 0; nt < 8; nt++) {
            const int r0 = erow + mt * 16;
            const int c = ecol + nt * 8;
            const size_t off0 = (size_t)r0 * N + c;
            const size_t off1 = (size_t)(r0 + 8) * N + c;
            float2 v0 = make_float2(acc[mt][nt][0], acc[mt][nt][1]);
            float2 v1 = make_float2(acc[mt][nt][2], acc[mt][nt][3]);
            if (add) {
                float2 a0 = *(const float2*)(add + off0);
                float2 a1 = *(const float2*)(add + off1);
                v0.x += a0.x; v0.y += a0.y;
                v1.x += a1.x; v1.y += a1.y;
            }
            *(float2*)(C + off0) = v0;
            *(float2*)(C + off1) = v1;
            if (C2) {
                *(float2*)(C2 + off0) = v0;
                *(float2*)(C2 + off1) = v1;
            }
        }
    }
}

// ---------------------------------------------------------------------------
// Fused gate_up + SiLU GEMM (1-product):
// per CTA: gate tile (B rows n0..) and up tile (B rows I_DIM+n0..),
// epilogue silu(g)*u -> fp16 hi to Hout [S, I_DIM].
// ---------------------------------------------------------------------------
__global__ __launch_bounds__(256, 1)
void gemm_gu_kernel(const __half* __restrict__ Ahi,
                    const __half* __restrict__ Bhi,
                    __half* __restrict__ Hout, int M, int K)
{
    constexpr uint32_t STG = 3 * TILE_B;
    extern __shared__ char smc[];
    const uint32_t sbase = smem_u32(smc);
    const int tid = threadIdx.x;
    const int lane = tid & 31;
    const int wm = (tid >> 5) & 3;
    const int wn = tid >> 7;
    const int m0 = blockIdx.x * BM;
    const int n0 = blockIdx.y * BN;
    const int NCH = K / KC;

    const int q0r = tid >> 2, q0c = tid & 3;
    const int q1r = (tid + 256) >> 2, q1c = tid & 3;

    float acc_g[2][8][4], acc_u[2][8][4];
#pragma unroll
    for (int mt = 0; mt < 2; mt++)
#pragma unroll
        for (int nt = 0; nt < 8; nt++)
#pragma unroll
            for (int e = 0; e < 4; e++) { acc_g[mt][nt][e] = 0.f; acc_u[mt][nt][e] = 0.f; }

    auto issue = [&](int kc, int buf) {
        const uint32_t st = sbase + buf * STG;
        const int kb = kc * KC;
        const size_t gA0 = (size_t)(m0 + q0r) * K + kb + q0c * 8;
        const size_t gA1 = (size_t)(m0 + q1r) * K + kb + q1c * 8;
        const size_t gG0 = (size_t)(n0 + q0r) * K + kb + q0c * 8;
        const size_t gG1 = (size_t)(n0 + q1r) * K + kb + q1c * 8;
        const size_t gU0 = (size_t)(I_DIM + n0 + q0r) * K + kb + q0c * 8;
        const size_t gU1 = (size_t)(I_DIM + n0 + q1r) * K + kb + q1c * 8;
        const uint32_t s0 = st + q0r * ROWB + q0c * 16;
        const uint32_t s1 = st + q1r * ROWB + q1c * 16;
        cp16(s0, Ahi + gA0);
        cp16(s1, Ahi + gA1);
        cp16(s0 + TILE_B, Bhi + gG0);
        cp16(s1 + TILE_B, Bhi + gG1);
        cp16(s0 + 2 * TILE_B, Bhi + gU0);
        cp16(s1 + 2 * TILE_B, Bhi + gU1);
        cp_commit();
    };

    issue(0, 0);

    for (int kc = 0; kc < NCH; kc++) {
        if (kc + 1 < NCH) {
            issue(kc + 1, (kc + 1) & 1);
            cp_wait<1>();
        } else {
            cp_wait<0>();
        }
        __syncthreads();

        const uint32_t st = sbase + (kc & 1) * STG;
        const uint32_t sAh = st;
        const uint32_t sBg = st + TILE_B;
        const uint32_t sBu = st + 2 * TILE_B;

        const int aRow = wm * 32 + (lane & 15);
        const int aKof = (lane >> 4) * 8;
        const int bIdx = lane & 7;
        const int bSel = lane >> 3;
        const int bRowBase = wn * 64 + ((bSel >> 1) * 8) + bIdx;
        const int bKof = (bSel & 1) * 8;

#pragma unroll
        for (int ks = 0; ks < KC; ks += 16) {
            uint32_t ah[2][4];
#pragma unroll
            for (int mt = 0; mt < 2; mt++) {
                const uint32_t off = (uint32_t)(aRow + mt * 16) * ROWB +
                                     (uint32_t)(ks + aKof) * 2;
                ldm4(ah[mt], sAh + off);
            }
            uint32_t bg[8][2], bu[8][2];
#pragma unroll
            for (int p = 0; p < 4; p++) {
                const uint32_t off = (uint32_t)(bRowBase + p * 16) * ROWB +
                                     (uint32_t)(ks + bKof) * 2;
                uint32_t r4[4];
                ldm4(r4, sBg + off);
                bg[2 * p][0] = r4[0]; bg[2 * p][1] = r4[1];
                bg[2 * p + 1][0] = r4[2]; bg[2 * p + 1][1] = r4[3];
                ldm4(r4, sBu + off);
                bu[2 * p][0] = r4[0]; bu[2 * p][1] = r4[1];
                bu[2 * p + 1][0] = r4[2]; bu[2 * p + 1][1] = r4[3];
            }
#pragma unroll
            for (int mt = 0; mt < 2; mt++)
#pragma unroll
                for (int nt = 0; nt < 8; nt++) {
                    mma_f16(acc_g[mt][nt], ah[mt], bg[nt]);
                    mma_f16(acc_u[mt][nt], ah[mt], bu[nt]);
                }
        }
        __syncthreads();
    }

    // Epilogue: silu(g)*u -> fp16
    const int erow = m0 + wm * 32 + (lane >> 2);
    const int ecol = n0 + wn * 64 + (lane & 3) * 2;
#pragma unroll
    for (int mt = 0; mt < 2; mt++) {
#pragma unroll
        for (int nt = 0; nt < 8; nt++) {
            const int r0 = erow + mt * 16;
            const int c = ecol + nt * 8;
            const float h00 = silu_mul(acc_g[mt][nt][0], acc_u[mt][nt][0]);
            const float h01 = silu_mul(acc_g[mt][nt][1], acc_u[mt][nt][1]);
            const float h10 = silu_mul(acc_g[mt][nt][2], acc_u[mt][nt][2]);
            const float h11 = silu_mul(acc_g[mt][nt][3], acc_u[mt][nt][3]);
            *(uint32_t*)&Hout[(size_t)r0 * I_DIM + c] = packh2(h00, h01);
            *(uint32_t*)&Hout[(size_t)(r0 + 8) * I_DIM + c] = packh2(h10, h11);
        }
    }
}

// ---------------------------------------------------------------------------
// RoPE + split qkv fp32 -> fp16 hi/lo planes
// ---------------------------------------------------------------------------
__global__ void rope_split_kernel(const float* __restrict__ qkv,
                                  __half* __restrict__ oh,
                                  __half* __restrict__ ol)
{
    const int idx = blockIdx.x * blockDim.x + threadIdx.x;
    const int total = S_LEN * 3072;
    if (idx >= total) return;
    const int slot = idx % 3072;
    const int s = idx / 3072;
    const size_t rb = (size_t)s * QKV_N;

    if (slot < 2560) {
        const int head = slot >> 6;
        const int d = slot & 63;
        const int col = head * HD + d;
        const float inv = exp2f((float)d * (-13.287712379549449f / 64.f));
        const float ang = (float)s * inv;
        float sn, c;
        sincosf(ang, &sn, &c);
        const float x1 = qkv[rb + col];
        const float x2 = qkv[rb + col + 64];
        const float y1 = x1 * c - x2 * sn;
        const float y2 = x2 * c + x1 * sn;
        __half h1, l1, h2, l2;
        split1(y1, h1, l1);
        split1(y2, h2, l2);
        oh[rb + col] = h1; oh[rb + col + 64] = h2;
        ol[rb + col] = l1; ol[rb + col + 64] = l2;
    } else {
        const int c0 = 5120 + (slot - 2560) * 2;
        const float x1 = qkv[rb + c0];
        const float x2 = qkv[rb + c0 + 1];
        __half h1, l1, h2, l2;
        split1(x1, h1, l1);
        split1(x2, h2, l2);
        oh[rb + c0] = h1; oh[rb + c0 + 1] = h2;
        ol[rb + c0] = l1; ol[rb + c0 + 1] = l2;
    }
}

// ---------------------------------------------------------------------------
// Tensor-core flash attention (fp16 hi/lo, 3-product; unchanged)
// ---------------------------------------------------------------------------
__global__ __launch_bounds__(256, 1)
void attn_mma_kernel(const __half* __restrict__ qph,
                     const __half* __restrict__ qpl,
                     __half* __restrict__ outh, __half* __restrict__ outl)
{
    extern __shared__ char smc[];
    const uint32_t sb = smem_u32(smc);
    const uint32_t sQh = sb;
    const uint32_t sQl = sb + BR * AROWB;
    const uint32_t sKh = sb + 2 * BR * AROWB;
    const uint32_t sKl = sKh + BC * AROWB;
    const uint32_t sVh = sKl + BC * AROWB;
    const uint32_t sVl = sVh + BC * AROWB;

    const int tid = threadIdx.x;
    const int lane = tid & 31;
    const int warp = tid >> 5;
    const int mb = blockIdx.x;
    const int head = blockIdx.y;
    const int kh = head >> 2;
    const float scale = 0.088388347648318447f;

    const int qcol = head * HD;
    const int kcol = NQ * HD + kh * HD;
    const int vcol = (NQ + NKV) * HD + kh * HD;

    {
        const int chunk = tid & 15;
        const int rbase = tid >> 4;
#pragma unroll
        for (int i = 0; i < 8; i++) {
            const int row = rbase + i * 16;
            const size_t g = (size_t)(mb * BR + row) * QKV_N + qcol + chunk * 8;
            const uint32_t so = row * AROWB + chunk * 16;
            cp16(sQh + so, qph + g);
            cp16(sQl + so, qpl + g);
        }
    }
    cp_commit();

    float m0 = -1e30f, m1 = -1e30f, l0 = 0.f, l1 = 0.f;
    float acc_o[16][4];
#pragma unroll
    for (int nt = 0; nt < 16; nt++)
#pragma unroll
        for (int e = 0; e < 4; e++) acc_o[nt][e] = 0.f;

    const int aRow = warp * 16 + (lane & 15);
    const int aKof = (lane >> 4) * 8;
    const int bIdx = lane & 7;
    const int bSel = lane >> 3;
    const int bRowBase = (bSel >> 1) * 8 + bIdx;
    const int bKof = (bSel & 1) * 8;
    const int vRow = lane & 15;
    const int vCof = (lane >> 4) * 8;

    const int r0 = lane >> 2;
    const int cq = lane & 3;
    const int grow0 = mb * BR + warp * 16 + r0;
    const int grow1 = grow0 + 8;

    const int ntiles = 2 * mb + 2;
    for (int nb = 0; nb < ntiles; nb++) {
        __syncthreads();
        {
            const int chunk = tid & 15;
            const int rbase = tid >> 4;
#pragma unroll
            for (int i = 0; i < 4; i++) {
                const int row = rbase + i * 16;
                const size_t gk = (size_t)(nb * BC + row) * QKV_N + kcol + chunk * 8;
                const size_t gv = (size_t)(nb * BC + row) * QKV_N + vcol + chunk * 8;
                const uint32_t so = row * AROWB + chunk * 16;
                cp16(sKh + so, qph + gk);
                cp16(sKl + so, qpl + gk);
                cp16(sVh + so, qph + gv);
                cp16(sVl + so, qpl + gv);
            }
        }
        cp_commit();
        cp_wait<0>();
        __syncthreads();

        float accs[8][4];
#pragma unroll
        for (int nt = 0; nt < 8; nt++)
#pragma unroll
            for (int e = 0; e < 4; e++) accs[nt][e] = 0.f;

#pragma unroll
        for (int ks = 0; ks < 8; ks++) {
            uint32_t aqh[4], aql[4];
            const uint32_t aoff = (uint32_t)aRow * AROWB + (uint32_t)(ks * 16 + aKof) * 2;
            ldm4(aqh, sQh + aoff);
            ldm4(aql, sQl + aoff);
            uint32_t bh[8][2], bl[8][2];
#pragma unroll
            for (int p = 0; p < 4; p++) {
                const uint32_t boff = (uint32_t)(bRowBase + p * 16) * AROWB +
                                      (uint32_t)(ks * 16 + bKof) * 2;
                uint32_t r4[4];
                ldm4(r4, sKh + boff);
                bh[2 * p][0] = r4[0]; bh[2 * p][1] = r4[1];
                bh[2 * p + 1][0] = r4[2]; bh[2 * p + 1][1] = r4[3];
                ldm4(r4, sKl + boff);
                bl[2 * p][0] = r4[0]; bl[2 * p][1] = r4[1];
                bl[2 * p + 1][0] = r4[2]; bl[2 * p + 1][1] = r4[3];
            }
#pragma unroll
            for (int nt = 0; nt < 8; nt++) {
                mma_f16(accs[nt], aqh, bh[nt]);
                mma_f16(accs[nt], aqh, bl[nt]);
                mma_f16(accs[nt], aql, bh[nt]);
            }
        }

        float rmax0 = -1e30f, rmax1 = -1e30f;
#pragma unroll
        for (int nt = 0; nt < 8; nt++) {
            const int cbase = nb * BC + nt * 8 + cq * 2;
#pragma unroll
            for (int e = 0; e < 4; e++) {
                float s = accs[nt][e] * scale;
                const int col = cbase + (e & 1);
                const int row = (e < 2) ? grow0 : grow1;
                if (col > row) s = -1e30f;
                accs[nt][e] = s;
            }
            rmax0 = fmaxf(rmax0, fmaxf(accs[nt][0], accs[nt][1]));
            rmax1 = fmaxf(rmax1, fmaxf(accs[nt][2], accs[nt][3]));
        }
        rmax0 = fmaxf(rmax0, __shfl_xor_sync(0xffffffffu, rmax0, 1));
        rmax0 = fmaxf(rmax0, __shfl_xor_sync(0xffffffffu, rmax0, 2));
        rmax1 = fmaxf(rmax1, __shfl_xor_sync(0xffffffffu, rmax1, 1));
        rmax1 = fmaxf(rmax1, __shfl_xor_sync(0xffffffffu, rmax1, 2));
        const float mn0 = fmaxf(m0, rmax0), mn1 = fmaxf(m1, rmax1);
        const float cf0 = __expf(m0 - mn0), cf1 = __expf(m1 - mn1);
        m0 = mn0; m1 = mn1;
        float s0 = 0.f, s1 = 0.f;
#pragma unroll
        for (int nt = 0; nt < 8; nt++) {
            accs[nt][0] = __expf(accs[nt][0] - mn0);
            accs[nt][1] = __expf(accs[nt][1] - mn0);
            accs[nt][2] = __expf(accs[nt][2] - mn1);
            accs[nt][3] = __expf(accs[nt][3] - mn1);
            s0 += accs[nt][0] + accs[nt][1];
            s1 += accs[nt][2] + accs[nt][3];
        }
        s0 += __shfl_xor_sync(0xffffffffu, s0, 1);
        s0 += __shfl_xor_sync(0xffffffffu, s0, 2);
        s1 += __shfl_xor_sync(0xffffffffu, s1, 1);
        s1 += __shfl_xor_sync(0xffffffffu, s1, 2);
        l0 = l0 * cf0 + s0;
        l1 = l1 * cf1 + s1;
#pragma unroll
        for (int nt = 0; nt < 16; nt++) {
            acc_o[nt][0] *= cf0; acc_o[nt][1] *= cf0;
            acc_o[nt][2] *= cf1; acc_o[nt][3] *= cf1;
        }

#pragma unroll
        for (int kb = 0; kb < 4; kb++) {
            uint32_t ph[4], pl[4];
            {
                const float* s0p = accs[2 * kb];
                const float* s1p = accs[2 * kb + 1];
                float h00 = __half2float(__float2half_rn(s0p[0]));
                float h01 = __half2float(__float2half_rn(s0p[1]));
                float h02 = __half2float(__float2half_rn(s0p[2]));
                float h03 = __half2float(__float2half_rn(s0p[3]));
                float h10 = __half2float(__float2half_rn(s1p[0]));
                float h11 = __half2float(__float2half_rn(s1p[1]));
                float h12 = __half2float(__float2half_rn(s1p[2]));
                float h13 = __half2float(__float2half_rn(s1p[3]));
                ph[0] = packh2(s0p[0], s0p[1]);
                ph[1] = packh2(s0p[2], s0p[3]);
                ph[2] = packh2(s1p[0], s1p[1]);
                ph[3] = packh2(s1p[2], s1p[3]);
                pl[0] = packh2(s0p[0] - h00, s0p[1] - h01);
                pl[1] = packh2(s0p[2] - h02, s0p[3] - h03);
                pl[2] = packh2(s1p[0] - h10, s1p[1] - h11);
                pl[3] = packh2(s1p[2] - h12, s1p[3] - h13);
            }
#pragma unroll
            for (int np = 0; np < 8; np++) {
                const uint32_t voff = (uint32_t)(kb * 16 + vRow) * AROWB +
                                      (uint32_t)(np * 16 + vCof) * 2;
                uint32_t rv[4], rl[4];
                ldm4t(rv, sVh + voff);
                ldm4t(rl, sVl + voff);
                uint32_t vh0[2] = {rv[0], rv[1]};
                uint32_t vh1[2] = {rv[2], rv[3]};
                uint32_t vl0[2] = {rl[0], rl[1]};
                uint32_t vl1[2] = {rl[2], rl[3]};
                mma_f16(acc_o[2 * np], ph, vh0);
                mma_f16(acc_o[2 * np], ph, vl0);
                mma_f16(acc_o[2 * np], pl, vh0);
                mma_f16(acc_o[2 * np + 1], ph, vh1);
                mma_f16(acc_o[2 * np + 1], ph, vl1);
                mma_f16(acc_o[2 * np + 1], pl, vh1);
            }
        }
    }

    const float inv0 = 1.f / l0, inv1 = 1.f / l1;
#pragma unroll
    for (int nt = 0; nt < 16; nt++) {
        const float v00 = acc_o[nt][0] * inv0;
        const float v01 = acc_o[nt][1] * inv0;
        const float v10 = acc_o[nt][2] * inv1;
        const float v11 = acc_o[nt][3] * inv1;
        const size_t o0 = (size_t)grow0 * (NQ * HD) + qcol + nt * 8 + cq * 2;
        const size_t o1 = (size_t)grow1 * (NQ * HD) + qcol + nt * 8 + cq * 2;
        const uint32_t h0 = packh2(v00, v01);
        const uint32_t h1 = packh2(v10, v11);
        *(uint32_t*)&outh[o0] = h0;
        *(uint32_t*)&outh[o1] = h1;
        const __half2* hp0 = (const __half2*)&h0;
        const __half2* hp1 = (const __half2*)&h1;
        *(uint32_t*)&outl[o0] = packh2(v00 - __half2float(hp0->x),
                                       v01 - __half2float(hp0->y));
        *(uint32_t*)&outl[o1] = packh2(v10 - __half2float(hp1->x),
                                       v11 - __half2float(hp1->y));
    }
}

// ---------------------------------------------------------------------------
// Launch
// ---------------------------------------------------------------------------
extern "C" void kernel_launch(void* const* d_in, const int* in_sizes, int n_in,
                              void* d_out, int out_size)
{
    (void)in_sizes; (void)n_in;
    const float* hidden = (const float*)d_in[1];
    const float* w_qkv = (const float*)d_in[2];
    const float* w_o = (const float*)d_in[3];
    const float* w_gu = (const float*)d_in[4];
    const float* w_down = (const float*)d_in[5];
    const float* ln1 = (const float*)d_in[6];
    const float* ln2 = (const float*)d_in[7];

    float* out = (float*)d_out;
    const size_t SH = (size_t)S_LEN * H_DIM;
    float* out_resid = ((size_t)out_size >= 2 * SH) ? (out + SH) : nullptr;

    float *qkv, *resid;
    cudaGetSymbolAddress((void**)&qkv, g_qkv);
    cudaGetSymbolAddress((void**)&resid, g_resid);
    __half *qkvh, *qkvl;
    cudaGetSymbolAddress((void**)&qkvh, g_qkvh);
    cudaGetSymbolAddress((void**)&qkvl, g_qkvl);
    __half *wqkvh, *woh, *wguh, *wdh;
    __half *xbh, *xbl, *abh, *abl, *hbh;
    cudaGetSymbolAddress((void**)&wqkvh, g_wqkvT_hi);
    cudaGetSymbolAddress((void**)&woh, g_woT_hi);
    cudaGetSymbolAddress((void**)&wguh, g_wguT_hi);
    cudaGetSymbolAddress((void**)&wdh, g_wdownT_hi);
    cudaGetSymbolAddress((void**)&xbh, g_xb_hi);
    cudaGetSymbolAddress((void**)&xbl, g_xb_lo);
    cudaGetSymbolAddress((void**)&abh, g_ab_hi);
    cudaGetSymbolAddress((void**)&abl, g_ab_lo);
    cudaGetSymbolAddress((void**)&hbh, g_hb_hi);

    cudaFuncSetAttribute(attn_mma_kernel,
                         cudaFuncAttributeMaxDynamicSharedMemorySize, ATT_SMEM);
    const int SMEM2 = 2 * 3 * TILE_B;
    const int SMEM1 = 2 * 2 * TILE_B;
    const int SMEMGU = 2 * 3 * TILE_B;
    cudaFuncSetAttribute(gemm_mma_kernel<2>,
                         cudaFuncAttributeMaxDynamicSharedMemorySize, SMEM2);
    cudaFuncSetAttribute(gemm_mma_kernel<1>,
                         cudaFuncAttributeMaxDynamicSharedMemorySize, SMEM1);
    cudaFuncSetAttribute(gemm_gu_kernel,
                         cudaFuncAttributeMaxDynamicSharedMemorySize, SMEMGU);

    // 0. Weight transpose + split (hi planes only)
    wt_transpose_kernel<<<dim3(QKV_N / 32, H_DIM / 32), 256>>>(w_qkv, wqkvh, nullptr, H_DIM, QKV_N);
    wt_transpose_kernel<<<dim3(H_DIM / 32, (NQ * HD) / 32), 256>>>(w_o, woh, nullptr, NQ * HD, H_DIM);
    wt_transpose_kernel<<<dim3((2 * I_DIM) / 32, H_DIM / 32), 256>>>(w_gu, wguh, nullptr, H_DIM, 2 * I_DIM);
    wt_transpose_kernel<<<dim3(H_DIM / 32, I_DIM / 32), 256>>>(w_down, wdh, nullptr, I_DIM, H_DIM);

    // 1. RMSNorm 1 -> hi/lo
    rmsnorm_split_kernel<<<S_LEN, 256>>>(hidden, ln1, xbh, xbl);

    // 2. QKV projection (2-product: Ah*Bh + Al*Bh)
    gemm_mma_kernel<2><<<dim3(S_LEN / BM, QKV_N / BN), 256, SMEM2>>>(
        xbh, xbl, wqkvh, qkv, S_LEN, QKV_N, H_DIM, nullptr, nullptr);

    // 3. RoPE + split qkv -> fp16 hi/lo planes
    {
        const int total = S_LEN * 3072;
        rope_split_kernel<<<(total + 255) / 256, 256>>>(qkv, qkvh, qkvl);
    }

    // 4. Tensor-core attention -> o-proj operands (hi/lo)
    attn_mma_kernel<<<dim3(S_LEN / BR, NQ), 256, ATT_SMEM>>>(qkvh, qkvl, abh, abl);

    // 5. O projection (2-product) + residual
    gemm_mma_kernel<2><<<dim3(S_LEN / BM, H_DIM / BN), 256, SMEM2>>>(
        abh, abl, woh, resid, S_LEN, H_DIM, NQ * HD, hidden, out_resid);

    // 6. RMSNorm 2 -> hi only
    rmsnorm_split_kernel<<<S_LEN, 256>>>(resid, ln2, xbh, nullptr);

    // 7+8. Fused gate_up + SiLU -> hb fp16
    gemm_gu_kernel<<<dim3(S_LEN / BM, I_DIM / BN), 256, SMEMGU>>>(
        xbh, wguh, hbh, S_LEN, H_DIM);

    // 9. down (1-product) -> out
    gemm_mma_kernel<1><<<dim3(S_LEN / BM, H_DIM / BN), 256, SMEM1>>>(
        hbh, nullptr, wdh, out, S_LEN, H_DIM, I_DIM, nullptr, nullptr);
}

// round 10
// speedup vs baseline: 4.6638x; 1.0999x over previous
#include <cuda_runtime.h>
#include <cuda_fp16.h>
#include <math.h>
#include <stdint.h>

#define H_DIM 4096
#define S_LEN 2048
#define NQ 32
#define NKV 8
#define HD 128
#define I_DIM 14336
#define QKV_N ((NQ + 2 * NKV) * HD) /* 6144 */
#define EPS 1e-5f

// GEMM tiling (mma.sync path)
#define BM 128
#define BN 128
#define KC 32
#define ROWB 80                       // bytes per smem row (64B data + 16B pad)
#define TILE_B (128 * ROWB)

// Attention tiling
#define BR 128
#define BC 64
#define AROWB 272
#define ATT_SMEM (2 * BR * AROWB + 4 * BC * AROWB)   // 139264

// ---------------------------------------------------------------------------
// Scratch (device globals)
// ---------------------------------------------------------------------------
__device__ float g_qkv[(size_t)S_LEN * QKV_N];
__device__ float g_resid[(size_t)S_LEN * H_DIM];

__device__ __half g_qkvh[(size_t)S_LEN * QKV_N];
__device__ __half g_qkvl[(size_t)S_LEN * QKV_N];

__device__ __half g_wqkvT_hi[(size_t)QKV_N * H_DIM];
__device__ __half g_woT_hi[(size_t)H_DIM * (NQ * HD)];
__device__ __half g_wguT_hi[(size_t)(2 * I_DIM) * H_DIM];
__device__ __half g_wdownT_hi[(size_t)H_DIM * I_DIM];

__device__ __half g_xb_hi[(size_t)S_LEN * H_DIM];
__device__ __half g_ab_hi[(size_t)S_LEN * NQ * HD];
__device__ __half g_hb_hi[(size_t)S_LEN * I_DIM];

// ---------------------------------------------------------------------------
// PTX helpers
// ---------------------------------------------------------------------------
__device__ __forceinline__ uint32_t smem_u32(const void* p) {
    uint32_t a;
    asm("{ .reg .u64 t; cvta.to.shared.u64 t, %1; cvt.u32.u64 %0, t; }"
        : "=r"(a) : "l"(p));
    return a;
}
__device__ __forceinline__ void cp16(uint32_t saddr, const void* g) {
    asm volatile("cp.async.cg.shared.global [%0], [%1], 16;"
                 :: "r"(saddr), "l"(g) : "memory");
}
__device__ __forceinline__ void cp_commit() {
    asm volatile("cp.async.commit_group;" ::: "memory");
}
template <int N>
__device__ __forceinline__ void cp_wait() {
    asm volatile("cp.async.wait_group %0;" :: "n"(N) : "memory");
}
__device__ __forceinline__ void ldm4(uint32_t* r, uint32_t addr) {
    asm volatile("ldmatrix.sync.aligned.m8n8.x4.shared.b16 {%0,%1,%2,%3}, [%4];"
                 : "=r"(r[0]), "=r"(r[1]), "=r"(r[2]), "=r"(r[3]) : "r"(addr));
}
__device__ __forceinline__ void ldm4t(uint32_t* r, uint32_t addr) {
    asm volatile("ldmatrix.sync.aligned.m8n8.x4.trans.shared.b16 {%0,%1,%2,%3}, [%4];"
                 : "=r"(r[0]), "=r"(r[1]), "=r"(r[2]), "=r"(r[3]) : "r"(addr));
}
__device__ __forceinline__ void mma_f16(float* d, const uint32_t* a,
                                        const uint32_t* b) {
    asm volatile(
        "mma.sync.aligned.m16n8k16.row.col.f32.f16.f16.f32 "
        "{%0,%1,%2,%3}, {%4,%5,%6,%7}, {%8,%9}, {%0,%1,%2,%3};"
        : "+f"(d[0]), "+f"(d[1]), "+f"(d[2]), "+f"(d[3])
        : "r"(a[0]), "r"(a[1]), "r"(a[2]), "r"(a[3]), "r"(b[0]), "r"(b[1]));
}
__device__ __forceinline__ void split1(float x, __half& h, __half& l) {
    h = __float2half_rn(x);
    l = __float2half_rn(x - __half2float(h));
}
__device__ __forceinline__ void split4(float4 v, uint2& hi, uint2& lo) {
    __half h0, h1, h2, h3, l0, l1, l2, l3;
    split1(v.x, h0, l0); split1(v.y, h1, l1);
    split1(v.z, h2, l2); split1(v.w, h3, l3);
    hi.x = ((uint32_t)__half_as_ushort(h1) << 16) | __half_as_ushort(h0);
    hi.y = ((uint32_t)__half_as_ushort(h3) << 16) | __half_as_ushort(h2);
    lo.x = ((uint32_t)__half_as_ushort(l1) << 16) | __half_as_ushort(l0);
    lo.y = ((uint32_t)__half_as_ushort(l3) << 16) | __half_as_ushort(l2);
}
__device__ __forceinline__ uint32_t packh2(float a, float b) {
    __half2 h = __floats2half2_rn(a, b);
    return *(uint32_t*)&h;
}
__device__ __forceinline__ float silu_mul(float g, float u) {
    return g / (1.f + __expf(-g)) * u;
}

// ---------------------------------------------------------------------------
// Weight transpose: W[K,N] fp32 -> Thi [N,K] fp16
// ---------------------------------------------------------------------------
__global__ __launch_bounds__(256)
void wt_transpose_kernel(const float* __restrict__ W,
                         __half* __restrict__ Thi, int K, int N)
{
    __shared__ float t[32][33];
    const int tx = threadIdx.x & 31, ty = threadIdx.x >> 5;
    const int n = blockIdx.x * 32 + tx;
#pragma unroll
    for (int i = 0; i < 4; i++) {
        const int k = blockIdx.y * 32 + ty + i * 8;
        t[ty + i * 8][tx] = W[(size_t)k * N + n];
    }
    __syncthreads();
    const int k2 = blockIdx.y * 32 + tx;
#pragma unroll
    for (int i = 0; i < 4; i++) {
        const int n2 = blockIdx.x * 32 + ty + i * 8;
        Thi[(size_t)n2 * K + k2] = __float2half_rn(t[tx][ty + i * 8]);
    }
}

// ---------------------------------------------------------------------------
// RMSNorm -> fp16 hi (single plane)
// ---------------------------------------------------------------------------
__global__ __launch_bounds__(256)
void rmsnorm_h_kernel(const float* __restrict__ x, const float* __restrict__ w,
                      __half* __restrict__ ohi)
{
    const int row = blockIdx.x;
    const int t = threadIdx.x;
    const float4* xr = (const float4*)(x + (size_t)row * H_DIM);
    const float4* wr = (const float4*)w;

    float4 v[4];
    float ss = 0.f;
#pragma unroll
    for (int i = 0; i < 4; i++) {
        v[i] = xr[t + 256 * i];
        ss += v[i].x * v[i].x + v[i].y * v[i].y + v[i].z * v[i].z + v[i].w * v[i].w;
    }
#pragma unroll
    for (int o = 16; o; o >>= 1) ss += __shfl_xor_sync(0xffffffffu, ss, o);
    __shared__ float wsum[8];
    if ((t & 31) == 0) wsum[t >> 5] = ss;
    __syncthreads();
    float tot = wsum[0] + wsum[1] + wsum[2] + wsum[3] +
                wsum[4] + wsum[5] + wsum[6] + wsum[7];
    const float sc = rsqrtf(tot * (1.f / H_DIM) + EPS);

    uint2* hr = (uint2*)(ohi + (size_t)row * H_DIM);
#pragma unroll
    for (int i = 0; i < 4; i++) {
        float4 wv = wr[t + 256 * i];
        uint2 h;
        h.x = packh2(v[i].x * sc * wv.x, v[i].y * sc * wv.y);
        h.y = packh2(v[i].z * sc * wv.z, v[i].w * sc * wv.w);
        hr[t + 256 * i] = h;
    }
}

// ---------------------------------------------------------------------------
// mma.sync fp16 GEMM, 1-product: C[M,N] = Ah[M,K] @ Bh^T (B stored [N,K]).
// Optional residual add + dual write.
// ---------------------------------------------------------------------------
__global__ __launch_bounds__(256, 1)
void gemm_mma1_kernel(const __half* __restrict__ Ahi,
                      const __half* __restrict__ Bhi,
                      float* __restrict__ C, int M, int N, int K,
                      const float* __restrict__ add, float* __restrict__ C2)
{
    constexpr uint32_t STG = 2 * TILE_B;
    extern __shared__ char smc[];
    const uint32_t sbase = smem_u32(smc);
    const int tid = threadIdx.x;
    const int lane = tid & 31;
    const int wm = (tid >> 5) & 3;
    const int wn = tid >> 7;
    const int m0 = blockIdx.x * BM;
    const int n0 = blockIdx.y * BN;
    const int NCH = K / KC;

    const int q0r = tid >> 2, q0c = tid & 3;
    const int q1r = (tid + 256) >> 2, q1c = tid & 3;

    float acc[2][8][4];
#pragma unroll
    for (int mt = 0; mt < 2; mt++)
#pragma unroll
        for (int nt = 0; nt < 8; nt++)
#pragma unroll
            for (int e = 0; e < 4; e++) acc[mt][nt][e] = 0.f;

    auto issue = [&](int kc, int buf) {
        const uint32_t st = sbase + buf * STG;
        const int kb = kc * KC;
        const size_t gA0 = (size_t)(m0 + q0r) * K + kb + q0c * 8;
        const size_t gA1 = (size_t)(m0 + q1r) * K + kb + q1c * 8;
        const size_t gB0 = (size_t)(n0 + q0r) * K + kb + q0c * 8;
        const size_t gB1 = (size_t)(n0 + q1r) * K + kb + q1c * 8;
        const uint32_t s0 = st + q0r * ROWB + q0c * 16;
        const uint32_t s1 = st + q1r * ROWB + q1c * 16;
        cp16(s0, Ahi + gA0);
        cp16(s1, Ahi + gA1);
        cp16(s0 + TILE_B, Bhi + gB0);
        cp16(s1 + TILE_B, Bhi + gB1);
        cp_commit();
    };

    issue(0, 0);

    for (int kc = 0; kc < NCH; kc++) {
        if (kc + 1 < NCH) {
            issue(kc + 1, (kc + 1) & 1);
            cp_wait<1>();
        } else {
            cp_wait<0>();
        }
        __syncthreads();

        const uint32_t st = sbase + (kc & 1) * STG;
        const uint32_t sAh = st;
        const uint32_t sBh = st + TILE_B;

        const int aRow = wm * 32 + (lane & 15);
        const int aKof = (lane >> 4) * 8;
        const int bIdx = lane & 7;
        const int bSel = lane >> 3;
        const int bRowBase = wn * 64 + ((bSel >> 1) * 8) + bIdx;
        const int bKof = (bSel & 1) * 8;

#pragma unroll
        for (int ks = 0; ks < KC; ks += 16) {
            uint32_t ah[2][4];
#pragma unroll
            for (int mt = 0; mt < 2; mt++) {
                const uint32_t off = (uint32_t)(aRow + mt * 16) * ROWB +
                                     (uint32_t)(ks + aKof) * 2;
                ldm4(ah[mt], sAh + off);
            }
            uint32_t bh[8][2];
#pragma unroll
            for (int p = 0; p < 4; p++) {
                const uint32_t off = (uint32_t)(bRowBase + p * 16) * ROWB +
                                     (uint32_t)(ks + bKof) * 2;
                uint32_t r4[4];
                ldm4(r4, sBh + off);
                bh[2 * p][0] = r4[0]; bh[2 * p][1] = r4[1];
                bh[2 * p + 1][0] = r4[2]; bh[2 * p + 1][1] = r4[3];
            }
#pragma unroll
            for (int mt = 0; mt < 2; mt++)
#pragma unroll
                for (int nt = 0; nt < 8; nt++)
                    mma_f16(acc[mt][nt], ah[mt], bh[nt]);
        }
        __syncthreads();
    }

    const int erow = m0 + wm * 32 + (lane >> 2);
    const int ecol = n0 + wn * 64 + (lane & 3) * 2;
#pragma unroll
    for (int mt = 0; mt < 2; mt++) {
#pragma unroll
        for (int nt = 0; nt < 8; nt++) {
            const int r0 = erow + mt * 16;
            const int c = ecol + nt * 8;
            const size_t off0 = (size_t)r0 * N + c;
            const size_t off1 = (size_t)(r0 + 8) * N + c;
            float2 v0 = make_float2(acc[mt][nt][0], acc[mt][nt][1]);
            float2 v1 = make_float2(acc[mt][nt][2], acc[mt][nt][3]);
            if (add) {
                float2 a0 = *(const float2*)(add + off0);
                float2 a1 = *(const float2*)(add + off1);
                v0.x += a0.x; v0.y += a0.y;
                v1.x += a1.x; v1.y += a1.y;
            }
            *(float2*)(C + off0) = v0;
            *(float2*)(C + off1) = v1;
            if (C2) {
                *(float2*)(C2 + off0) = v0;
                *(float2*)(C2 + off1) = v1;
            }
        }
    }
}

// ---------------------------------------------------------------------------
// Fused gate_up + SiLU GEMM (1-product) -> fp16 Hout [S, I_DIM]
// ---------------------------------------------------------------------------
__global__ __launch_bounds__(256, 1)
void gemm_gu_kernel(const __half* __restrict__ Ahi,
                    const __half* __restrict__ Bhi,
                    __half* __restrict__ Hout, int M, int K)
{
    constexpr uint32_t STG = 3 * TILE_B;
    extern __shared__ char smc[];
    const uint32_t sbase = smem_u32(smc);
    const int tid = threadIdx.x;
    const int lane = tid & 31;
    const int wm = (tid >> 5) & 3;
    const int wn = tid >> 7;
    const int m0 = blockIdx.x * BM;
    const int n0 = blockIdx.y * BN;
    const int NCH = K / KC;

    const int q0r = tid >> 2, q0c = tid & 3;
    const int q1r = (tid + 256) >> 2, q1c = tid & 3;

    float acc_g[2][8][4], acc_u[2][8][4];
#pragma unroll
    for (int mt = 0; mt < 2; mt++)
#pragma unroll
        for (int nt = 0; nt < 8; nt++)
#pragma unroll
            for (int e = 0; e < 4; e++) { acc_g[mt][nt][e] = 0.f; acc_u[mt][nt][e] = 0.f; }

    auto issue = [&](int kc, int buf) {
        const uint32_t st = sbase + buf * STG;
        const int kb = kc * KC;
        const size_t gA0 = (size_t)(m0 + q0r) * K + kb + q0c * 8;
        const size_t gA1 = (size_t)(m0 + q1r) * K + kb + q1c * 8;
        const size_t gG0 = (size_t)(n0 + q0r) * K + kb + q0c * 8;
        const size_t gG1 = (size_t)(n0 + q1r) * K + kb + q1c * 8;
        const size_t gU0 = (size_t)(I_DIM + n0 + q0r) * K + kb + q0c * 8;
        const size_t gU1 = (size_t)(I_DIM + n0 + q1r) * K + kb + q1c * 8;
        const uint32_t s0 = st + q0r * ROWB + q0c * 16;
        const uint32_t s1 = st + q1r * ROWB + q1c * 16;
        cp16(s0, Ahi + gA0);
        cp16(s1, Ahi + gA1);
        cp16(s0 + TILE_B, Bhi + gG0);
        cp16(s1 + TILE_B, Bhi + gG1);
        cp16(s0 + 2 * TILE_B, Bhi + gU0);
        cp16(s1 + 2 * TILE_B, Bhi + gU1);
        cp_commit();
    };

    issue(0, 0);

    for (int kc = 0; kc < NCH; kc++) {
        if (kc + 1 < NCH) {
            issue(kc + 1, (kc + 1) & 1);
            cp_wait<1>();
        } else {
            cp_wait<0>();
        }
        __syncthreads();

        const uint32_t st = sbase + (kc & 1) * STG;
        const uint32_t sAh = st;
        const uint32_t sBg = st + TILE_B;
        const uint32_t sBu = st + 2 * TILE_B;

        const int aRow = wm * 32 + (lane & 15);
        const int aKof = (lane >> 4) * 8;
        const int bIdx = lane & 7;
        const int bSel = lane >> 3;
        const int bRowBase = wn * 64 + ((bSel >> 1) * 8) + bIdx;
        const int bKof = (bSel & 1) * 8;

#pragma unroll
        for (int ks = 0; ks < KC; ks += 16) {
            uint32_t ah[2][4];
#pragma unroll
            for (int mt = 0; mt < 2; mt++) {
                const uint32_t off = (uint32_t)(aRow + mt * 16) * ROWB +
                                     (uint32_t)(ks + aKof) * 2;
                ldm4(ah[mt], sAh + off);
            }
            uint32_t bg[8][2], bu[8][2];
#pragma unroll
            for (int p = 0; p < 4; p++) {
                const uint32_t off = (uint32_t)(bRowBase + p * 16) * ROWB +
                                     (uint32_t)(ks + bKof) * 2;
                uint32_t r4[4];
                ldm4(r4, sBg + off);
                bg[2 * p][0] = r4[0]; bg[2 * p][1] = r4[1];
                bg[2 * p + 1][0] = r4[2]; bg[2 * p + 1][1] = r4[3];
                ldm4(r4, sBu + off);
                bu[2 * p][0] = r4[0]; bu[2 * p][1] = r4[1];
                bu[2 * p + 1][0] = r4[2]; bu[2 * p + 1][1] = r4[3];
            }
#pragma unroll
            for (int mt = 0; mt < 2; mt++)
#pragma unroll
                for (int nt = 0; nt < 8; nt++) {
                    mma_f16(acc_g[mt][nt], ah[mt], bg[nt]);
                    mma_f16(acc_u[mt][nt], ah[mt], bu[nt]);
                }
        }
        __syncthreads();
    }

    const int erow = m0 + wm * 32 + (lane >> 2);
    const int ecol = n0 + wn * 64 + (lane & 3) * 2;
#pragma unroll
    for (int mt = 0; mt < 2; mt++) {
#pragma unroll
        for (int nt = 0; nt < 8; nt++) {
            const int r0 = erow + mt * 16;
            const int c = ecol + nt * 8;
            const float h00 = silu_mul(acc_g[mt][nt][0], acc_u[mt][nt][0]);
            const float h01 = silu_mul(acc_g[mt][nt][1], acc_u[mt][nt][1]);
            const float h10 = silu_mul(acc_g[mt][nt][2], acc_u[mt][nt][2]);
            const float h11 = silu_mul(acc_g[mt][nt][3], acc_u[mt][nt][3]);
            *(uint32_t*)&Hout[(size_t)r0 * I_DIM + c] = packh2(h00, h01);
            *(uint32_t*)&Hout[(size_t)(r0 + 8) * I_DIM + c] = packh2(h10, h11);
        }
    }
}

// ---------------------------------------------------------------------------
// RoPE + split qkv fp32 -> fp16 hi/lo planes
// ---------------------------------------------------------------------------
__global__ void rope_split_kernel(const float* __restrict__ qkv,
                                  __half* __restrict__ oh,
                                  __half* __restrict__ ol)
{
    const int idx = blockIdx.x * blockDim.x + threadIdx.x;
    const int total = S_LEN * 3072;
    if (idx >= total) return;
    const int slot = idx % 3072;
    const int s = idx / 3072;
    const size_t rb = (size_t)s * QKV_N;

    if (slot < 2560) {
        const int head = slot >> 6;
        const int d = slot & 63;
        const int col = head * HD + d;
        const float inv = exp2f((float)d * (-13.287712379549449f / 64.f));
        const float ang = (float)s * inv;
        float sn, c;
        sincosf(ang, &sn, &c);
        const float x1 = qkv[rb + col];
        const float x2 = qkv[rb + col + 64];
        const float y1 = x1 * c - x2 * sn;
        const float y2 = x2 * c + x1 * sn;
        __half h1, l1, h2, l2;
        split1(y1, h1, l1);
        split1(y2, h2, l2);
        oh[rb + col] = h1; oh[rb + col + 64] = h2;
        ol[rb + col] = l1; ol[rb + col + 64] = l2;
    } else {
        const int c0 = 5120 + (slot - 2560) * 2;
        const float x1 = qkv[rb + c0];
        const float x2 = qkv[rb + c0 + 1];
        __half h1, l1, h2, l2;
        split1(x1, h1, l1);
        split1(x2, h2, l2);
        oh[rb + c0] = h1; oh[rb + c0 + 1] = h2;
        ol[rb + c0] = l1; ol[rb + c0 + 1] = l2;
    }
}

// ---------------------------------------------------------------------------
// Tensor-core flash attention (fp16 hi/lo, 3-product). Output: single fp16
// plane (o-proj is now 1-product).
// ---------------------------------------------------------------------------
__global__ __launch_bounds__(256, 1)
void attn_mma_kernel(const __half* __restrict__ qph,
                     const __half* __restrict__ qpl,
                     __half* __restrict__ outh)
{
    extern __shared__ char smc[];
    const uint32_t sb = smem_u32(smc);
    const uint32_t sQh = sb;
    const uint32_t sQl = sb + BR * AROWB;
    const uint32_t sKh = sb + 2 * BR * AROWB;
    const uint32_t sKl = sKh + BC * AROWB;
    const uint32_t sVh = sKl + BC * AROWB;
    const uint32_t sVl = sVh + BC * AROWB;

    const int tid = threadIdx.x;
    const int lane = tid & 31;
    const int warp = tid >> 5;
    const int mb = blockIdx.x;
    const int head = blockIdx.y;
    const int kh = head >> 2;
    const float scale = 0.088388347648318447f;

    const int qcol = head * HD;
    const int kcol = NQ * HD + kh * HD;
    const int vcol = (NQ + NKV) * HD + kh * HD;

    {
        const int chunk = tid & 15;
        const int rbase = tid >> 4;
#pragma unroll
        for (int i = 0; i < 8; i++) {
            const int row = rbase + i * 16;
            const size_t g = (size_t)(mb * BR + row) * QKV_N + qcol + chunk * 8;
            const uint32_t so = row * AROWB + chunk * 16;
            cp16(sQh + so, qph + g);
            cp16(sQl + so, qpl + g);
        }
    }
    cp_commit();

    float m0 = -1e30f, m1 = -1e30f, l0 = 0.f, l1 = 0.f;
    float acc_o[16][4];
#pragma unroll
    for (int nt = 0; nt < 16; nt++)
#pragma unroll
        for (int e = 0; e < 4; e++) acc_o[nt][e] = 0.f;

    const int aRow = warp * 16 + (lane & 15);
    const int aKof = (lane >> 4) * 8;
    const int bIdx = lane & 7;
    const int bSel = lane >> 3;
    const int bRowBase = (bSel >> 1) * 8 + bIdx;
    const int bKof = (bSel & 1) * 8;
    const int vRow = lane & 15;
    const int vCof = (lane >> 4) * 8;

    const int r0 = lane >> 2;
    const int cq = lane & 3;
    const int grow0 = mb * BR + warp * 16 + r0;
    const int grow1 = grow0 + 8;

    const int ntiles = 2 * mb + 2;
    for (int nb = 0; nb < ntiles; nb++) {
        __syncthreads();
        {
            const int chunk = tid & 15;
            const int rbase = tid >> 4;
#pragma unroll
            for (int i = 0; i < 4; i++) {
                const int row = rbase + i * 16;
                const size_t gk = (size_t)(nb * BC + row) * QKV_N + kcol + chunk * 8;
                const size_t gv = (size_t)(nb * BC + row) * QKV_N + vcol + chunk * 8;
                const uint32_t so = row * AROWB + chunk * 16;
                cp16(sKh + so, qph + gk);
                cp16(sKl + so, qpl + gk);
                cp16(sVh + so, qph + gv);
                cp16(sVl + so, qpl + gv);
            }
        }
        cp_commit();
        cp_wait<0>();
        __syncthreads();

        float accs[8][4];
#pragma unroll
        for (int nt = 0; nt < 8; nt++)
#pragma unroll
            for (int e = 0; e < 4; e++) accs[nt][e] = 0.f;

#pragma unroll
        for (int ks = 0; ks < 8; ks++) {
            uint32_t aqh[4], aql[4];
            const uint32_t aoff = (uint32_t)aRow * AROWB + (uint32_t)(ks * 16 + aKof) * 2;
            ldm4(aqh, sQh + aoff);
            ldm4(aql, sQl + aoff);
            uint32_t bh[8][2], bl[8][2];
#pragma unroll
            for (int p = 0; p < 4; p++) {
                const uint32_t boff = (uint32_t)(bRowBase + p * 16) * AROWB +
                                      (uint32_t)(ks * 16 + bKof) * 2;
                uint32_t r4[4];
                ldm4(r4, sKh + boff);
                bh[2 * p][0] = r4[0]; bh[2 * p][1] = r4[1];
                bh[2 * p + 1][0] = r4[2]; bh[2 * p + 1][1] = r4[3];
                ldm4(r4, sKl + boff);
                bl[2 * p][0] = r4[0]; bl[2 * p][1] = r4[1];
                bl[2 * p + 1][0] = r4[2]; bl[2 * p + 1][1] = r4[3];
            }
#pragma unroll
            for (int nt = 0; nt < 8; nt++) {
                mma_f16(accs[nt], aqh, bh[nt]);
                mma_f16(accs[nt], aqh, bl[nt]);
                mma_f16(accs[nt], aql, bh[nt]);
            }
        }

        float rmax0 = -1e30f, rmax1 = -1e30f;
#pragma unroll
        for (int nt = 0; nt < 8; nt++) {
            const int cbase = nb * BC + nt * 8 + cq * 2;
#pragma unroll
            for (int e = 0; e < 4; e++) {
                float s = accs[nt][e] * scale;
                const int col = cbase + (e & 1);
                const int row = (e < 2) ? grow0 : grow1;
                if (col > row) s = -1e30f;
                accs[nt][e] = s;
            }
            rmax0 = fmaxf(rmax0, fmaxf(accs[nt][0], accs[nt][1]));
            rmax1 = fmaxf(rmax1, fmaxf(accs[nt][2], accs[nt][3]));
        }
        rmax0 = fmaxf(rmax0, __shfl_xor_sync(0xffffffffu, rmax0, 1));
        rmax0 = fmaxf(rmax0, __shfl_xor_sync(0xffffffffu, rmax0, 2));
        rmax1 = fmaxf(rmax1, __shfl_xor_sync(0xffffffffu, rmax1, 1));
        rmax1 = fmaxf(rmax1, __shfl_xor_sync(0xffffffffu, rmax1, 2));
        const float mn0 = fmaxf(m0, rmax0), mn1 = fmaxf(m1, rmax1);
        const float cf0 = __expf(m0 - mn0), cf1 = __expf(m1 - mn1);
        m0 = mn0; m1 = mn1;
        float s0 = 0.f, s1 = 0.f;
#pragma unroll
        for (int nt = 0; nt < 8; nt++) {
            accs[nt][0] = __expf(accs[nt][0] - mn0);
            accs[nt][1] = __expf(accs[nt][1] - mn0);
            accs[nt][2] = __expf(accs[nt][2] - mn1);
            accs[nt][3] = __expf(accs[nt][3] - mn1);
            s0 += accs[nt][0] + accs[nt][1];
            s1 += accs[nt][2] + accs[nt][3];
        }
        s0 += __shfl_xor_sync(0xffffffffu, s0, 1);
        s0 += __shfl_xor_sync(0xffffffffu, s0, 2);
        s1 += __shfl_xor_sync(0xffffffffu, s1, 1);
        s1 += __shfl_xor_sync(0xffffffffu, s1, 2);
        l0 = l0 * cf0 + s0;
        l1 = l1 * cf1 + s1;
#pragma unroll
        for (int nt = 0; nt < 16; nt++) {
            acc_o[nt][0] *= cf0; acc_o[nt][1] *= cf0;
            acc_o[nt][2] *= cf1; acc_o[nt][3] *= cf1;
        }

#pragma unroll
        for (int kb = 0; kb < 4; kb++) {
            uint32_t ph[4], pl[4];
            {
                const float* s0p = accs[2 * kb];
                const float* s1p = accs[2 * kb + 1];
                float h00 = __half2float(__float2half_rn(s0p[0]));
                float h01 = __half2float(__float2half_rn(s0p[1]));
                float h02 = __half2float(__float2half_rn(s0p[2]));
                float h03 = __half2float(__float2half_rn(s0p[3]));
                float h10 = __half2float(__float2half_rn(s1p[0]));
                float h11 = __half2float(__float2half_rn(s1p[1]));
                float h12 = __half2float(__float2half_rn(s1p[2]));
                float h13 = __half2float(__float2half_rn(s1p[3]));
                ph[0] = packh2(s0p[0], s0p[1]);
                ph[1] = packh2(s0p[2], s0p[3]);
                ph[2] = packh2(s1p[0], s1p[1]);
                ph[3] = packh2(s1p[2], s1p[3]);
                pl[0] = packh2(s0p[0] - h00, s0p[1] - h01);
                pl[1] = packh2(s0p[2] - h02, s0p[3] - h03);
                pl[2] = packh2(s1p[0] - h10, s1p[1] - h11);
                pl[3] = packh2(s1p[2] - h12, s1p[3] - h13);
            }
#pragma unroll
            for (int np = 0; np < 8; np++) {
                const uint32_t voff = (uint32_t)(kb * 16 + vRow) * AROWB +
                                      (uint32_t)(np * 16 + vCof) * 2;
                uint32_t rv[4], rl[4];
                ldm4t(rv, sVh + voff);
                ldm4t(rl, sVl + voff);
                uint32_t vh0[2] = {rv[0], rv[1]};
                uint32_t vh1[2] = {rv[2], rv[3]};
                uint32_t vl0[2] = {rl[0], rl[1]};
                uint32_t vl1[2] = {rl[2], rl[3]};
                mma_f16(acc_o[2 * np], ph, vh0);
                mma_f16(acc_o[2 * np], ph, vl0);
                mma_f16(acc_o[2 * np], pl, vh0);
                mma_f16(acc_o[2 * np + 1], ph, vh1);
                mma_f16(acc_o[2 * np + 1], ph, vl1);
                mma_f16(acc_o[2 * np + 1], pl, vh1);
            }
        }
    }

    const float inv0 = 1.f / l0, inv1 = 1.f / l1;
#pragma unroll
    for (int nt = 0; nt < 16; nt++) {
        const size_t o0 = (size_t)grow0 * (NQ * HD) + qcol + nt * 8 + cq * 2;
        const size_t o1 = (size_t)grow1 * (NQ * HD) + qcol + nt * 8 + cq * 2;
        *(uint32_t*)&outh[o0] = packh2(acc_o[nt][0] * inv0, acc_o[nt][1] * inv0);
        *(uint32_t*)&outh[o1] = packh2(acc_o[nt][2] * inv1, acc_o[nt][3] * inv1);
    }
}

// ---------------------------------------------------------------------------
// Launch
// ---------------------------------------------------------------------------
extern "C" void kernel_launch(void* const* d_in, const int* in_sizes, int n_in,
                              void* d_out, int out_size)
{
    (void)in_sizes; (void)n_in;
    const float* hidden = (const float*)d_in[1];
    const float* w_qkv = (const float*)d_in[2];
    const float* w_o = (const float*)d_in[3];
    const float* w_gu = (const float*)d_in[4];
    const float* w_down = (const float*)d_in[5];
    const float* ln1 = (const float*)d_in[6];
    const float* ln2 = (const float*)d_in[7];

    float* out = (float*)d_out;
    const size_t SH = (size_t)S_LEN * H_DIM;
    float* out_resid = ((size_t)out_size >= 2 * SH) ? (out + SH) : nullptr;

    float *qkv, *resid;
    cudaGetSymbolAddress((void**)&qkv, g_qkv);
    cudaGetSymbolAddress((void**)&resid, g_resid);
    __half *qkvh, *qkvl;
    cudaGetSymbolAddress((void**)&qkvh, g_qkvh);
    cudaGetSymbolAddress((void**)&qkvl, g_qkvl);
    __half *wqkvh, *woh, *wguh, *wdh;
    __half *xbh, *abh, *hbh;
    cudaGetSymbolAddress((void**)&wqkvh, g_wqkvT_hi);
    cudaGetSymbolAddress((void**)&woh, g_woT_hi);
    cudaGetSymbolAddress((void**)&wguh, g_wguT_hi);
    cudaGetSymbolAddress((void**)&wdh, g_wdownT_hi);
    cudaGetSymbolAddress((void**)&xbh, g_xb_hi);
    cudaGetSymbolAddress((void**)&abh, g_ab_hi);
    cudaGetSymbolAddress((void**)&hbh, g_hb_hi);

    cudaFuncSetAttribute(attn_mma_kernel,
                         cudaFuncAttributeMaxDynamicSharedMemorySize, ATT_SMEM);
    const int SMEM1 = 2 * 2 * TILE_B;
    const int SMEMGU = 2 * 3 * TILE_B;
    cudaFuncSetAttribute(gemm_mma1_kernel,
                         cudaFuncAttributeMaxDynamicSharedMemorySize, SMEM1);
    cudaFuncSetAttribute(gemm_gu_kernel,
                         cudaFuncAttributeMaxDynamicSharedMemorySize, SMEMGU);

    // 0. Weight transpose (fp16 hi planes)
    wt_transpose_kernel<<<dim3(QKV_N / 32, H_DIM / 32), 256>>>(w_qkv, wqkvh, H_DIM, QKV_N);
    wt_transpose_kernel<<<dim3(H_DIM / 32, (NQ * HD) / 32), 256>>>(w_o, woh, NQ * HD, H_DIM);
    wt_transpose_kernel<<<dim3((2 * I_DIM) / 32, H_DIM / 32), 256>>>(w_gu, wguh, H_DIM, 2 * I_DIM);
    wt_transpose_kernel<<<dim3(H_DIM / 32, I_DIM / 32), 256>>>(w_down, wdh, I_DIM, H_DIM);

    // 1. RMSNorm 1 -> fp16 hi
    rmsnorm_h_kernel<<<S_LEN, 256>>>(hidden, ln1, xbh);

    // 2. QKV projection (1-product)
    gemm_mma1_kernel<<<dim3(S_LEN / BM, QKV_N / BN), 256, SMEM1>>>(
        xbh, wqkvh, qkv, S_LEN, QKV_N, H_DIM, nullptr, nullptr);

    // 3. RoPE + split qkv -> fp16 hi/lo planes (attention stays near-exact)
    {
        const int total = S_LEN * 3072;
        rope_split_kernel<<<(total + 255) / 256, 256>>>(qkv, qkvh, qkvl);
    }

    // 4. Tensor-core attention -> fp16 o-proj operand
    attn_mma_kernel<<<dim3(S_LEN / BR, NQ), 256, ATT_SMEM>>>(qkvh, qkvl, abh);

    // 5. O projection (1-product) + residual
    gemm_mma1_kernel<<<dim3(S_LEN / BM, H_DIM / BN), 256, SMEM1>>>(
        abh, woh, resid, S_LEN, H_DIM, NQ * HD, hidden, out_resid);

    // 6. RMSNorm 2 -> fp16 hi
    rmsnorm_h_kernel<<<S_LEN, 256>>>(resid, ln2, xbh);

    // 7+8. Fused gate_up + SiLU -> hb fp16
    gemm_gu_kernel<<<dim3(S_LEN / BM, I_DIM / BN), 256, SMEMGU>>>(
        xbh, wguh, hbh, S_LEN, H_DIM);

    // 9. down (1-product) -> out
    gemm_mma1_kernel<<<dim3(S_LEN / BM, H_DIM / BN), 256, SMEM1>>>(
        hbh, wdh, out, S_LEN, H_DIM, I_DIM, nullptr, nullptr);
}

// round 11
// speedup vs baseline: 4.8173x; 1.0329x over previous
#include <cuda_runtime.h>
#include <cuda_fp16.h>
#include <math.h>
#include <stdint.h>

#define H_DIM 4096
#define S_LEN 2048
#define NQ 32
#define NKV 8
#define HD 128
#define I_DIM 14336
#define QKV_N ((NQ + 2 * NKV) * HD) /* 6144 */
#define EPS 1e-5f

// GEMM tiling (mma.sync path)
#define BM 128
#define BN 128
#define KC 32
#define ROWB 80                       // bytes per smem row (64B data + 16B pad)
#define TILE_B (128 * ROWB)

// Attention tiling
#define BR 128
#define BC 64
#define AROWB 272
#define KVSTG (4 * BC * AROWB)                         // 69632 per stage
#define ATT_SMEM (2 * BR * AROWB + 2 * KVSTG)          // 208896

// ---------------------------------------------------------------------------
// Scratch (device globals)
// ---------------------------------------------------------------------------
__device__ float g_qkv[(size_t)S_LEN * QKV_N];
__device__ float g_resid[(size_t)S_LEN * H_DIM];

__device__ __half g_qkvh[(size_t)S_LEN * QKV_N];
__device__ __half g_qkvl[(size_t)S_LEN * QKV_N];

__device__ __half g_wqkvT_hi[(size_t)QKV_N * H_DIM];
__device__ __half g_woT_hi[(size_t)H_DIM * (NQ * HD)];
__device__ __half g_wguT_hi[(size_t)(2 * I_DIM) * H_DIM];
__device__ __half g_wdownT_hi[(size_t)H_DIM * I_DIM];

__device__ __half g_xb_hi[(size_t)S_LEN * H_DIM];
__device__ __half g_ab_hi[(size_t)S_LEN * NQ * HD];
__device__ __half g_hb_hi[(size_t)S_LEN * I_DIM];

// ---------------------------------------------------------------------------
// PTX helpers
// ---------------------------------------------------------------------------
__device__ __forceinline__ uint32_t smem_u32(const void* p) {
    uint32_t a;
    asm("{ .reg .u64 t; cvta.to.shared.u64 t, %1; cvt.u32.u64 %0, t; }"
        : "=r"(a) : "l"(p));
    return a;
}
__device__ __forceinline__ void cp16(uint32_t saddr, const void* g) {
    asm volatile("cp.async.cg.shared.global [%0], [%1], 16;"
                 :: "r"(saddr), "l"(g) : "memory");
}
__device__ __forceinline__ void cp_commit() {
    asm volatile("cp.async.commit_group;" ::: "memory");
}
template <int N>
__device__ __forceinline__ void cp_wait() {
    asm volatile("cp.async.wait_group %0;" :: "n"(N) : "memory");
}
__device__ __forceinline__ void ldm4(uint32_t* r, uint32_t addr) {
    asm volatile("ldmatrix.sync.aligned.m8n8.x4.shared.b16 {%0,%1,%2,%3}, [%4];"
                 : "=r"(r[0]), "=r"(r[1]), "=r"(r[2]), "=r"(r[3]) : "r"(addr));
}
__device__ __forceinline__ void ldm4t(uint32_t* r, uint32_t addr) {
    asm volatile("ldmatrix.sync.aligned.m8n8.x4.trans.shared.b16 {%0,%1,%2,%3}, [%4];"
                 : "=r"(r[0]), "=r"(r[1]), "=r"(r[2]), "=r"(r[3]) : "r"(addr));
}
__device__ __forceinline__ void mma_f16(float* d, const uint32_t* a,
                                        const uint32_t* b) {
    asm volatile(
        "mma.sync.aligned.m16n8k16.row.col.f32.f16.f16.f32 "
        "{%0,%1,%2,%3}, {%4,%5,%6,%7}, {%8,%9}, {%0,%1,%2,%3};"
        : "+f"(d[0]), "+f"(d[1]), "+f"(d[2]), "+f"(d[3])
        : "r"(a[0]), "r"(a[1]), "r"(a[2]), "r"(a[3]), "r"(b[0]), "r"(b[1]));
}
__device__ __forceinline__ void split1(float x, __half& h, __half& l) {
    h = __float2half_rn(x);
    l = __float2half_rn(x - __half2float(h));
}
__device__ __forceinline__ uint32_t packh2(float a, float b) {
    __half2 h = __floats2half2_rn(a, b);
    return *(uint32_t*)&h;
}
__device__ __forceinline__ float silu_mul(float g, float u) {
    return g / (1.f + __expf(-g)) * u;
}

// ---------------------------------------------------------------------------
// Weight transpose: W[K,N] fp32 -> Thi [N,K] fp16.
// Tile: 64 K-rows x 32 N-cols; vectorized uint2 (4-half) stores.
// ---------------------------------------------------------------------------
__global__ __launch_bounds__(256)
void wt_transpose_kernel(const float* __restrict__ W,
                         __half* __restrict__ Thi, int K, int N)
{
    __shared__ float t[32][65];   // [n_local][k_local], stride 65 = conflict-free
    const int tid = threadIdx.x;
    const int n = blockIdx.x * 32 + (tid & 31);
    const int kb = blockIdx.y * 64;
#pragma unroll
    for (int i = 0; i < 8; i++) {
        const int kl = (tid >> 5) + i * 8;
        t[tid & 31][kl] = W[(size_t)(kb + kl) * N + n];
    }
    __syncthreads();
    const int kq = (tid & 15) * 4;
#pragma unroll
    for (int j = 0; j < 2; j++) {
        const int nr = (tid >> 4) + j * 16;
        const int n2 = blockIdx.x * 32 + nr;
        uint2 o;
        o.x = packh2(t[nr][kq + 0], t[nr][kq + 1]);
        o.y = packh2(t[nr][kq + 2], t[nr][kq + 3]);
        *(uint2*)&Thi[(size_t)n2 * K + kb + kq] = o;
    }
}

// ---------------------------------------------------------------------------
// RMSNorm -> fp16 hi (single plane)
// ---------------------------------------------------------------------------
__global__ __launch_bounds__(256)
void rmsnorm_h_kernel(const float* __restrict__ x, const float* __restrict__ w,
                      __half* __restrict__ ohi)
{
    const int row = blockIdx.x;
    const int t = threadIdx.x;
    const float4* xr = (const float4*)(x + (size_t)row * H_DIM);
    const float4* wr = (const float4*)w;

    float4 v[4];
    float ss = 0.f;
#pragma unroll
    for (int i = 0; i < 4; i++) {
        v[i] = xr[t + 256 * i];
        ss += v[i].x * v[i].x + v[i].y * v[i].y + v[i].z * v[i].z + v[i].w * v[i].w;
    }
#pragma unroll
    for (int o = 16; o; o >>= 1) ss += __shfl_xor_sync(0xffffffffu, ss, o);
    __shared__ float wsum[8];
    if ((t & 31) == 0) wsum[t >> 5] = ss;
    __syncthreads();
    float tot = wsum[0] + wsum[1] + wsum[2] + wsum[3] +
                wsum[4] + wsum[5] + wsum[6] + wsum[7];
    const float sc = rsqrtf(tot * (1.f / H_DIM) + EPS);

    uint2* hr = (uint2*)(ohi + (size_t)row * H_DIM);
#pragma unroll
    for (int i = 0; i < 4; i++) {
        float4 wv = wr[t + 256 * i];
        uint2 h;
        h.x = packh2(v[i].x * sc * wv.x, v[i].y * sc * wv.y);
        h.y = packh2(v[i].z * sc * wv.z, v[i].w * sc * wv.w);
        hr[t + 256 * i] = h;
    }
}

// ---------------------------------------------------------------------------
// mma.sync fp16 GEMM, 1-product, 3-stage cp.async pipeline.
// ---------------------------------------------------------------------------
__global__ __launch_bounds__(256, 1)
void gemm_mma1_kernel(const __half* __restrict__ Ahi,
                      const __half* __restrict__ Bhi,
                      float* __restrict__ C, int M, int N, int K,
                      const float* __restrict__ add, float* __restrict__ C2)
{
    constexpr uint32_t STG = 2 * TILE_B;
    extern __shared__ char smc[];
    const uint32_t sbase = smem_u32(smc);
    const int tid = threadIdx.x;
    const int lane = tid & 31;
    const int wm = (tid >> 5) & 3;
    const int wn = tid >> 7;
    const int m0 = blockIdx.x * BM;
    const int n0 = blockIdx.y * BN;
    const int NCH = K / KC;

    const int q0r = tid >> 2, q0c = tid & 3;
    const int q1r = (tid + 256) >> 2, q1c = tid & 3;

    float acc[2][8][4];
#pragma unroll
    for (int mt = 0; mt < 2; mt++)
#pragma unroll
        for (int nt = 0; nt < 8; nt++)
#pragma unroll
            for (int e = 0; e < 4; e++) acc[mt][nt][e] = 0.f;

    auto issue = [&](int kc, int buf) {
        const uint32_t st = sbase + buf * STG;
        const int kb = kc * KC;
        const size_t gA0 = (size_t)(m0 + q0r) * K + kb + q0c * 8;
        const size_t gA1 = (size_t)(m0 + q1r) * K + kb + q1c * 8;
        const size_t gB0 = (size_t)(n0 + q0r) * K + kb + q0c * 8;
        const size_t gB1 = (size_t)(n0 + q1r) * K + kb + q1c * 8;
        const uint32_t s0 = st + q0r * ROWB + q0c * 16;
        const uint32_t s1 = st + q1r * ROWB + q1c * 16;
        cp16(s0, Ahi + gA0);
        cp16(s1, Ahi + gA1);
        cp16(s0 + TILE_B, Bhi + gB0);
        cp16(s1 + TILE_B, Bhi + gB1);
        cp_commit();
    };

    issue(0, 0);
    issue(1, 1);

    for (int kc = 0; kc < NCH; kc++) {
        if (kc + 2 < NCH) {
            issue(kc + 2, (kc + 2) % 3);
            cp_wait<2>();
        } else if (kc + 1 < NCH) {
            cp_wait<1>();
        } else {
            cp_wait<0>();
        }
        __syncthreads();

        const uint32_t st = sbase + (kc % 3) * STG;
        const uint32_t sAh = st;
        const uint32_t sBh = st + TILE_B;

        const int aRow = wm * 32 + (lane & 15);
        const int aKof = (lane >> 4) * 8;
        const int bIdx = lane & 7;
        const int bSel = lane >> 3;
        const int bRowBase = wn * 64 + ((bSel >> 1) * 8) + bIdx;
        const int bKof = (bSel & 1) * 8;

#pragma unroll
        for (int ks = 0; ks < KC; ks += 16) {
            uint32_t ah[2][4];
#pragma unroll
            for (int mt = 0; mt < 2; mt++) {
                const uint32_t off = (uint32_t)(aRow + mt * 16) * ROWB +
                                     (uint32_t)(ks + aKof) * 2;
                ldm4(ah[mt], sAh + off);
            }
            uint32_t bh[8][2];
#pragma unroll
            for (int p = 0; p < 4; p++) {
                const uint32_t off = (uint32_t)(bRowBase + p * 16) * ROWB +
                                     (uint32_t)(ks + bKof) * 2;
                uint32_t r4[4];
                ldm4(r4, sBh + off);
                bh[2 * p][0] = r4[0]; bh[2 * p][1] = r4[1];
                bh[2 * p + 1][0] = r4[2]; bh[2 * p + 1][1] = r4[3];
            }
#pragma unroll
            for (int mt = 0; mt < 2; mt++)
#pragma unroll
                for (int nt = 0; nt < 8; nt++)
                    mma_f16(acc[mt][nt], ah[mt], bh[nt]);
        }
        __syncthreads();
    }

    const int erow = m0 + wm * 32 + (lane >> 2);
    const int ecol = n0 + wn * 64 + (lane & 3) * 2;
#pragma unroll
    for (int mt = 0; mt < 2; mt++) {
#pragma unroll
        for (int nt = 0; nt < 8; nt++) {
            const int r0 = erow + mt * 16;
            const int c = ecol + nt * 8;
            const size_t off0 = (size_t)r0 * N + c;
            const size_t off1 = (size_t)(r0 + 8) * N + c;
            float2 v0 = make_float2(acc[mt][nt][0], acc[mt][nt][1]);
            float2 v1 = make_float2(acc[mt][nt][2], acc[mt][nt][3]);
            if (add) {
                float2 a0 = *(const float2*)(add + off0);
                float2 a1 = *(const float2*)(add + off1);
                v0.x += a0.x; v0.y += a0.y;
                v1.x += a1.x; v1.y += a1.y;
            }
            *(float2*)(C + off0) = v0;
            *(float2*)(C + off1) = v1;
            if (C2) {
                *(float2*)(C2 + off0) = v0;
                *(float2*)(C2 + off1) = v1;
            }
        }
    }
}

// ---------------------------------------------------------------------------
// Fused gate_up + SiLU GEMM (1-product, 3-stage) -> fp16 Hout [S, I_DIM]
// ---------------------------------------------------------------------------
__global__ __launch_bounds__(256, 1)
void gemm_gu_kernel(const __half* __restrict__ Ahi,
                    const __half* __restrict__ Bhi,
                    __half* __restrict__ Hout, int M, int K)
{
    constexpr uint32_t STG = 3 * TILE_B;
    extern __shared__ char smc[];
    const uint32_t sbase = smem_u32(smc);
    const int tid = threadIdx.x;
    const int lane = tid & 31;
    const int wm = (tid >> 5) & 3;
    const int wn = tid >> 7;
    const int m0 = blockIdx.x * BM;
    const int n0 = blockIdx.y * BN;
    const int NCH = K / KC;

    const int q0r = tid >> 2, q0c = tid & 3;
    const int q1r = (tid + 256) >> 2, q1c = tid & 3;

    float acc_g[2][8][4], acc_u[2][8][4];
#pragma unroll
    for (int mt = 0; mt < 2; mt++)
#pragma unroll
        for (int nt = 0; nt < 8; nt++)
#pragma unroll
            for (int e = 0; e < 4; e++) { acc_g[mt][nt][e] = 0.f; acc_u[mt][nt][e] = 0.f; }

    auto issue = [&](int kc, int buf) {
        const uint32_t st = sbase + buf * STG;
        const int kb = kc * KC;
        const size_t gA0 = (size_t)(m0 + q0r) * K + kb + q0c * 8;
        const size_t gA1 = (size_t)(m0 + q1r) * K + kb + q1c * 8;
        const size_t gG0 = (size_t)(n0 + q0r) * K + kb + q0c * 8;
        const size_t gG1 = (size_t)(n0 + q1r) * K + kb + q1c * 8;
        const size_t gU0 = (size_t)(I_DIM + n0 + q0r) * K + kb + q0c * 8;
        const size_t gU1 = (size_t)(I_DIM + n0 + q1r) * K + kb + q1c * 8;
        const uint32_t s0 = st + q0r * ROWB + q0c * 16;
        const uint32_t s1 = st + q1r * ROWB + q1c * 16;
        cp16(s0, Ahi + gA0);
        cp16(s1, Ahi + gA1);
        cp16(s0 + TILE_B, Bhi + gG0);
        cp16(s1 + TILE_B, Bhi + gG1);
        cp16(s0 + 2 * TILE_B, Bhi + gU0);
        cp16(s1 + 2 * TILE_B, Bhi + gU1);
        cp_commit();
    };

    issue(0, 0);
    issue(1, 1);

    for (int kc = 0; kc < NCH; kc++) {
        if (kc + 2 < NCH) {
            issue(kc + 2, (kc + 2) % 3);
            cp_wait<2>();
        } else if (kc + 1 < NCH) {
            cp_wait<1>();
        } else {
            cp_wait<0>();
        }
        __syncthreads();

        const uint32_t st = sbase + (kc % 3) * STG;
        const uint32_t sAh = st;
        const uint32_t sBg = st + TILE_B;
        const uint32_t sBu = st + 2 * TILE_B;

        const int aRow = wm * 32 + (lane & 15);
        const int aKof = (lane >> 4) * 8;
        const int bIdx = lane & 7;
        const int bSel = lane >> 3;
        const int bRowBase = wn * 64 + ((bSel >> 1) * 8) + bIdx;
        const int bKof = (bSel & 1) * 8;

#pragma unroll
        for (int ks = 0; ks < KC; ks += 16) {
            uint32_t ah[2][4];
#pragma unroll
            for (int mt = 0; mt < 2; mt++) {
                const uint32_t off = (uint32_t)(aRow + mt * 16) * ROWB +
                                     (uint32_t)(ks + aKof) * 2;
                ldm4(ah[mt], sAh + off);
            }
            uint32_t bg[8][2], bu[8][2];
#pragma unroll
            for (int p = 0; p < 4; p++) {
                const uint32_t off = (uint32_t)(bRowBase + p * 16) * ROWB +
                                     (uint32_t)(ks + bKof) * 2;
                uint32_t r4[4];
                ldm4(r4, sBg + off);
                bg[2 * p][0] = r4[0]; bg[2 * p][1] = r4[1];
                bg[2 * p + 1][0] = r4[2]; bg[2 * p + 1][1] = r4[3];
                ldm4(r4, sBu + off);
                bu[2 * p][0] = r4[0]; bu[2 * p][1] = r4[1];
                bu[2 * p + 1][0] = r4[2]; bu[2 * p + 1][1] = r4[3];
            }
#pragma unroll
            for (int mt = 0; mt < 2; mt++)
#pragma unroll
                for (int nt = 0; nt < 8; nt++) {
                    mma_f16(acc_g[mt][nt], ah[mt], bg[nt]);
                    mma_f16(acc_u[mt][nt], ah[mt], bu[nt]);
                }
        }
        __syncthreads();
    }

    const int erow = m0 + wm * 32 + (lane >> 2);
    const int ecol = n0 + wn * 64 + (lane & 3) * 2;
#pragma unroll
    for (int mt = 0; mt < 2; mt++) {
#pragma unroll
        for (int nt = 0; nt < 8; nt++) {
            const int r0 = erow + mt * 16;
            const int c = ecol + nt * 8;
            const float h00 = silu_mul(acc_g[mt][nt][0], acc_u[mt][nt][0]);
            const float h01 = silu_mul(acc_g[mt][nt][1], acc_u[mt][nt][1]);
            const float h10 = silu_mul(acc_g[mt][nt][2], acc_u[mt][nt][2]);
            const float h11 = silu_mul(acc_g[mt][nt][3], acc_u[mt][nt][3]);
            *(uint32_t*)&Hout[(size_t)r0 * I_DIM + c] = packh2(h00, h01);
            *(uint32_t*)&Hout[(size_t)(r0 + 8) * I_DIM + c] = packh2(h10, h11);
        }
    }
}

// ---------------------------------------------------------------------------
// RoPE + split qkv fp32 -> fp16 hi/lo planes
// ---------------------------------------------------------------------------
__global__ void rope_split_kernel(const float* __restrict__ qkv,
                                  __half* __restrict__ oh,
                                  __half* __restrict__ ol)
{
    const int idx = blockIdx.x * blockDim.x + threadIdx.x;
    const int total = S_LEN * 3072;
    if (idx >= total) return;
    const int slot = idx % 3072;
    const int s = idx / 3072;
    const size_t rb = (size_t)s * QKV_N;

    if (slot < 2560) {
        const int head = slot >> 6;
        const int d = slot & 63;
        const int col = head * HD + d;
        const float inv = exp2f((float)d * (-13.287712379549449f / 64.f));
        const float ang = (float)s * inv;
        float sn, c;
        sincosf(ang, &sn, &c);
        const float x1 = qkv[rb + col];
        const float x2 = qkv[rb + col + 64];
        const float y1 = x1 * c - x2 * sn;
        const float y2 = x2 * c + x1 * sn;
        __half h1, l1, h2, l2;
        split1(y1, h1, l1);
        split1(y2, h2, l2);
        oh[rb + col] = h1; oh[rb + col + 64] = h2;
        ol[rb + col] = l1; ol[rb + col + 64] = l2;
    } else {
        const int c0 = 5120 + (slot - 2560) * 2;
        const float x1 = qkv[rb + c0];
        const float x2 = qkv[rb + c0 + 1];
        __half h1, l1, h2, l2;
        split1(x1, h1, l1);
        split1(x2, h2, l2);
        oh[rb + c0] = h1; oh[rb + c0 + 1] = h2;
        ol[rb + c0] = l1; ol[rb + c0 + 1] = l2;
    }
}

// ---------------------------------------------------------------------------
// Tensor-core flash attention (fp16 hi/lo, 3-product) with double-buffered
// K/V tiles. Output: single fp16 plane.
// ---------------------------------------------------------------------------
__global__ __launch_bounds__(256, 1)
void attn_mma_kernel(const __half* __restrict__ qph,
                     const __half* __restrict__ qpl,
                     __half* __restrict__ outh)
{
    extern __shared__ char smc[];
    const uint32_t sb = smem_u32(smc);
    const uint32_t sQh = sb;
    const uint32_t sQl = sb + BR * AROWB;
    const uint32_t kvb = sb + 2 * BR * AROWB;

    const int tid = threadIdx.x;
    const int lane = tid & 31;
    const int warp = tid >> 5;
    const int mb = blockIdx.x;
    const int head = blockIdx.y;
    const int kh = head >> 2;
    const float scale = 0.088388347648318447f;

    const int qcol = head * HD;
    const int kcol = NQ * HD + kh * HD;
    const int vcol = (NQ + NKV) * HD + kh * HD;

    // Q (hi/lo) async load — its own commit group
    {
        const int chunk = tid & 15;
        const int rbase = tid >> 4;
#pragma unroll
        for (int i = 0; i < 8; i++) {
            const int row = rbase + i * 16;
            const size_t g = (size_t)(mb * BR + row) * QKV_N + qcol + chunk * 8;
            const uint32_t so = row * AROWB + chunk * 16;
            cp16(sQh + so, qph + g);
            cp16(sQl + so, qpl + g);
        }
    }
    cp_commit();

    auto issue_kv = [&](int nb, int buf) {
        const uint32_t st = kvb + buf * KVSTG;
        const int chunk = tid & 15;
        const int rbase = tid >> 4;
#pragma unroll
        for (int i = 0; i < 4; i++) {
            const int row = rbase + i * 16;
            const size_t gk = (size_t)(nb * BC + row) * QKV_N + kcol + chunk * 8;
            const size_t gv = (size_t)(nb * BC + row) * QKV_N + vcol + chunk * 8;
            const uint32_t so = row * AROWB + chunk * 16;
            cp16(st + so, qph + gk);                      // Kh
            cp16(st + BC * AROWB + so, qpl + gk);         // Kl
            cp16(st + 2 * BC * AROWB + so, qph + gv);     // Vh
            cp16(st + 3 * BC * AROWB + so, qpl + gv);     // Vl
        }
        cp_commit();
    };

    float m0 = -1e30f, m1 = -1e30f, l0 = 0.f, l1 = 0.f;
    float acc_o[16][4];
#pragma unroll
    for (int nt = 0; nt < 16; nt++)
#pragma unroll
        for (int e = 0; e < 4; e++) acc_o[nt][e] = 0.f;

    const int aRow = warp * 16 + (lane & 15);
    const int aKof = (lane >> 4) * 8;
    const int bIdx = lane & 7;
    const int bSel = lane >> 3;
    const int bRowBase = (bSel >> 1) * 8 + bIdx;
    const int bKof = (bSel & 1) * 8;
    const int vRow = lane & 15;
    const int vCof = (lane >> 4) * 8;

    const int r0 = lane >> 2;
    const int cq = lane & 3;
    const int grow0 = mb * BR + warp * 16 + r0;
    const int grow1 = grow0 + 8;

    const int ntiles = 2 * mb + 2;
    issue_kv(0, 0);

    for (int nb = 0; nb < ntiles; nb++) {
        if (nb + 1 < ntiles) {
            issue_kv(nb + 1, (nb + 1) & 1);
            cp_wait<1>();
        } else {
            cp_wait<0>();
        }
        __syncthreads();

        const uint32_t st = kvb + (nb & 1) * KVSTG;
        const uint32_t sKh = st;
        const uint32_t sKl = st + BC * AROWB;
        const uint32_t sVh = st + 2 * BC * AROWB;
        const uint32_t sVl = st + 3 * BC * AROWB;

        float accs[8][4];
#pragma unroll
        for (int nt = 0; nt < 8; nt++)
#pragma unroll
            for (int e = 0; e < 4; e++) accs[nt][e] = 0.f;

#pragma unroll
        for (int ks = 0; ks < 8; ks++) {
            uint32_t aqh[4], aql[4];
            const uint32_t aoff = (uint32_t)aRow * AROWB + (uint32_t)(ks * 16 + aKof) * 2;
            ldm4(aqh, sQh + aoff);
            ldm4(aql, sQl + aoff);
            uint32_t bh[8][2], bl[8][2];
#pragma unroll
            for (int p = 0; p < 4; p++) {
                const uint32_t boff = (uint32_t)(bRowBase + p * 16) * AROWB +
                                      (uint32_t)(ks * 16 + bKof) * 2;
                uint32_t r4[4];
                ldm4(r4, sKh + boff);
                bh[2 * p][0] = r4[0]; bh[2 * p][1] = r4[1];
                bh[2 * p + 1][0] = r4[2]; bh[2 * p + 1][1] = r4[3];
                ldm4(r4, sKl + boff);
                bl[2 * p][0] = r4[0]; bl[2 * p][1] = r4[1];
                bl[2 * p + 1][0] = r4[2]; bl[2 * p + 1][1] = r4[3];
            }
#pragma unroll
            for (int nt = 0; nt < 8; nt++) {
                mma_f16(accs[nt], aqh, bh[nt]);
                mma_f16(accs[nt], aqh, bl[nt]);
                mma_f16(accs[nt], aql, bh[nt]);
            }
        }

        float rmax0 = -1e30f, rmax1 = -1e30f;
#pragma unroll
        for (int nt = 0; nt < 8; nt++) {
            const int cbase = nb * BC + nt * 8 + cq * 2;
#pragma unroll
            for (int e = 0; e < 4; e++) {
                float s = accs[nt][e] * scale;
                const int col = cbase + (e & 1);
                const int row = (e < 2) ? grow0 : grow1;
                if (col > row) s = -1e30f;
                accs[nt][e] = s;
            }
            rmax0 = fmaxf(rmax0, fmaxf(accs[nt][0], accs[nt][1]));
            rmax1 = fmaxf(rmax1, fmaxf(accs[nt][2], accs[nt][3]));
        }
        rmax0 = fmaxf(rmax0, __shfl_xor_sync(0xffffffffu, rmax0, 1));
        rmax0 = fmaxf(rmax0, __shfl_xor_sync(0xffffffffu, rmax0, 2));
        rmax1 = fmaxf(rmax1, __shfl_xor_sync(0xffffffffu, rmax1, 1));
        rmax1 = fmaxf(rmax1, __shfl_xor_sync(0xffffffffu, rmax1, 2));
        const float mn0 = fmaxf(m0, rmax0), mn1 = fmaxf(m1, rmax1);
        const float cf0 = __expf(m0 - mn0), cf1 = __expf(m1 - mn1);
        m0 = mn0; m1 = mn1;
        float s0 = 0.f, s1 = 0.f;
#pragma unroll
        for (int nt = 0; nt < 8; nt++) {
            accs[nt][0] = __expf(accs[nt][0] - mn0);
            accs[nt][1] = __expf(accs[nt][1] - mn0);
            accs[nt][2] = __expf(accs[nt][2] - mn1);
            accs[nt][3] = __expf(accs[nt][3] - mn1);
            s0 += accs[nt][0] + accs[nt][1];
            s1 += accs[nt][2] + accs[nt][3];
        }
        s0 += __shfl_xor_sync(0xffffffffu, s0, 1);
        s0 += __shfl_xor_sync(0xffffffffu, s0, 2);
        s1 += __shfl_xor_sync(0xffffffffu, s1, 1);
        s1 += __shfl_xor_sync(0xffffffffu, s1, 2);
        l0 = l0 * cf0 + s0;
        l1 = l1 * cf1 + s1;
#pragma unroll
        for (int nt = 0; nt < 16; nt++) {
            acc_o[nt][0] *= cf0; acc_o[nt][1] *= cf0;
            acc_o[nt][2] *= cf1; acc_o[nt][3] *= cf1;
        }

#pragma unroll
        for (int kb = 0; kb < 4; kb++) {
            uint32_t ph[4], pl[4];
            {
                const float* s0p = accs[2 * kb];
                const float* s1p = accs[2 * kb + 1];
                float h00 = __half2float(__float2half_rn(s0p[0]));
                float h01 = __half2float(__float2half_rn(s0p[1]));
                float h02 = __half2float(__float2half_rn(s0p[2]));
                float h03 = __half2float(__float2half_rn(s0p[3]));
                float h10 = __half2float(__float2half_rn(s1p[0]));
                float h11 = __half2float(__float2half_rn(s1p[1]));
                float h12 = __half2float(__float2half_rn(s1p[2]));
                float h13 = __half2float(__float2half_rn(s1p[3]));
                ph[0] = packh2(s0p[0], s0p[1]);
                ph[1] = packh2(s0p[2], s0p[3]);
                ph[2] = packh2(s1p[0], s1p[1]);
                ph[3] = packh2(s1p[2], s1p[3]);
                pl[0] = packh2(s0p[0] - h00, s0p[1] - h01);
                pl[1] = packh2(s0p[2] - h02, s0p[3] - h03);
                pl[2] = packh2(s1p[0] - h10, s1p[1] - h11);
                pl[3] = packh2(s1p[2] - h12, s1p[3] - h13);
            }
#pragma unroll
            for (int np = 0; np < 8; np++) {
                const uint32_t voff = (uint32_t)(kb * 16 + vRow) * AROWB +
                                      (uint32_t)(np * 16 + vCof) * 2;
                uint32_t rv[4], rl[4];
                ldm4t(rv, sVh + voff);
                ldm4t(rl, sVl + voff);
                uint32_t vh0[2] = {rv[0], rv[1]};
                uint32_t vh1[2] = {rv[2], rv[3]};
                uint32_t vl0[2] = {rl[0], rl[1]};
                uint32_t vl1[2] = {rl[2], rl[3]};
                mma_f16(acc_o[2 * np], ph, vh0);
                mma_f16(acc_o[2 * np], ph, vl0);
                mma_f16(acc_o[2 * np], pl, vh0);
                mma_f16(acc_o[2 * np + 1], ph, vh1);
                mma_f16(acc_o[2 * np + 1], ph, vl1);
                mma_f16(acc_o[2 * np + 1], pl, vh1);
            }
        }
        __syncthreads();   // buffer consumed before it is re-filled
    }

    const float inv0 = 1.f / l0, inv1 = 1.f / l1;
#pragma unroll
    for (int nt = 0; nt < 16; nt++) {
        const size_t o0 = (size_t)grow0 * (NQ * HD) + qcol + nt * 8 + cq * 2;
        const size_t o1 = (size_t)grow1 * (NQ * HD) + qcol + nt * 8 + cq * 2;
        *(uint32_t*)&outh[o0] = packh2(acc_o[nt][0] * inv0, acc_o[nt][1] * inv0);
        *(uint32_t*)&outh[o1] = packh2(acc_o[nt][2] * inv1, acc_o[nt][3] * inv1);
    }
}

// ---------------------------------------------------------------------------
// Launch
// ---------------------------------------------------------------------------
extern "C" void kernel_launch(void* const* d_in, const int* in_sizes, int n_in,
                              void* d_out, int out_size)
{
    (void)in_sizes; (void)n_in;
    const float* hidden = (const float*)d_in[1];
    const float* w_qkv = (const float*)d_in[2];
    const float* w_o = (const float*)d_in[3];
    const float* w_gu = (const float*)d_in[4];
    const float* w_down = (const float*)d_in[5];
    const float* ln1 = (const float*)d_in[6];
    const float* ln2 = (const float*)d_in[7];

    float* out = (float*)d_out;
    const size_t SH = (size_t)S_LEN * H_DIM;
    float* out_resid = ((size_t)out_size >= 2 * SH) ? (out + SH) : nullptr;

    float *qkv, *resid;
    cudaGetSymbolAddress((void**)&qkv, g_qkv);
    cudaGetSymbolAddress((void**)&resid, g_resid);
    __half *qkvh, *qkvl;
    cudaGetSymbolAddress((void**)&qkvh, g_qkvh);
    cudaGetSymbolAddress((void**)&qkvl, g_qkvl);
    __half *wqkvh, *woh, *wguh, *wdh;
    __half *xbh, *abh, *hbh;
    cudaGetSymbolAddress((void**)&wqkvh, g_wqkvT_hi);
    cudaGetSymbolAddress((void**)&woh, g_woT_hi);
    cudaGetSymbolAddress((void**)&wguh, g_wguT_hi);
    cudaGetSymbolAddress((void**)&wdh, g_wdownT_hi);
    cudaGetSymbolAddress((void**)&xbh, g_xb_hi);
    cudaGetSymbolAddress((void**)&abh, g_ab_hi);
    cudaGetSymbolAddress((void**)&hbh, g_hb_hi);

    cudaFuncSetAttribute(attn_mma_kernel,
                         cudaFuncAttributeMaxDynamicSharedMemorySize, ATT_SMEM);
    const int SMEM1 = 3 * 2 * TILE_B;    // 61440 (3-stage)
    const int SMEMGU = 3 * 3 * TILE_B;   // 92160 (3-stage)
    cudaFuncSetAttribute(gemm_mma1_kernel,
                         cudaFuncAttributeMaxDynamicSharedMemorySize, SMEM1);
    cudaFuncSetAttribute(gemm_gu_kernel,
                         cudaFuncAttributeMaxDynamicSharedMemorySize, SMEMGU);

    // 0. Weight transpose (fp16 hi planes), vectorized
    wt_transpose_kernel<<<dim3(QKV_N / 32, H_DIM / 64), 256>>>(w_qkv, wqkvh, H_DIM, QKV_N);
    wt_transpose_kernel<<<dim3(H_DIM / 32, (NQ * HD) / 64), 256>>>(w_o, woh, NQ * HD, H_DIM);
    wt_transpose_kernel<<<dim3((2 * I_DIM) / 32, H_DIM / 64), 256>>>(w_gu, wguh, H_DIM, 2 * I_DIM);
    wt_transpose_kernel<<<dim3(H_DIM / 32, I_DIM / 64), 256>>>(w_down, wdh, I_DIM, H_DIM);

    // 1. RMSNorm 1 -> fp16 hi
    rmsnorm_h_kernel<<<S_LEN, 256>>>(hidden, ln1, xbh);

    // 2. QKV projection (1-product)
    gemm_mma1_kernel<<<dim3(S_LEN / BM, QKV_N / BN), 256, SMEM1>>>(
        xbh, wqkvh, qkv, S_LEN, QKV_N, H_DIM, nullptr, nullptr);

    // 3. RoPE + split qkv -> fp16 hi/lo planes
    {
        const int total = S_LEN * 3072;
        rope_split_kernel<<<(total + 255) / 256, 256>>>(qkv, qkvh, qkvl);
    }

    // 4. Tensor-core attention (double-buffered KV) -> fp16 o-proj operand
    attn_mma_kernel<<<dim3(S_LEN / BR, NQ), 256, ATT_SMEM>>>(qkvh, qkvl, abh);

    // 5. O projection (1-product) + residual
    gemm_mma1_kernel<<<dim3(S_LEN / BM, H_DIM / BN), 256, SMEM1>>>(
        abh, woh, resid, S_LEN, H_DIM, NQ * HD, hidden, out_resid);

    // 6. RMSNorm 2 -> fp16 hi
    rmsnorm_h_kernel<<<S_LEN, 256>>>(resid, ln2, xbh);

    // 7+8. Fused gate_up + SiLU -> hb fp16
    gemm_gu_kernel<<<dim3(S_LEN / BM, I_DIM / BN), 256, SMEMGU>>>(
        xbh, wguh, hbh, S_LEN, H_DIM);

    // 9. down (1-product) -> out
    gemm_mma1_kernel<<<dim3(S_LEN / BM, H_DIM / BN), 256, SMEM1>>>(
        hbh, wdh, out, S_LEN, H_DIM, I_DIM, nullptr, nullptr);
}

// round 12
// speedup vs baseline: 5.1425x; 1.0675x over previous
#include <cuda_runtime.h>
#include <cuda_fp16.h>
#include <math.h>
#include <stdint.h>

#define H_DIM 4096
#define S_LEN 2048
#define NQ 32
#define NKV 8
#define HD 128
#define I_DIM 14336
#define QKV_N ((NQ + 2 * NKV) * HD) /* 6144 */
#define EPS 1e-5f

// GEMM tiling
#define BM 128
#define KC 32
#define ROWB 80                       // bytes per smem row (64B data + 16B pad)
#define TILE_B (128 * ROWB)
// wide kernel: 128x256 tile, A(128)+B(256) rows per stage
#define STG256 (384 * ROWB)           // 30720

// Attention tiling
#define BR 128
#define BC 64
#define AROWB 272
#define KVSTG (4 * BC * AROWB)
#define ATT_SMEM (2 * BR * AROWB + 2 * KVSTG)   // 208896

// ---------------------------------------------------------------------------
// Scratch (device globals)
// ---------------------------------------------------------------------------
__device__ float g_qkv[(size_t)S_LEN * QKV_N];
__device__ float g_resid[(size_t)S_LEN * H_DIM];

__device__ __half g_qkvh[(size_t)S_LEN * QKV_N];
__device__ __half g_qkvl[(size_t)S_LEN * QKV_N];

__device__ __half g_wqkvT_hi[(size_t)QKV_N * H_DIM];
__device__ __half g_woT_hi[(size_t)H_DIM * (NQ * HD)];
__device__ __half g_wguT_hi[(size_t)(2 * I_DIM) * H_DIM];
__device__ __half g_wdownT_hi[(size_t)H_DIM * I_DIM];

__device__ __half g_xb_hi[(size_t)S_LEN * H_DIM];
__device__ __half g_ab_hi[(size_t)S_LEN * NQ * HD];
__device__ __half g_hb_hi[(size_t)S_LEN * I_DIM];

// ---------------------------------------------------------------------------
// PTX helpers
// ---------------------------------------------------------------------------
__device__ __forceinline__ uint32_t smem_u32(const void* p) {
    uint32_t a;
    asm("{ .reg .u64 t; cvta.to.shared.u64 t, %1; cvt.u32.u64 %0, t; }"
        : "=r"(a) : "l"(p));
    return a;
}
__device__ __forceinline__ void cp16(uint32_t saddr, const void* g) {
    asm volatile("cp.async.cg.shared.global [%0], [%1], 16;"
                 :: "r"(saddr), "l"(g) : "memory");
}
__device__ __forceinline__ void cp_commit() {
    asm volatile("cp.async.commit_group;" ::: "memory");
}
template <int N>
__device__ __forceinline__ void cp_wait() {
    asm volatile("cp.async.wait_group %0;" :: "n"(N) : "memory");
}
__device__ __forceinline__ void ldm4(uint32_t* r, uint32_t addr) {
    asm volatile("ldmatrix.sync.aligned.m8n8.x4.shared.b16 {%0,%1,%2,%3}, [%4];"
                 : "=r"(r[0]), "=r"(r[1]), "=r"(r[2]), "=r"(r[3]) : "r"(addr));
}
__device__ __forceinline__ void ldm4t(uint32_t* r, uint32_t addr) {
    asm volatile("ldmatrix.sync.aligned.m8n8.x4.trans.shared.b16 {%0,%1,%2,%3}, [%4];"
                 : "=r"(r[0]), "=r"(r[1]), "=r"(r[2]), "=r"(r[3]) : "r"(addr));
}
__device__ __forceinline__ void mma_f16(float* d, const uint32_t* a,
                                        const uint32_t* b) {
    asm volatile(
        "mma.sync.aligned.m16n8k16.row.col.f32.f16.f16.f32 "
        "{%0,%1,%2,%3}, {%4,%5,%6,%7}, {%8,%9}, {%0,%1,%2,%3};"
        : "+f"(d[0]), "+f"(d[1]), "+f"(d[2]), "+f"(d[3])
        : "r"(a[0]), "r"(a[1]), "r"(a[2]), "r"(a[3]), "r"(b[0]), "r"(b[1]));
}
__device__ __forceinline__ void split1(float x, __half& h, __half& l) {
    h = __float2half_rn(x);
    l = __float2half_rn(x - __half2float(h));
}
__device__ __forceinline__ uint32_t packh2(float a, float b) {
    __half2 h = __floats2half2_rn(a, b);
    return *(uint32_t*)&h;
}
__device__ __forceinline__ float silu_mul(float g, float u) {
    return g / (1.f + __expf(-g)) * u;
}

// ---------------------------------------------------------------------------
// Weight transpose: W[K,N] fp32 -> Thi [N,K] fp16 (vectorized)
// ---------------------------------------------------------------------------
__global__ __launch_bounds__(256)
void wt_transpose_kernel(const float* __restrict__ W,
                         __half* __restrict__ Thi, int K, int N)
{
    __shared__ float t[32][65];
    const int tid = threadIdx.x;
    const int n = blockIdx.x * 32 + (tid & 31);
    const int kb = blockIdx.y * 64;
#pragma unroll
    for (int i = 0; i < 8; i++) {
        const int kl = (tid >> 5) + i * 8;
        t[tid & 31][kl] = W[(size_t)(kb + kl) * N + n];
    }
    __syncthreads();
    const int kq = (tid & 15) * 4;
#pragma unroll
    for (int j = 0; j < 2; j++) {
        const int nr = (tid >> 4) + j * 16;
        const int n2 = blockIdx.x * 32 + nr;
        uint2 o;
        o.x = packh2(t[nr][kq + 0], t[nr][kq + 1]);
        o.y = packh2(t[nr][kq + 2], t[nr][kq + 3]);
        *(uint2*)&Thi[(size_t)n2 * K + kb + kq] = o;
    }
}

// ---------------------------------------------------------------------------
// RMSNorm -> fp16 hi
// ---------------------------------------------------------------------------
__global__ __launch_bounds__(256)
void rmsnorm_h_kernel(const float* __restrict__ x, const float* __restrict__ w,
                      __half* __restrict__ ohi)
{
    const int row = blockIdx.x;
    const int t = threadIdx.x;
    const float4* xr = (const float4*)(x + (size_t)row * H_DIM);
    const float4* wr = (const float4*)w;

    float4 v[4];
    float ss = 0.f;
#pragma unroll
    for (int i = 0; i < 4; i++) {
        v[i] = xr[t + 256 * i];
        ss += v[i].x * v[i].x + v[i].y * v[i].y + v[i].z * v[i].z + v[i].w * v[i].w;
    }
#pragma unroll
    for (int o = 16; o; o >>= 1) ss += __shfl_xor_sync(0xffffffffu, ss, o);
    __shared__ float wsum[8];
    if ((t & 31) == 0) wsum[t >> 5] = ss;
    __syncthreads();
    float tot = wsum[0] + wsum[1] + wsum[2] + wsum[3] +
                wsum[4] + wsum[5] + wsum[6] + wsum[7];
    const float sc = rsqrtf(tot * (1.f / H_DIM) + EPS);

    uint2* hr = (uint2*)(ohi + (size_t)row * H_DIM);
#pragma unroll
    for (int i = 0; i < 4; i++) {
        float4 wv = wr[t + 256 * i];
        uint2 h;
        h.x = packh2(v[i].x * sc * wv.x, v[i].y * sc * wv.y);
        h.y = packh2(v[i].z * sc * wv.z, v[i].w * sc * wv.w);
        hr[t + 256 * i] = h;
    }
}

// ---------------------------------------------------------------------------
// mma.sync fp16 GEMM, 1-product, 128x256 tile, 3-stage pipeline.
// 8 warps = 2m x 4n, each 64x64. B frags consumed per-ldmatrix.
// ---------------------------------------------------------------------------
__global__ __launch_bounds__(256, 1)
void gemm_mma1_kernel(const __half* __restrict__ Ahi,
                      const __half* __restrict__ Bhi,
                      float* __restrict__ C, int M, int N, int K,
                      const float* __restrict__ add, float* __restrict__ C2)
{
    extern __shared__ char smc[];
    const uint32_t sbase = smem_u32(smc);
    const int tid = threadIdx.x;
    const int lane = tid & 31;
    const int wm = (tid >> 5) & 1;        // 2 m-halves of 64 rows
    const int wn = (tid >> 6);            // 4 n-quarters of 64 cols
    const int m0 = blockIdx.x * BM;
    const int n0 = blockIdx.y * 256;
    const int NCH = K / KC;

    float acc[4][8][4];
#pragma unroll
    for (int mt = 0; mt < 4; mt++)
#pragma unroll
        for (int nt = 0; nt < 8; nt++)
#pragma unroll
            for (int e = 0; e < 4; e++) acc[mt][nt][e] = 0.f;

    // 384 combined rows per stage: A rows 0..127, B rows 128..383
    auto issue = [&](int kc, int buf) {
        const uint32_t st = sbase + buf * STG256;
        const int kb = kc * KC;
#pragma unroll
        for (int i = 0; i < 6; i++) {
            const int lin = tid + i * 256;
            const int r = lin >> 2;
            const int c = lin & 3;
            const __half* src = (r < 128)
                ? (Ahi + (size_t)(m0 + r) * K + kb + c * 8)
                : (Bhi + (size_t)(n0 + r - 128) * K + kb + c * 8);
            cp16(st + r * ROWB + c * 16, src);
        }
        cp_commit();
    };

    issue(0, 0);
    issue(1, 1);

    const int aRowL = (lane & 15);
    const int aKof = (lane >> 4) * 8;
    const int bIdx = lane & 7;
    const int bSel = lane >> 3;
    const int bKof = (bSel & 1) * 8;
    const uint32_t sBoff = 128 * ROWB;

    for (int kc = 0; kc < NCH; kc++) {
        if (kc + 2 < NCH) {
            issue(kc + 2, (kc + 2) % 3);
            cp_wait<2>();
        } else if (kc + 1 < NCH) {
            cp_wait<1>();
        } else {
            cp_wait<0>();
        }
        __syncthreads();

        const uint32_t st = sbase + (kc % 3) * STG256;
        const uint32_t sA = st;
        const uint32_t sB = st + sBoff;

#pragma unroll
        for (int ks = 0; ks < KC; ks += 16) {
            uint32_t ah[4][4];
#pragma unroll
            for (int mt = 0; mt < 4; mt++) {
                const uint32_t off =
                    (uint32_t)(wm * 64 + mt * 16 + aRowL) * ROWB +
                    (uint32_t)(ks + aKof) * 2;
                ldm4(ah[mt], sA + off);
            }
#pragma unroll
            for (int p = 0; p < 4; p++) {
                const uint32_t off =
                    (uint32_t)(wn * 64 + p * 16 + (bSel >> 1) * 8 + bIdx) * ROWB +
                    (uint32_t)(ks + bKof) * 2;
                uint32_t r4[4];
                ldm4(r4, sB + off);
                uint32_t b0[2] = {r4[0], r4[1]};
                uint32_t b1[2] = {r4[2], r4[3]};
#pragma unroll
                for (int mt = 0; mt < 4; mt++) {
                    mma_f16(acc[mt][2 * p], ah[mt], b0);
                    mma_f16(acc[mt][2 * p + 1], ah[mt], b1);
                }
            }
        }
        __syncthreads();
    }

    const int erowL = lane >> 2;
    const int ecolL = (lane & 3) * 2;
#pragma unroll
    for (int mt = 0; mt < 4; mt++) {
#pragma unroll
        for (int nt = 0; nt < 8; nt++) {
            const int r0 = m0 + wm * 64 + mt * 16 + erowL;
            const int c = n0 + wn * 64 + nt * 8 + ecolL;
            const size_t off0 = (size_t)r0 * N + c;
            const size_t off1 = (size_t)(r0 + 8) * N + c;
            float2 v0 = make_float2(acc[mt][nt][0], acc[mt][nt][1]);
            float2 v1 = make_float2(acc[mt][nt][2], acc[mt][nt][3]);
            if (add) {
                float2 a0 = *(const float2*)(add + off0);
                float2 a1 = *(const float2*)(add + off1);
                v0.x += a0.x; v0.y += a0.y;
                v1.x += a1.x; v1.y += a1.y;
            }
            *(float2*)(C + off0) = v0;
            *(float2*)(C + off1) = v1;
            if (C2) {
                *(float2*)(C2 + off0) = v0;
                *(float2*)(C2 + off1) = v1;
            }
        }
    }
}

// ---------------------------------------------------------------------------
// Fused gate_up + SiLU GEMM (1-product, 3-stage, 128x128x2) -> fp16 Hout
// ---------------------------------------------------------------------------
__global__ __launch_bounds__(256, 1)
void gemm_gu_kernel(const __half* __restrict__ Ahi,
                    const __half* __restrict__ Bhi,
                    __half* __restrict__ Hout, int M, int K)
{
    constexpr uint32_t STG = 3 * TILE_B;
    extern __shared__ char smc[];
    const uint32_t sbase = smem_u32(smc);
    const int tid = threadIdx.x;
    const int lane = tid & 31;
    const int wm = (tid >> 5) & 3;
    const int wn = tid >> 7;
    const int m0 = blockIdx.x * BM;
    const int n0 = blockIdx.y * 128;
    const int NCH = K / KC;

    const int q0r = tid >> 2, q0c = tid & 3;
    const int q1r = (tid + 256) >> 2, q1c = tid & 3;

    float acc_g[2][8][4], acc_u[2][8][4];
#pragma unroll
    for (int mt = 0; mt < 2; mt++)
#pragma unroll
        for (int nt = 0; nt < 8; nt++)
#pragma unroll
            for (int e = 0; e < 4; e++) { acc_g[mt][nt][e] = 0.f; acc_u[mt][nt][e] = 0.f; }

    auto issue = [&](int kc, int buf) {
        const uint32_t st = sbase + buf * STG;
        const int kb = kc * KC;
        const size_t gA0 = (size_t)(m0 + q0r) * K + kb + q0c * 8;
        const size_t gA1 = (size_t)(m0 + q1r) * K + kb + q1c * 8;
        const size_t gG0 = (size_t)(n0 + q0r) * K + kb + q0c * 8;
        const size_t gG1 = (size_t)(n0 + q1r) * K + kb + q1c * 8;
        const size_t gU0 = (size_t)(I_DIM + n0 + q0r) * K + kb + q0c * 8;
        const size_t gU1 = (size_t)(I_DIM + n0 + q1r) * K + kb + q1c * 8;
        const uint32_t s0 = st + q0r * ROWB + q0c * 16;
        const uint32_t s1 = st + q1r * ROWB + q1c * 16;
        cp16(s0, Ahi + gA0);
        cp16(s1, Ahi + gA1);
        cp16(s0 + TILE_B, Bhi + gG0);
        cp16(s1 + TILE_B, Bhi + gG1);
        cp16(s0 + 2 * TILE_B, Bhi + gU0);
        cp16(s1 + 2 * TILE_B, Bhi + gU1);
        cp_commit();
    };

    issue(0, 0);
    issue(1, 1);

    for (int kc = 0; kc < NCH; kc++) {
        if (kc + 2 < NCH) {
            issue(kc + 2, (kc + 2) % 3);
            cp_wait<2>();
        } else if (kc + 1 < NCH) {
            cp_wait<1>();
        } else {
            cp_wait<0>();
        }
        __syncthreads();

        const uint32_t st = sbase + (kc % 3) * STG;
        const uint32_t sAh = st;
        const uint32_t sBg = st + TILE_B;
        const uint32_t sBu = st + 2 * TILE_B;

        const int aRow = wm * 32 + (lane & 15);
        const int aKof = (lane >> 4) * 8;
        const int bIdx = lane & 7;
        const int bSel = lane >> 3;
        const int bRowBase = wn * 64 + ((bSel >> 1) * 8) + bIdx;
        const int bKof = (bSel & 1) * 8;

#pragma unroll
        for (int ks = 0; ks < KC; ks += 16) {
            uint32_t ah[2][4];
#pragma unroll
            for (int mt = 0; mt < 2; mt++) {
                const uint32_t off = (uint32_t)(aRow + mt * 16) * ROWB +
                                     (uint32_t)(ks + aKof) * 2;
                ldm4(ah[mt], sAh + off);
            }
            uint32_t bg[8][2], bu[8][2];
#pragma unroll
            for (int p = 0; p < 4; p++) {
                const uint32_t off = (uint32_t)(bRowBase + p * 16) * ROWB +
                                     (uint32_t)(ks + bKof) * 2;
                uint32_t r4[4];
                ldm4(r4, sBg + off);
                bg[2 * p][0] = r4[0]; bg[2 * p][1] = r4[1];
                bg[2 * p + 1][0] = r4[2]; bg[2 * p + 1][1] = r4[3];
                ldm4(r4, sBu + off);
                bu[2 * p][0] = r4[0]; bu[2 * p][1] = r4[1];
                bu[2 * p + 1][0] = r4[2]; bu[2 * p + 1][1] = r4[3];
            }
#pragma unroll
            for (int mt = 0; mt < 2; mt++)
#pragma unroll
                for (int nt = 0; nt < 8; nt++) {
                    mma_f16(acc_g[mt][nt], ah[mt], bg[nt]);
                    mma_f16(acc_u[mt][nt], ah[mt], bu[nt]);
                }
        }
        __syncthreads();
    }

    const int erow = m0 + wm * 32 + (lane >> 2);
    const int ecol = n0 + wn * 64 + (lane & 3) * 2;
#pragma unroll
    for (int mt = 0; mt < 2; mt++) {
#pragma unroll
        for (int nt = 0; nt < 8; nt++) {
            const int r0 = erow + mt * 16;
            const int c = ecol + nt * 8;
            const float h00 = silu_mul(acc_g[mt][nt][0], acc_u[mt][nt][0]);
            const float h01 = silu_mul(acc_g[mt][nt][1], acc_u[mt][nt][1]);
            const float h10 = silu_mul(acc_g[mt][nt][2], acc_u[mt][nt][2]);
            const float h11 = silu_mul(acc_g[mt][nt][3], acc_u[mt][nt][3]);
            *(uint32_t*)&Hout[(size_t)r0 * I_DIM + c] = packh2(h00, h01);
            *(uint32_t*)&Hout[(size_t)(r0 + 8) * I_DIM + c] = packh2(h10, h11);
        }
    }
}

// ---------------------------------------------------------------------------
// RoPE + split qkv fp32 -> fp16 hi/lo planes
// ---------------------------------------------------------------------------
__global__ void rope_split_kernel(const float* __restrict__ qkv,
                                  __half* __restrict__ oh,
                                  __half* __restrict__ ol)
{
    const int idx = blockIdx.x * blockDim.x + threadIdx.x;
    const int total = S_LEN * 3072;
    if (idx >= total) return;
    const int slot = idx % 3072;
    const int s = idx / 3072;
    const size_t rb = (size_t)s * QKV_N;

    if (slot < 2560) {
        const int head = slot >> 6;
        const int d = slot & 63;
        const int col = head * HD + d;
        const float inv = exp2f((float)d * (-13.287712379549449f / 64.f));
        const float ang = (float)s * inv;
        float sn, c;
        sincosf(ang, &sn, &c);
        const float x1 = qkv[rb + col];
        const float x2 = qkv[rb + col + 64];
        const float y1 = x1 * c - x2 * sn;
        const float y2 = x2 * c + x1 * sn;
        __half h1, l1, h2, l2;
        split1(y1, h1, l1);
        split1(y2, h2, l2);
        oh[rb + col] = h1; oh[rb + col + 64] = h2;
        ol[rb + col] = l1; ol[rb + col + 64] = l2;
    } else {
        const int c0 = 5120 + (slot - 2560) * 2;
        const float x1 = qkv[rb + c0];
        const float x2 = qkv[rb + c0 + 1];
        __half h1, l1, h2, l2;
        split1(x1, h1, l1);
        split1(x2, h2, l2);
        oh[rb + c0] = h1; oh[rb + c0 + 1] = h2;
        ol[rb + c0] = l1; ol[rb + c0 + 1] = l2;
    }
}

// ---------------------------------------------------------------------------
// Tensor-core flash attention (fp16 hi/lo, 3-product), double-buffered KV.
// ---------------------------------------------------------------------------
__global__ __launch_bounds__(256, 1)
void attn_mma_kernel(const __half* __restrict__ qph,
                     const __half* __restrict__ qpl,
                     __half* __restrict__ outh)
{
    extern __shared__ char smc[];
    const uint32_t sb = smem_u32(smc);
    const uint32_t sQh = sb;
    const uint32_t sQl = sb + BR * AROWB;
    const uint32_t kvb = sb + 2 * BR * AROWB;

    const int tid = threadIdx.x;
    const int lane = tid & 31;
    const int warp = tid >> 5;
    const int mb = blockIdx.x;
    const int head = blockIdx.y;
    const int kh = head >> 2;
    const float scale = 0.088388347648318447f;

    const int qcol = head * HD;
    const int kcol = NQ * HD + kh * HD;
    const int vcol = (NQ + NKV) * HD + kh * HD;

    {
        const int chunk = tid & 15;
        const int rbase = tid >> 4;
#pragma unroll
        for (int i = 0; i < 8; i++) {
            const int row = rbase + i * 16;
            const size_t g = (size_t)(mb * BR + row) * QKV_N + qcol + chunk * 8;
            const uint32_t so = row * AROWB + chunk * 16;
            cp16(sQh + so, qph + g);
            cp16(sQl + so, qpl + g);
        }
    }
    cp_commit();

    auto issue_kv = [&](int nb, int buf) {
        const uint32_t st = kvb + buf * KVSTG;
        const int chunk = tid & 15;
        const int rbase = tid >> 4;
#pragma unroll
        for (int i = 0; i < 4; i++) {
            const int row = rbase + i * 16;
            const size_t gk = (size_t)(nb * BC + row) * QKV_N + kcol + chunk * 8;
            const size_t gv = (size_t)(nb * BC + row) * QKV_N + vcol + chunk * 8;
            const uint32_t so = row * AROWB + chunk * 16;
            cp16(st + so, qph + gk);
            cp16(st + BC * AROWB + so, qpl + gk);
            cp16(st + 2 * BC * AROWB + so, qph + gv);
            cp16(st + 3 * BC * AROWB + so, qpl + gv);
        }
        cp_commit();
    };

    float m0 = -1e30f, m1 = -1e30f, l0 = 0.f, l1 = 0.f;
    float acc_o[16][4];
#pragma unroll
    for (int nt = 0; nt < 16; nt++)
#pragma unroll
        for (int e = 0; e < 4; e++) acc_o[nt][e] = 0.f;

    const int aRow = warp * 16 + (lane & 15);
    const int aKof = (lane >> 4) * 8;
    const int bIdx = lane & 7;
    const int bSel = lane >> 3;
    const int bRowBase = (bSel >> 1) * 8 + bIdx;
    const int bKof = (bSel & 1) * 8;
    const int vRow = lane & 15;
    const int vCof = (lane >> 4) * 8;

    const int r0 = lane >> 2;
    const int cq = lane & 3;
    const int grow0 = mb * BR + warp * 16 + r0;
    const int grow1 = grow0 + 8;

    const int ntiles = 2 * mb + 2;
    issue_kv(0, 0);

    for (int nb = 0; nb < ntiles; nb++) {
        if (nb + 1 < ntiles) {
            issue_kv(nb + 1, (nb + 1) & 1);
            cp_wait<1>();
        } else {
            cp_wait<0>();
        }
        __syncthreads();

        const uint32_t st = kvb + (nb & 1) * KVSTG;
        const uint32_t sKh = st;
        const uint32_t sKl = st + BC * AROWB;
        const uint32_t sVh = st + 2 * BC * AROWB;
        const uint32_t sVl = st + 3 * BC * AROWB;

        float accs[8][4];
#pragma unroll
        for (int nt = 0; nt < 8; nt++)
#pragma unroll
            for (int e = 0; e < 4; e++) accs[nt][e] = 0.f;

#pragma unroll
        for (int ks = 0; ks < 8; ks++) {
            uint32_t aqh[4], aql[4];
            const uint32_t aoff = (uint32_t)aRow * AROWB + (uint32_t)(ks * 16 + aKof) * 2;
            ldm4(aqh, sQh + aoff);
            ldm4(aql, sQl + aoff);
            uint32_t bh[8][2], bl[8][2];
#pragma unroll
            for (int p = 0; p < 4; p++) {
                const uint32_t boff = (uint32_t)(bRowBase + p * 16) * AROWB +
                                      (uint32_t)(ks * 16 + bKof) * 2;
                uint32_t r4[4];
                ldm4(r4, sKh + boff);
                bh[2 * p][0] = r4[0]; bh[2 * p][1] = r4[1];
                bh[2 * p + 1][0] = r4[2]; bh[2 * p + 1][1] = r4[3];
                ldm4(r4, sKl + boff);
                bl[2 * p][0] = r4[0]; bl[2 * p][1] = r4[1];
                bl[2 * p + 1][0] = r4[2]; bl[2 * p + 1][1] = r4[3];
            }
#pragma unroll
            for (int nt = 0; nt < 8; nt++) {
                mma_f16(accs[nt], aqh, bh[nt]);
                mma_f16(accs[nt], aqh, bl[nt]);
                mma_f16(accs[nt], aql, bh[nt]);
            }
        }

        float rmax0 = -1e30f, rmax1 = -1e30f;
#pragma unroll
        for (int nt = 0; nt < 8; nt++) {
            const int cbase = nb * BC + nt * 8 + cq * 2;
#pragma unroll
            for (int e = 0; e < 4; e++) {
                float s = accs[nt][e] * scale;
                const int col = cbase + (e & 1);
                const int row = (e < 2) ? grow0 : grow1;
                if (col > row) s = -1e30f;
                accs[nt][e] = s;
            }
            rmax0 = fmaxf(rmax0, fmaxf(accs[nt][0], accs[nt][1]));
            rmax1 = fmaxf(rmax1, fmaxf(accs[nt][2], accs[nt][3]));
        }
        rmax0 = fmaxf(rmax0, __shfl_xor_sync(0xffffffffu, rmax0, 1));
        rmax0 = fmaxf(rmax0, __shfl_xor_sync(0xffffffffu, rmax0, 2));
        rmax1 = fmaxf(rmax1, __shfl_xor_sync(0xffffffffu, rmax1, 1));
        rmax1 = fmaxf(rmax1, __shfl_xor_sync(0xffffffffu, rmax1, 2));
        const float mn0 = fmaxf(m0, rmax0), mn1 = fmaxf(m1, rmax1);
        const float cf0 = __expf(m0 - mn0), cf1 = __expf(m1 - mn1);
        m0 = mn0; m1 = mn1;
        float s0 = 0.f, s1 = 0.f;
#pragma unroll
        for (int nt = 0; nt < 8; nt++) {
            accs[nt][0] = __expf(accs[nt][0] - mn0);
            accs[nt][1] = __expf(accs[nt][1] - mn0);
            accs[nt][2] = __expf(accs[nt][2] - mn1);
            accs[nt][3] = __expf(accs[nt][3] - mn1);
            s0 += accs[nt][0] + accs[nt][1];
            s1 += accs[nt][2] + accs[nt][3];
        }
        s0 += __shfl_xor_sync(0xffffffffu, s0, 1);
        s0 += __shfl_xor_sync(0xffffffffu, s0, 2);
        s1 += __shfl_xor_sync(0xffffffffu, s1, 1);
        s1 += __shfl_xor_sync(0xffffffffu, s1, 2);
        l0 = l0 * cf0 + s0;
        l1 = l1 * cf1 + s1;
#pragma unroll
        for (int nt = 0; nt < 16; nt++) {
            acc_o[nt][0] *= cf0; acc_o[nt][1] *= cf0;
            acc_o[nt][2] *= cf1; acc_o[nt][3] *= cf1;
        }

#pragma unroll
        for (int kb = 0; kb < 4; kb++) {
            uint32_t ph[4], pl[4];
            {
                const float* s0p = accs[2 * kb];
                const float* s1p = accs[2 * kb + 1];
                float h00 = __half2float(__float2half_rn(s0p[0]));
                float h01 = __half2float(__float2half_rn(s0p[1]));
                float h02 = __half2float(__float2half_rn(s0p[2]));
                float h03 = __half2float(__float2half_rn(s0p[3]));
                float h10 = __half2float(__float2half_rn(s1p[0]));
                float h11 = __half2float(__float2half_rn(s1p[1]));
                float h12 = __half2float(__float2half_rn(s1p[2]));
                float h13 = __half2float(__float2half_rn(s1p[3]));
                ph[0] = packh2(s0p[0], s0p[1]);
                ph[1] = packh2(s0p[2], s0p[3]);
                ph[2] = packh2(s1p[0], s1p[1]);
                ph[3] = packh2(s1p[2], s1p[3]);
                pl[0] = packh2(s0p[0] - h00, s0p[1] - h01);
                pl[1] = packh2(s0p[2] - h02, s0p[3] - h03);
                pl[2] = packh2(s1p[0] - h10, s1p[1] - h11);
                pl[3] = packh2(s1p[2] - h12, s1p[3] - h13);
            }
#pragma unroll
            for (int np = 0; np < 8; np++) {
                const uint32_t voff = (uint32_t)(kb * 16 + vRow) * AROWB +
                                      (uint32_t)(np * 16 + vCof) * 2;
                uint32_t rv[4], rl[4];
                ldm4t(rv, sVh + voff);
                ldm4t(rl, sVl + voff);
                uint32_t vh0[2] = {rv[0], rv[1]};
                uint32_t vh1[2] = {rv[2], rv[3]};
                uint32_t vl0[2] = {rl[0], rl[1]};
                uint32_t vl1[2] = {rl[2], rl[3]};
                mma_f16(acc_o[2 * np], ph, vh0);
                mma_f16(acc_o[2 * np], ph, vl0);
                mma_f16(acc_o[2 * np], pl, vh0);
                mma_f16(acc_o[2 * np + 1], ph, vh1);
                mma_f16(acc_o[2 * np + 1], ph, vl1);
                mma_f16(acc_o[2 * np + 1], pl, vh1);
            }
        }
        __syncthreads();
    }

    const float inv0 = 1.f / l0, inv1 = 1.f / l1;
#pragma unroll
    for (int nt = 0; nt < 16; nt++) {
        const size_t o0 = (size_t)grow0 * (NQ * HD) + qcol + nt * 8 + cq * 2;
        const size_t o1 = (size_t)grow1 * (NQ * HD) + qcol + nt * 8 + cq * 2;
        *(uint32_t*)&outh[o0] = packh2(acc_o[nt][0] * inv0, acc_o[nt][1] * inv0);
        *(uint32_t*)&outh[o1] = packh2(acc_o[nt][2] * inv1, acc_o[nt][3] * inv1);
    }
}

// ---------------------------------------------------------------------------
// Launch
// ---------------------------------------------------------------------------
extern "C" void kernel_launch(void* const* d_in, const int* in_sizes, int n_in,
                              void* d_out, int out_size)
{
    (void)in_sizes; (void)n_in;
    const float* hidden = (const float*)d_in[1];
    const float* w_qkv = (const float*)d_in[2];
    const float* w_o = (const float*)d_in[3];
    const float* w_gu = (const float*)d_in[4];
    const float* w_down = (const float*)d_in[5];
    const float* ln1 = (const float*)d_in[6];
    const float* ln2 = (const float*)d_in[7];

    float* out = (float*)d_out;
    const size_t SH = (size_t)S_LEN * H_DIM;
    float* out_resid = ((size_t)out_size >= 2 * SH) ? (out + SH) : nullptr;

    float *qkv, *resid;
    cudaGetSymbolAddress((void**)&qkv, g_qkv);
    cudaGetSymbolAddress((void**)&resid, g_resid);
    __half *qkvh, *qkvl;
    cudaGetSymbolAddress((void**)&qkvh, g_qkvh);
    cudaGetSymbolAddress((void**)&qkvl, g_qkvl);
    __half *wqkvh, *woh, *wguh, *wdh;
    __half *xbh, *abh, *hbh;
    cudaGetSymbolAddress((void**)&wqkvh, g_wqkvT_hi);
    cudaGetSymbolAddress((void**)&woh, g_woT_hi);
    cudaGetSymbolAddress((void**)&wguh, g_wguT_hi);
    cudaGetSymbolAddress((void**)&wdh, g_wdownT_hi);
    cudaGetSymbolAddress((void**)&xbh, g_xb_hi);
    cudaGetSymbolAddress((void**)&abh, g_ab_hi);
    cudaGetSymbolAddress((void**)&hbh, g_hb_hi);

    cudaFuncSetAttribute(attn_mma_kernel,
                         cudaFuncAttributeMaxDynamicSharedMemorySize, ATT_SMEM);
    const int SMEM1 = 3 * STG256;        // 92160 (3-stage, 128x256)
    const int SMEMGU = 3 * 3 * TILE_B;   // 92160
    cudaFuncSetAttribute(gemm_mma1_kernel,
                         cudaFuncAttributeMaxDynamicSharedMemorySize, SMEM1);
    cudaFuncSetAttribute(gemm_gu_kernel,
                         cudaFuncAttributeMaxDynamicSharedMemorySize, SMEMGU);

    // 0. Weight transpose (fp16 hi planes)
    wt_transpose_kernel<<<dim3(QKV_N / 32, H_DIM / 64), 256>>>(w_qkv, wqkvh, H_DIM, QKV_N);
    wt_transpose_kernel<<<dim3(H_DIM / 32, (NQ * HD) / 64), 256>>>(w_o, woh, NQ * HD, H_DIM);
    wt_transpose_kernel<<<dim3((2 * I_DIM) / 32, H_DIM / 64), 256>>>(w_gu, wguh, H_DIM, 2 * I_DIM);
    wt_transpose_kernel<<<dim3(H_DIM / 32, I_DIM / 64), 256>>>(w_down, wdh, I_DIM, H_DIM);

    // 1. RMSNorm 1 -> fp16 hi
    rmsnorm_h_kernel<<<S_LEN, 256>>>(hidden, ln1, xbh);

    // 2. QKV projection (1-product, 128x256)
    gemm_mma1_kernel<<<dim3(S_LEN / BM, QKV_N / 256), 256, SMEM1>>>(
        xbh, wqkvh, qkv, S_LEN, QKV_N, H_DIM, nullptr, nullptr);

    // 3. RoPE + split
    {
        const int total = S_LEN * 3072;
        rope_split_kernel<<<(total + 255) / 256, 256>>>(qkv, qkvh, qkvl);
    }

    // 4. Attention
    attn_mma_kernel<<<dim3(S_LEN / BR, NQ), 256, ATT_SMEM>>>(qkvh, qkvl, abh);

    // 5. O projection (1-product, 128x256) + residual
    gemm_mma1_kernel<<<dim3(S_LEN / BM, H_DIM / 256), 256, SMEM1>>>(
        abh, woh, resid, S_LEN, H_DIM, NQ * HD, hidden, out_resid);

    // 6. RMSNorm 2 -> fp16 hi
    rmsnorm_h_kernel<<<S_LEN, 256>>>(resid, ln2, xbh);

    // 7+8. Fused gate_up + SiLU
    gemm_gu_kernel<<<dim3(S_LEN / BM, I_DIM / 128), 256, SMEMGU>>>(
        xbh, wguh, hbh, S_LEN, H_DIM);

    // 9. down (1-product, 128x256) -> out
    gemm_mma1_kernel<<<dim3(S_LEN / BM, H_DIM / 256), 256, SMEM1>>>(
        hbh, wdh, out, S_LEN, H_DIM, I_DIM, nullptr, nullptr);
}

// round 13
// speedup vs baseline: 5.2459x; 1.0201x over previous
#include <cuda_runtime.h>
#include <cuda_fp16.h>
#include <math.h>
#include <stdint.h>

#define H_DIM 4096
#define S_LEN 2048
#define NQ 32
#define NKV 8
#define HD 128
#define I_DIM 14336
#define QKV_N ((NQ + 2 * NKV) * HD) /* 6144 */
#define EPS 1e-5f

// GEMM tiling
#define BM 128
#define KC 32
#define ROWB 80                       // bytes per smem row (64B data + 16B pad)
#define TILE_B (128 * ROWB)
#define STG256 (384 * ROWB)           // 128x256 tile stage: A(128)+B(256) rows

// Attention tiling
#define BR 128
#define BC 64
#define AROWB 272
#define KVSTG (3 * BC * AROWB)                       // Kh,Kl,Vh = 52224
#define ATT_SMEM (BR * AROWB + 2 * KVSTG)            // 139264

// ---------------------------------------------------------------------------
// Scratch (device globals)
// ---------------------------------------------------------------------------
__device__ float g_qkv[(size_t)S_LEN * QKV_N];
__device__ float g_resid[(size_t)S_LEN * H_DIM];

__device__ __half g_qkvh[(size_t)S_LEN * QKV_N];
__device__ __half g_qkvl[(size_t)S_LEN * QKV_N];

__device__ __half g_wqkvT_hi[(size_t)QKV_N * H_DIM];
__device__ __half g_woT_hi[(size_t)H_DIM * (NQ * HD)];
__device__ __half g_wguT_hi[(size_t)(2 * I_DIM) * H_DIM];
__device__ __half g_wdownT_hi[(size_t)H_DIM * I_DIM];

__device__ __half g_xb_hi[(size_t)S_LEN * H_DIM];
__device__ __half g_ab_hi[(size_t)S_LEN * NQ * HD];
__device__ __half g_hb_hi[(size_t)S_LEN * I_DIM];

// ---------------------------------------------------------------------------
// PTX helpers
// ---------------------------------------------------------------------------
__device__ __forceinline__ uint32_t smem_u32(const void* p) {
    uint32_t a;
    asm("{ .reg .u64 t; cvta.to.shared.u64 t, %1; cvt.u32.u64 %0, t; }"
        : "=r"(a) : "l"(p));
    return a;
}
__device__ __forceinline__ void cp16(uint32_t saddr, const void* g) {
    asm volatile("cp.async.cg.shared.global [%0], [%1], 16;"
                 :: "r"(saddr), "l"(g) : "memory");
}
__device__ __forceinline__ void cp_commit() {
    asm volatile("cp.async.commit_group;" ::: "memory");
}
template <int N>
__device__ __forceinline__ void cp_wait() {
    asm volatile("cp.async.wait_group %0;" :: "n"(N) : "memory");
}
__device__ __forceinline__ void ldm4(uint32_t* r, uint32_t addr) {
    asm volatile("ldmatrix.sync.aligned.m8n8.x4.shared.b16 {%0,%1,%2,%3}, [%4];"
                 : "=r"(r[0]), "=r"(r[1]), "=r"(r[2]), "=r"(r[3]) : "r"(addr));
}
__device__ __forceinline__ void ldm4t(uint32_t* r, uint32_t addr) {
    asm volatile("ldmatrix.sync.aligned.m8n8.x4.trans.shared.b16 {%0,%1,%2,%3}, [%4];"
                 : "=r"(r[0]), "=r"(r[1]), "=r"(r[2]), "=r"(r[3]) : "r"(addr));
}
__device__ __forceinline__ void mma_f16(float* d, const uint32_t* a,
                                        const uint32_t* b) {
    asm volatile(
        "mma.sync.aligned.m16n8k16.row.col.f32.f16.f16.f32 "
        "{%0,%1,%2,%3}, {%4,%5,%6,%7}, {%8,%9}, {%0,%1,%2,%3};"
        : "+f"(d[0]), "+f"(d[1]), "+f"(d[2]), "+f"(d[3])
        : "r"(a[0]), "r"(a[1]), "r"(a[2]), "r"(a[3]), "r"(b[0]), "r"(b[1]));
}
__device__ __forceinline__ void split1(float x, __half& h, __half& l) {
    h = __float2half_rn(x);
    l = __float2half_rn(x - __half2float(h));
}
__device__ __forceinline__ uint32_t packh2(float a, float b) {
    __half2 h = __floats2half2_rn(a, b);
    return *(uint32_t*)&h;
}
__device__ __forceinline__ float silu_mul(float g, float u) {
    return g / (1.f + __expf(-g)) * u;
}

// ---------------------------------------------------------------------------
// Weight transpose: W[K,N] fp32 -> Thi [N,K] fp16 (vectorized)
// ---------------------------------------------------------------------------
__global__ __launch_bounds__(256)
void wt_transpose_kernel(const float* __restrict__ W,
                         __half* __restrict__ Thi, int K, int N)
{
    __shared__ float t[32][65];
    const int tid = threadIdx.x;
    const int n = blockIdx.x * 32 + (tid & 31);
    const int kb = blockIdx.y * 64;
#pragma unroll
    for (int i = 0; i < 8; i++) {
        const int kl = (tid >> 5) + i * 8;
        t[tid & 31][kl] = W[(size_t)(kb + kl) * N + n];
    }
    __syncthreads();
    const int kq = (tid & 15) * 4;
#pragma unroll
    for (int j = 0; j < 2; j++) {
        const int nr = (tid >> 4) + j * 16;
        const int n2 = blockIdx.x * 32 + nr;
        uint2 o;
        o.x = packh2(t[nr][kq + 0], t[nr][kq + 1]);
        o.y = packh2(t[nr][kq + 2], t[nr][kq + 3]);
        *(uint2*)&Thi[(size_t)n2 * K + kb + kq] = o;
    }
}

// ---------------------------------------------------------------------------
// RMSNorm -> fp16 hi
// ---------------------------------------------------------------------------
__global__ __launch_bounds__(256)
void rmsnorm_h_kernel(const float* __restrict__ x, const float* __restrict__ w,
                      __half* __restrict__ ohi)
{
    const int row = blockIdx.x;
    const int t = threadIdx.x;
    const float4* xr = (const float4*)(x + (size_t)row * H_DIM);
    const float4* wr = (const float4*)w;

    float4 v[4];
    float ss = 0.f;
#pragma unroll
    for (int i = 0; i < 4; i++) {
        v[i] = xr[t + 256 * i];
        ss += v[i].x * v[i].x + v[i].y * v[i].y + v[i].z * v[i].z + v[i].w * v[i].w;
    }
#pragma unroll
    for (int o = 16; o; o >>= 1) ss += __shfl_xor_sync(0xffffffffu, ss, o);
    __shared__ float wsum[8];
    if ((t & 31) == 0) wsum[t >> 5] = ss;
    __syncthreads();
    float tot = wsum[0] + wsum[1] + wsum[2] + wsum[3] +
                wsum[4] + wsum[5] + wsum[6] + wsum[7];
    const float sc = rsqrtf(tot * (1.f / H_DIM) + EPS);

    uint2* hr = (uint2*)(ohi + (size_t)row * H_DIM);
#pragma unroll
    for (int i = 0; i < 4; i++) {
        float4 wv = wr[t + 256 * i];
        uint2 h;
        h.x = packh2(v[i].x * sc * wv.x, v[i].y * sc * wv.y);
        h.y = packh2(v[i].z * sc * wv.z, v[i].w * sc * wv.w);
        hr[t + 256 * i] = h;
    }
}

// ---------------------------------------------------------------------------
// mma.sync fp16 GEMM, 1-product, 128x256 tile, 3-stage pipeline.
// ---------------------------------------------------------------------------
__global__ __launch_bounds__(256, 1)
void gemm_mma1_kernel(const __half* __restrict__ Ahi,
                      const __half* __restrict__ Bhi,
                      float* __restrict__ C, int M, int N, int K,
                      const float* __restrict__ add, float* __restrict__ C2)
{
    extern __shared__ char smc[];
    const uint32_t sbase = smem_u32(smc);
    const int tid = threadIdx.x;
    const int lane = tid & 31;
    const int wm = (tid >> 5) & 1;
    const int wn = (tid >> 6);
    const int m0 = blockIdx.x * BM;
    const int n0 = blockIdx.y * 256;
    const int NCH = K / KC;

    float acc[4][8][4];
#pragma unroll
    for (int mt = 0; mt < 4; mt++)
#pragma unroll
        for (int nt = 0; nt < 8; nt++)
#pragma unroll
            for (int e = 0; e < 4; e++) acc[mt][nt][e] = 0.f;

    auto issue = [&](int kc, int buf) {
        const uint32_t st = sbase + buf * STG256;
        const int kb = kc * KC;
#pragma unroll
        for (int i = 0; i < 6; i++) {
            const int lin = tid + i * 256;
            const int r = lin >> 2;
            const int c = lin & 3;
            const __half* src = (r < 128)
                ? (Ahi + (size_t)(m0 + r) * K + kb + c * 8)
                : (Bhi + (size_t)(n0 + r - 128) * K + kb + c * 8);
            cp16(st + r * ROWB + c * 16, src);
        }
        cp_commit();
    };

    issue(0, 0);
    issue(1, 1);

    const int aRowL = (lane & 15);
    const int aKof = (lane >> 4) * 8;
    const int bIdx = lane & 7;
    const int bSel = lane >> 3;
    const int bKof = (bSel & 1) * 8;
    const uint32_t sBoff = 128 * ROWB;

    for (int kc = 0; kc < NCH; kc++) {
        if (kc + 2 < NCH) {
            issue(kc + 2, (kc + 2) % 3);
            cp_wait<2>();
        } else if (kc + 1 < NCH) {
            cp_wait<1>();
        } else {
            cp_wait<0>();
        }
        __syncthreads();

        const uint32_t st = sbase + (kc % 3) * STG256;
        const uint32_t sA = st;
        const uint32_t sB = st + sBoff;

#pragma unroll
        for (int ks = 0; ks < KC; ks += 16) {
            uint32_t ah[4][4];
#pragma unroll
            for (int mt = 0; mt < 4; mt++) {
                const uint32_t off =
                    (uint32_t)(wm * 64 + mt * 16 + aRowL) * ROWB +
                    (uint32_t)(ks + aKof) * 2;
                ldm4(ah[mt], sA + off);
            }
#pragma unroll
            for (int p = 0; p < 4; p++) {
                const uint32_t off =
                    (uint32_t)(wn * 64 + p * 16 + (bSel >> 1) * 8 + bIdx) * ROWB +
                    (uint32_t)(ks + bKof) * 2;
                uint32_t r4[4];
                ldm4(r4, sB + off);
                uint32_t b0[2] = {r4[0], r4[1]};
                uint32_t b1[2] = {r4[2], r4[3]};
#pragma unroll
                for (int mt = 0; mt < 4; mt++) {
                    mma_f16(acc[mt][2 * p], ah[mt], b0);
                    mma_f16(acc[mt][2 * p + 1], ah[mt], b1);
                }
            }
        }
        __syncthreads();
    }

    const int erowL = lane >> 2;
    const int ecolL = (lane & 3) * 2;
#pragma unroll
    for (int mt = 0; mt < 4; mt++) {
#pragma unroll
        for (int nt = 0; nt < 8; nt++) {
            const int r0 = m0 + wm * 64 + mt * 16 + erowL;
            const int c = n0 + wn * 64 + nt * 8 + ecolL;
            const size_t off0 = (size_t)r0 * N + c;
            const size_t off1 = (size_t)(r0 + 8) * N + c;
            float2 v0 = make_float2(acc[mt][nt][0], acc[mt][nt][1]);
            float2 v1 = make_float2(acc[mt][nt][2], acc[mt][nt][3]);
            if (add) {
                float2 a0 = *(const float2*)(add + off0);
                float2 a1 = *(const float2*)(add + off1);
                v0.x += a0.x; v0.y += a0.y;
                v1.x += a1.x; v1.y += a1.y;
            }
            *(float2*)(C + off0) = v0;
            *(float2*)(C + off1) = v1;
            if (C2) {
                *(float2*)(C2 + off0) = v0;
                *(float2*)(C2 + off1) = v1;
            }
        }
    }
}

// ---------------------------------------------------------------------------
// Fused gate_up + SiLU GEMM (1-product, 3-stage) -> fp16 Hout [S, I_DIM]
// ---------------------------------------------------------------------------
__global__ __launch_bounds__(256, 1)
void gemm_gu_kernel(const __half* __restrict__ Ahi,
                    const __half* __restrict__ Bhi,
                    __half* __restrict__ Hout, int M, int K)
{
    constexpr uint32_t STG = 3 * TILE_B;
    extern __shared__ char smc[];
    const uint32_t sbase = smem_u32(smc);
    const int tid = threadIdx.x;
    const int lane = tid & 31;
    const int wm = (tid >> 5) & 3;
    const int wn = tid >> 7;
    const int m0 = blockIdx.x * BM;
    const int n0 = blockIdx.y * 128;
    const int NCH = K / KC;

    const int q0r = tid >> 2, q0c = tid & 3;
    const int q1r = (tid + 256) >> 2, q1c = tid & 3;

    float acc_g[2][8][4], acc_u[2][8][4];
#pragma unroll
    for (int mt = 0; mt < 2; mt++)
#pragma unroll
        for (int nt = 0; nt < 8; nt++)
#pragma unroll
            for (int e = 0; e < 4; e++) { acc_g[mt][nt][e] = 0.f; acc_u[mt][nt][e] = 0.f; }

    auto issue = [&](int kc, int buf) {
        const uint32_t st = sbase + buf * STG;
        const int kb = kc * KC;
        const size_t gA0 = (size_t)(m0 + q0r) * K + kb + q0c * 8;
        const size_t gA1 = (size_t)(m0 + q1r) * K + kb + q1c * 8;
        const size_t gG0 = (size_t)(n0 + q0r) * K + kb + q0c * 8;
        const size_t gG1 = (size_t)(n0 + q1r) * K + kb + q1c * 8;
        const size_t gU0 = (size_t)(I_DIM + n0 + q0r) * K + kb + q0c * 8;
        const size_t gU1 = (size_t)(I_DIM + n0 + q1r) * K + kb + q1c * 8;
        const uint32_t s0 = st + q0r * ROWB + q0c * 16;
        const uint32_t s1 = st + q1r * ROWB + q1c * 16;
        cp16(s0, Ahi + gA0);
        cp16(s1, Ahi + gA1);
        cp16(s0 + TILE_B, Bhi + gG0);
        cp16(s1 + TILE_B, Bhi + gG1);
        cp16(s0 + 2 * TILE_B, Bhi + gU0);
        cp16(s1 + 2 * TILE_B, Bhi + gU1);
        cp_commit();
    };

    issue(0, 0);
    issue(1, 1);

    for (int kc = 0; kc < NCH; kc++) {
        if (kc + 2 < NCH) {
            issue(kc + 2, (kc + 2) % 3);
            cp_wait<2>();
        } else if (kc + 1 < NCH) {
            cp_wait<1>();
        } else {
            cp_wait<0>();
        }
        __syncthreads();

        const uint32_t st = sbase + (kc % 3) * STG;
        const uint32_t sAh = st;
        const uint32_t sBg = st + TILE_B;
        const uint32_t sBu = st + 2 * TILE_B;

        const int aRow = wm * 32 + (lane & 15);
        const int aKof = (lane >> 4) * 8;
        const int bIdx = lane & 7;
        const int bSel = lane >> 3;
        const int bRowBase = wn * 64 + ((bSel >> 1) * 8) + bIdx;
        const int bKof = (bSel & 1) * 8;

#pragma unroll
        for (int ks = 0; ks < KC; ks += 16) {
            uint32_t ah[2][4];
#pragma unroll
            for (int mt = 0; mt < 2; mt++) {
                const uint32_t off = (uint32_t)(aRow + mt * 16) * ROWB +
                                     (uint32_t)(ks + aKof) * 2;
                ldm4(ah[mt], sAh + off);
            }
            uint32_t bg[8][2], bu[8][2];
#pragma unroll
            for (int p = 0; p < 4; p++) {
                const uint32_t off = (uint32_t)(bRowBase + p * 16) * ROWB +
                                     (uint32_t)(ks + bKof) * 2;
                uint32_t r4[4];
                ldm4(r4, sBg + off);
                bg[2 * p][0] = r4[0]; bg[2 * p][1] = r4[1];
                bg[2 * p + 1][0] = r4[2]; bg[2 * p + 1][1] = r4[3];
                ldm4(r4, sBu + off);
                bu[2 * p][0] = r4[0]; bu[2 * p][1] = r4[1];
                bu[2 * p + 1][0] = r4[2]; bu[2 * p + 1][1] = r4[3];
            }
#pragma unroll
            for (int mt = 0; mt < 2; mt++)
#pragma unroll
                for (int nt = 0; nt < 8; nt++) {
                    mma_f16(acc_g[mt][nt], ah[mt], bg[nt]);
                    mma_f16(acc_u[mt][nt], ah[mt], bu[nt]);
                }
        }
        __syncthreads();
    }

    const int erow = m0 + wm * 32 + (lane >> 2);
    const int ecol = n0 + wn * 64 + (lane & 3) * 2;
#pragma unroll
    for (int mt = 0; mt < 2; mt++) {
#pragma unroll
        for (int nt = 0; nt < 8; nt++) {
            const int r0 = erow + mt * 16;
            const int c = ecol + nt * 8;
            const float h00 = silu_mul(acc_g[mt][nt][0], acc_u[mt][nt][0]);
            const float h01 = silu_mul(acc_g[mt][nt][1], acc_u[mt][nt][1]);
            const float h10 = silu_mul(acc_g[mt][nt][2], acc_u[mt][nt][2]);
            const float h11 = silu_mul(acc_g[mt][nt][3], acc_u[mt][nt][3]);
            *(uint32_t*)&Hout[(size_t)r0 * I_DIM + c] = packh2(h00, h01);
            *(uint32_t*)&Hout[(size_t)(r0 + 8) * I_DIM + c] = packh2(h10, h11);
        }
    }
}

// ---------------------------------------------------------------------------
// RoPE + split qkv fp32 -> fp16 planes. lo written only where attention
// consumes it (k heads); q and v need hi only.
// ---------------------------------------------------------------------------
__global__ void rope_split_kernel(const float* __restrict__ qkv,
                                  __half* __restrict__ oh,
                                  __half* __restrict__ ol)
{
    const int idx = blockIdx.x * blockDim.x + threadIdx.x;
    const int total = S_LEN * 3072;
    if (idx >= total) return;
    const int slot = idx % 3072;
    const int s = idx / 3072;
    const size_t rb = (size_t)s * QKV_N;

    if (slot < 2560) {
        const int head = slot >> 6;
        const int d = slot & 63;
        const int col = head * HD + d;
        const float inv = exp2f((float)d * (-13.287712379549449f / 64.f));
        const float ang = (float)s * inv;
        float sn, c;
        sincosf(ang, &sn, &c);
        const float x1 = qkv[rb + col];
        const float x2 = qkv[rb + col + 64];
        const float y1 = x1 * c - x2 * sn;
        const float y2 = x2 * c + x1 * sn;
        __half h1, l1, h2, l2;
        split1(y1, h1, l1);
        split1(y2, h2, l2);
        oh[rb + col] = h1; oh[rb + col + 64] = h2;
        if (head >= NQ) {      // k heads: attention needs the lo plane
            ol[rb + col] = l1; ol[rb + col + 64] = l2;
        }
    } else {
        const int c0 = 5120 + (slot - 2560) * 2;
        oh[rb + c0] = __float2half_rn(qkv[rb + c0]);
        oh[rb + c0 + 1] = __float2half_rn(qkv[rb + c0 + 1]);
    }
}

// ---------------------------------------------------------------------------
// Tensor-core flash attention: QK = Qh*(Kh+Kl), PV = (Ph+Pl)*Vh.
// Double-buffered K/V; reversed mb order for causal load balance.
// ---------------------------------------------------------------------------
__global__ __launch_bounds__(256, 1)
void attn_mma_kernel(const __half* __restrict__ qph,
                     const __half* __restrict__ qpl,
                     __half* __restrict__ outh)
{
    extern __shared__ char smc[];
    const uint32_t sb = smem_u32(smc);
    const uint32_t sQh = sb;
    const uint32_t kvb = sb + BR * AROWB;

    const int tid = threadIdx.x;
    const int lane = tid & 31;
    const int warp = tid >> 5;
    const int mb = (int)gridDim.x - 1 - (int)blockIdx.x;   // heavy CTAs first
    const int head = blockIdx.y;
    const int kh = head >> 2;
    const float scale = 0.088388347648318447f;

    const int qcol = head * HD;
    const int kcol = NQ * HD + kh * HD;
    const int vcol = (NQ + NKV) * HD + kh * HD;

    // Q hi only
    {
        const int chunk = tid & 15;
        const int rbase = tid >> 4;
#pragma unroll
        for (int i = 0; i < 8; i++) {
            const int row = rbase + i * 16;
            const size_t g = (size_t)(mb * BR + row) * QKV_N + qcol + chunk * 8;
            cp16(sQh + row * AROWB + chunk * 16, qph + g);
        }
    }
    cp_commit();

    auto issue_kv = [&](int nb, int buf) {
        const uint32_t st = kvb + buf * KVSTG;
        const int chunk = tid & 15;
        const int rbase = tid >> 4;
#pragma unroll
        for (int i = 0; i < 4; i++) {
            const int row = rbase + i * 16;
            const size_t gk = (size_t)(nb * BC + row) * QKV_N + kcol + chunk * 8;
            const size_t gv = (size_t)(nb * BC + row) * QKV_N + vcol + chunk * 8;
            const uint32_t so = row * AROWB + chunk * 16;
            cp16(st + so, qph + gk);                      // Kh
            cp16(st + BC * AROWB + so, qpl + gk);         // Kl
            cp16(st + 2 * BC * AROWB + so, qph + gv);     // Vh
        }
        cp_commit();
    };

    float m0 = -1e30f, m1 = -1e30f, l0 = 0.f, l1 = 0.f;
    float acc_o[16][4];
#pragma unroll
    for (int nt = 0; nt < 16; nt++)
#pragma unroll
        for (int e = 0; e < 4; e++) acc_o[nt][e] = 0.f;

    const int aRow = warp * 16 + (lane & 15);
    const int aKof = (lane >> 4) * 8;
    const int bIdx = lane & 7;
    const int bSel = lane >> 3;
    const int bRowBase = (bSel >> 1) * 8 + bIdx;
    const int bKof = (bSel & 1) * 8;
    const int vRow = lane & 15;
    const int vCof = (lane >> 4) * 8;

    const int r0 = lane >> 2;
    const int cq = lane & 3;
    const int grow0 = mb * BR + warp * 16 + r0;
    const int grow1 = grow0 + 8;

    const int ntiles = 2 * mb + 2;
    issue_kv(0, 0);

    for (int nb = 0; nb < ntiles; nb++) {
        if (nb + 1 < ntiles) {
            issue_kv(nb + 1, (nb + 1) & 1);
            cp_wait<1>();
        } else {
            cp_wait<0>();
        }
        __syncthreads();

        const uint32_t st = kvb + (nb & 1) * KVSTG;
        const uint32_t sKh = st;
        const uint32_t sKl = st + BC * AROWB;
        const uint32_t sVh = st + 2 * BC * AROWB;

        // ---- S = Qh * (Kh + Kl) ----
        float accs[8][4];
#pragma unroll
        for (int nt = 0; nt < 8; nt++)
#pragma unroll
            for (int e = 0; e < 4; e++) accs[nt][e] = 0.f;

#pragma unroll
        for (int ks = 0; ks < 8; ks++) {
            uint32_t aqh[4];
            const uint32_t aoff = (uint32_t)aRow * AROWB + (uint32_t)(ks * 16 + aKof) * 2;
            ldm4(aqh, sQh + aoff);
#pragma unroll
            for (int p = 0; p < 4; p++) {
                const uint32_t boff = (uint32_t)(bRowBase + p * 16) * AROWB +
                                      (uint32_t)(ks * 16 + bKof) * 2;
                uint32_t r4[4];
                ldm4(r4, sKh + boff);
                uint32_t bh0[2] = {r4[0], r4[1]};
                uint32_t bh1[2] = {r4[2], r4[3]};
                mma_f16(accs[2 * p], aqh, bh0);
                mma_f16(accs[2 * p + 1], aqh, bh1);
                ldm4(r4, sKl + boff);
                uint32_t bl0[2] = {r4[0], r4[1]};
                uint32_t bl1[2] = {r4[2], r4[3]};
                mma_f16(accs[2 * p], aqh, bl0);
                mma_f16(accs[2 * p + 1], aqh, bl1);
            }
        }

        // ---- scale + causal mask + online softmax ----
        float rmax0 = -1e30f, rmax1 = -1e30f;
#pragma unroll
        for (int nt = 0; nt < 8; nt++) {
            const int cbase = nb * BC + nt * 8 + cq * 2;
#pragma unroll
            for (int e = 0; e < 4; e++) {
                float s = accs[nt][e] * scale;
                const int col = cbase + (e & 1);
                const int row = (e < 2) ? grow0 : grow1;
                if (col > row) s = -1e30f;
                accs[nt][e] = s;
            }
            rmax0 = fmaxf(rmax0, fmaxf(accs[nt][0], accs[nt][1]));
            rmax1 = fmaxf(rmax1, fmaxf(accs[nt][2], accs[nt][3]));
        }
        rmax0 = fmaxf(rmax0, __shfl_xor_sync(0xffffffffu, rmax0, 1));
        rmax0 = fmaxf(rmax0, __shfl_xor_sync(0xffffffffu, rmax0, 2));
        rmax1 = fmaxf(rmax1, __shfl_xor_sync(0xffffffffu, rmax1, 1));
        rmax1 = fmaxf(rmax1, __shfl_xor_sync(0xffffffffu, rmax1, 2));
        const float mn0 = fmaxf(m0, rmax0), mn1 = fmaxf(m1, rmax1);
        const float cf0 = __expf(m0 - mn0), cf1 = __expf(m1 - mn1);
        m0 = mn0; m1 = mn1;
        float s0 = 0.f, s1 = 0.f;
#pragma unroll
        for (int nt = 0; nt < 8; nt++) {
            accs[nt][0] = __expf(accs[nt][0] - mn0);
            accs[nt][1] = __expf(accs[nt][1] - mn0);
            accs[nt][2] = __expf(accs[nt][2] - mn1);
            accs[nt][3] = __expf(accs[nt][3] - mn1);
            s0 += accs[nt][0] + accs[nt][1];
            s1 += accs[nt][2] + accs[nt][3];
        }
        s0 += __shfl_xor_sync(0xffffffffu, s0, 1);
        s0 += __shfl_xor_sync(0xffffffffu, s0, 2);
        s1 += __shfl_xor_sync(0xffffffffu, s1, 1);
        s1 += __shfl_xor_sync(0xffffffffu, s1, 2);
        l0 = l0 * cf0 + s0;
        l1 = l1 * cf1 + s1;
#pragma unroll
        for (int nt = 0; nt < 16; nt++) {
            acc_o[nt][0] *= cf0; acc_o[nt][1] *= cf0;
            acc_o[nt][2] *= cf1; acc_o[nt][3] *= cf1;
        }

        // ---- O += (Ph + Pl) * Vh ----
#pragma unroll
        for (int kb = 0; kb < 4; kb++) {
            uint32_t ph[4], pl[4];
            {
                const float* s0p = accs[2 * kb];
                const float* s1p = accs[2 * kb + 1];
                float h00 = __half2float(__float2half_rn(s0p[0]));
                float h01 = __half2float(__float2half_rn(s0p[1]));
                float h02 = __half2float(__float2half_rn(s0p[2]));
                float h03 = __half2float(__float2half_rn(s0p[3]));
                float h10 = __half2float(__float2half_rn(s1p[0]));
                float h11 = __half2float(__float2half_rn(s1p[1]));
                float h12 = __half2float(__float2half_rn(s1p[2]));
                float h13 = __half2float(__float2half_rn(s1p[3]));
                ph[0] = packh2(s0p[0], s0p[1]);
                ph[1] = packh2(s0p[2], s0p[3]);
                ph[2] = packh2(s1p[0], s1p[1]);
                ph[3] = packh2(s1p[2], s1p[3]);
                pl[0] = packh2(s0p[0] - h00, s0p[1] - h01);
                pl[1] = packh2(s0p[2] - h02, s0p[3] - h03);
                pl[2] = packh2(s1p[0] - h10, s1p[1] - h11);
                pl[3] = packh2(s1p[2] - h12, s1p[3] - h13);
            }
#pragma unroll
            for (int np = 0; np < 8; np++) {
                const uint32_t voff = (uint32_t)(kb * 16 + vRow) * AROWB +
                                      (uint32_t)(np * 16 + vCof) * 2;
                uint32_t rv[4];
                ldm4t(rv, sVh + voff);
                uint32_t vh0[2] = {rv[0], rv[1]};
                uint32_t vh1[2] = {rv[2], rv[3]};
                mma_f16(acc_o[2 * np], ph, vh0);
                mma_f16(acc_o[2 * np], pl, vh0);
                mma_f16(acc_o[2 * np + 1], ph, vh1);
                mma_f16(acc_o[2 * np + 1], pl, vh1);
            }
        }
        __syncthreads();
    }

    const float inv0 = 1.f / l0, inv1 = 1.f / l1;
#pragma unroll
    for (int nt = 0; nt < 16; nt++) {
        const size_t o0 = (size_t)grow0 * (NQ * HD) + qcol + nt * 8 + cq * 2;
        const size_t o1 = (size_t)grow1 * (NQ * HD) + qcol + nt * 8 + cq * 2;
        *(uint32_t*)&outh[o0] = packh2(acc_o[nt][0] * inv0, acc_o[nt][1] * inv0);
        *(uint32_t*)&outh[o1] = packh2(acc_o[nt][2] * inv1, acc_o[nt][3] * inv1);
    }
}

// ---------------------------------------------------------------------------
// Launch
// ---------------------------------------------------------------------------
extern "C" void kernel_launch(void* const* d_in, const int* in_sizes, int n_in,
                              void* d_out, int out_size)
{
    (void)in_sizes; (void)n_in;
    const float* hidden = (const float*)d_in[1];
    const float* w_qkv = (const float*)d_in[2];
    const float* w_o = (const float*)d_in[3];
    const float* w_gu = (const float*)d_in[4];
    const float* w_down = (const float*)d_in[5];
    const float* ln1 = (const float*)d_in[6];
    const float* ln2 = (const float*)d_in[7];

    float* out = (float*)d_out;
    const size_t SH = (size_t)S_LEN * H_DIM;
    float* out_resid = ((size_t)out_size >= 2 * SH) ? (out + SH) : nullptr;

    float *qkv, *resid;
    cudaGetSymbolAddress((void**)&qkv, g_qkv);
    cudaGetSymbolAddress((void**)&resid, g_resid);
    __half *qkvh, *qkvl;
    cudaGetSymbolAddress((void**)&qkvh, g_qkvh);
    cudaGetSymbolAddress((void**)&qkvl, g_qkvl);
    __half *wqkvh, *woh, *wguh, *wdh;
    __half *xbh, *abh, *hbh;
    cudaGetSymbolAddress((void**)&wqkvh, g_wqkvT_hi);
    cudaGetSymbolAddress((void**)&woh, g_woT_hi);
    cudaGetSymbolAddress((void**)&wguh, g_wguT_hi);
    cudaGetSymbolAddress((void**)&wdh, g_wdownT_hi);
    cudaGetSymbolAddress((void**)&xbh, g_xb_hi);
    cudaGetSymbolAddress((void**)&abh, g_ab_hi);
    cudaGetSymbolAddress((void**)&hbh, g_hb_hi);

    cudaFuncSetAttribute(attn_mma_kernel,
                         cudaFuncAttributeMaxDynamicSharedMemorySize, ATT_SMEM);
    const int SMEM1 = 3 * STG256;        // 92160
    const int SMEMGU = 3 * 3 * TILE_B;   // 92160
    cudaFuncSetAttribute(gemm_mma1_kernel,
                         cudaFuncAttributeMaxDynamicSharedMemorySize, SMEM1);
    cudaFuncSetAttribute(gemm_gu_kernel,
                         cudaFuncAttributeMaxDynamicSharedMemorySize, SMEMGU);

    // 0. Weight transpose (fp16 hi planes)
    wt_transpose_kernel<<<dim3(QKV_N / 32, H_DIM / 64), 256>>>(w_qkv, wqkvh, H_DIM, QKV_N);
    wt_transpose_kernel<<<dim3(H_DIM / 32, (NQ * HD) / 64), 256>>>(w_o, woh, NQ * HD, H_DIM);
    wt_transpose_kernel<<<dim3((2 * I_DIM) / 32, H_DIM / 64), 256>>>(w_gu, wguh, H_DIM, 2 * I_DIM);
    wt_transpose_kernel<<<dim3(H_DIM / 32, I_DIM / 64), 256>>>(w_down, wdh, I_DIM, H_DIM);

    // 1. RMSNorm 1 -> fp16 hi
    rmsnorm_h_kernel<<<S_LEN, 256>>>(hidden, ln1, xbh);

    // 2. QKV projection (1-product, 128x256)
    gemm_mma1_kernel<<<dim3(S_LEN / BM, QKV_N / 256), 256, SMEM1>>>(
        xbh, wqkvh, qkv, S_LEN, QKV_N, H_DIM, nullptr, nullptr);

    // 3. RoPE + split
    {
        const int total = S_LEN * 3072;
        rope_split_kernel<<<(total + 255) / 256, 256>>>(qkv, qkvh, qkvl);
    }

    // 4. Attention (2-product QK and PV, balanced launch order)
    attn_mma_kernel<<<dim3(S_LEN / BR, NQ), 256, ATT_SMEM>>>(qkvh, qkvl, abh);

    // 5. O projection (1-product, 128x256) + residual
    gemm_mma1_kernel<<<dim3(S_LEN / BM, H_DIM / 256), 256, SMEM1>>>(
        abh, woh, resid, S_LEN, H_DIM, NQ * HD, hidden, out_resid);

    // 6. RMSNorm 2 -> fp16 hi
    rmsnorm_h_kernel<<<S_LEN, 256>>>(resid, ln2, xbh);

    // 7+8. Fused gate_up + SiLU
    gemm_gu_kernel<<<dim3(S_LEN / BM, I_DIM / 128), 256, SMEMGU>>>(
        xbh, wguh, hbh, S_LEN, H_DIM);

    // 9. down (1-product, 128x256) -> out
    gemm_mma1_kernel<<<dim3(S_LEN / BM, H_DIM / 256), 256, SMEM1>>>(
        hbh, wdh, out, S_LEN, H_DIM, I_DIM, nullptr, nullptr);
}

// round 15
// speedup vs baseline: 5.4577x; 1.0404x over previous
#include <cuda_runtime.h>
#include <cuda_fp16.h>
#include <math.h>
#include <stdint.h>

#define H_DIM 4096
#define S_LEN 2048
#define NQ 32
#define NKV 8
#define HD 128
#define I_DIM 14336
#define QKV_N ((NQ + 2 * NKV) * HD) /* 6144 */
#define EPS 1e-5f

// GEMM tiling
#define BM 128
#define KC 32
#define ROWB 80
#define TILE_B (128 * ROWB)
#define STG256 (384 * ROWB)

// Attention tiling
#define BR 128
#define BC 64
#define AROWB 272
#define KVSTG (3 * BC * AROWB)
#define ATT_SMEM (BR * AROWB + 2 * KVSTG)   // 139264

// ---------------------------------------------------------------------------
// Scratch (device globals)
// ---------------------------------------------------------------------------
__device__ float g_qkv[(size_t)S_LEN * QKV_N];
__device__ float g_resid[(size_t)S_LEN * H_DIM];

__device__ __half g_qkvh[(size_t)S_LEN * QKV_N];
__device__ __half g_qkvl[(size_t)S_LEN * QKV_N];

__device__ __half g_wqkvT_hi[(size_t)QKV_N * H_DIM];
__device__ __half g_woT_hi[(size_t)H_DIM * (NQ * HD)];
__device__ __half g_wguT_hi[(size_t)(2 * I_DIM) * H_DIM];
__device__ __half g_wdownT_hi[(size_t)H_DIM * I_DIM];

__device__ __half g_xb_hi[(size_t)S_LEN * H_DIM];
__device__ __half g_ab_hi[(size_t)S_LEN * NQ * HD];
__device__ __half g_hb_hi[(size_t)S_LEN * I_DIM];

// ---------------------------------------------------------------------------
// PTX helpers
// ---------------------------------------------------------------------------
__device__ __forceinline__ uint32_t smem_u32(const void* p) {
    uint32_t a;
    asm("{ .reg .u64 t; cvta.to.shared.u64 t, %1; cvt.u32.u64 %0, t; }"
        : "=r"(a) : "l"(p));
    return a;
}
__device__ __forceinline__ void cp16(uint32_t saddr, const void* g) {
    asm volatile("cp.async.cg.shared.global [%0], [%1], 16;"
                 :: "r"(saddr), "l"(g) : "memory");
}
__device__ __forceinline__ void cp_commit() {
    asm volatile("cp.async.commit_group;" ::: "memory");
}
template <int N>
__device__ __forceinline__ void cp_wait() {
    asm volatile("cp.async.wait_group %0;" :: "n"(N) : "memory");
}
__device__ __forceinline__ void ldm4(uint32_t* r, uint32_t addr) {
    asm volatile("ldmatrix.sync.aligned.m8n8.x4.shared.b16 {%0,%1,%2,%3}, [%4];"
                 : "=r"(r[0]), "=r"(r[1]), "=r"(r[2]), "=r"(r[3]) : "r"(addr));
}
__device__ __forceinline__ void ldm4t(uint32_t* r, uint32_t addr) {
    asm volatile("ldmatrix.sync.aligned.m8n8.x4.trans.shared.b16 {%0,%1,%2,%3}, [%4];"
                 : "=r"(r[0]), "=r"(r[1]), "=r"(r[2]), "=r"(r[3]) : "r"(addr));
}
__device__ __forceinline__ void mma_f16(float* d, const uint32_t* a,
                                        const uint32_t* b) {
    asm volatile(
        "mma.sync.aligned.m16n8k16.row.col.f32.f16.f16.f32 "
        "{%0,%1,%2,%3}, {%4,%5,%6,%7}, {%8,%9}, {%0,%1,%2,%3};"
        : "+f"(d[0]), "+f"(d[1]), "+f"(d[2]), "+f"(d[3])
        : "r"(a[0]), "r"(a[1]), "r"(a[2]), "r"(a[3]), "r"(b[0]), "r"(b[1]));
}
__device__ __forceinline__ void split1(float x, __half& h, __half& l) {
    h = __float2half_rn(x);
    l = __float2half_rn(x - __half2float(h));
}
__device__ __forceinline__ uint32_t packh2(float a, float b) {
    __half2 h = __floats2half2_rn(a, b);
    return *(uint32_t*)&h;
}
__device__ __forceinline__ float silu_mul(float g, float u) {
    return g / (1.f + __expf(-g)) * u;
}

// ---------------------------------------------------------------------------
// Weight transpose: W[K,N] fp32 -> Thi [N,K] fp16 (vectorized)
// ---------------------------------------------------------------------------
__global__ __launch_bounds__(256)
void wt_transpose_kernel(const float* __restrict__ W,
                         __half* __restrict__ Thi, int K, int N)
{
    __shared__ float t[32][65];
    const int tid = threadIdx.x;
    const int n = blockIdx.x * 32 + (tid & 31);
    const int kb = blockIdx.y * 64;
#pragma unroll
    for (int i = 0; i < 8; i++) {
        const int kl = (tid >> 5) + i * 8;
        t[tid & 31][kl] = W[(size_t)(kb + kl) * N + n];
    }
    __syncthreads();
    const int kq = (tid & 15) * 4;
#pragma unroll
    for (int j = 0; j < 2; j++) {
        const int nr = (tid >> 4) + j * 16;
        const int n2 = blockIdx.x * 32 + nr;
        uint2 o;
        o.x = packh2(t[nr][kq + 0], t[nr][kq + 1]);
        o.y = packh2(t[nr][kq + 2], t[nr][kq + 3]);
        *(uint2*)&Thi[(size_t)n2 * K + kb + kq] = o;
    }
}

// ---------------------------------------------------------------------------
// RMSNorm -> fp16 hi
// ---------------------------------------------------------------------------
__global__ __launch_bounds__(256)
void rmsnorm_h_kernel(const float* __restrict__ x, const float* __restrict__ w,
                      __half* __restrict__ ohi)
{
    const int row = blockIdx.x;
    const int t = threadIdx.x;
    const float4* xr = (const float4*)(x + (size_t)row * H_DIM);
    const float4* wr = (const float4*)w;

    float4 v[4];
    float ss = 0.f;
#pragma unroll
    for (int i = 0; i < 4; i++) {
        v[i] = xr[t + 256 * i];
        ss += v[i].x * v[i].x + v[i].y * v[i].y + v[i].z * v[i].z + v[i].w * v[i].w;
    }
#pragma unroll
    for (int o = 16; o; o >>= 1) ss += __shfl_xor_sync(0xffffffffu, ss, o);
    __shared__ float wsum[8];
    if ((t & 31) == 0) wsum[t >> 5] = ss;
    __syncthreads();
    float tot = wsum[0] + wsum[1] + wsum[2] + wsum[3] +
                wsum[4] + wsum[5] + wsum[6] + wsum[7];
    const float sc = rsqrtf(tot * (1.f / H_DIM) + EPS);

    uint2* hr = (uint2*)(ohi + (size_t)row * H_DIM);
#pragma unroll
    for (int i = 0; i < 4; i++) {
        float4 wv = wr[t + 256 * i];
        uint2 h;
        h.x = packh2(v[i].x * sc * wv.x, v[i].y * sc * wv.y);
        h.y = packh2(v[i].z * sc * wv.z, v[i].w * sc * wv.w);
        hr[t + 256 * i] = h;
    }
}

// ---------------------------------------------------------------------------
// mma.sync fp16 GEMM, 1-product, 128x256 tile, 3-stage single-sync pipeline.
// Loop: {wait<1>; sync; issue(kc+2); compute(kc)}. At the wait, groups
// 0..kc+1 are issued; <=1 pending means group kc is complete. The sync
// guarantees compute(kc-1) finished, so issue(kc+2) -> buf (kc-1)%3 is safe.
// ---------------------------------------------------------------------------
__global__ __launch_bounds__(256, 1)
void gemm_mma1_kernel(const __half* __restrict__ Ahi,
                      const __half* __restrict__ Bhi,
                      float* __restrict__ C, int M, int N, int K,
                      const float* __restrict__ add, float* __restrict__ C2)
{
    extern __shared__ char smc[];
    const uint32_t sbase = smem_u32(smc);
    const int tid = threadIdx.x;
    const int lane = tid & 31;
    const int wm = (tid >> 5) & 1;
    const int wn = (tid >> 6);
    const int m0 = blockIdx.x * BM;
    const int n0 = blockIdx.y * 256;
    const int NCH = K / KC;

    float acc[4][8][4];
#pragma unroll
    for (int mt = 0; mt < 4; mt++)
#pragma unroll
        for (int nt = 0; nt < 8; nt++)
#pragma unroll
            for (int e = 0; e < 4; e++) acc[mt][nt][e] = 0.f;

    auto issue = [&](int kc, int buf) {
        const uint32_t st = sbase + buf * STG256;
        const int kb = kc * KC;
#pragma unroll
        for (int i = 0; i < 6; i++) {
            const int lin = tid + i * 256;
            const int r = lin >> 2;
            const int c = lin & 3;
            const __half* src = (r < 128)
                ? (Ahi + (size_t)(m0 + r) * K + kb + c * 8)
                : (Bhi + (size_t)(n0 + r - 128) * K + kb + c * 8);
            cp16(st + r * ROWB + c * 16, src);
        }
        cp_commit();
    };

    issue(0, 0);
    issue(1, 1);

    const int aRowL = (lane & 15);
    const int aKof = (lane >> 4) * 8;
    const int bIdx = lane & 7;
    const int bSel = lane >> 3;
    const int bKof = (bSel & 1) * 8;
    const uint32_t sBoff = 128 * ROWB;

    for (int kc = 0; kc < NCH; kc++) {
        if (kc + 1 < NCH) {
            cp_wait<1>();
        } else {
            cp_wait<0>();
        }
        __syncthreads();
        if (kc + 2 < NCH) issue(kc + 2, (kc + 2) % 3);

        const uint32_t st = sbase + (kc % 3) * STG256;
        const uint32_t sA = st;
        const uint32_t sB = st + sBoff;

#pragma unroll
        for (int ks = 0; ks < KC; ks += 16) {
            uint32_t ah[4][4];
#pragma unroll
            for (int mt = 0; mt < 4; mt++) {
                const uint32_t off =
                    (uint32_t)(wm * 64 + mt * 16 + aRowL) * ROWB +
                    (uint32_t)(ks + aKof) * 2;
                ldm4(ah[mt], sA + off);
            }
#pragma unroll
            for (int p = 0; p < 4; p++) {
                const uint32_t off =
                    (uint32_t)(wn * 64 + p * 16 + (bSel >> 1) * 8 + bIdx) * ROWB +
                    (uint32_t)(ks + bKof) * 2;
                uint32_t r4[4];
                ldm4(r4, sB + off);
                uint32_t b0[2] = {r4[0], r4[1]};
                uint32_t b1[2] = {r4[2], r4[3]};
#pragma unroll
                for (int mt = 0; mt < 4; mt++) {
                    mma_f16(acc[mt][2 * p], ah[mt], b0);
                    mma_f16(acc[mt][2 * p + 1], ah[mt], b1);
                }
            }
        }
    }

    const int erowL = lane >> 2;
    const int ecolL = (lane & 3) * 2;
#pragma unroll
    for (int mt = 0; mt < 4; mt++) {
#pragma unroll
        for (int nt = 0; nt < 8; nt++) {
            const int r0 = m0 + wm * 64 + mt * 16 + erowL;
            const int c = n0 + wn * 64 + nt * 8 + ecolL;
            const size_t off0 = (size_t)r0 * N + c;
            const size_t off1 = (size_t)(r0 + 8) * N + c;
            float2 v0 = make_float2(acc[mt][nt][0], acc[mt][nt][1]);
            float2 v1 = make_float2(acc[mt][nt][2], acc[mt][nt][3]);
            if (add) {
                float2 a0 = *(const float2*)(add + off0);
                float2 a1 = *(const float2*)(add + off1);
                v0.x += a0.x; v0.y += a0.y;
                v1.x += a1.x; v1.y += a1.y;
            }
            *(float2*)(C + off0) = v0;
            *(float2*)(C + off1) = v1;
            if (C2) {
                *(float2*)(C2 + off0) = v0;
                *(float2*)(C2 + off1) = v1;
            }
        }
    }
}

// ---------------------------------------------------------------------------
// Fused gate_up + SiLU GEMM (1-product, 3-stage single-sync) -> fp16 Hout
// ---------------------------------------------------------------------------
__global__ __launch_bounds__(256, 1)
void gemm_gu_kernel(const __half* __restrict__ Ahi,
                    const __half* __restrict__ Bhi,
                    __half* __restrict__ Hout, int M, int K)
{
    constexpr uint32_t STG = 3 * TILE_B;
    extern __shared__ char smc[];
    const uint32_t sbase = smem_u32(smc);
    const int tid = threadIdx.x;
    const int lane = tid & 31;
    const int wm = (tid >> 5) & 3;
    const int wn = tid >> 7;
    const int m0 = blockIdx.x * BM;
    const int n0 = blockIdx.y * 128;
    const int NCH = K / KC;

    const int q0r = tid >> 2, q0c = tid & 3;
    const int q1r = (tid + 256) >> 2, q1c = tid & 3;

    float acc_g[2][8][4], acc_u[2][8][4];
#pragma unroll
    for (int mt = 0; mt < 2; mt++)
#pragma unroll
        for (int nt = 0; nt < 8; nt++)
#pragma unroll
            for (int e = 0; e < 4; e++) { acc_g[mt][nt][e] = 0.f; acc_u[mt][nt][e] = 0.f; }

    auto issue = [&](int kc, int buf) {
        const uint32_t st = sbase + buf * STG;
        const int kb = kc * KC;
        const size_t gA0 = (size_t)(m0 + q0r) * K + kb + q0c * 8;
        const size_t gA1 = (size_t)(m0 + q1r) * K + kb + q1c * 8;
        const size_t gG0 = (size_t)(n0 + q0r) * K + kb + q0c * 8;
        const size_t gG1 = (size_t)(n0 + q1r) * K + kb + q1c * 8;
        const size_t gU0 = (size_t)(I_DIM + n0 + q0r) * K + kb + q0c * 8;
        const size_t gU1 = (size_t)(I_DIM + n0 + q1r) * K + kb + q1c * 8;
        const uint32_t s0 = st + q0r * ROWB + q0c * 16;
        const uint32_t s1 = st + q1r * ROWB + q1c * 16;
        cp16(s0, Ahi + gA0);
        cp16(s1, Ahi + gA1);
        cp16(s0 + TILE_B, Bhi + gG0);
        cp16(s1 + TILE_B, Bhi + gG1);
        cp16(s0 + 2 * TILE_B, Bhi + gU0);
        cp16(s1 + 2 * TILE_B, Bhi + gU1);
        cp_commit();
    };

    issue(0, 0);
    issue(1, 1);

    for (int kc = 0; kc < NCH; kc++) {
        if (kc + 1 < NCH) {
            cp_wait<1>();
        } else {
            cp_wait<0>();
        }
        __syncthreads();
        if (kc + 2 < NCH) issue(kc + 2, (kc + 2) % 3);

        const uint32_t st = sbase + (kc % 3) * STG;
        const uint32_t sAh = st;
        const uint32_t sBg = st + TILE_B;
        const uint32_t sBu = st + 2 * TILE_B;

        const int aRow = wm * 32 + (lane & 15);
        const int aKof = (lane >> 4) * 8;
        const int bIdx = lane & 7;
        const int bSel = lane >> 3;
        const int bRowBase = wn * 64 + ((bSel >> 1) * 8) + bIdx;
        const int bKof = (bSel & 1) * 8;

#pragma unroll
        for (int ks = 0; ks < KC; ks += 16) {
            uint32_t ah[2][4];
#pragma unroll
            for (int mt = 0; mt < 2; mt++) {
                const uint32_t off = (uint32_t)(aRow + mt * 16) * ROWB +
                                     (uint32_t)(ks + aKof) * 2;
                ldm4(ah[mt], sAh + off);
            }
            uint32_t bg[8][2], bu[8][2];
#pragma unroll
            for (int p = 0; p < 4; p++) {
                const uint32_t off = (uint32_t)(bRowBase + p * 16) * ROWB +
                                     (uint32_t)(ks + bKof) * 2;
                uint32_t r4[4];
                ldm4(r4, sBg + off);
                bg[2 * p][0] = r4[0]; bg[2 * p][1] = r4[1];
                bg[2 * p + 1][0] = r4[2]; bg[2 * p + 1][1] = r4[3];
                ldm4(r4, sBu + off);
                bu[2 * p][0] = r4[0]; bu[2 * p][1] = r4[1];
                bu[2 * p + 1][0] = r4[2]; bu[2 * p + 1][1] = r4[3];
            }
#pragma unroll
            for (int mt = 0; mt < 2; mt++)
#pragma unroll
                for (int nt = 0; nt < 8; nt++) {
                    mma_f16(acc_g[mt][nt], ah[mt], bg[nt]);
                    mma_f16(acc_u[mt][nt], ah[mt], bu[nt]);
                }
        }
    }

    const int erow = m0 + wm * 32 + (lane >> 2);
    const int ecol = n0 + wn * 64 + (lane & 3) * 2;
#pragma unroll
    for (int mt = 0; mt < 2; mt++) {
#pragma unroll
        for (int nt = 0; nt < 8; nt++) {
            const int r0 = erow + mt * 16;
            const int c = ecol + nt * 8;
            const float h00 = silu_mul(acc_g[mt][nt][0], acc_u[mt][nt][0]);
            const float h01 = silu_mul(acc_g[mt][nt][1], acc_u[mt][nt][1]);
            const float h10 = silu_mul(acc_g[mt][nt][2], acc_u[mt][nt][2]);
            const float h11 = silu_mul(acc_g[mt][nt][3], acc_u[mt][nt][3]);
            *(uint32_t*)&Hout[(size_t)r0 * I_DIM + c] = packh2(h00, h01);
            *(uint32_t*)&Hout[(size_t)(r0 + 8) * I_DIM + c] = packh2(h10, h11);
        }
    }
}

// ---------------------------------------------------------------------------
// RoPE + split qkv fp32 -> fp16 planes (lo only for k heads)
// ---------------------------------------------------------------------------
__global__ void rope_split_kernel(const float* __restrict__ qkv,
                                  __half* __restrict__ oh,
                                  __half* __restrict__ ol)
{
    const int idx = blockIdx.x * blockDim.x + threadIdx.x;
    const int total = S_LEN * 3072;
    if (idx >= total) return;
    const int slot = idx % 3072;
    const int s = idx / 3072;
    const size_t rb = (size_t)s * QKV_N;

    if (slot < 2560) {
        const int head = slot >> 6;
        const int d = slot & 63;
        const int col = head * HD + d;
        const float inv = exp2f((float)d * (-13.287712379549449f / 64.f));
        const float ang = (float)s * inv;
        float sn, c;
        sincosf(ang, &sn, &c);
        const float x1 = qkv[rb + col];
        const float x2 = qkv[rb + col + 64];
        const float y1 = x1 * c - x2 * sn;
        const float y2 = x2 * c + x1 * sn;
        __half h1, l1, h2, l2;
        split1(y1, h1, l1);
        split1(y2, h2, l2);
        oh[rb + col] = h1; oh[rb + col + 64] = h2;
        if (head >= NQ) {
            ol[rb + col] = l1; ol[rb + col + 64] = l2;
        }
    } else {
        const int c0 = 5120 + (slot - 2560) * 2;
        oh[rb + c0] = __float2half_rn(qkv[rb + c0]);
        oh[rb + c0 + 1] = __float2half_rn(qkv[rb + c0 + 1]);
    }
}

// ---------------------------------------------------------------------------
// Tensor-core flash attention: QK = Qh*(Kh+Kl), PV = Ph*Vh.
// Double-buffered K/V; wait<1> (groups: Q, kv0..kv(nb+1) issued; kv(nb+1)
// may remain pending). Trailing sync guards buffer reuse before re-issue.
// ---------------------------------------------------------------------------
__global__ __launch_bounds__(256, 1)
void attn_mma_kernel(const __half* __restrict__ qph,
                     const __half* __restrict__ qpl,
                     __half* __restrict__ outh)
{
    extern __shared__ char smc[];
    const uint32_t sb = smem_u32(smc);
    const uint32_t sQh = sb;
    const uint32_t kvb = sb + BR * AROWB;

    const int tid = threadIdx.x;
    const int lane = tid & 31;
    const int warp = tid >> 5;
    const int mb = (int)gridDim.x - 1 - (int)blockIdx.x;
    const int head = blockIdx.y;
    const int kh = head >> 2;
    const float scale = 0.088388347648318447f;

    const int qcol = head * HD;
    const int kcol = NQ * HD + kh * HD;
    const int vcol = (NQ + NKV) * HD + kh * HD;

    // Q hi only
    {
        const int chunk = tid & 15;
        const int rbase = tid >> 4;
#pragma unroll
        for (int i = 0; i < 8; i++) {
            const int row = rbase + i * 16;
            const size_t g = (size_t)(mb * BR + row) * QKV_N + qcol + chunk * 8;
            cp16(sQh + row * AROWB + chunk * 16, qph + g);
        }
    }
    cp_commit();

    auto issue_kv = [&](int nb, int buf) {
        const uint32_t st = kvb + buf * KVSTG;
        const int chunk = tid & 15;
        const int rbase = tid >> 4;
#pragma unroll
        for (int i = 0; i < 4; i++) {
            const int row = rbase + i * 16;
            const size_t gk = (size_t)(nb * BC + row) * QKV_N + kcol + chunk * 8;
            const size_t gv = (size_t)(nb * BC + row) * QKV_N + vcol + chunk * 8;
            const uint32_t so = row * AROWB + chunk * 16;
            cp16(st + so, qph + gk);
            cp16(st + BC * AROWB + so, qpl + gk);
            cp16(st + 2 * BC * AROWB + so, qph + gv);
        }
        cp_commit();
    };

    float m0 = -1e30f, m1 = -1e30f, l0 = 0.f, l1 = 0.f;
    float acc_o[16][4];
#pragma unroll
    for (int nt = 0; nt < 16; nt++)
#pragma unroll
        for (int e = 0; e < 4; e++) acc_o[nt][e] = 0.f;

    const int aRow = warp * 16 + (lane & 15);
    const int aKof = (lane >> 4) * 8;
    const int bIdx = lane & 7;
    const int bSel = lane >> 3;
    const int bRowBase = (bSel >> 1) * 8 + bIdx;
    const int bKof = (bSel & 1) * 8;
    const int vRow = lane & 15;
    const int vCof = (lane >> 4) * 8;

    const int r0 = lane >> 2;
    const int cq = lane & 3;
    const int grow0 = mb * BR + warp * 16 + r0;
    const int grow1 = grow0 + 8;

    const int ntiles = 2 * mb + 2;
    issue_kv(0, 0);
    issue_kv(1, 1);

    for (int nb = 0; nb < ntiles; nb++) {
        if (nb + 1 < ntiles) {
            cp_wait<1>();       // Q and kv(nb) complete; kv(nb+1) may pend
        } else {
            cp_wait<0>();
        }
        __syncthreads();

        const uint32_t st = kvb + (nb & 1) * KVSTG;
        const uint32_t sKh = st;
        const uint32_t sKl = st + BC * AROWB;
        const uint32_t sVh = st + 2 * BC * AROWB;

        // ---- S = Qh * (Kh + Kl) ----
        float accs[8][4];
#pragma unroll
        for (int nt = 0; nt < 8; nt++)
#pragma unroll
            for (int e = 0; e < 4; e++) accs[nt][e] = 0.f;

#pragma unroll
        for (int ks = 0; ks < 8; ks++) {
            uint32_t aqh[4];
            const uint32_t aoff = (uint32_t)aRow * AROWB + (uint32_t)(ks * 16 + aKof) * 2;
            ldm4(aqh, sQh + aoff);
#pragma unroll
            for (int p = 0; p < 4; p++) {
                const uint32_t boff = (uint32_t)(bRowBase + p * 16) * AROWB +
                                      (uint32_t)(ks * 16 + bKof) * 2;
                uint32_t r4[4];
                ldm4(r4, sKh + boff);
                uint32_t bh0[2] = {r4[0], r4[1]};
                uint32_t bh1[2] = {r4[2], r4[3]};
                mma_f16(accs[2 * p], aqh, bh0);
                mma_f16(accs[2 * p + 1], aqh, bh1);
                ldm4(r4, sKl + boff);
                uint32_t bl0[2] = {r4[0], r4[1]};
                uint32_t bl1[2] = {r4[2], r4[3]};
                mma_f16(accs[2 * p], aqh, bl0);
                mma_f16(accs[2 * p + 1], aqh, bl1);
            }
        }

        // ---- scale + causal mask + online softmax ----
        float rmax0 = -1e30f, rmax1 = -1e30f;
#pragma unroll
        for (int nt = 0; nt < 8; nt++) {
            const int cbase = nb * BC + nt * 8 + cq * 2;
#pragma unroll
            for (int e = 0; e < 4; e++) {
                float s = accs[nt][e] * scale;
                const int col = cbase + (e & 1);
                const int row = (e < 2) ? grow0 : grow1;
                if (col > row) s = -1e30f;
                accs[nt][e] = s;
            }
            rmax0 = fmaxf(rmax0, fmaxf(accs[nt][0], accs[nt][1]));
            rmax1 = fmaxf(rmax1, fmaxf(accs[nt][2], accs[nt][3]));
        }
        rmax0 = fmaxf(rmax0, __shfl_xor_sync(0xffffffffu, rmax0, 1));
        rmax0 = fmaxf(rmax0, __shfl_xor_sync(0xffffffffu, rmax0, 2));
        rmax1 = fmaxf(rmax1, __shfl_xor_sync(0xffffffffu, rmax1, 1));
        rmax1 = fmaxf(rmax1, __shfl_xor_sync(0xffffffffu, rmax1, 2));
        const float mn0 = fmaxf(m0, rmax0), mn1 = fmaxf(m1, rmax1);
        const float cf0 = __expf(m0 - mn0), cf1 = __expf(m1 - mn1);
        m0 = mn0; m1 = mn1;
        float s0 = 0.f, s1 = 0.f;
#pragma unroll
        for (int nt = 0; nt < 8; nt++) {
            accs[nt][0] = __expf(accs[nt][0] - mn0);
            accs[nt][1] = __expf(accs[nt][1] - mn0);
            accs[nt][2] = __expf(accs[nt][2] - mn1);
            accs[nt][3] = __expf(accs[nt][3] - mn1);
            s0 += accs[nt][0] + accs[nt][1];
            s1 += accs[nt][2] + accs[nt][3];
        }
        s0 += __shfl_xor_sync(0xffffffffu, s0, 1);
        s0 += __shfl_xor_sync(0xffffffffu, s0, 2);
        s1 += __shfl_xor_sync(0xffffffffu, s1, 1);
        s1 += __shfl_xor_sync(0xffffffffu, s1, 2);
        l0 = l0 * cf0 + s0;
        l1 = l1 * cf1 + s1;
#pragma unroll
        for (int nt = 0; nt < 16; nt++) {
            acc_o[nt][0] *= cf0; acc_o[nt][1] *= cf0;
            acc_o[nt][2] *= cf1; acc_o[nt][3] *= cf1;
        }

        // ---- O += Ph * Vh (1-product) ----
#pragma unroll
        for (int kb = 0; kb < 4; kb++) {
            uint32_t ph[4];
            {
                const float* s0p = accs[2 * kb];
                const float* s1p = accs[2 * kb + 1];
                ph[0] = packh2(s0p[0], s0p[1]);
                ph[1] = packh2(s0p[2], s0p[3]);
                ph[2] = packh2(s1p[0], s1p[1]);
                ph[3] = packh2(s1p[2], s1p[3]);
            }
#pragma unroll
            for (int np = 0; np < 8; np++) {
                const uint32_t voff = (uint32_t)(kb * 16 + vRow) * AROWB +
                                      (uint32_t)(np * 16 + vCof) * 2;
                uint32_t rv[4];
                ldm4t(rv, sVh + voff);
                uint32_t vh0[2] = {rv[0], rv[1]};
                uint32_t vh1[2] = {rv[2], rv[3]};
                mma_f16(acc_o[2 * np], ph, vh0);
                mma_f16(acc_o[2 * np + 1], ph, vh1);
            }
        }
        __syncthreads();                  // buffer nb consumed by all warps
        if (nb + 2 < ntiles) issue_kv(nb + 2, nb & 1);
    }

    const float inv0 = 1.f / l0, inv1 = 1.f / l1;
#pragma unroll
    for (int nt = 0; nt < 16; nt++) {
        const size_t o0 = (size_t)grow0 * (NQ * HD) + qcol + nt * 8 + cq * 2;
        const size_t o1 = (size_t)grow1 * (NQ * HD) + qcol + nt * 8 + cq * 2;
        *(uint32_t*)&outh[o0] = packh2(acc_o[nt][0] * inv0, acc_o[nt][1] * inv0);
        *(uint32_t*)&outh[o1] = packh2(acc_o[nt][2] * inv1, acc_o[nt][3] * inv1);
    }
}

// ---------------------------------------------------------------------------
// Launch
// ---------------------------------------------------------------------------
extern "C" void kernel_launch(void* const* d_in, const int* in_sizes, int n_in,
                              void* d_out, int out_size)
{
    (void)in_sizes; (void)n_in;
    const float* hidden = (const float*)d_in[1];
    const float* w_qkv = (const float*)d_in[2];
    const float* w_o = (const float*)d_in[3];
    const float* w_gu = (const float*)d_in[4];
    const float* w_down = (const float*)d_in[5];
    const float* ln1 = (const float*)d_in[6];
    const float* ln2 = (const float*)d_in[7];

    float* out = (float*)d_out;
    const size_t SH = (size_t)S_LEN * H_DIM;
    float* out_resid = ((size_t)out_size >= 2 * SH) ? (out + SH) : nullptr;

    float *qkv, *resid;
    cudaGetSymbolAddress((void**)&qkv, g_qkv);
    cudaGetSymbolAddress((void**)&resid, g_resid);
    __half *qkvh, *qkvl;
    cudaGetSymbolAddress((void**)&qkvh, g_qkvh);
    cudaGetSymbolAddress((void**)&qkvl, g_qkvl);
    __half *wqkvh, *woh, *wguh, *wdh;
    __half *xbh, *abh, *hbh;
    cudaGetSymbolAddress((void**)&wqkvh, g_wqkvT_hi);
    cudaGetSymbolAddress((void**)&woh, g_woT_hi);
    cudaGetSymbolAddress((void**)&wguh, g_wguT_hi);
    cudaGetSymbolAddress((void**)&wdh, g_wdownT_hi);
    cudaGetSymbolAddress((void**)&xbh, g_xb_hi);
    cudaGetSymbolAddress((void**)&abh, g_ab_hi);
    cudaGetSymbolAddress((void**)&hbh, g_hb_hi);

    cudaFuncSetAttribute(attn_mma_kernel,
                         cudaFuncAttributeMaxDynamicSharedMemorySize, ATT_SMEM);
    const int SMEM1 = 3 * STG256;
    const int SMEMGU = 3 * 3 * TILE_B;
    cudaFuncSetAttribute(gemm_mma1_kernel,
                         cudaFuncAttributeMaxDynamicSharedMemorySize, SMEM1);
    cudaFuncSetAttribute(gemm_gu_kernel,
                         cudaFuncAttributeMaxDynamicSharedMemorySize, SMEMGU);

    // 0. Weight transpose (fp16 hi planes)
    wt_transpose_kernel<<<dim3(QKV_N / 32, H_DIM / 64), 256>>>(w_qkv, wqkvh, H_DIM, QKV_N);
    wt_transpose_kernel<<<dim3(H_DIM / 32, (NQ * HD) / 64), 256>>>(w_o, woh, NQ * HD, H_DIM);
    wt_transpose_kernel<<<dim3((2 * I_DIM) / 32, H_DIM / 64), 256>>>(w_gu, wguh, H_DIM, 2 * I_DIM);
    wt_transpose_kernel<<<dim3(H_DIM / 32, I_DIM / 64), 256>>>(w_down, wdh, I_DIM, H_DIM);

    // 1. RMSNorm 1 -> fp16 hi
    rmsnorm_h_kernel<<<S_LEN, 256>>>(hidden, ln1, xbh);

    // 2. QKV projection
    gemm_mma1_kernel<<<dim3(S_LEN / BM, QKV_N / 256), 256, SMEM1>>>(
        xbh, wqkvh, qkv, S_LEN, QKV_N, H_DIM, nullptr, nullptr);

    // 3. RoPE + split
    {
        const int total = S_LEN * 3072;
        rope_split_kernel<<<(total + 255) / 256, 256>>>(qkv, qkvh, qkvl);
    }

    // 4. Attention
    attn_mma_kernel<<<dim3(S_LEN / BR, NQ), 256, ATT_SMEM>>>(qkvh, qkvl, abh);

    // 5. O projection + residual
    gemm_mma1_kernel<<<dim3(S_LEN / BM, H_DIM / 256), 256, SMEM1>>>(
        abh, woh, resid, S_LEN, H_DIM, NQ * HD, hidden, out_resid);

    // 6. RMSNorm 2 -> fp16 hi
    rmsnorm_h_kernel<<<S_LEN, 256>>>(resid, ln2, xbh);

    // 7+8. Fused gate_up + SiLU
    gemm_gu_kernel<<<dim3(S_LEN / BM, I_DIM / 128), 256, SMEMGU>>>(
        xbh, wguh, hbh, S_LEN, H_DIM);

    // 9. down -> out
    gemm_mma1_kernel<<<dim3(S_LEN / BM, H_DIM / 256), 256, SMEM1>>>(
        hbh, wdh, out, S_LEN, H_DIM, I_DIM, nullptr, nullptr);
}

// round 16
// speedup vs baseline: 5.5327x; 1.0137x over previous
#include <cuda_runtime.h>
#include <cuda_fp16.h>
#include <math.h>
#include <stdint.h>

#define H_DIM 4096
#define S_LEN 2048
#define NQ 32
#define NKV 8
#define HD 128
#define I_DIM 14336
#define QKV_N ((NQ + 2 * NKV) * HD) /* 6144 */
#define EPS 1e-5f

// GEMM tiling
#define BM 128
#define KC 32
#define ROWB 80
#define TILE_B (128 * ROWB)
#define STG256 (384 * ROWB)

// Attention tiling
#define BR 128
#define BC 64
#define AROWB 272
#define KVSTG (2 * BC * AROWB)                       // Kh,Vh = 34816
#define ATT_SMEM (BR * AROWB + 2 * KVSTG)            // 104448

// ---------------------------------------------------------------------------
// Scratch (device globals)
// ---------------------------------------------------------------------------
__device__ float g_qkv[(size_t)S_LEN * QKV_N];
__device__ float g_resid[(size_t)S_LEN * H_DIM];

__device__ __half g_qkvh[(size_t)S_LEN * QKV_N];

__device__ __half g_wqkvT_hi[(size_t)QKV_N * H_DIM];
__device__ __half g_woT_hi[(size_t)H_DIM * (NQ * HD)];
__device__ __half g_wguT_hi[(size_t)(2 * I_DIM) * H_DIM];
__device__ __half g_wdownT_hi[(size_t)H_DIM * I_DIM];

__device__ __half g_xb_hi[(size_t)S_LEN * H_DIM];
__device__ __half g_ab_hi[(size_t)S_LEN * NQ * HD];
__device__ __half g_hb_hi[(size_t)S_LEN * I_DIM];

// ---------------------------------------------------------------------------
// PTX helpers
// ---------------------------------------------------------------------------
__device__ __forceinline__ uint32_t smem_u32(const void* p) {
    uint32_t a;
    asm("{ .reg .u64 t; cvta.to.shared.u64 t, %1; cvt.u32.u64 %0, t; }"
        : "=r"(a) : "l"(p));
    return a;
}
__device__ __forceinline__ void cp16(uint32_t saddr, const void* g) {
    asm volatile("cp.async.cg.shared.global [%0], [%1], 16;"
                 :: "r"(saddr), "l"(g) : "memory");
}
__device__ __forceinline__ void cp_commit() {
    asm volatile("cp.async.commit_group;" ::: "memory");
}
template <int N>
__device__ __forceinline__ void cp_wait() {
    asm volatile("cp.async.wait_group %0;" :: "n"(N) : "memory");
}
__device__ __forceinline__ void ldm4(uint32_t* r, uint32_t addr) {
    asm volatile("ldmatrix.sync.aligned.m8n8.x4.shared.b16 {%0,%1,%2,%3}, [%4];"
                 : "=r"(r[0]), "=r"(r[1]), "=r"(r[2]), "=r"(r[3]) : "r"(addr));
}
__device__ __forceinline__ void ldm4t(uint32_t* r, uint32_t addr) {
    asm volatile("ldmatrix.sync.aligned.m8n8.x4.trans.shared.b16 {%0,%1,%2,%3}, [%4];"
                 : "=r"(r[0]), "=r"(r[1]), "=r"(r[2]), "=r"(r[3]) : "r"(addr));
}
__device__ __forceinline__ void mma_f16(float* d, const uint32_t* a,
                                        const uint32_t* b) {
    asm volatile(
        "mma.sync.aligned.m16n8k16.row.col.f32.f16.f16.f32 "
        "{%0,%1,%2,%3}, {%4,%5,%6,%7}, {%8,%9}, {%0,%1,%2,%3};"
        : "+f"(d[0]), "+f"(d[1]), "+f"(d[2]), "+f"(d[3])
        : "r"(a[0]), "r"(a[1]), "r"(a[2]), "r"(a[3]), "r"(b[0]), "r"(b[1]));
}
__device__ __forceinline__ uint32_t packh2(float a, float b) {
    __half2 h = __floats2half2_rn(a, b);
    return *(uint32_t*)&h;
}
__device__ __forceinline__ float silu_mul(float g, float u) {
    return g / (1.f + __expf(-g)) * u;
}

// ---------------------------------------------------------------------------
// Weight transpose: W[K,N] fp32 -> Thi [N,K] fp16 (vectorized)
// ---------------------------------------------------------------------------
__global__ __launch_bounds__(256)
void wt_transpose_kernel(const float* __restrict__ W,
                         __half* __restrict__ Thi, int K, int N)
{
    __shared__ float t[32][65];
    const int tid = threadIdx.x;
    const int n = blockIdx.x * 32 + (tid & 31);
    const int kb = blockIdx.y * 64;
#pragma unroll
    for (int i = 0; i < 8; i++) {
        const int kl = (tid >> 5) + i * 8;
        t[tid & 31][kl] = W[(size_t)(kb + kl) * N + n];
    }
    __syncthreads();
    const int kq = (tid & 15) * 4;
#pragma unroll
    for (int j = 0; j < 2; j++) {
        const int nr = (tid >> 4) + j * 16;
        const int n2 = blockIdx.x * 32 + nr;
        uint2 o;
        o.x = packh2(t[nr][kq + 0], t[nr][kq + 1]);
        o.y = packh2(t[nr][kq + 2], t[nr][kq + 3]);
        *(uint2*)&Thi[(size_t)n2 * K + kb + kq] = o;
    }
}

// ---------------------------------------------------------------------------
// RMSNorm -> fp16 hi
// ---------------------------------------------------------------------------
__global__ __launch_bounds__(256)
void rmsnorm_h_kernel(const float* __restrict__ x, const float* __restrict__ w,
                      __half* __restrict__ ohi)
{
    const int row = blockIdx.x;
    const int t = threadIdx.x;
    const float4* xr = (const float4*)(x + (size_t)row * H_DIM);
    const float4* wr = (const float4*)w;

    float4 v[4];
    float ss = 0.f;
#pragma unroll
    for (int i = 0; i < 4; i++) {
        v[i] = xr[t + 256 * i];
        ss += v[i].x * v[i].x + v[i].y * v[i].y + v[i].z * v[i].z + v[i].w * v[i].w;
    }
#pragma unroll
    for (int o = 16; o; o >>= 1) ss += __shfl_xor_sync(0xffffffffu, ss, o);
    __shared__ float wsum[8];
    if ((t & 31) == 0) wsum[t >> 5] = ss;
    __syncthreads();
    float tot = wsum[0] + wsum[1] + wsum[2] + wsum[3] +
                wsum[4] + wsum[5] + wsum[6] + wsum[7];
    const float sc = rsqrtf(tot * (1.f / H_DIM) + EPS);

    uint2* hr = (uint2*)(ohi + (size_t)row * H_DIM);
#pragma unroll
    for (int i = 0; i < 4; i++) {
        float4 wv = wr[t + 256 * i];
        uint2 h;
        h.x = packh2(v[i].x * sc * wv.x, v[i].y * sc * wv.y);
        h.y = packh2(v[i].z * sc * wv.z, v[i].w * sc * wv.w);
        hr[t + 256 * i] = h;
    }
}

// ---------------------------------------------------------------------------
// mma.sync fp16 GEMM, 1-product, 128x256 tile, 3-stage single-sync pipeline.
// ---------------------------------------------------------------------------
__global__ __launch_bounds__(256, 1)
void gemm_mma1_kernel(const __half* __restrict__ Ahi,
                      const __half* __restrict__ Bhi,
                      float* __restrict__ C, int M, int N, int K,
                      const float* __restrict__ add, float* __restrict__ C2)
{
    extern __shared__ char smc[];
    const uint32_t sbase = smem_u32(smc);
    const int tid = threadIdx.x;
    const int lane = tid & 31;
    const int wm = (tid >> 5) & 1;
    const int wn = (tid >> 6);
    const int m0 = blockIdx.x * BM;
    const int n0 = blockIdx.y * 256;
    const int NCH = K / KC;

    float acc[4][8][4];
#pragma unroll
    for (int mt = 0; mt < 4; mt++)
#pragma unroll
        for (int nt = 0; nt < 8; nt++)
#pragma unroll
            for (int e = 0; e < 4; e++) acc[mt][nt][e] = 0.f;

    auto issue = [&](int kc, int buf) {
        const uint32_t st = sbase + buf * STG256;
        const int kb = kc * KC;
#pragma unroll
        for (int i = 0; i < 6; i++) {
            const int lin = tid + i * 256;
            const int r = lin >> 2;
            const int c = lin & 3;
            const __half* src = (r < 128)
                ? (Ahi + (size_t)(m0 + r) * K + kb + c * 8)
                : (Bhi + (size_t)(n0 + r - 128) * K + kb + c * 8);
            cp16(st + r * ROWB + c * 16, src);
        }
        cp_commit();
    };

    issue(0, 0);
    issue(1, 1);

    const int aRowL = (lane & 15);
    const int aKof = (lane >> 4) * 8;
    const int bIdx = lane & 7;
    const int bSel = lane >> 3;
    const int bKof = (bSel & 1) * 8;
    const uint32_t sBoff = 128 * ROWB;

    for (int kc = 0; kc < NCH; kc++) {
        if (kc + 1 < NCH) {
            cp_wait<1>();
        } else {
            cp_wait<0>();
        }
        __syncthreads();
        if (kc + 2 < NCH) issue(kc + 2, (kc + 2) % 3);

        const uint32_t st = sbase + (kc % 3) * STG256;
        const uint32_t sA = st;
        const uint32_t sB = st + sBoff;

#pragma unroll
        for (int ks = 0; ks < KC; ks += 16) {
            uint32_t ah[4][4];
#pragma unroll
            for (int mt = 0; mt < 4; mt++) {
                const uint32_t off =
                    (uint32_t)(wm * 64 + mt * 16 + aRowL) * ROWB +
                    (uint32_t)(ks + aKof) * 2;
                ldm4(ah[mt], sA + off);
            }
#pragma unroll
            for (int p = 0; p < 4; p++) {
                const uint32_t off =
                    (uint32_t)(wn * 64 + p * 16 + (bSel >> 1) * 8 + bIdx) * ROWB +
                    (uint32_t)(ks + bKof) * 2;
                uint32_t r4[4];
                ldm4(r4, sB + off);
                uint32_t b0[2] = {r4[0], r4[1]};
                uint32_t b1[2] = {r4[2], r4[3]};
#pragma unroll
                for (int mt = 0; mt < 4; mt++) {
                    mma_f16(acc[mt][2 * p], ah[mt], b0);
                    mma_f16(acc[mt][2 * p + 1], ah[mt], b1);
                }
            }
        }
    }

    const int erowL = lane >> 2;
    const int ecolL = (lane & 3) * 2;
#pragma unroll
    for (int mt = 0; mt < 4; mt++) {
#pragma unroll
        for (int nt = 0; nt < 8; nt++) {
            const int r0 = m0 + wm * 64 + mt * 16 + erowL;
            const int c = n0 + wn * 64 + nt * 8 + ecolL;
            const size_t off0 = (size_t)r0 * N + c;
            const size_t off1 = (size_t)(r0 + 8) * N + c;
            float2 v0 = make_float2(acc[mt][nt][0], acc[mt][nt][1]);
            float2 v1 = make_float2(acc[mt][nt][2], acc[mt][nt][3]);
            if (add) {
                float2 a0 = *(const float2*)(add + off0);
                float2 a1 = *(const float2*)(add + off1);
                v0.x += a0.x; v0.y += a0.y;
                v1.x += a1.x; v1.y += a1.y;
            }
            *(float2*)(C + off0) = v0;
            *(float2*)(C + off1) = v1;
            if (C2) {
                *(float2*)(C2 + off0) = v0;
                *(float2*)(C2 + off1) = v1;
            }
        }
    }
}

// ---------------------------------------------------------------------------
// Fused gate_up + SiLU GEMM (1-product, 3-stage single-sync) -> fp16 Hout
// ---------------------------------------------------------------------------
__global__ __launch_bounds__(256, 1)
void gemm_gu_kernel(const __half* __restrict__ Ahi,
                    const __half* __restrict__ Bhi,
                    __half* __restrict__ Hout, int M, int K)
{
    constexpr uint32_t STG = 3 * TILE_B;
    extern __shared__ char smc[];
    const uint32_t sbase = smem_u32(smc);
    const int tid = threadIdx.x;
    const int lane = tid & 31;
    const int wm = (tid >> 5) & 3;
    const int wn = tid >> 7;
    const int m0 = blockIdx.x * BM;
    const int n0 = blockIdx.y * 128;
    const int NCH = K / KC;

    const int q0r = tid >> 2, q0c = tid & 3;
    const int q1r = (tid + 256) >> 2, q1c = tid & 3;

    float acc_g[2][8][4], acc_u[2][8][4];
#pragma unroll
    for (int mt = 0; mt < 2; mt++)
#pragma unroll
        for (int nt = 0; nt < 8; nt++)
#pragma unroll
            for (int e = 0; e < 4; e++) { acc_g[mt][nt][e] = 0.f; acc_u[mt][nt][e] = 0.f; }

    auto issue = [&](int kc, int buf) {
        const uint32_t st = sbase + buf * STG;
        const int kb = kc * KC;
        const size_t gA0 = (size_t)(m0 + q0r) * K + kb + q0c * 8;
        const size_t gA1 = (size_t)(m0 + q1r) * K + kb + q1c * 8;
        const size_t gG0 = (size_t)(n0 + q0r) * K + kb + q0c * 8;
        const size_t gG1 = (size_t)(n0 + q1r) * K + kb + q1c * 8;
        const size_t gU0 = (size_t)(I_DIM + n0 + q0r) * K + kb + q0c * 8;
        const size_t gU1 = (size_t)(I_DIM + n0 + q1r) * K + kb + q1c * 8;
        const uint32_t s0 = st + q0r * ROWB + q0c * 16;
        const uint32_t s1 = st + q1r * ROWB + q1c * 16;
        cp16(s0, Ahi + gA0);
        cp16(s1, Ahi + gA1);
        cp16(s0 + TILE_B, Bhi + gG0);
        cp16(s1 + TILE_B, Bhi + gG1);
        cp16(s0 + 2 * TILE_B, Bhi + gU0);
        cp16(s1 + 2 * TILE_B, Bhi + gU1);
        cp_commit();
    };

    issue(0, 0);
    issue(1, 1);

    for (int kc = 0; kc < NCH; kc++) {
        if (kc + 1 < NCH) {
            cp_wait<1>();
        } else {
            cp_wait<0>();
        }
        __syncthreads();
        if (kc + 2 < NCH) issue(kc + 2, (kc + 2) % 3);

        const uint32_t st = sbase + (kc % 3) * STG;
        const uint32_t sAh = st;
        const uint32_t sBg = st + TILE_B;
        const uint32_t sBu = st + 2 * TILE_B;

        const int aRow = wm * 32 + (lane & 15);
        const int aKof = (lane >> 4) * 8;
        const int bIdx = lane & 7;
        const int bSel = lane >> 3;
        const int bRowBase = wn * 64 + ((bSel >> 1) * 8) + bIdx;
        const int bKof = (bSel & 1) * 8;

#pragma unroll
        for (int ks = 0; ks < KC; ks += 16) {
            uint32_t ah[2][4];
#pragma unroll
            for (int mt = 0; mt < 2; mt++) {
                const uint32_t off = (uint32_t)(aRow + mt * 16) * ROWB +
                                     (uint32_t)(ks + aKof) * 2;
                ldm4(ah[mt], sAh + off);
            }
            uint32_t bg[8][2], bu[8][2];
#pragma unroll
            for (int p = 0; p < 4; p++) {
                const uint32_t off = (uint32_t)(bRowBase + p * 16) * ROWB +
                                     (uint32_t)(ks + bKof) * 2;
                uint32_t r4[4];
                ldm4(r4, sBg + off);
                bg[2 * p][0] = r4[0]; bg[2 * p][1] = r4[1];
                bg[2 * p + 1][0] = r4[2]; bg[2 * p + 1][1] = r4[3];
                ldm4(r4, sBu + off);
                bu[2 * p][0] = r4[0]; bu[2 * p][1] = r4[1];
                bu[2 * p + 1][0] = r4[2]; bu[2 * p + 1][1] = r4[3];
            }
#pragma unroll
            for (int mt = 0; mt < 2; mt++)
#pragma unroll
                for (int nt = 0; nt < 8; nt++) {
                    mma_f16(acc_g[mt][nt], ah[mt], bg[nt]);
                    mma_f16(acc_u[mt][nt], ah[mt], bu[nt]);
                }
        }
    }

    const int erow = m0 + wm * 32 + (lane >> 2);
    const int ecol = n0 + wn * 64 + (lane & 3) * 2;
#pragma unroll
    for (int mt = 0; mt < 2; mt++) {
#pragma unroll
        for (int nt = 0; nt < 8; nt++) {
            const int r0 = erow + mt * 16;
            const int c = ecol + nt * 8;
            const float h00 = silu_mul(acc_g[mt][nt][0], acc_u[mt][nt][0]);
            const float h01 = silu_mul(acc_g[mt][nt][1], acc_u[mt][nt][1]);
            const float h10 = silu_mul(acc_g[mt][nt][2], acc_u[mt][nt][2]);
            const float h11 = silu_mul(acc_g[mt][nt][3], acc_u[mt][nt][3]);
            *(uint32_t*)&Hout[(size_t)r0 * I_DIM + c] = packh2(h00, h01);
            *(uint32_t*)&Hout[(size_t)(r0 + 8) * I_DIM + c] = packh2(h10, h11);
        }
    }
}

// ---------------------------------------------------------------------------
// RoPE + fp16 convert (hi plane only)
// ---------------------------------------------------------------------------
__global__ void rope_split_kernel(const float* __restrict__ qkv,
                                  __half* __restrict__ oh)
{
    const int idx = blockIdx.x * blockDim.x + threadIdx.x;
    const int total = S_LEN * 3072;
    if (idx >= total) return;
    const int slot = idx % 3072;
    const int s = idx / 3072;
    const size_t rb = (size_t)s * QKV_N;

    if (slot < 2560) {
        const int head = slot >> 6;
        const int d = slot & 63;
        const int col = head * HD + d;
        const float inv = exp2f((float)d * (-13.287712379549449f / 64.f));
        const float ang = (float)s * inv;
        float sn, c;
        sincosf(ang, &sn, &c);
        const float x1 = qkv[rb + col];
        const float x2 = qkv[rb + col + 64];
        oh[rb + col] = __float2half_rn(x1 * c - x2 * sn);
        oh[rb + col + 64] = __float2half_rn(x2 * c + x1 * sn);
    } else {
        const int c0 = 5120 + (slot - 2560) * 2;
        oh[rb + c0] = __float2half_rn(qkv[rb + c0]);
        oh[rb + c0 + 1] = __float2half_rn(qkv[rb + c0 + 1]);
    }
}

// ---------------------------------------------------------------------------
// Tensor-core flash attention: QK = Qh*Kh, PV = Ph*Vh (all hi-plane fp16).
// Double-buffered K/V, single-sync pipeline, reversed mb order.
// ---------------------------------------------------------------------------
__global__ __launch_bounds__(256, 1)
void attn_mma_kernel(const __half* __restrict__ qph,
                     __half* __restrict__ outh)
{
    extern __shared__ char smc[];
    const uint32_t sb = smem_u32(smc);
    const uint32_t sQh = sb;
    const uint32_t kvb = sb + BR * AROWB;

    const int tid = threadIdx.x;
    const int lane = tid & 31;
    const int warp = tid >> 5;
    const int mb = (int)gridDim.x - 1 - (int)blockIdx.x;
    const int head = blockIdx.y;
    const int kh = head >> 2;
    const float scale = 0.088388347648318447f;

    const int qcol = head * HD;
    const int kcol = NQ * HD + kh * HD;
    const int vcol = (NQ + NKV) * HD + kh * HD;

    // Q hi
    {
        const int chunk = tid & 15;
        const int rbase = tid >> 4;
#pragma unroll
        for (int i = 0; i < 8; i++) {
            const int row = rbase + i * 16;
            const size_t g = (size_t)(mb * BR + row) * QKV_N + qcol + chunk * 8;
            cp16(sQh + row * AROWB + chunk * 16, qph + g);
        }
    }
    cp_commit();

    auto issue_kv = [&](int nb, int buf) {
        const uint32_t st = kvb + buf * KVSTG;
        const int chunk = tid & 15;
        const int rbase = tid >> 4;
#pragma unroll
        for (int i = 0; i < 4; i++) {
            const int row = rbase + i * 16;
            const size_t gk = (size_t)(nb * BC + row) * QKV_N + kcol + chunk * 8;
            const size_t gv = (size_t)(nb * BC + row) * QKV_N + vcol + chunk * 8;
            const uint32_t so = row * AROWB + chunk * 16;
            cp16(st + so, qph + gk);                      // Kh
            cp16(st + BC * AROWB + so, qph + gv);         // Vh
        }
        cp_commit();
    };

    float m0 = -1e30f, m1 = -1e30f, l0 = 0.f, l1 = 0.f;
    float acc_o[16][4];
#pragma unroll
    for (int nt = 0; nt < 16; nt++)
#pragma unroll
        for (int e = 0; e < 4; e++) acc_o[nt][e] = 0.f;

    const int aRow = warp * 16 + (lane & 15);
    const int aKof = (lane >> 4) * 8;
    const int bIdx = lane & 7;
    const int bSel = lane >> 3;
    const int bRowBase = (bSel >> 1) * 8 + bIdx;
    const int bKof = (bSel & 1) * 8;
    const int vRow = lane & 15;
    const int vCof = (lane >> 4) * 8;

    const int r0 = lane >> 2;
    const int cq = lane & 3;
    const int grow0 = mb * BR + warp * 16 + r0;
    const int grow1 = grow0 + 8;

    const int ntiles = 2 * mb + 2;
    issue_kv(0, 0);
    issue_kv(1, 1);

    for (int nb = 0; nb < ntiles; nb++) {
        if (nb + 1 < ntiles) {
            cp_wait<1>();
        } else {
            cp_wait<0>();
        }
        __syncthreads();

        const uint32_t st = kvb + (nb & 1) * KVSTG;
        const uint32_t sKh = st;
        const uint32_t sVh = st + BC * AROWB;

        // ---- S = Qh * Kh ----
        float accs[8][4];
#pragma unroll
        for (int nt = 0; nt < 8; nt++)
#pragma unroll
            for (int e = 0; e < 4; e++) accs[nt][e] = 0.f;

#pragma unroll
        for (int ks = 0; ks < 8; ks++) {
            uint32_t aqh[4];
            const uint32_t aoff = (uint32_t)aRow * AROWB + (uint32_t)(ks * 16 + aKof) * 2;
            ldm4(aqh, sQh + aoff);
#pragma unroll
            for (int p = 0; p < 4; p++) {
                const uint32_t boff = (uint32_t)(bRowBase + p * 16) * AROWB +
                                      (uint32_t)(ks * 16 + bKof) * 2;
                uint32_t r4[4];
                ldm4(r4, sKh + boff);
                uint32_t bh0[2] = {r4[0], r4[1]};
                uint32_t bh1[2] = {r4[2], r4[3]};
                mma_f16(accs[2 * p], aqh, bh0);
                mma_f16(accs[2 * p + 1], aqh, bh1);
            }
        }

        // ---- scale + causal mask + online softmax ----
        float rmax0 = -1e30f, rmax1 = -1e30f;
#pragma unroll
        for (int nt = 0; nt < 8; nt++) {
            const int cbase = nb * BC + nt * 8 + cq * 2;
#pragma unroll
            for (int e = 0; e < 4; e++) {
                float s = accs[nt][e] * scale;
                const int col = cbase + (e & 1);
                const int row = (e < 2) ? grow0 : grow1;
                if (col > row) s = -1e30f;
                accs[nt][e] = s;
            }
            rmax0 = fmaxf(rmax0, fmaxf(accs[nt][0], accs[nt][1]));
            rmax1 = fmaxf(rmax1, fmaxf(accs[nt][2], accs[nt][3]));
        }
        rmax0 = fmaxf(rmax0, __shfl_xor_sync(0xffffffffu, rmax0, 1));
        rmax0 = fmaxf(rmax0, __shfl_xor_sync(0xffffffffu, rmax0, 2));
        rmax1 = fmaxf(rmax1, __shfl_xor_sync(0xffffffffu, rmax1, 1));
        rmax1 = fmaxf(rmax1, __shfl_xor_sync(0xffffffffu, rmax1, 2));
        const float mn0 = fmaxf(m0, rmax0), mn1 = fmaxf(m1, rmax1);
        const float cf0 = __expf(m0 - mn0), cf1 = __expf(m1 - mn1);
        m0 = mn0; m1 = mn1;
        float s0 = 0.f, s1 = 0.f;
#pragma unroll
        for (int nt = 0; nt < 8; nt++) {
            accs[nt][0] = __expf(accs[nt][0] - mn0);
            accs[nt][1] = __expf(accs[nt][1] - mn0);
            accs[nt][2] = __expf(accs[nt][2] - mn1);
            accs[nt][3] = __expf(accs[nt][3] - mn1);
            s0 += accs[nt][0] + accs[nt][1];
            s1 += accs[nt][2] + accs[nt][3];
        }
        s0 += __shfl_xor_sync(0xffffffffu, s0, 1);
        s0 += __shfl_xor_sync(0xffffffffu, s0, 2);
        s1 += __shfl_xor_sync(0xffffffffu, s1, 1);
        s1 += __shfl_xor_sync(0xffffffffu, s1, 2);
        l0 = l0 * cf0 + s0;
        l1 = l1 * cf1 + s1;
#pragma unroll
        for (int nt = 0; nt < 16; nt++) {
            acc_o[nt][0] *= cf0; acc_o[nt][1] *= cf0;
            acc_o[nt][2] *= cf1; acc_o[nt][3] *= cf1;
        }

        // ---- O += Ph * Vh ----
#pragma unroll
        for (int kb = 0; kb < 4; kb++) {
            uint32_t ph[4];
            {
                const float* s0p = accs[2 * kb];
                const float* s1p = accs[2 * kb + 1];
                ph[0] = packh2(s0p[0], s0p[1]);
                ph[1] = packh2(s0p[2], s0p[3]);
                ph[2] = packh2(s1p[0], s1p[1]);
                ph[3] = packh2(s1p[2], s1p[3]);
            }
#pragma unroll
            for (int np = 0; np < 8; np++) {
                const uint32_t voff = (uint32_t)(kb * 16 + vRow) * AROWB +
                                      (uint32_t)(np * 16 + vCof) * 2;
                uint32_t rv[4];
                ldm4t(rv, sVh + voff);
                uint32_t vh0[2] = {rv[0], rv[1]};
                uint32_t vh1[2] = {rv[2], rv[3]};
                mma_f16(acc_o[2 * np], ph, vh0);
                mma_f16(acc_o[2 * np + 1], ph, vh1);
            }
        }
        __syncthreads();
        if (nb + 2 < ntiles) issue_kv(nb + 2, nb & 1);
    }

    const float inv0 = 1.f / l0, inv1 = 1.f / l1;
#pragma unroll
    for (int nt = 0; nt < 16; nt++) {
        const size_t o0 = (size_t)grow0 * (NQ * HD) + qcol + nt * 8 + cq * 2;
        const size_t o1 = (size_t)grow1 * (NQ * HD) + qcol + nt * 8 + cq * 2;
        *(uint32_t*)&outh[o0] = packh2(acc_o[nt][0] * inv0, acc_o[nt][1] * inv0);
        *(uint32_t*)&outh[o1] = packh2(acc_o[nt][2] * inv1, acc_o[nt][3] * inv1);
    }
}

// ---------------------------------------------------------------------------
// Launch
// ---------------------------------------------------------------------------
extern "C" void kernel_launch(void* const* d_in, const int* in_sizes, int n_in,
                              void* d_out, int out_size)
{
    (void)in_sizes; (void)n_in;
    const float* hidden = (const float*)d_in[1];
    const float* w_qkv = (const float*)d_in[2];
    const float* w_o = (const float*)d_in[3];
    const float* w_gu = (const float*)d_in[4];
    const float* w_down = (const float*)d_in[5];
    const float* ln1 = (const float*)d_in[6];
    const float* ln2 = (const float*)d_in[7];

    float* out = (float*)d_out;
    const size_t SH = (size_t)S_LEN * H_DIM;
    float* out_resid = ((size_t)out_size >= 2 * SH) ? (out + SH) : nullptr;

    float *qkv, *resid;
    cudaGetSymbolAddress((void**)&qkv, g_qkv);
    cudaGetSymbolAddress((void**)&resid, g_resid);
    __half *qkvh;
    cudaGetSymbolAddress((void**)&qkvh, g_qkvh);
    __half *wqkvh, *woh, *wguh, *wdh;
    __half *xbh, *abh, *hbh;
    cudaGetSymbolAddress((void**)&wqkvh, g_wqkvT_hi);
    cudaGetSymbolAddress((void**)&woh, g_woT_hi);
    cudaGetSymbolAddress((void**)&wguh, g_wguT_hi);
    cudaGetSymbolAddress((void**)&wdh, g_wdownT_hi);
    cudaGetSymbolAddress((void**)&xbh, g_xb_hi);
    cudaGetSymbolAddress((void**)&abh, g_ab_hi);
    cudaGetSymbolAddress((void**)&hbh, g_hb_hi);

    cudaFuncSetAttribute(attn_mma_kernel,
                         cudaFuncAttributeMaxDynamicSharedMemorySize, ATT_SMEM);
    const int SMEM1 = 3 * STG256;
    const int SMEMGU = 3 * 3 * TILE_B;
    cudaFuncSetAttribute(gemm_mma1_kernel,
                         cudaFuncAttributeMaxDynamicSharedMemorySize, SMEM1);
    cudaFuncSetAttribute(gemm_gu_kernel,
                         cudaFuncAttributeMaxDynamicSharedMemorySize, SMEMGU);

    // 0. Weight transpose (fp16 hi planes)
    wt_transpose_kernel<<<dim3(QKV_N / 32, H_DIM / 64), 256>>>(w_qkv, wqkvh, H_DIM, QKV_N);
    wt_transpose_kernel<<<dim3(H_DIM / 32, (NQ * HD) / 64), 256>>>(w_o, woh, NQ * HD, H_DIM);
    wt_transpose_kernel<<<dim3((2 * I_DIM) / 32, H_DIM / 64), 256>>>(w_gu, wguh, H_DIM, 2 * I_DIM);
    wt_transpose_kernel<<<dim3(H_DIM / 32, I_DIM / 64), 256>>>(w_down, wdh, I_DIM, H_DIM);

    // 1. RMSNorm 1 -> fp16 hi
    rmsnorm_h_kernel<<<S_LEN, 256>>>(hidden, ln1, xbh);

    // 2. QKV projection
    gemm_mma1_kernel<<<dim3(S_LEN / BM, QKV_N / 256), 256, SMEM1>>>(
        xbh, wqkvh, qkv, S_LEN, QKV_N, H_DIM, nullptr, nullptr);

    // 3. RoPE + fp16 convert
    {
        const int total = S_LEN * 3072;
        rope_split_kernel<<<(total + 255) / 256, 256>>>(qkv, qkvh);
    }

    // 4. Attention (hi-plane only)
    attn_mma_kernel<<<dim3(S_LEN / BR, NQ), 256, ATT_SMEM>>>(qkvh, abh);

    // 5. O projection + residual
    gemm_mma1_kernel<<<dim3(S_LEN / BM, H_DIM / 256), 256, SMEM1>>>(
        abh, woh, resid, S_LEN, H_DIM, NQ * HD, hidden, out_resid);

    // 6. RMSNorm 2 -> fp16 hi
    rmsnorm_h_kernel<<<S_LEN, 256>>>(resid, ln2, xbh);

    // 7+8. Fused gate_up + SiLU
    gemm_gu_kernel<<<dim3(S_LEN / BM, I_DIM / 128), 256, SMEMGU>>>(
        xbh, wguh, hbh, S_LEN, H_DIM);

    // 9. down -> out
    gemm_mma1_kernel<<<dim3(S_LEN / BM, H_DIM / 256), 256, SMEM1>>>(
        hbh, wdh, out, S_LEN, H_DIM, I_DIM, nullptr, nullptr);
}

// round 17
// speedup vs baseline: 6.5272x; 1.1797x over previous
#include <cuda_runtime.h>
#include <cuda_fp16.h>
#include <math.h>
#include <stdint.h>

#define H_DIM 4096
#define S_LEN 2048
#define NQ 32
#define NKV 8
#define HD 128
#define I_DIM 14336
#define QKV_N ((NQ + 2 * NKV) * HD) /* 6144 */
#define EPS 1e-5f

// GEMM tiling (KC=64: 128B data + 16B pad per row)
#define BM 128
#define KC 64
#define ROWB 144
#define TILE_B (128 * ROWB)
#define STG256 (384 * ROWB)           // 55296

// Attention tiling
#define BR 128
#define BC 64
#define AROWB 272
#define KVSTG (2 * BC * AROWB)
#define ATT_SMEM (BR * AROWB + 2 * KVSTG)   // 104448

// ---------------------------------------------------------------------------
// Scratch (device globals)
// ---------------------------------------------------------------------------
__device__ float g_resid[(size_t)S_LEN * H_DIM];

__device__ __half g_qkvh[(size_t)S_LEN * QKV_N];

__device__ __half g_wqkvT_hi[(size_t)QKV_N * H_DIM];
__device__ __half g_woT_hi[(size_t)H_DIM * (NQ * HD)];
__device__ __half g_wguT_hi[(size_t)(2 * I_DIM) * H_DIM];
__device__ __half g_wdownT_hi[(size_t)H_DIM * I_DIM];

__device__ __half g_xb_hi[(size_t)S_LEN * H_DIM];
__device__ __half g_ab_hi[(size_t)S_LEN * NQ * HD];
__device__ __half g_hb_hi[(size_t)S_LEN * I_DIM];

// ---------------------------------------------------------------------------
// PTX helpers
// ---------------------------------------------------------------------------
__device__ __forceinline__ uint32_t smem_u32(const void* p) {
    uint32_t a;
    asm("{ .reg .u64 t; cvta.to.shared.u64 t, %1; cvt.u32.u64 %0, t; }"
        : "=r"(a) : "l"(p));
    return a;
}
__device__ __forceinline__ void cp16(uint32_t saddr, const void* g) {
    asm volatile("cp.async.cg.shared.global [%0], [%1], 16;"
                 :: "r"(saddr), "l"(g) : "memory");
}
__device__ __forceinline__ void cp_commit() {
    asm volatile("cp.async.commit_group;" ::: "memory");
}
template <int N>
__device__ __forceinline__ void cp_wait() {
    asm volatile("cp.async.wait_group %0;" :: "n"(N) : "memory");
}
__device__ __forceinline__ void ldm4(uint32_t* r, uint32_t addr) {
    asm volatile("ldmatrix.sync.aligned.m8n8.x4.shared.b16 {%0,%1,%2,%3}, [%4];"
                 : "=r"(r[0]), "=r"(r[1]), "=r"(r[2]), "=r"(r[3]) : "r"(addr));
}
__device__ __forceinline__ void ldm4t(uint32_t* r, uint32_t addr) {
    asm volatile("ldmatrix.sync.aligned.m8n8.x4.trans.shared.b16 {%0,%1,%2,%3}, [%4];"
                 : "=r"(r[0]), "=r"(r[1]), "=r"(r[2]), "=r"(r[3]) : "r"(addr));
}
__device__ __forceinline__ void mma_f16(float* d, const uint32_t* a,
                                        const uint32_t* b) {
    asm volatile(
        "mma.sync.aligned.m16n8k16.row.col.f32.f16.f16.f32 "
        "{%0,%1,%2,%3}, {%4,%5,%6,%7}, {%8,%9}, {%0,%1,%2,%3};"
        : "+f"(d[0]), "+f"(d[1]), "+f"(d[2]), "+f"(d[3])
        : "r"(a[0]), "r"(a[1]), "r"(a[2]), "r"(a[3]), "r"(b[0]), "r"(b[1]));
}
__device__ __forceinline__ uint32_t packh2(float a, float b) {
    __half2 h = __floats2half2_rn(a, b);
    return *(uint32_t*)&h;
}
__device__ __forceinline__ float silu_mul(float g, float u) {
    return g / (1.f + __expf(-g)) * u;
}

// ---------------------------------------------------------------------------
// Weight transpose: W[K,N] fp32 -> Thi [N,K] fp16 (vectorized)
// ---------------------------------------------------------------------------
__global__ __launch_bounds__(256)
void wt_transpose_kernel(const float* __restrict__ W,
                         __half* __restrict__ Thi, int K, int N)
{
    __shared__ float t[32][65];
    const int tid = threadIdx.x;
    const int n = blockIdx.x * 32 + (tid & 31);
    const int kb = blockIdx.y * 64;
#pragma unroll
    for (int i = 0; i < 8; i++) {
        const int kl = (tid >> 5) + i * 8;
        t[tid & 31][kl] = W[(size_t)(kb + kl) * N + n];
    }
    __syncthreads();
    const int kq = (tid & 15) * 4;
#pragma unroll
    for (int j = 0; j < 2; j++) {
        const int nr = (tid >> 4) + j * 16;
        const int n2 = blockIdx.x * 32 + nr;
        uint2 o;
        o.x = packh2(t[nr][kq + 0], t[nr][kq + 1]);
        o.y = packh2(t[nr][kq + 2], t[nr][kq + 3]);
        *(uint2*)&Thi[(size_t)n2 * K + kb + kq] = o;
    }
}

// ---------------------------------------------------------------------------
// RMSNorm -> fp16 hi
// ---------------------------------------------------------------------------
__global__ __launch_bounds__(256)
void rmsnorm_h_kernel(const float* __restrict__ x, const float* __restrict__ w,
                      __half* __restrict__ ohi)
{
    const int row = blockIdx.x;
    const int t = threadIdx.x;
    const float4* xr = (const float4*)(x + (size_t)row * H_DIM);
    const float4* wr = (const float4*)w;

    float4 v[4];
    float ss = 0.f;
#pragma unroll
    for (int i = 0; i < 4; i++) {
        v[i] = xr[t + 256 * i];
        ss += v[i].x * v[i].x + v[i].y * v[i].y + v[i].z * v[i].z + v[i].w * v[i].w;
    }
#pragma unroll
    for (int o = 16; o; o >>= 1) ss += __shfl_xor_sync(0xffffffffu, ss, o);
    __shared__ float wsum[8];
    if ((t & 31) == 0) wsum[t >> 5] = ss;
    __syncthreads();
    float tot = wsum[0] + wsum[1] + wsum[2] + wsum[3] +
                wsum[4] + wsum[5] + wsum[6] + wsum[7];
    const float sc = rsqrtf(tot * (1.f / H_DIM) + EPS);

    uint2* hr = (uint2*)(ohi + (size_t)row * H_DIM);
#pragma unroll
    for (int i = 0; i < 4; i++) {
        float4 wv = wr[t + 256 * i];
        uint2 h;
        h.x = packh2(v[i].x * sc * wv.x, v[i].y * sc * wv.y);
        h.y = packh2(v[i].z * sc * wv.z, v[i].w * sc * wv.w);
        hr[t + 256 * i] = h;
    }
}

// ---------------------------------------------------------------------------
// mma.sync fp16 GEMM, 1-product, 128x256 tile, KC=64, 3-stage single-sync.
// HOUT: write fp16 (qkv path) instead of fp32.
// ---------------------------------------------------------------------------
template <bool HOUT>
__global__ __launch_bounds__(256, 1)
void gemm_mma1_kernel(const __half* __restrict__ Ahi,
                      const __half* __restrict__ Bhi,
                      void* __restrict__ Cv, int M, int N, int K,
                      const float* __restrict__ add, float* __restrict__ C2)
{
    extern __shared__ char smc[];
    const uint32_t sbase = smem_u32(smc);
    const int tid = threadIdx.x;
    const int lane = tid & 31;
    const int wm = (tid >> 5) & 1;
    const int wn = (tid >> 6);
    const int m0 = blockIdx.x * BM;
    const int n0 = blockIdx.y * 256;
    const int NCH = K / KC;

    float acc[4][8][4];
#pragma unroll
    for (int mt = 0; mt < 4; mt++)
#pragma unroll
        for (int nt = 0; nt < 8; nt++)
#pragma unroll
            for (int e = 0; e < 4; e++) acc[mt][nt][e] = 0.f;

    auto issue = [&](int kc, int buf) {
        const uint32_t st = sbase + buf * STG256;
        const int kb = kc * KC;
#pragma unroll
        for (int i = 0; i < 12; i++) {
            const int lin = tid + i * 256;
            const int r = lin >> 3;        // 0..383
            const int c = lin & 7;         // 8 x 16B chunks per row
            const __half* src = (r < 128)
                ? (Ahi + (size_t)(m0 + r) * K + kb + c * 8)
                : (Bhi + (size_t)(n0 + r - 128) * K + kb + c * 8);
            cp16(st + r * ROWB + c * 16, src);
        }
        cp_commit();
    };

    issue(0, 0);
    issue(1, 1);

    const int aRowL = (lane & 15);
    const int aKof = (lane >> 4) * 8;
    const int bIdx = lane & 7;
    const int bSel = lane >> 3;
    const int bKof = (bSel & 1) * 8;
    const uint32_t sBoff = 128 * ROWB;

    for (int kc = 0; kc < NCH; kc++) {
        if (kc + 1 < NCH) {
            cp_wait<1>();
        } else {
            cp_wait<0>();
        }
        __syncthreads();
        if (kc + 2 < NCH) issue(kc + 2, (kc + 2) % 3);

        const uint32_t st = sbase + (kc % 3) * STG256;
        const uint32_t sA = st;
        const uint32_t sB = st + sBoff;

#pragma unroll
        for (int ks = 0; ks < KC; ks += 16) {
            uint32_t ah[4][4];
#pragma unroll
            for (int mt = 0; mt < 4; mt++) {
                const uint32_t off =
                    (uint32_t)(wm * 64 + mt * 16 + aRowL) * ROWB +
                    (uint32_t)(ks + aKof) * 2;
                ldm4(ah[mt], sA + off);
            }
#pragma unroll
            for (int p = 0; p < 4; p++) {
                const uint32_t off =
                    (uint32_t)(wn * 64 + p * 16 + (bSel >> 1) * 8 + bIdx) * ROWB +
                    (uint32_t)(ks + bKof) * 2;
                uint32_t r4[4];
                ldm4(r4, sB + off);
                uint32_t b0[2] = {r4[0], r4[1]};
                uint32_t b1[2] = {r4[2], r4[3]};
#pragma unroll
                for (int mt = 0; mt < 4; mt++) {
                    mma_f16(acc[mt][2 * p], ah[mt], b0);
                    mma_f16(acc[mt][2 * p + 1], ah[mt], b1);
                }
            }
        }
    }

    const int erowL = lane >> 2;
    const int ecolL = (lane & 3) * 2;
#pragma unroll
    for (int mt = 0; mt < 4; mt++) {
#pragma unroll
        for (int nt = 0; nt < 8; nt++) {
            const int r0 = m0 + wm * 64 + mt * 16 + erowL;
            const int c = n0 + wn * 64 + nt * 8 + ecolL;
            const size_t off0 = (size_t)r0 * N + c;
            const size_t off1 = (size_t)(r0 + 8) * N + c;
            if (HOUT) {
                __half* Ch = (__half*)Cv;
                *(uint32_t*)&Ch[off0] = packh2(acc[mt][nt][0], acc[mt][nt][1]);
                *(uint32_t*)&Ch[off1] = packh2(acc[mt][nt][2], acc[mt][nt][3]);
            } else {
                float* C = (float*)Cv;
                float2 v0 = make_float2(acc[mt][nt][0], acc[mt][nt][1]);
                float2 v1 = make_float2(acc[mt][nt][2], acc[mt][nt][3]);
                if (add) {
                    float2 a0 = *(const float2*)(add + off0);
                    float2 a1 = *(const float2*)(add + off1);
                    v0.x += a0.x; v0.y += a0.y;
                    v1.x += a1.x; v1.y += a1.y;
                }
                *(float2*)(C + off0) = v0;
                *(float2*)(C + off1) = v1;
                if (C2) {
                    *(float2*)(C2 + off0) = v0;
                    *(float2*)(C2 + off1) = v1;
                }
            }
        }
    }
}

// ---------------------------------------------------------------------------
// Fused gate_up + SiLU GEMM (1-product, KC=64, 3-stage single-sync)
// ---------------------------------------------------------------------------
__global__ __launch_bounds__(256, 1)
void gemm_gu_kernel(const __half* __restrict__ Ahi,
                    const __half* __restrict__ Bhi,
                    __half* __restrict__ Hout, int M, int K)
{
    constexpr uint32_t STG = 3 * TILE_B;
    extern __shared__ char smc[];
    const uint32_t sbase = smem_u32(smc);
    const int tid = threadIdx.x;
    const int lane = tid & 31;
    const int wm = (tid >> 5) & 3;
    const int wn = tid >> 7;
    const int m0 = blockIdx.x * BM;
    const int n0 = blockIdx.y * 128;
    const int NCH = K / KC;

    float acc_g[2][8][4], acc_u[2][8][4];
#pragma unroll
    for (int mt = 0; mt < 2; mt++)
#pragma unroll
        for (int nt = 0; nt < 8; nt++)
#pragma unroll
            for (int e = 0; e < 4; e++) { acc_g[mt][nt][e] = 0.f; acc_u[mt][nt][e] = 0.f; }

    auto issue = [&](int kc, int buf) {
        const uint32_t st = sbase + buf * STG;
        const int kb = kc * KC;
#pragma unroll
        for (int j = 0; j < 4; j++) {
            const int lin = tid + j * 256;
            const int r = lin >> 3;        // 0..127
            const int c = lin & 7;
            const uint32_t so = r * ROWB + c * 16;
            cp16(st + so, Ahi + (size_t)(m0 + r) * K + kb + c * 8);
            cp16(st + TILE_B + so, Bhi + (size_t)(n0 + r) * K + kb + c * 8);
            cp16(st + 2 * TILE_B + so,
                 Bhi + (size_t)(I_DIM + n0 + r) * K + kb + c * 8);
        }
        cp_commit();
    };

    issue(0, 0);
    issue(1, 1);

    for (int kc = 0; kc < NCH; kc++) {
        if (kc + 1 < NCH) {
            cp_wait<1>();
        } else {
            cp_wait<0>();
        }
        __syncthreads();
        if (kc + 2 < NCH) issue(kc + 2, (kc + 2) % 3);

        const uint32_t st = sbase + (kc % 3) * STG;
        const uint32_t sAh = st;
        const uint32_t sBg = st + TILE_B;
        const uint32_t sBu = st + 2 * TILE_B;

        const int aRow = wm * 32 + (lane & 15);
        const int aKof = (lane >> 4) * 8;
        const int bIdx = lane & 7;
        const int bSel = lane >> 3;
        const int bRowBase = wn * 64 + ((bSel >> 1) * 8) + bIdx;
        const int bKof = (bSel & 1) * 8;

#pragma unroll
        for (int ks = 0; ks < KC; ks += 16) {
            uint32_t ah[2][4];
#pragma unroll
            for (int mt = 0; mt < 2; mt++) {
                const uint32_t off = (uint32_t)(aRow + mt * 16) * ROWB +
                                     (uint32_t)(ks + aKof) * 2;
                ldm4(ah[mt], sAh + off);
            }
#pragma unroll
            for (int p = 0; p < 4; p++) {
                const uint32_t off = (uint32_t)(bRowBase + p * 16) * ROWB +
                                     (uint32_t)(ks + bKof) * 2;
                uint32_t r4[4];
                ldm4(r4, sBg + off);
                uint32_t g0[2] = {r4[0], r4[1]};
                uint32_t g1[2] = {r4[2], r4[3]};
#pragma unroll
                for (int mt = 0; mt < 2; mt++) {
                    mma_f16(acc_g[mt][2 * p], ah[mt], g0);
                    mma_f16(acc_g[mt][2 * p + 1], ah[mt], g1);
                }
                ldm4(r4, sBu + off);
                uint32_t u0[2] = {r4[0], r4[1]};
                uint32_t u1[2] = {r4[2], r4[3]};
#pragma unroll
                for (int mt = 0; mt < 2; mt++) {
                    mma_f16(acc_u[mt][2 * p], ah[mt], u0);
                    mma_f16(acc_u[mt][2 * p + 1], ah[mt], u1);
                }
            }
        }
    }

    const int erow = m0 + wm * 32 + (lane >> 2);
    const int ecol = n0 + wn * 64 + (lane & 3) * 2;
#pragma unroll
    for (int mt = 0; mt < 2; mt++) {
#pragma unroll
        for (int nt = 0; nt < 8; nt++) {
            const int r0 = erow + mt * 16;
            const int c = ecol + nt * 8;
            const float h00 = silu_mul(acc_g[mt][nt][0], acc_u[mt][nt][0]);
            const float h01 = silu_mul(acc_g[mt][nt][1], acc_u[mt][nt][1]);
            const float h10 = silu_mul(acc_g[mt][nt][2], acc_u[mt][nt][2]);
            const float h11 = silu_mul(acc_g[mt][nt][3], acc_u[mt][nt][3]);
            *(uint32_t*)&Hout[(size_t)r0 * I_DIM + c] = packh2(h00, h01);
            *(uint32_t*)&Hout[(size_t)(r0 + 8) * I_DIM + c] = packh2(h10, h11);
        }
    }
}

// ---------------------------------------------------------------------------
// RoPE in-place on fp16 q,k heads (v untouched)
// ---------------------------------------------------------------------------
__global__ void rope_h_kernel(__half* __restrict__ qk)
{
    const int idx = blockIdx.x * blockDim.x + threadIdx.x;
    const int total = S_LEN * 2560;         // 40 heads x 64 dims
    if (idx >= total) return;
    const int slot = idx % 2560;
    const int s = idx / 2560;
    const int head = slot >> 6;
    const int d = slot & 63;
    const size_t base = (size_t)s * QKV_N + head * HD + d;

    const float inv = exp2f((float)d * (-13.287712379549449f / 64.f));
    const float ang = (float)s * inv;
    float sn, c;
    sincosf(ang, &sn, &c);
    const float x1 = __half2float(qk[base]);
    const float x2 = __half2float(qk[base + 64]);
    qk[base] = __float2half_rn(x1 * c - x2 * sn);
    qk[base + 64] = __float2half_rn(x2 * c + x1 * sn);
}

// ---------------------------------------------------------------------------
// Tensor-core flash attention: QK = Qh*Kh, PV = Ph*Vh.
// Double-buffered K/V, reversed mb order.
// ---------------------------------------------------------------------------
__global__ __launch_bounds__(256, 1)
void attn_mma_kernel(const __half* __restrict__ qph,
                     __half* __restrict__ outh)
{
    extern __shared__ char smc[];
    const uint32_t sb = smem_u32(smc);
    const uint32_t sQh = sb;
    const uint32_t kvb = sb + BR * AROWB;

    const int tid = threadIdx.x;
    const int lane = tid & 31;
    const int warp = tid >> 5;
    const int mb = (int)gridDim.x - 1 - (int)blockIdx.x;
    const int head = blockIdx.y;
    const int kh = head >> 2;
    const float scale = 0.088388347648318447f;

    const int qcol = head * HD;
    const int kcol = NQ * HD + kh * HD;
    const int vcol = (NQ + NKV) * HD + kh * HD;

    {
        const int chunk = tid & 15;
        const int rbase = tid >> 4;
#pragma unroll
        for (int i = 0; i < 8; i++) {
            const int row = rbase + i * 16;
            const size_t g = (size_t)(mb * BR + row) * QKV_N + qcol + chunk * 8;
            cp16(sQh + row * AROWB + chunk * 16, qph + g);
        }
    }
    cp_commit();

    auto issue_kv = [&](int nb, int buf) {
        const uint32_t st = kvb + buf * KVSTG;
        const int chunk = tid & 15;
        const int rbase = tid >> 4;
#pragma unroll
        for (int i = 0; i < 4; i++) {
            const int row = rbase + i * 16;
            const size_t gk = (size_t)(nb * BC + row) * QKV_N + kcol + chunk * 8;
            const size_t gv = (size_t)(nb * BC + row) * QKV_N + vcol + chunk * 8;
            const uint32_t so = row * AROWB + chunk * 16;
            cp16(st + so, qph + gk);
            cp16(st + BC * AROWB + so, qph + gv);
        }
        cp_commit();
    };

    float m0 = -1e30f, m1 = -1e30f, l0 = 0.f, l1 = 0.f;
    float acc_o[16][4];
#pragma unroll
    for (int nt = 0; nt < 16; nt++)
#pragma unroll
        for (int e = 0; e < 4; e++) acc_o[nt][e] = 0.f;

    const int aRow = warp * 16 + (lane & 15);
    const int aKof = (lane >> 4) * 8;
    const int bIdx = lane & 7;
    const int bSel = lane >> 3;
    const int bRowBase = (bSel >> 1) * 8 + bIdx;
    const int bKof = (bSel & 1) * 8;
    const int vRow = lane & 15;
    const int vCof = (lane >> 4) * 8;

    const int r0 = lane >> 2;
    const int cq = lane & 3;
    const int grow0 = mb * BR + warp * 16 + r0;
    const int grow1 = grow0 + 8;

    const int ntiles = 2 * mb + 2;
    issue_kv(0, 0);
    issue_kv(1, 1);

    for (int nb = 0; nb < ntiles; nb++) {
        if (nb + 1 < ntiles) {
            cp_wait<1>();
        } else {
            cp_wait<0>();
        }
        __syncthreads();

        const uint32_t st = kvb + (nb & 1) * KVSTG;
        const uint32_t sKh = st;
        const uint32_t sVh = st + BC * AROWB;

        float accs[8][4];
#pragma unroll
        for (int nt = 0; nt < 8; nt++)
#pragma unroll
            for (int e = 0; e < 4; e++) accs[nt][e] = 0.f;

#pragma unroll
        for (int ks = 0; ks < 8; ks++) {
            uint32_t aqh[4];
            const uint32_t aoff = (uint32_t)aRow * AROWB + (uint32_t)(ks * 16 + aKof) * 2;
            ldm4(aqh, sQh + aoff);
#pragma unroll
            for (int p = 0; p < 4; p++) {
                const uint32_t boff = (uint32_t)(bRowBase + p * 16) * AROWB +
                                      (uint32_t)(ks * 16 + bKof) * 2;
                uint32_t r4[4];
                ldm4(r4, sKh + boff);
                uint32_t bh0[2] = {r4[0], r4[1]};
                uint32_t bh1[2] = {r4[2], r4[3]};
                mma_f16(accs[2 * p], aqh, bh0);
                mma_f16(accs[2 * p + 1], aqh, bh1);
            }
        }

        float rmax0 = -1e30f, rmax1 = -1e30f;
#pragma unroll
        for (int nt = 0; nt < 8; nt++) {
            const int cbase = nb * BC + nt * 8 + cq * 2;
#pragma unroll
            for (int e = 0; e < 4; e++) {
                float s = accs[nt][e] * scale;
                const int col = cbase + (e & 1);
                const int row = (e < 2) ? grow0 : grow1;
                if (col > row) s = -1e30f;
                accs[nt][e] = s;
            }
            rmax0 = fmaxf(rmax0, fmaxf(accs[nt][0], accs[nt][1]));
            rmax1 = fmaxf(rmax1, fmaxf(accs[nt][2], accs[nt][3]));
        }
        rmax0 = fmaxf(rmax0, __shfl_xor_sync(0xffffffffu, rmax0, 1));
        rmax0 = fmaxf(rmax0, __shfl_xor_sync(0xffffffffu, rmax0, 2));
        rmax1 = fmaxf(rmax1, __shfl_xor_sync(0xffffffffu, rmax1, 1));
        rmax1 = fmaxf(rmax1, __shfl_xor_sync(0xffffffffu, rmax1, 2));
        const float mn0 = fmaxf(m0, rmax0), mn1 = fmaxf(m1, rmax1);
        const float cf0 = __expf(m0 - mn0), cf1 = __expf(m1 - mn1);
        m0 = mn0; m1 = mn1;
        float s0 = 0.f, s1 = 0.f;
#pragma unroll
        for (int nt = 0; nt < 8; nt++) {
            accs[nt][0] = __expf(accs[nt][0] - mn0);
            accs[nt][1] = __expf(accs[nt][1] - mn0);
            accs[nt][2] = __expf(accs[nt][2] - mn1);
            accs[nt][3] = __expf(accs[nt][3] - mn1);
            s0 += accs[nt][0] + accs[nt][1];
            s1 += accs[nt][2] + accs[nt][3];
        }
        s0 += __shfl_xor_sync(0xffffffffu, s0, 1);
        s0 += __shfl_xor_sync(0xffffffffu, s0, 2);
        s1 += __shfl_xor_sync(0xffffffffu, s1, 1);
        s1 += __shfl_xor_sync(0xffffffffu, s1, 2);
        l0 = l0 * cf0 + s0;
        l1 = l1 * cf1 + s1;
#pragma unroll
        for (int nt = 0; nt < 16; nt++) {
            acc_o[nt][0] *= cf0; acc_o[nt][1] *= cf0;
            acc_o[nt][2] *= cf1; acc_o[nt][3] *= cf1;
        }

#pragma unroll
        for (int kb = 0; kb < 4; kb++) {
            uint32_t ph[4];
            {
                const float* s0p = accs[2 * kb];
                const float* s1p = accs[2 * kb + 1];
                ph[0] = packh2(s0p[0], s0p[1]);
                ph[1] = packh2(s0p[2], s0p[3]);
                ph[2] = packh2(s1p[0], s1p[1]);
                ph[3] = packh2(s1p[2], s1p[3]);
            }
#pragma unroll
            for (int np = 0; np < 8; np++) {
                const uint32_t voff = (uint32_t)(kb * 16 + vRow) * AROWB +
                                      (uint32_t)(np * 16 + vCof) * 2;
                uint32_t rv[4];
                ldm4t(rv, sVh + voff);
                uint32_t vh0[2] = {rv[0], rv[1]};
                uint32_t vh1[2] = {rv[2], rv[3]};
                mma_f16(acc_o[2 * np], ph, vh0);
                mma_f16(acc_o[2 * np + 1], ph, vh1);
            }
        }
        __syncthreads();
        if (nb + 2 < ntiles) issue_kv(nb + 2, nb & 1);
    }

    const float inv0 = 1.f / l0, inv1 = 1.f / l1;
#pragma unroll
    for (int nt = 0; nt < 16; nt++) {
        const size_t o0 = (size_t)grow0 * (NQ * HD) + qcol + nt * 8 + cq * 2;
        const size_t o1 = (size_t)grow1 * (NQ * HD) + qcol + nt * 8 + cq * 2;
        *(uint32_t*)&outh[o0] = packh2(acc_o[nt][0] * inv0, acc_o[nt][1] * inv0);
        *(uint32_t*)&outh[o1] = packh2(acc_o[nt][2] * inv1, acc_o[nt][3] * inv1);
    }
}

// ---------------------------------------------------------------------------
// Launch
// ---------------------------------------------------------------------------
extern "C" void kernel_launch(void* const* d_in, const int* in_sizes, int n_in,
                              void* d_out, int out_size)
{
    (void)in_sizes; (void)n_in;
    const float* hidden = (const float*)d_in[1];
    const float* w_qkv = (const float*)d_in[2];
    const float* w_o = (const float*)d_in[3];
    const float* w_gu = (const float*)d_in[4];
    const float* w_down = (const float*)d_in[5];
    const float* ln1 = (const float*)d_in[6];
    const float* ln2 = (const float*)d_in[7];

    float* out = (float*)d_out;
    const size_t SH = (size_t)S_LEN * H_DIM;
    float* out_resid = ((size_t)out_size >= 2 * SH) ? (out + SH) : nullptr;

    float* resid;
    cudaGetSymbolAddress((void**)&resid, g_resid);
    __half *qkvh;
    cudaGetSymbolAddress((void**)&qkvh, g_qkvh);
    __half *wqkvh, *woh, *wguh, *wdh;
    __half *xbh, *abh, *hbh;
    cudaGetSymbolAddress((void**)&wqkvh, g_wqkvT_hi);
    cudaGetSymbolAddress((void**)&woh, g_woT_hi);
    cudaGetSymbolAddress((void**)&wguh, g_wguT_hi);
    cudaGetSymbolAddress((void**)&wdh, g_wdownT_hi);
    cudaGetSymbolAddress((void**)&xbh, g_xb_hi);
    cudaGetSymbolAddress((void**)&abh, g_ab_hi);
    cudaGetSymbolAddress((void**)&hbh, g_hb_hi);

    cudaFuncSetAttribute(attn_mma_kernel,
                         cudaFuncAttributeMaxDynamicSharedMemorySize, ATT_SMEM);
    const int SMEM1 = 3 * STG256;        // 165888
    const int SMEMGU = 3 * 3 * TILE_B;   // 165888
    cudaFuncSetAttribute(gemm_mma1_kernel<false>,
                         cudaFuncAttributeMaxDynamicSharedMemorySize, SMEM1);
    cudaFuncSetAttribute(gemm_mma1_kernel<true>,
                         cudaFuncAttributeMaxDynamicSharedMemorySize, SMEM1);
    cudaFuncSetAttribute(gemm_gu_kernel,
                         cudaFuncAttributeMaxDynamicSharedMemorySize, SMEMGU);

    // 0. Weight transpose (fp16 hi planes)
    wt_transpose_kernel<<<dim3(QKV_N / 32, H_DIM / 64), 256>>>(w_qkv, wqkvh, H_DIM, QKV_N);
    wt_transpose_kernel<<<dim3(H_DIM / 32, (NQ * HD) / 64), 256>>>(w_o, woh, NQ * HD, H_DIM);
    wt_transpose_kernel<<<dim3((2 * I_DIM) / 32, H_DIM / 64), 256>>>(w_gu, wguh, H_DIM, 2 * I_DIM);
    wt_transpose_kernel<<<dim3(H_DIM / 32, I_DIM / 64), 256>>>(w_down, wdh, I_DIM, H_DIM);

    // 1. RMSNorm 1 -> fp16 hi
    rmsnorm_h_kernel<<<S_LEN, 256>>>(hidden, ln1, xbh);

    // 2. QKV projection -> fp16 directly
    gemm_mma1_kernel<true><<<dim3(S_LEN / BM, QKV_N / 256), 256, SMEM1>>>(
        xbh, wqkvh, qkvh, S_LEN, QKV_N, H_DIM, nullptr, nullptr);

    // 3. RoPE in place on fp16 q,k
    {
        const int total = S_LEN * 2560;
        rope_h_kernel<<<(total + 255) / 256, 256>>>(qkvh);
    }

    // 4. Attention
    attn_mma_kernel<<<dim3(S_LEN / BR, NQ), 256, ATT_SMEM>>>(qkvh, abh);

    // 5. O projection + residual
    gemm_mma1_kernel<false><<<dim3(S_LEN / BM, H_DIM / 256), 256, SMEM1>>>(
        abh, woh, resid, S_LEN, H_DIM, NQ * HD, hidden, out_resid);

    // 6. RMSNorm 2 -> fp16 hi
    rmsnorm_h_kernel<<<S_LEN, 256>>>(resid, ln2, xbh);

    // 7+8. Fused gate_up + SiLU
    gemm_gu_kernel<<<dim3(S_LEN / BM, I_DIM / 128), 256, SMEMGU>>>(
        xbh, wguh, hbh, S_LEN, H_DIM);

    // 9. down -> out
    gemm_mma1_kernel<false><<<dim3(S_LEN / BM, H_DIM / 256), 256, SMEM1>>>(
        hbh, wdh, out, S_LEN, H_DIM, I_DIM, nullptr, nullptr);
}